// round 8
// baseline (speedup 1.0000x reference)
#include <cuda_runtime.h>
#include <math.h>

#define Bn 4
#define Sn 1024
#define Dn 1024
#define Hn 16
#define HDn 64
#define Cn 64
#define NCn 16
#define DFFn 256
#define EPSc 1e-6f
#define BSD (Bn*Sn*Dn)

typedef unsigned long long u64;
__device__ __forceinline__ u64 f2pack(float lo, float hi) {
    u64 r; asm("mov.b64 %0, {%1, %2};" : "=l"(r) : "f"(lo), "f"(hi)); return r;
}
__device__ __forceinline__ void f2unpack(u64 p, float& lo, float& hi) {
    asm("mov.b64 {%0, %1}, %2;" : "=f"(lo), "=f"(hi) : "l"(p));
}
__device__ __forceinline__ u64 ffma2(u64 a, u64 b, u64 c) {
    u64 d; asm("fma.rn.f32x2 %0, %1, %2, %3;" : "=l"(d) : "l"(a), "l"(b), "l"(c)); return d;
}
__device__ __forceinline__ void f4tou2(float4 f, u64& p0, u64& p1) {
    p0 = f2pack(f.x, f.y); p1 = f2pack(f.z, f.w);
}
__device__ __forceinline__ unsigned f2tf32(float f) {
    unsigned r; asm("cvt.rna.tf32.f32 %0, %1;" : "=r"(r) : "f"(f)); return r;
}
__device__ __forceinline__ void mma_tf32(float* c, const unsigned* a, const unsigned* b) {
    asm volatile("mma.sync.aligned.m16n8k8.row.col.f32.tf32.tf32.f32 "
        "{%0,%1,%2,%3}, {%4,%5,%6,%7}, {%8,%9}, {%0,%1,%2,%3};"
        : "+f"(c[0]), "+f"(c[1]), "+f"(c[2]), "+f"(c[3])
        : "r"(a[0]), "r"(a[1]), "r"(a[2]), "r"(a[3]), "r"(b[0]), "r"(b[1]));
}

__device__ float g_h [BSD];
__device__ float g_q [BSD];
__device__ float g_k [BSD];
__device__ float g_v [BSD];
__device__ float g_o [BSD];
__device__ float g_x1[BSD];
__device__ float g_lr[Bn*Hn*Sn];
__device__ float g_W1s [Bn*Hn*16384];
__device__ float g_W2s [Bn*Hn*16384];
__device__ float g_W2Ts[Bn*Hn*16384];
__device__ float g_X2  [Bn*Hn*16384];
__device__ float g_gZ1 [Bn*Hn*16384];
__device__ float g_X2b [Bn*Hn*16384];

__device__ __forceinline__ float warpsum(float v) {
#pragma unroll
    for (int o = 16; o > 0; o >>= 1) v += __shfl_xor_sync(0xffffffffu, v, o);
    return v;
}
__device__ __forceinline__ float hsum16(float v) {
#pragma unroll
    for (int o = 8; o > 0; o >>= 1) v += __shfl_xor_sync(0xffffffffu, v, o);
    return v;
}
__device__ __forceinline__ float hmax16(float v) {
#pragma unroll
    for (int o = 8; o > 0; o >>= 1) v = fmaxf(v, __shfl_xor_sync(0xffffffffu, v, o));
    return v;
}
__device__ __forceinline__ float blocksum256(float v) {
    __shared__ float red[8];
    int lane = threadIdx.x & 31, w = threadIdx.x >> 5;
    v = warpsum(v);
    if (lane == 0) red[w] = v;
    __syncthreads();
    float r = (lane < 8) ? red[lane] : 0.f;
    r = warpsum(r);
    __syncthreads();
    return r;
}
__device__ __forceinline__ float tanh_fast(float x) {
    float e = __expf(2.f * x);
    return 1.f - __fdividef(2.f, e + 1.f);
}

// ---------------- LayerNorm rows of 1024 ----------------
__global__ __launch_bounds__(256) void ln_kernel(
    const float* __restrict__ x, const float* __restrict__ g,
    const float* __restrict__ b, float* __restrict__ y)
{
    int row = blockIdx.x, tid = threadIdx.x;
    const float* xr = x + (size_t)row * Dn;
    float v[4]; float s = 0.f;
#pragma unroll
    for (int i = 0; i < 4; i++) { v[i] = xr[tid + 256 * i]; s += v[i]; }
    s = blocksum256(s);
    float mu = s * (1.f / Dn), ss = 0.f;
#pragma unroll
    for (int i = 0; i < 4; i++) { float d = v[i] - mu; ss += d * d; }
    ss = blocksum256(ss);
    float rstd = rsqrtf(ss * (1.f / Dn) + EPSc);
    float* yr = y + (size_t)row * Dn;
#pragma unroll
    for (int i = 0; i < 4; i++) {
        int c = tid + 256 * i;
        yr[c] = (v[i] - mu) * rstd * g[c] + b[c];
    }
}

// ---------------- tf32 tensor-core GEMM ----------------
#define GSTR 136
__device__ __forceinline__ void gemm_core(
    const float* __restrict__ A, const float* __restrict__ B, float* __restrict__ C,
    const float* __restrict__ bias, const float* __restrict__ res,
    const float* __restrict__ gate, int bm, int bn)
{
    const int N = 1024, K = 1024, BK = 16;
    __shared__ unsigned As[BK][GSTR];
    __shared__ unsigned Bs[BK][GSTR];
    int t = threadIdx.x;
    int warp = t >> 5, lane = t & 31;
    int wm = warp >> 1, wn = warp & 1;
    int g = lane >> 2, tg = lane & 3;

    float acc[2][8][4];
#pragma unroll
    for (int mt = 0; mt < 2; mt++)
#pragma unroll
        for (int nt = 0; nt < 8; nt++)
#pragma unroll
            for (int r = 0; r < 4; r++) acc[mt][nt][r] = 0.f;

    int r128 = t >> 1, kc = (t & 1) * 8;
    const float* Ab = A + (size_t)(bm + r128) * K + kc;
    const float* Bb = B + (size_t)(bn + r128) * K + kc;
    float4 a0 = *(const float4*)(Ab);
    float4 a1 = *(const float4*)(Ab + 4);
    float4 b0 = *(const float4*)(Bb);
    float4 b1 = *(const float4*)(Bb + 4);

    for (int k0 = 0; k0 < K; k0 += BK) {
        As[kc+0][r128]=f2tf32(a0.x); As[kc+1][r128]=f2tf32(a0.y);
        As[kc+2][r128]=f2tf32(a0.z); As[kc+3][r128]=f2tf32(a0.w);
        As[kc+4][r128]=f2tf32(a1.x); As[kc+5][r128]=f2tf32(a1.y);
        As[kc+6][r128]=f2tf32(a1.z); As[kc+7][r128]=f2tf32(a1.w);
        Bs[kc+0][r128]=f2tf32(b0.x); Bs[kc+1][r128]=f2tf32(b0.y);
        Bs[kc+2][r128]=f2tf32(b0.z); Bs[kc+3][r128]=f2tf32(b0.w);
        Bs[kc+4][r128]=f2tf32(b1.x); Bs[kc+5][r128]=f2tf32(b1.y);
        Bs[kc+6][r128]=f2tf32(b1.z); Bs[kc+7][r128]=f2tf32(b1.w);
        __syncthreads();
        if (k0 + BK < K) {
            a0 = *(const float4*)(Ab + k0 + BK);
            a1 = *(const float4*)(Ab + k0 + BK + 4);
            b0 = *(const float4*)(Bb + k0 + BK);
            b1 = *(const float4*)(Bb + k0 + BK + 4);
        }
#pragma unroll
        for (int ks = 0; ks < 2; ks++) {
            int kb = ks * 8;
            unsigned af[2][4], bf[8][2];
#pragma unroll
            for (int mt = 0; mt < 2; mt++) {
                int mb = wm * 32 + mt * 16 + g;
                af[mt][0] = As[kb+tg  ][mb];
                af[mt][1] = As[kb+tg  ][mb+8];
                af[mt][2] = As[kb+tg+4][mb];
                af[mt][3] = As[kb+tg+4][mb+8];
            }
#pragma unroll
            for (int nt = 0; nt < 8; nt++) {
                int nb = wn * 64 + nt * 8 + g;
                bf[nt][0] = Bs[kb+tg  ][nb];
                bf[nt][1] = Bs[kb+tg+4][nb];
            }
#pragma unroll
            for (int mt = 0; mt < 2; mt++)
#pragma unroll
                for (int nt = 0; nt < 8; nt++)
                    mma_tf32(acc[mt][nt], af[mt], bf[nt]);
        }
        __syncthreads();
    }

    float bs2[8][2], gv2[8][2];
#pragma unroll
    for (int nt = 0; nt < 8; nt++) {
        int col = bn + wn * 64 + nt * 8 + tg * 2;
        if (bias) { bs2[nt][0] = bias[col]; bs2[nt][1] = bias[col+1]; }
        else      { bs2[nt][0] = 0.f;       bs2[nt][1] = 0.f; }
        if (gate) { gv2[nt][0] = tanhf(gate[col]); gv2[nt][1] = tanhf(gate[col+1]); }
    }
#pragma unroll
    for (int mt = 0; mt < 2; mt++) {
        int row0 = bm + wm * 32 + mt * 16 + g;
#pragma unroll
        for (int nt = 0; nt < 8; nt++) {
            int col = bn + wn * 64 + nt * 8 + tg * 2;
            float v0 = acc[mt][nt][0] + bs2[nt][0];
            float v1 = acc[mt][nt][1] + bs2[nt][1];
            float v2 = acc[mt][nt][2] + bs2[nt][0];
            float v3 = acc[mt][nt][3] + bs2[nt][1];
            if (gate) {
                float2 r0 = *(const float2*)(res + (size_t)row0 * N + col);
                float2 r1 = *(const float2*)(res + (size_t)(row0+8) * N + col);
                v0 = r0.x + gv2[nt][0] * v0; v1 = r0.y + gv2[nt][1] * v1;
                v2 = r1.x + gv2[nt][0] * v2; v3 = r1.y + gv2[nt][1] * v3;
            } else if (res) {
                float2 r0 = *(const float2*)(res + (size_t)row0 * N + col);
                float2 r1 = *(const float2*)(res + (size_t)(row0+8) * N + col);
                v0 += r0.x; v1 += r0.y; v2 += r1.x; v3 += r1.y;
            }
            *(float2*)(C + (size_t)row0 * N + col)     = make_float2(v0, v1);
            *(float2*)(C + (size_t)(row0+8) * N + col) = make_float2(v2, v3);
        }
    }
}

__global__ __launch_bounds__(256, 2) void gemm_nt_kernel(
    const float* __restrict__ A, const float* __restrict__ B, float* __restrict__ C,
    const float* __restrict__ bias, const float* __restrict__ res,
    const float* __restrict__ gate)
{
    gemm_core(A, B, C, bias, res, gate, blockIdx.y * 128, blockIdx.x * 128);
}

__global__ __launch_bounds__(256, 2) void gemm3_nt_kernel(
    const float* __restrict__ A,
    const float* __restrict__ B0, const float* __restrict__ B1, const float* __restrict__ B2,
    float* __restrict__ C0, float* __restrict__ C1, float* __restrict__ C2,
    const float* __restrict__ b0, const float* __restrict__ b1, const float* __restrict__ b2)
{
    const float* B; float* C; const float* bias;
    if (blockIdx.z == 0)      { B = B0; C = C0; bias = b0; }
    else if (blockIdx.z == 1) { B = B1; C = C1; bias = b1; }
    else                      { B = B2; C = C2; bias = b2; }
    gemm_core(A, B, C, bias, nullptr, nullptr, blockIdx.y * 128, blockIdx.x * 128);
}

// ---------------- Flash attention (FFMA2) ----------------
#define AQ 68
#define AK 68
#define AP 65
#define ATT_SMEM ((64*AQ + 64*AK + 64*64 + 64*AP) * 4)

__global__ __launch_bounds__(256) void attn_flash_kernel(
    const float* __restrict__ q, const float* __restrict__ k,
    const float* __restrict__ v, float* __restrict__ o)
{
    extern __shared__ float sm[];
    float* Qs = sm;
    float* Ks = Qs + 64 * AQ;
    float* Vs = Ks + 64 * AK;
    float* Ps = Vs + 64 * 64;

    int qt = blockIdx.x, bh = blockIdx.y;
    int b = bh >> 4, h = bh & 15;
    int tid = threadIdx.x, tx = tid & 15, ty = tid >> 4;
    size_t base = ((size_t)b * Sn) * Dn + h * HDn;

    for (int idx = tid; idx < 4096; idx += 256) {
        int r = idx >> 6, e = idx & 63;
        Qs[r * AQ + e] = q[base + (size_t)(qt * 64 + r) * Dn + e] * 0.125f;
    }
    float m[4], l[4];
    u64 oa2[4][2];
#pragma unroll
    for (int u = 0; u < 4; u++) {
        m[u] = -1e30f; l[u] = 0.f;
        oa2[u][0] = 0ULL; oa2[u][1] = 0ULL;
    }
    __syncthreads();

    for (int kt = 0; kt <= qt; kt++) {
        for (int idx = tid; idx < 4096; idx += 256) {
            int r = idx >> 6, e = idx & 63;
            size_t g = base + (size_t)(kt * 64 + r) * Dn + e;
            Ks[r * AK + e] = k[g];
            Vs[r * 64 + e] = v[g];
        }
        __syncthreads();

        u64 s2[4][4];
#pragma unroll
        for (int u = 0; u < 4; u++)
#pragma unroll
            for (int vv = 0; vv < 4; vv++) s2[u][vv] = 0ULL;
#pragma unroll 2
        for (int e0 = 0; e0 < 64; e0 += 4) {
            u64 qa2[4][2], ka2[4][2];
#pragma unroll
            for (int u = 0; u < 4; u++) {
                float4 f = *(const float4*)(Qs + (ty*4+u)*AQ + e0);
                f4tou2(f, qa2[u][0], qa2[u][1]);
            }
#pragma unroll
            for (int vv = 0; vv < 4; vv++) {
                float4 f = *(const float4*)(Ks + (tx*4+vv)*AK + e0);
                f4tou2(f, ka2[vv][0], ka2[vv][1]);
            }
#pragma unroll
            for (int u = 0; u < 4; u++)
#pragma unroll
                for (int vv = 0; vv < 4; vv++) {
                    s2[u][vv] = ffma2(qa2[u][0], ka2[vv][0], s2[u][vv]);
                    s2[u][vv] = ffma2(qa2[u][1], ka2[vv][1], s2[u][vv]);
                }
        }
        float acc[4][4];
#pragma unroll
        for (int u = 0; u < 4; u++)
#pragma unroll
            for (int vv = 0; vv < 4; vv++) {
                float lo, hi; f2unpack(s2[u][vv], lo, hi);
                acc[u][vv] = lo + hi;
            }
        bool diag = (kt == qt);
#pragma unroll
        for (int u = 0; u < 4; u++) {
            int r = ty * 4 + u;
            float mx = -1e30f;
#pragma unroll
            for (int vv = 0; vv < 4; vv++) {
                int c = tx * 4 + vv;
                if (diag && c > r) acc[u][vv] = -1e30f;
                mx = fmaxf(mx, acc[u][vv]);
            }
            mx = hmax16(mx);
            float nm = fmaxf(m[u], mx);
            float corr = __expf(m[u] - nm);
            float ps = 0.f;
#pragma unroll
            for (int vv = 0; vv < 4; vv++) {
                float p = __expf(acc[u][vv] - nm);
                Ps[r * AP + tx * 4 + vv] = p;
                ps += p;
            }
            ps = hsum16(ps);
            l[u] = l[u] * corr + ps;
            m[u] = nm;
            u64 c2 = f2pack(corr, corr);
            u64 z = 0ULL;
            oa2[u][0] = ffma2(oa2[u][0], c2, z);
            oa2[u][1] = ffma2(oa2[u][1], c2, z);
        }
        __syncthreads();
#pragma unroll 4
        for (int kc = 0; kc < 64; kc++) {
            float4 v4 = *(const float4*)(Vs + kc * 64 + tx * 4);
            u64 v2[2];
            f4tou2(v4, v2[0], v2[1]);
#pragma unroll
            for (int u = 0; u < 4; u++) {
                float p = Ps[(ty * 4 + u) * AP + kc];
                u64 p2 = f2pack(p, p);
                oa2[u][0] = ffma2(p2, v2[0], oa2[u][0]);
                oa2[u][1] = ffma2(p2, v2[1], oa2[u][1]);
            }
        }
        __syncthreads();
    }
#pragma unroll
    for (int u = 0; u < 4; u++) {
        float inv = __fdividef(1.f, l[u]);
        float o0, o1, o2, o3;
        f2unpack(oa2[u][0], o0, o1);
        f2unpack(oa2[u][1], o2, o3);
        size_t g = base + (size_t)(qt * 64 + ty * 4 + u) * Dn + tx * 4;
        *(float4*)(o + g) = make_float4(o0*inv, o1*inv, o2*inv, o3*inv);
    }
}

// ---------------- prep & lr ----------------
__global__ __launch_bounds__(256) void prep_kernel(
    float* __restrict__ XQ, float* __restrict__ XK, float* __restrict__ XV,
    const float* __restrict__ nw, const float* __restrict__ nb)
{
    int w = (blockIdx.x * blockDim.x + threadIdx.x) >> 5;
    if (w >= Bn * Sn * Hn) return;
    int lane = threadIdx.x & 31;
    int h = w & 15, bs = w >> 4;
    size_t base = (size_t)bs * Dn + h * HDn;
    float q0 = XQ[base + lane], q1 = XQ[base + lane + 32];
    float qi = 1.f / fmaxf(sqrtf(warpsum(q0*q0 + q1*q1)), 1e-12f);
    XQ[base + lane] = q0 * qi; XQ[base + lane + 32] = q1 * qi;
    float k0 = XK[base + lane], k1 = XK[base + lane + 32];
    float ki = 1.f / fmaxf(sqrtf(warpsum(k0*k0 + k1*k1)), 1e-12f);
    k0 *= ki; k1 *= ki;
    XK[base + lane] = k0; XK[base + lane + 32] = k1;
    float v0 = XV[base + lane], v1 = XV[base + lane + 32];
    float mu = warpsum(v0 + v1) * (1.f / 64.f);
    float d0 = v0 - mu, d1 = v1 - mu;
    float var = warpsum(d0*d0 + d1*d1) * (1.f / 64.f);
    float rstd = rsqrtf(var + EPSc);
    XV[base + lane]      = nw[h*64+lane]    * d0 * rstd + nb[h*64+lane]    + k0;
    XV[base + lane + 32] = nw[h*64+lane+32] * d1 * rstd + nb[h*64+lane+32] + k1;
}

__global__ __launch_bounds__(256) void lr_kernel(
    const float* __restrict__ x1, const float* __restrict__ lrw,
    const float* __restrict__ lrb, float* __restrict__ lro)
{
    int w = (blockIdx.x * blockDim.x + threadIdx.x) >> 5;
    if (w >= Bn * Sn * Hn) return;
    int lane = threadIdx.x & 31;
    int h = w & 15, bs = w >> 4;
    int b = bs >> 10, s = bs & (Sn - 1);
    const float* xr = x1 + (size_t)bs * Dn;
    const float* wr = lrw + h * Dn;
    float acc = 0.f;
    for (int c = lane; c < Dn; c += 32) acc += xr[c] * wr[c];
    acc = warpsum(acc);
    if (lane == 0)
        lro[(size_t)(b * Hn + h) * Sn + s] = 1.f / (1.f + __expf(-(acc + lrb[h])));
}

// ---------------- TTT scan, 1024 threads ----------------
#define TP 65
#define PS 68
#define SCAN_SMEM ((3*64*TP + 2*64*PS + 256 + 64 + 64) * 4)

__global__ __launch_bounds__(1024) void ttt_scan_kernel(
    const float* __restrict__ XQ, const float* __restrict__ XK, const float* __restrict__ XV,
    const float* __restrict__ lr,
    const float* __restrict__ W1i, const float* __restrict__ b1i,
    const float* __restrict__ W2i, const float* __restrict__ b2i,
    const float* __restrict__ nw,  const float* __restrict__ nb,
    float* __restrict__ W1G, float* __restrict__ W2G, float* __restrict__ W2TG,
    float* __restrict__ X2G, float* __restrict__ gZ1G, float* __restrict__ X2bG,
    float* __restrict__ outp)
{
    extern __shared__ float sm[];
    float* sxq  = sm;
    float* sxk  = sxq + 64 * TP;
    float* sxv  = sxk + 64 * TP;
    float* ssc  = sxv + 64 * TP;
    float* sgZ2 = ssc + 64 * PS;
    float* b1sm = sgZ2 + 64 * PS;
    float* b2sm = b1sm + 256;
    float* seta = b2sm + 64;

    int bh = blockIdx.x, b = bh >> 4, h = bh & 15;
    int tid = threadIdx.x, w = tid >> 5, l = tid & 31;   // 32 warps
    int ty2 = tid >> 4, tx2 = tid & 15;                  // 64 x 16
    int ft = tid >> 3, jt = tid & 7;                     // 128 x 8
    float* W1r  = W1G  + (size_t)bh * 16384;
    float* W2r  = W2G  + (size_t)bh * 16384;
    float* W2Tr = W2TG + (size_t)bh * 16384;
    float* X2r  = X2G  + (size_t)bh * 16384;
    float* gZ1r = gZ1G + (size_t)bh * 16384;
    float* X2br = X2bG + (size_t)bh * 16384;
    const float* nwh = nw + h * 64;
    const float* nbh = nb + h * 64;

    for (int idx = tid; idx < 16384; idx += 1024) {
        W1r[idx] = W1i[(size_t)h * 16384 + idx];
        W2r[idx] = W2i[(size_t)h * 16384 + idx];
        int e = idx >> 8, f = idx & 255;
        W2Tr[idx] = W2i[(size_t)h * 16384 + f * 64 + e];
    }
    if (tid < 256) b1sm[tid] = b1i[h * 256 + tid];
    if (tid < 64)  b2sm[tid] = b2i[h * 64 + tid];
    __syncthreads();

    for (int n = 0; n < NCn; n++) {
        size_t tokbase = (size_t)b * Sn + n * Cn;
        for (int idx = tid; idx < 4096; idx += 1024) {
            int i = idx >> 6, e = idx & 63;
            size_t g = (tokbase + i) * Dn + h * 64 + e;
            sxq[i * TP + e] = XQ[g];
            sxk[i * TP + e] = XK[g];
            sxv[i * TP + e] = XV[g];
        }
        if (tid < 64) seta[tid] = lr[(size_t)bh * Sn + n * 64 + tid] * (1.f / 64.f);
        __syncthreads();

        // A: Z1 = xk@W1 + b1 -> X2, gZ1=gelu'  (rows w*2+u, cols l*8)
        {
            u64 acc2[2][4];
            {
                float4 bb0 = *(const float4*)(b1sm + l * 8);
                float4 bb1 = *(const float4*)(b1sm + l * 8 + 4);
                u64 p0, p1, p2, p3;
                f4tou2(bb0, p0, p1); f4tou2(bb1, p2, p3);
#pragma unroll
                for (int u = 0; u < 2; u++) {
                    acc2[u][0] = p0; acc2[u][1] = p1; acc2[u][2] = p2; acc2[u][3] = p3;
                }
            }
#pragma unroll 4
            for (int e = 0; e < 64; e++) {
                float4 w0 = *(const float4*)(W1r + e * 256 + l * 8);
                float4 w1 = *(const float4*)(W1r + e * 256 + l * 8 + 4);
                u64 w2[4];
                f4tou2(w0, w2[0], w2[1]); f4tou2(w1, w2[2], w2[3]);
#pragma unroll
                for (int u = 0; u < 2; u++) {
                    float a = sxk[(w * 2 + u) * TP + e];
                    u64 a2 = f2pack(a, a);
#pragma unroll
                    for (int p = 0; p < 4; p++) acc2[u][p] = ffma2(a2, w2[p], acc2[u][p]);
                }
            }
#pragma unroll
            for (int u = 0; u < 2; u++) {
                int row = w * 2 + u;
                float zz[8], x2v[8], gbv[8];
#pragma unroll
                for (int p = 0; p < 4; p++) f2unpack(acc2[u][p], zz[2*p], zz[2*p+1]);
#pragma unroll
                for (int v = 0; v < 8; v++) {
                    float z = zz[v];
                    float t = tanh_fast(0.79788456f * (z + 0.044715f * z * z * z));
                    x2v[v] = 0.5f * z * (1.f + t);
                    gbv[v] = 0.5f * z * (1.f - t * t) * (0.79788456f + 0.1070322243f * z * z)
                           + 0.5f * (1.f + t);
                }
                float4* xp = (float4*)(X2r + row * 256 + l * 8);
                xp[0] = make_float4(x2v[0],x2v[1],x2v[2],x2v[3]);
                xp[1] = make_float4(x2v[4],x2v[5],x2v[6],x2v[7]);
                float4* gp = (float4*)(gZ1r + row * 256 + l * 8);
                gp[0] = make_float4(gbv[0],gbv[1],gbv[2],gbv[3]);
                gp[1] = make_float4(gbv[4],gbv[5],gbv[6],gbv[7]);
            }
        }
        __syncthreads();

        // B: Z2 = X2@W2 + b2 -> ssc  (row ty2, cols tx2*4)
        {
            float acc[4];
#pragma unroll
            for (int v = 0; v < 4; v++) acc[v] = b2sm[tx2 * 4 + v];
#pragma unroll 4
            for (int f0 = 0; f0 < 256; f0 += 4) {
                float4 a4 = *(const float4*)(X2r + ty2*256 + f0);
                float4 b4[4];
#pragma unroll
                for (int d = 0; d < 4; d++) b4[d] = *(const float4*)(W2r + (f0+d)*64 + tx2*4);
                acc[0] += a4.x*b4[0].x + a4.y*b4[1].x + a4.z*b4[2].x + a4.w*b4[3].x;
                acc[1] += a4.x*b4[0].y + a4.y*b4[1].y + a4.z*b4[2].y + a4.w*b4[3].y;
                acc[2] += a4.x*b4[0].z + a4.y*b4[1].z + a4.z*b4[2].z + a4.w*b4[3].z;
                acc[3] += a4.x*b4[0].w + a4.y*b4[1].w + a4.z*b4[2].w + a4.w*b4[3].w;
            }
#pragma unroll
            for (int v = 0; v < 4; v++) ssc[ty2*PS + tx2*4+v] = acc[v];
        }
        __syncthreads();

        // C: gZ2 = ln_l2_bwd(Z2, xv-xk)
        for (int i = w; i < 64; i += 32) {
            float z0 = ssc[i*PS + l], z1 = ssc[i*PS + l + 32];
            float mu = warpsum(z0 + z1) * (1.f/64.f);
            float d0 = z0 - mu, d1 = z1 - mu;
            float var = warpsum(d0*d0 + d1*d1) * (1.f/64.f);
            float rstd = rsqrtf(var + EPSc);
            float xh0 = d0 * rstd, xh1 = d1 * rstd;
            float g0 = nwh[l], g1 = nwh[l+32];
            float t0 = sxv[i*TP + l] - sxk[i*TP + l];
            float t1 = sxv[i*TP + l + 32] - sxk[i*TP + l + 32];
            float gh0 = (g0*xh0 + nbh[l]    - t0) * g0;
            float gh1 = (g1*xh1 + nbh[l+32] - t1) * g1;
            float sgh = warpsum(gh0 + gh1);
            float sgx = warpsum(gh0*xh0 + gh1*xh1);
            float cc = rstd * (1.f/64.f);
            sgZ2[i*PS + l]      = (64.f*gh0 - sgh - xh0*sgx) * cc;
            sgZ2[i*PS + l + 32] = (64.f*gh1 - sgh - xh1*sgx) * cc;
        }
        __syncthreads();

        // D: gZ1 = (gZ2 @ W2^T) * gb
        {
            u64 acc2[2][4];
#pragma unroll
            for (int u = 0; u < 2; u++)
#pragma unroll
                for (int p = 0; p < 4; p++) acc2[u][p] = 0ULL;
#pragma unroll 4
            for (int e = 0; e < 64; e++) {
                float4 w0 = *(const float4*)(W2Tr + e*256 + l*8);
                float4 w1 = *(const float4*)(W2Tr + e*256 + l*8 + 4);
                u64 w2[4];
                f4tou2(w0, w2[0], w2[1]); f4tou2(w1, w2[2], w2[3]);
#pragma unroll
                for (int u = 0; u < 2; u++) {
                    float a = sgZ2[(w*2+u)*PS + e];
                    u64 a2 = f2pack(a, a);
#pragma unroll
                    for (int p = 0; p < 4; p++) acc2[u][p] = ffma2(a2, w2[p], acc2[u][p]);
                }
            }
#pragma unroll
            for (int u = 0; u < 2; u++) {
                int row = w * 2 + u;
                float av[8];
#pragma unroll
                for (int p = 0; p < 4; p++) f2unpack(acc2[u][p], av[2*p], av[2*p+1]);
                float4* gp = (float4*)(gZ1r + row * 256 + l * 8);
                float4 g0 = gp[0], g1 = gp[1];
                gp[0] = make_float4(av[0]*g0.x, av[1]*g0.y, av[2]*g0.z, av[3]*g0.w);
                gp[1] = make_float4(av[4]*g1.x, av[5]*g1.y, av[6]*g1.z, av[7]*g1.w);
            }
        }
        __syncthreads();

        // E: coef1 = eta[k]*(tril(xq@xk^T)+1) -> ssc  (row ty2, cols tx2*4)
        {
            float acc[4] = {0.f, 0.f, 0.f, 0.f};
            if (tx2 * 4 <= ty2) {
#pragma unroll 4
                for (int e = 0; e < 64; e++) {
                    float a = sxq[ty2*TP + e];
#pragma unroll
                    for (int v = 0; v < 4; v++) acc[v] += a * sxk[(tx2*4+v)*TP + e];
                }
            }
#pragma unroll
            for (int v = 0; v < 4; v++) {
                int kk = tx2 * 4 + v;
                ssc[ty2*PS + kk] = (kk <= ty2) ? seta[kk] * (acc[v] + 1.f) : 0.f;
            }
        }
        __syncthreads();

        // F: Z1b = xq@W1 + b1 - coef1@gZ1 ; X2b = gelu
        {
            u64 acc2[2][4];
            {
                float4 bb0 = *(const float4*)(b1sm + l * 8);
                float4 bb1 = *(const float4*)(b1sm + l * 8 + 4);
                u64 p0, p1, p2, p3;
                f4tou2(bb0, p0, p1); f4tou2(bb1, p2, p3);
#pragma unroll
                for (int u = 0; u < 2; u++) {
                    acc2[u][0] = p0; acc2[u][1] = p1; acc2[u][2] = p2; acc2[u][3] = p3;
                }
            }
#pragma unroll 4
            for (int e = 0; e < 64; e++) {
                float4 w0 = *(const float4*)(W1r + e*256 + l*8);
                float4 w1 = *(const float4*)(W1r + e*256 + l*8 + 4);
                u64 w2[4];
                f4tou2(w0, w2[0], w2[1]); f4tou2(w1, w2[2], w2[3]);
#pragma unroll
                for (int u = 0; u < 2; u++) {
                    float a = sxq[(w*2+u)*TP + e];
                    u64 a2 = f2pack(a, a);
#pragma unroll
                    for (int p = 0; p < 4; p++) acc2[u][p] = ffma2(a2, w2[p], acc2[u][p]);
                }
            }
#pragma unroll 4
            for (int k2 = 0; k2 < 64; k2++) {
                float4 g0 = *(const float4*)(gZ1r + k2*256 + l*8);
                float4 g1 = *(const float4*)(gZ1r + k2*256 + l*8 + 4);
                u64 gv2[4];
                f4tou2(g0, gv2[0], gv2[1]); f4tou2(g1, gv2[2], gv2[3]);
#pragma unroll
                for (int u = 0; u < 2; u++) {
                    float c = -ssc[(w*2+u)*PS + k2];
                    u64 c2 = f2pack(c, c);
#pragma unroll
                    for (int p = 0; p < 4; p++) acc2[u][p] = ffma2(c2, gv2[p], acc2[u][p]);
                }
            }
#pragma unroll
            for (int u = 0; u < 2; u++) {
                int row = w * 2 + u;
                float zz[8], xv2[8];
#pragma unroll
                for (int p = 0; p < 4; p++) f2unpack(acc2[u][p], zz[2*p], zz[2*p+1]);
#pragma unroll
                for (int v = 0; v < 8; v++) {
                    float z = zz[v];
                    float t = tanh_fast(0.79788456f * (z + 0.044715f * z * z * z));
                    xv2[v] = 0.5f * z * (1.f + t);
                }
                float4* xp = (float4*)(X2br + row * 256 + l * 8);
                xp[0] = make_float4(xv2[0],xv2[1],xv2[2],xv2[3]);
                xp[1] = make_float4(xv2[4],xv2[5],xv2[6],xv2[7]);
            }
        }
        __syncthreads();

        // G: coef2 = eta[j]*(tril(X2b@X2^T)+1) -> ssc  (row ty2, cols tx2*4)
        {
            float acc[4] = {0.f, 0.f, 0.f, 0.f};
            if (tx2 * 4 <= ty2) {
#pragma unroll 2
                for (int f0 = 0; f0 < 256; f0 += 4) {
                    float4 a4 = *(const float4*)(X2br + ty2*256 + f0);
#pragma unroll
                    for (int v = 0; v < 4; v++) {
                        float4 b4 = *(const float4*)(X2r + (tx2*4+v)*256 + f0);
                        acc[v] += a4.x*b4.x + a4.y*b4.y + a4.z*b4.z + a4.w*b4.w;
                    }
                }
            }
#pragma unroll
            for (int v = 0; v < 4; v++) {
                int j = tx2 * 4 + v;
                ssc[ty2*PS + j] = (j <= ty2) ? seta[j] * (acc[v] + 1.f) : 0.f;
            }
        }
        __syncthreads();

        // H: Z2b = X2b@W2 + b2 - coef2@gZ2 -> sxv  (row ty2, cols tx2*4)
        {
            float acc[4];
#pragma unroll
            for (int v = 0; v < 4; v++) acc[v] = b2sm[tx2 * 4 + v];
#pragma unroll 4
            for (int f0 = 0; f0 < 256; f0 += 4) {
                float4 a4 = *(const float4*)(X2br + ty2*256 + f0);
                float4 b4[4];
#pragma unroll
                for (int d = 0; d < 4; d++) b4[d] = *(const float4*)(W2r + (f0+d)*64 + tx2*4);
                acc[0] += a4.x*b4[0].x + a4.y*b4[1].x + a4.z*b4[2].x + a4.w*b4[3].x;
                acc[1] += a4.x*b4[0].y + a4.y*b4[1].y + a4.z*b4[2].y + a4.w*b4[3].y;
                acc[2] += a4.x*b4[0].z + a4.y*b4[1].z + a4.z*b4[2].z + a4.w*b4[3].z;
                acc[3] += a4.x*b4[0].w + a4.y*b4[1].w + a4.z*b4[2].w + a4.w*b4[3].w;
            }
#pragma unroll 4
            for (int k2 = 0; k2 < 64; k2++) {
                float c = ssc[ty2*PS + k2];
                float4 gv4 = *(const float4*)(sgZ2 + k2*PS + tx2*4);
                acc[0] -= c * gv4.x; acc[1] -= c * gv4.y;
                acc[2] -= c * gv4.z; acc[3] -= c * gv4.w;
            }
#pragma unroll
            for (int v = 0; v < 4; v++) sxv[ty2*TP + tx2*4+v] = acc[v];
        }
        __syncthreads();

        // I: out = xq + LN(Z2b)
        for (int i = w; i < 64; i += 32) {
            float z0 = sxv[i*TP + l], z1 = sxv[i*TP + l + 32];
            float mu = warpsum(z0 + z1) * (1.f/64.f);
            float d0 = z0 - mu, d1 = z1 - mu;
            float var = warpsum(d0*d0 + d1*d1) * (1.f/64.f);
            float rstd = rsqrtf(var + EPSc);
            size_t g = (tokbase + i) * Dn + h * 64;
            outp[g + l]      = sxq[i*TP + l]      + nwh[l]    * d0 * rstd + nbh[l];
            outp[g + l + 32] = sxq[i*TP + l + 32] + nwh[l+32] * d1 * rstd + nbh[l+32];
        }

        // J1: W1 -= (eta*xk)^T @ gZ1   (rows e = w*2+u, cols l*8)
        {
            u64 acc2[2][4];
#pragma unroll
            for (int u = 0; u < 2; u++)
#pragma unroll
                for (int p = 0; p < 4; p++) acc2[u][p] = 0ULL;
#pragma unroll 4
            for (int i = 0; i < 64; i++) {
                float et = seta[i];
                float4 g0 = *(const float4*)(gZ1r + i*256 + l*8);
                float4 g1 = *(const float4*)(gZ1r + i*256 + l*8 + 4);
                u64 gv2[4];
                f4tou2(g0, gv2[0], gv2[1]); f4tou2(g1, gv2[2], gv2[3]);
#pragma unroll
                for (int u = 0; u < 2; u++) {
                    float a = et * sxk[i*TP + w*2+u];
                    u64 a2 = f2pack(a, a);
#pragma unroll
                    for (int p = 0; p < 4; p++) acc2[u][p] = ffma2(a2, gv2[p], acc2[u][p]);
                }
            }
#pragma unroll
            for (int u = 0; u < 2; u++) {
                int e = w * 2 + u;
                float av[8];
#pragma unroll
                for (int p = 0; p < 4; p++) f2unpack(acc2[u][p], av[2*p], av[2*p+1]);
                float4* wp = (float4*)(W1r + e*256 + l*8);
                float4 o0 = wp[0], o1 = wp[1];
                wp[0] = make_float4(o0.x-av[0], o0.y-av[1], o0.z-av[2], o0.w-av[3]);
                wp[1] = make_float4(o1.x-av[4], o1.y-av[5], o1.z-av[6], o1.w-av[7]);
            }
        }
        // J2: b1
        if (tid < 256) {
            float acc = 0.f;
#pragma unroll 8
            for (int i = 0; i < 64; i++) acc += seta[i] * gZ1r[i*256 + tid];
            b1sm[tid] -= acc;
        }
        // J3: W2 and W2T   (f = ft*2+u, cols jt*8)
        {
            u64 acc2[2][4];
#pragma unroll
            for (int u = 0; u < 2; u++)
#pragma unroll
                for (int p = 0; p < 4; p++) acc2[u][p] = 0ULL;
#pragma unroll 4
            for (int i = 0; i < 64; i++) {
                float et = seta[i];
                float2 x0 = *(const float2*)(X2r + i*256 + ft*2);
                float4 gv0 = *(const float4*)(sgZ2 + i*PS + jt*8);
                float4 gv1 = *(const float4*)(sgZ2 + i*PS + jt*8 + 4);
                u64 gv2[4];
                f4tou2(gv0, gv2[0], gv2[1]); f4tou2(gv1, gv2[2], gv2[3]);
                float a[2] = {et*x0.x, et*x0.y};
#pragma unroll
                for (int u = 0; u < 2; u++) {
                    u64 a2 = f2pack(a[u], a[u]);
#pragma unroll
                    for (int p = 0; p < 4; p++) acc2[u][p] = ffma2(a2, gv2[p], acc2[u][p]);
                }
            }
#pragma unroll
            for (int u = 0; u < 2; u++) {
                int f = ft * 2 + u;
                float av[8];
#pragma unroll
                for (int p = 0; p < 4; p++) f2unpack(acc2[u][p], av[2*p], av[2*p+1]);
                float4* wp0 = (float4*)(W2r + f*64 + jt*8);
                float4* wp1 = (float4*)(W2r + f*64 + jt*8 + 4);
                float4 o0 = wp0[0], o1 = wp1[0];
                wp0[0] = make_float4(o0.x-av[0], o0.y-av[1], o0.z-av[2], o0.w-av[3]);
                wp1[0] = make_float4(o1.x-av[4], o1.y-av[5], o1.z-av[6], o1.w-av[7]);
#pragma unroll
                for (int v = 0; v < 8; v++)
                    W2Tr[(jt*8+v)*256 + f] -= av[v];
            }
        }
        // J4: b2
        if (tid < 64) {
            float acc = 0.f;
#pragma unroll 8
            for (int i = 0; i < 64; i++) acc += seta[i] * sgZ2[i*PS + tid];
            b2sm[tid] -= acc;
        }
        __syncthreads();
    }
}

// ---------------- Launch ----------------
extern "C" void kernel_launch(void* const* d_in, const int* in_sizes, int n_in,
                              void* d_out, int out_size)
{
    const float* x       = (const float*)d_in[0];
    const float* ln1_w   = (const float*)d_in[1];
    const float* ln1_b   = (const float*)d_in[2];
    const float* attn_wq = (const float*)d_in[3];
    const float* attn_wk = (const float*)d_in[4];
    const float* attn_wv = (const float*)d_in[5];
    const float* attn_wo = (const float*)d_in[6];
    const float* wq_w    = (const float*)d_in[7];
    const float* wq_b    = (const float*)d_in[8];
    const float* wk_w    = (const float*)d_in[9];
    const float* wk_b    = (const float*)d_in[10];
    const float* wv_w    = (const float*)d_in[11];
    const float* wv_b    = (const float*)d_in[12];
    const float* wo_w    = (const float*)d_in[13];
    const float* wo_b    = (const float*)d_in[14];
    const float* W1      = (const float*)d_in[15];
    const float* b1      = (const float*)d_in[16];
    const float* W2      = (const float*)d_in[17];
    const float* b2      = (const float*)d_in[18];
    const float* ttt_nw  = (const float*)d_in[19];
    const float* ttt_nb  = (const float*)d_in[20];
    const float* lr_w    = (const float*)d_in[21];
    const float* lr_b    = (const float*)d_in[22];
    const float* pn_w    = (const float*)d_in[23];
    const float* pn_b    = (const float*)d_in[24];
    const float* gate_a  = (const float*)d_in[25];
    float* out = (float*)d_out;

    float *p_h,*p_q,*p_k,*p_v,*p_o,*p_x1,*p_lr,*p_W1,*p_W2,*p_W2T,*p_X2,*p_gZ1,*p_X2b;
    cudaGetSymbolAddress((void**)&p_h,  g_h);
    cudaGetSymbolAddress((void**)&p_q,  g_q);
    cudaGetSymbolAddress((void**)&p_k,  g_k);
    cudaGetSymbolAddress((void**)&p_v,  g_v);
    cudaGetSymbolAddress((void**)&p_o,  g_o);
    cudaGetSymbolAddress((void**)&p_x1, g_x1);
    cudaGetSymbolAddress((void**)&p_lr, g_lr);
    cudaGetSymbolAddress((void**)&p_W1, g_W1s);
    cudaGetSymbolAddress((void**)&p_W2, g_W2s);
    cudaGetSymbolAddress((void**)&p_W2T,g_W2Ts);
    cudaGetSymbolAddress((void**)&p_X2, g_X2);
    cudaGetSymbolAddress((void**)&p_gZ1,g_gZ1);
    cudaGetSymbolAddress((void**)&p_X2b,g_X2b);

    cudaFuncSetAttribute(ttt_scan_kernel,   cudaFuncAttributeMaxDynamicSharedMemorySize, SCAN_SMEM);
    cudaFuncSetAttribute(attn_flash_kernel, cudaFuncAttributeMaxDynamicSharedMemorySize, ATT_SMEM);

    const int M = Bn * Sn;
    dim3 ggrid(Dn / 128, M / 128);
    dim3 ggrid3(Dn / 128, M / 128, 3);
    int nwarp_grid = (Bn * Sn * Hn) / 8;

    ln_kernel<<<M, 256>>>(x, ln1_w, ln1_b, p_h);
    gemm3_nt_kernel<<<ggrid3, 256>>>(p_h, attn_wq, attn_wk, attn_wv,
                                     p_q, p_k, p_v, nullptr, nullptr, nullptr);
    attn_flash_kernel<<<dim3(16, 64), 256, ATT_SMEM>>>(p_q, p_k, p_v, p_o);
    gemm_nt_kernel<<<ggrid, 256>>>(p_o, attn_wo, p_x1, nullptr, x, nullptr);
    gemm3_nt_kernel<<<ggrid3, 256>>>(p_x1, wq_w, wk_w, wv_w,
                                     p_q, p_k, p_v, wq_b, wk_b, wv_b);
    prep_kernel<<<nwarp_grid, 256>>>(p_q, p_k, p_v, ttt_nw, ttt_nb);
    lr_kernel<<<nwarp_grid, 256>>>(p_x1, lr_w, lr_b, p_lr);
    ttt_scan_kernel<<<Bn * Hn, 1024, SCAN_SMEM>>>(
        p_q, p_k, p_v, p_lr, W1, b1, W2, b2, ttt_nw, ttt_nb,
        p_W1, p_W2, p_W2T, p_X2, p_gZ1, p_X2b, p_o);
    ln_kernel<<<M, 256>>>(p_o, pn_w, pn_b, p_h);
    gemm_nt_kernel<<<ggrid, 256>>>(p_h, wo_w, out, wo_b, p_x1, gate_a);
}

// round 9
// speedup vs baseline: 1.3859x; 1.3859x over previous
#include <cuda_runtime.h>
#include <math.h>

#define Bn 4
#define Sn 1024
#define Dn 1024
#define Hn 16
#define HDn 64
#define Cn 64
#define NCn 16
#define DFFn 256
#define EPSc 1e-6f
#define BSD (Bn*Sn*Dn)

typedef unsigned long long u64;
__device__ __forceinline__ u64 f2pack(float lo, float hi) {
    u64 r; asm("mov.b64 %0, {%1, %2};" : "=l"(r) : "f"(lo), "f"(hi)); return r;
}
__device__ __forceinline__ void f2unpack(u64 p, float& lo, float& hi) {
    asm("mov.b64 {%0, %1}, %2;" : "=f"(lo), "=f"(hi) : "l"(p));
}
__device__ __forceinline__ u64 ffma2(u64 a, u64 b, u64 c) {
    u64 d; asm("fma.rn.f32x2 %0, %1, %2, %3;" : "=l"(d) : "l"(a), "l"(b), "l"(c)); return d;
}
__device__ __forceinline__ void f4tou2(float4 f, u64& p0, u64& p1) {
    p0 = f2pack(f.x, f.y); p1 = f2pack(f.z, f.w);
}
__device__ __forceinline__ unsigned f2tf32(float f) {
    unsigned r; asm("cvt.rna.tf32.f32 %0, %1;" : "=r"(r) : "f"(f)); return r;
}
__device__ __forceinline__ void mma_tf32(float* c, const unsigned* a, const unsigned* b) {
    asm volatile("mma.sync.aligned.m16n8k8.row.col.f32.tf32.tf32.f32 "
        "{%0,%1,%2,%3}, {%4,%5,%6,%7}, {%8,%9}, {%0,%1,%2,%3};"
        : "+f"(c[0]), "+f"(c[1]), "+f"(c[2]), "+f"(c[3])
        : "r"(a[0]), "r"(a[1]), "r"(a[2]), "r"(a[3]), "r"(b[0]), "r"(b[1]));
}

__device__ float g_h [BSD];
__device__ float g_q [BSD];
__device__ float g_k [BSD];
__device__ float g_v [BSD];
__device__ float g_o [BSD];
__device__ float g_x1[BSD];
__device__ float g_lr[Bn*Hn*Sn];
__device__ float g_W1s [Bn*Hn*16384];
__device__ float g_W2s [Bn*Hn*16384];
__device__ float g_W2Ts[Bn*Hn*16384];
__device__ float g_X2  [Bn*Hn*16384];
__device__ float g_gZ1 [Bn*Hn*16384];
__device__ float g_X2b [Bn*Hn*16384];

__device__ __forceinline__ float warpsum(float v) {
#pragma unroll
    for (int o = 16; o > 0; o >>= 1) v += __shfl_xor_sync(0xffffffffu, v, o);
    return v;
}
__device__ __forceinline__ float hsum16(float v) {
#pragma unroll
    for (int o = 8; o > 0; o >>= 1) v += __shfl_xor_sync(0xffffffffu, v, o);
    return v;
}
__device__ __forceinline__ float hmax16(float v) {
#pragma unroll
    for (int o = 8; o > 0; o >>= 1) v = fmaxf(v, __shfl_xor_sync(0xffffffffu, v, o));
    return v;
}
__device__ __forceinline__ float blocksum256(float v) {
    __shared__ float red[8];
    int lane = threadIdx.x & 31, w = threadIdx.x >> 5;
    v = warpsum(v);
    if (lane == 0) red[w] = v;
    __syncthreads();
    float r = (lane < 8) ? red[lane] : 0.f;
    r = warpsum(r);
    __syncthreads();
    return r;
}
__device__ __forceinline__ float tanh_fast(float x) {
    float e = __expf(2.f * x);
    return 1.f - __fdividef(2.f, e + 1.f);
}

// ---------------- LayerNorm rows of 1024 ----------------
__global__ __launch_bounds__(256) void ln_kernel(
    const float* __restrict__ x, const float* __restrict__ g,
    const float* __restrict__ b, float* __restrict__ y)
{
    int row = blockIdx.x, tid = threadIdx.x;
    const float* xr = x + (size_t)row * Dn;
    float v[4]; float s = 0.f;
#pragma unroll
    for (int i = 0; i < 4; i++) { v[i] = xr[tid + 256 * i]; s += v[i]; }
    s = blocksum256(s);
    float mu = s * (1.f / Dn), ss = 0.f;
#pragma unroll
    for (int i = 0; i < 4; i++) { float d = v[i] - mu; ss += d * d; }
    ss = blocksum256(ss);
    float rstd = rsqrtf(ss * (1.f / Dn) + EPSc);
    float* yr = y + (size_t)row * Dn;
#pragma unroll
    for (int i = 0; i < 4; i++) {
        int c = tid + 256 * i;
        yr[c] = (v[i] - mu) * rstd * g[c] + b[c];
    }
}

// ---------------- tf32 tensor-core GEMM ----------------
#define GSTR 136
__device__ __forceinline__ void gemm_core(
    const float* __restrict__ A, const float* __restrict__ B, float* __restrict__ C,
    const float* __restrict__ bias, const float* __restrict__ res,
    const float* __restrict__ gate, int bm, int bn)
{
    const int N = 1024, K = 1024, BK = 16;
    __shared__ unsigned As[BK][GSTR];
    __shared__ unsigned Bs[BK][GSTR];
    int t = threadIdx.x;
    int warp = t >> 5, lane = t & 31;
    int wm = warp >> 1, wn = warp & 1;
    int g = lane >> 2, tg = lane & 3;

    float acc[2][8][4];
#pragma unroll
    for (int mt = 0; mt < 2; mt++)
#pragma unroll
        for (int nt = 0; nt < 8; nt++)
#pragma unroll
            for (int r = 0; r < 4; r++) acc[mt][nt][r] = 0.f;

    int r128 = t >> 1, kc = (t & 1) * 8;
    const float* Ab = A + (size_t)(bm + r128) * K + kc;
    const float* Bb = B + (size_t)(bn + r128) * K + kc;
    float4 a0 = *(const float4*)(Ab);
    float4 a1 = *(const float4*)(Ab + 4);
    float4 b0 = *(const float4*)(Bb);
    float4 b1 = *(const float4*)(Bb + 4);

    for (int k0 = 0; k0 < K; k0 += BK) {
        As[kc+0][r128]=f2tf32(a0.x); As[kc+1][r128]=f2tf32(a0.y);
        As[kc+2][r128]=f2tf32(a0.z); As[kc+3][r128]=f2tf32(a0.w);
        As[kc+4][r128]=f2tf32(a1.x); As[kc+5][r128]=f2tf32(a1.y);
        As[kc+6][r128]=f2tf32(a1.z); As[kc+7][r128]=f2tf32(a1.w);
        Bs[kc+0][r128]=f2tf32(b0.x); Bs[kc+1][r128]=f2tf32(b0.y);
        Bs[kc+2][r128]=f2tf32(b0.z); Bs[kc+3][r128]=f2tf32(b0.w);
        Bs[kc+4][r128]=f2tf32(b1.x); Bs[kc+5][r128]=f2tf32(b1.y);
        Bs[kc+6][r128]=f2tf32(b1.z); Bs[kc+7][r128]=f2tf32(b1.w);
        __syncthreads();
        if (k0 + BK < K) {
            a0 = *(const float4*)(Ab + k0 + BK);
            a1 = *(const float4*)(Ab + k0 + BK + 4);
            b0 = *(const float4*)(Bb + k0 + BK);
            b1 = *(const float4*)(Bb + k0 + BK + 4);
        }
#pragma unroll
        for (int ks = 0; ks < 2; ks++) {
            int kb = ks * 8;
            unsigned af[2][4], bf[8][2];
#pragma unroll
            for (int mt = 0; mt < 2; mt++) {
                int mb = wm * 32 + mt * 16 + g;
                af[mt][0] = As[kb+tg  ][mb];
                af[mt][1] = As[kb+tg  ][mb+8];
                af[mt][2] = As[kb+tg+4][mb];
                af[mt][3] = As[kb+tg+4][mb+8];
            }
#pragma unroll
            for (int nt = 0; nt < 8; nt++) {
                int nb = wn * 64 + nt * 8 + g;
                bf[nt][0] = Bs[kb+tg  ][nb];
                bf[nt][1] = Bs[kb+tg+4][nb];
            }
#pragma unroll
            for (int mt = 0; mt < 2; mt++)
#pragma unroll
                for (int nt = 0; nt < 8; nt++)
                    mma_tf32(acc[mt][nt], af[mt], bf[nt]);
        }
        __syncthreads();
    }

    float bs2[8][2], gv2[8][2];
#pragma unroll
    for (int nt = 0; nt < 8; nt++) {
        int col = bn + wn * 64 + nt * 8 + tg * 2;
        if (bias) { bs2[nt][0] = bias[col]; bs2[nt][1] = bias[col+1]; }
        else      { bs2[nt][0] = 0.f;       bs2[nt][1] = 0.f; }
        if (gate) { gv2[nt][0] = tanhf(gate[col]); gv2[nt][1] = tanhf(gate[col+1]); }
    }
#pragma unroll
    for (int mt = 0; mt < 2; mt++) {
        int row0 = bm + wm * 32 + mt * 16 + g;
#pragma unroll
        for (int nt = 0; nt < 8; nt++) {
            int col = bn + wn * 64 + nt * 8 + tg * 2;
            float v0 = acc[mt][nt][0] + bs2[nt][0];
            float v1 = acc[mt][nt][1] + bs2[nt][1];
            float v2 = acc[mt][nt][2] + bs2[nt][0];
            float v3 = acc[mt][nt][3] + bs2[nt][1];
            if (gate) {
                float2 r0 = *(const float2*)(res + (size_t)row0 * N + col);
                float2 r1 = *(const float2*)(res + (size_t)(row0+8) * N + col);
                v0 = r0.x + gv2[nt][0] * v0; v1 = r0.y + gv2[nt][1] * v1;
                v2 = r1.x + gv2[nt][0] * v2; v3 = r1.y + gv2[nt][1] * v3;
            } else if (res) {
                float2 r0 = *(const float2*)(res + (size_t)row0 * N + col);
                float2 r1 = *(const float2*)(res + (size_t)(row0+8) * N + col);
                v0 += r0.x; v1 += r0.y; v2 += r1.x; v3 += r1.y;
            }
            *(float2*)(C + (size_t)row0 * N + col)     = make_float2(v0, v1);
            *(float2*)(C + (size_t)(row0+8) * N + col) = make_float2(v2, v3);
        }
    }
}

__global__ __launch_bounds__(256, 2) void gemm_nt_kernel(
    const float* __restrict__ A, const float* __restrict__ B, float* __restrict__ C,
    const float* __restrict__ bias, const float* __restrict__ res,
    const float* __restrict__ gate)
{
    gemm_core(A, B, C, bias, res, gate, blockIdx.y * 128, blockIdx.x * 128);
}

__global__ __launch_bounds__(256, 2) void gemm3_nt_kernel(
    const float* __restrict__ A,
    const float* __restrict__ B0, const float* __restrict__ B1, const float* __restrict__ B2,
    float* __restrict__ C0, float* __restrict__ C1, float* __restrict__ C2,
    const float* __restrict__ b0, const float* __restrict__ b1, const float* __restrict__ b2)
{
    const float* B; float* C; const float* bias;
    if (blockIdx.z == 0)      { B = B0; C = C0; bias = b0; }
    else if (blockIdx.z == 1) { B = B1; C = C1; bias = b1; }
    else                      { B = B2; C = C2; bias = b2; }
    gemm_core(A, B, C, bias, nullptr, nullptr, blockIdx.y * 128, blockIdx.x * 128);
}

// ---------------- Flash attention (FFMA2) ----------------
#define AQ 68
#define AK 68
#define AP 65
#define ATT_SMEM ((64*AQ + 64*AK + 64*64 + 64*AP) * 4)

__global__ __launch_bounds__(256) void attn_flash_kernel(
    const float* __restrict__ q, const float* __restrict__ k,
    const float* __restrict__ v, float* __restrict__ o)
{
    extern __shared__ float sm[];
    float* Qs = sm;
    float* Ks = Qs + 64 * AQ;
    float* Vs = Ks + 64 * AK;
    float* Ps = Vs + 64 * 64;

    int qt = blockIdx.x, bh = blockIdx.y;
    int b = bh >> 4, h = bh & 15;
    int tid = threadIdx.x, tx = tid & 15, ty = tid >> 4;
    size_t base = ((size_t)b * Sn) * Dn + h * HDn;

    for (int idx = tid; idx < 4096; idx += 256) {
        int r = idx >> 6, e = idx & 63;
        Qs[r * AQ + e] = q[base + (size_t)(qt * 64 + r) * Dn + e] * 0.125f;
    }
    float m[4], l[4];
    u64 oa2[4][2];
#pragma unroll
    for (int u = 0; u < 4; u++) {
        m[u] = -1e30f; l[u] = 0.f;
        oa2[u][0] = 0ULL; oa2[u][1] = 0ULL;
    }
    __syncthreads();

    for (int kt = 0; kt <= qt; kt++) {
        for (int idx = tid; idx < 4096; idx += 256) {
            int r = idx >> 6, e = idx & 63;
            size_t g = base + (size_t)(kt * 64 + r) * Dn + e;
            Ks[r * AK + e] = k[g];
            Vs[r * 64 + e] = v[g];
        }
        __syncthreads();

        u64 s2[4][4];
#pragma unroll
        for (int u = 0; u < 4; u++)
#pragma unroll
            for (int vv = 0; vv < 4; vv++) s2[u][vv] = 0ULL;
#pragma unroll 2
        for (int e0 = 0; e0 < 64; e0 += 4) {
            u64 qa2[4][2], ka2[4][2];
#pragma unroll
            for (int u = 0; u < 4; u++) {
                float4 f = *(const float4*)(Qs + (ty*4+u)*AQ + e0);
                f4tou2(f, qa2[u][0], qa2[u][1]);
            }
#pragma unroll
            for (int vv = 0; vv < 4; vv++) {
                float4 f = *(const float4*)(Ks + (tx*4+vv)*AK + e0);
                f4tou2(f, ka2[vv][0], ka2[vv][1]);
            }
#pragma unroll
            for (int u = 0; u < 4; u++)
#pragma unroll
                for (int vv = 0; vv < 4; vv++) {
                    s2[u][vv] = ffma2(qa2[u][0], ka2[vv][0], s2[u][vv]);
                    s2[u][vv] = ffma2(qa2[u][1], ka2[vv][1], s2[u][vv]);
                }
        }
        float acc[4][4];
#pragma unroll
        for (int u = 0; u < 4; u++)
#pragma unroll
            for (int vv = 0; vv < 4; vv++) {
                float lo, hi; f2unpack(s2[u][vv], lo, hi);
                acc[u][vv] = lo + hi;
            }
        bool diag = (kt == qt);
#pragma unroll
        for (int u = 0; u < 4; u++) {
            int r = ty * 4 + u;
            float mx = -1e30f;
#pragma unroll
            for (int vv = 0; vv < 4; vv++) {
                int c = tx * 4 + vv;
                if (diag && c > r) acc[u][vv] = -1e30f;
                mx = fmaxf(mx, acc[u][vv]);
            }
            mx = hmax16(mx);
            float nm = fmaxf(m[u], mx);
            float corr = __expf(m[u] - nm);
            float ps = 0.f;
#pragma unroll
            for (int vv = 0; vv < 4; vv++) {
                float p = __expf(acc[u][vv] - nm);
                Ps[r * AP + tx * 4 + vv] = p;
                ps += p;
            }
            ps = hsum16(ps);
            l[u] = l[u] * corr + ps;
            m[u] = nm;
            u64 c2 = f2pack(corr, corr);
            u64 z = 0ULL;
            oa2[u][0] = ffma2(oa2[u][0], c2, z);
            oa2[u][1] = ffma2(oa2[u][1], c2, z);
        }
        __syncthreads();
#pragma unroll 4
        for (int kc = 0; kc < 64; kc++) {
            float4 v4 = *(const float4*)(Vs + kc * 64 + tx * 4);
            u64 v2[2];
            f4tou2(v4, v2[0], v2[1]);
#pragma unroll
            for (int u = 0; u < 4; u++) {
                float p = Ps[(ty * 4 + u) * AP + kc];
                u64 p2 = f2pack(p, p);
                oa2[u][0] = ffma2(p2, v2[0], oa2[u][0]);
                oa2[u][1] = ffma2(p2, v2[1], oa2[u][1]);
            }
        }
        __syncthreads();
    }
#pragma unroll
    for (int u = 0; u < 4; u++) {
        float inv = __fdividef(1.f, l[u]);
        float o0, o1, o2, o3;
        f2unpack(oa2[u][0], o0, o1);
        f2unpack(oa2[u][1], o2, o3);
        size_t g = base + (size_t)(qt * 64 + ty * 4 + u) * Dn + tx * 4;
        *(float4*)(o + g) = make_float4(o0*inv, o1*inv, o2*inv, o3*inv);
    }
}

// ---------------- prep & lr ----------------
__global__ __launch_bounds__(256) void prep_kernel(
    float* __restrict__ XQ, float* __restrict__ XK, float* __restrict__ XV,
    const float* __restrict__ nw, const float* __restrict__ nb)
{
    int w = (blockIdx.x * blockDim.x + threadIdx.x) >> 5;
    if (w >= Bn * Sn * Hn) return;
    int lane = threadIdx.x & 31;
    int h = w & 15, bs = w >> 4;
    size_t base = (size_t)bs * Dn + h * HDn;
    float q0 = XQ[base + lane], q1 = XQ[base + lane + 32];
    float qi = 1.f / fmaxf(sqrtf(warpsum(q0*q0 + q1*q1)), 1e-12f);
    XQ[base + lane] = q0 * qi; XQ[base + lane + 32] = q1 * qi;
    float k0 = XK[base + lane], k1 = XK[base + lane + 32];
    float ki = 1.f / fmaxf(sqrtf(warpsum(k0*k0 + k1*k1)), 1e-12f);
    k0 *= ki; k1 *= ki;
    XK[base + lane] = k0; XK[base + lane + 32] = k1;
    float v0 = XV[base + lane], v1 = XV[base + lane + 32];
    float mu = warpsum(v0 + v1) * (1.f / 64.f);
    float d0 = v0 - mu, d1 = v1 - mu;
    float var = warpsum(d0*d0 + d1*d1) * (1.f / 64.f);
    float rstd = rsqrtf(var + EPSc);
    XV[base + lane]      = nw[h*64+lane]    * d0 * rstd + nb[h*64+lane]    + k0;
    XV[base + lane + 32] = nw[h*64+lane+32] * d1 * rstd + nb[h*64+lane+32] + k1;
}

__global__ __launch_bounds__(256) void lr_kernel(
    const float* __restrict__ x1, const float* __restrict__ lrw,
    const float* __restrict__ lrb, float* __restrict__ lro)
{
    int w = (blockIdx.x * blockDim.x + threadIdx.x) >> 5;
    if (w >= Bn * Sn * Hn) return;
    int lane = threadIdx.x & 31;
    int h = w & 15, bs = w >> 4;
    int b = bs >> 10, s = bs & (Sn - 1);
    const float* xr = x1 + (size_t)bs * Dn;
    const float* wr = lrw + h * Dn;
    float acc = 0.f;
    for (int c = lane; c < Dn; c += 32) acc += xr[c] * wr[c];
    acc = warpsum(acc);
    if (lane == 0)
        lro[(size_t)(b * Hn + h) * Sn + s] = 1.f / (1.f + __expf(-(acc + lrb[h])));
}

// ---------------- TTT scan, 512 threads, A/F fused ----------------
#define TP 65
#define PS 68
#define SCAN_SMEM ((3*64*TP + 2*64*PS + 256 + 64 + 64) * 4)

__global__ __launch_bounds__(512) void ttt_scan_kernel(
    const float* __restrict__ XQ, const float* __restrict__ XK, const float* __restrict__ XV,
    const float* __restrict__ lr,
    const float* __restrict__ W1i, const float* __restrict__ b1i,
    const float* __restrict__ W2i, const float* __restrict__ b2i,
    const float* __restrict__ nw,  const float* __restrict__ nb,
    float* __restrict__ W1G, float* __restrict__ W2G, float* __restrict__ W2TG,
    float* __restrict__ X2G, float* __restrict__ gZ1G, float* __restrict__ X2bG,
    float* __restrict__ outp)
{
    extern __shared__ float sm[];
    float* sxq  = sm;
    float* sxk  = sxq + 64 * TP;
    float* sxv  = sxk + 64 * TP;
    float* ssc  = sxv + 64 * TP;
    float* sgZ2 = ssc + 64 * PS;
    float* b1sm = sgZ2 + 64 * PS;
    float* b2sm = b1sm + 256;
    float* seta = b2sm + 64;

    int bh = blockIdx.x, b = bh >> 4, h = bh & 15;
    int tid = threadIdx.x, w = tid >> 5, l = tid & 31;
    int ty2 = tid >> 4, tx2 = tid & 15;
    int ft = tid >> 3, jt = tid & 7;
    float* W1r  = W1G  + (size_t)bh * 16384;
    float* W2r  = W2G  + (size_t)bh * 16384;
    float* W2Tr = W2TG + (size_t)bh * 16384;
    float* X2r  = X2G  + (size_t)bh * 16384;
    float* gZ1r = gZ1G + (size_t)bh * 16384;
    float* X2br = X2bG + (size_t)bh * 16384;
    const float* nwh = nw + h * 64;
    const float* nbh = nb + h * 64;

    for (int idx = tid; idx < 16384; idx += 512) {
        W1r[idx] = W1i[(size_t)h * 16384 + idx];
        W2r[idx] = W2i[(size_t)h * 16384 + idx];
        int e = idx >> 8, f = idx & 255;
        W2Tr[idx] = W2i[(size_t)h * 16384 + f * 64 + e];
    }
    if (tid < 256) b1sm[tid] = b1i[h * 256 + tid];
    if (tid < 64)  b2sm[tid] = b2i[h * 64 + tid];
    __syncthreads();

    for (int n = 0; n < NCn; n++) {
        size_t tokbase = (size_t)b * Sn + n * Cn;
        for (int idx = tid; idx < 4096; idx += 512) {
            int i = idx >> 6, e = idx & 63;
            size_t g = (tokbase + i) * Dn + h * 64 + e;
            sxq[i * TP + e] = XQ[g];
            sxk[i * TP + e] = XK[g];
            sxv[i * TP + e] = XV[g];
        }
        if (tid < 64) seta[tid] = lr[(size_t)bh * Sn + n * 64 + tid] * (1.f / 64.f);
        __syncthreads();

        // A (fused): one pass over W1 computes BOTH Z1=xk@W1+b1 (-> X2, gb)
        // and Z1q=xq@W1+b1 (-> raw into X2br for phase F).
        {
            u64 acc2[4][4], accq[4][4];
            {
                float4 bb0 = *(const float4*)(b1sm + l * 8);
                float4 bb1 = *(const float4*)(b1sm + l * 8 + 4);
                u64 p0, p1, p2, p3;
                f4tou2(bb0, p0, p1); f4tou2(bb1, p2, p3);
#pragma unroll
                for (int u = 0; u < 4; u++) {
                    acc2[u][0] = p0; acc2[u][1] = p1; acc2[u][2] = p2; acc2[u][3] = p3;
                    accq[u][0] = p0; accq[u][1] = p1; accq[u][2] = p2; accq[u][3] = p3;
                }
            }
#pragma unroll 2
            for (int e = 0; e < 64; e++) {
                float4 w0 = *(const float4*)(W1r + e * 256 + l * 8);
                float4 w1 = *(const float4*)(W1r + e * 256 + l * 8 + 4);
                u64 w2[4];
                f4tou2(w0, w2[0], w2[1]); f4tou2(w1, w2[2], w2[3]);
#pragma unroll
                for (int u = 0; u < 4; u++) {
                    float ak = sxk[(w * 4 + u) * TP + e];
                    float aq = sxq[(w * 4 + u) * TP + e];
                    u64 ak2 = f2pack(ak, ak);
                    u64 aq2 = f2pack(aq, aq);
#pragma unroll
                    for (int p = 0; p < 4; p++) {
                        acc2[u][p] = ffma2(ak2, w2[p], acc2[u][p]);
                        accq[u][p] = ffma2(aq2, w2[p], accq[u][p]);
                    }
                }
            }
#pragma unroll
            for (int u = 0; u < 4; u++) {
                int row = w * 4 + u;
                float zz[8], x2v[8], gbv[8], zq[8];
#pragma unroll
                for (int p = 0; p < 4; p++) {
                    f2unpack(acc2[u][p], zz[2*p], zz[2*p+1]);
                    f2unpack(accq[u][p], zq[2*p], zq[2*p+1]);
                }
#pragma unroll
                for (int v = 0; v < 8; v++) {
                    float z = zz[v];
                    float t = tanh_fast(0.79788456f * (z + 0.044715f * z * z * z));
                    x2v[v] = 0.5f * z * (1.f + t);
                    gbv[v] = 0.5f * z * (1.f - t * t) * (0.79788456f + 0.1070322243f * z * z)
                           + 0.5f * (1.f + t);
                }
                float4* xp = (float4*)(X2r + row * 256 + l * 8);
                xp[0] = make_float4(x2v[0],x2v[1],x2v[2],x2v[3]);
                xp[1] = make_float4(x2v[4],x2v[5],x2v[6],x2v[7]);
                float4* gp = (float4*)(gZ1r + row * 256 + l * 8);
                gp[0] = make_float4(gbv[0],gbv[1],gbv[2],gbv[3]);
                gp[1] = make_float4(gbv[4],gbv[5],gbv[6],gbv[7]);
                float4* qp = (float4*)(X2br + row * 256 + l * 8);
                qp[0] = make_float4(zq[0],zq[1],zq[2],zq[3]);
                qp[1] = make_float4(zq[4],zq[5],zq[6],zq[7]);
            }
        }
        __syncthreads();

        // B: Z2 = X2@W2 + b2 -> ssc
        {
            float acc[2][4];
#pragma unroll
            for (int u = 0; u < 2; u++)
#pragma unroll
                for (int v = 0; v < 4; v++) acc[u][v] = b2sm[tx2 * 4 + v];
#pragma unroll 4
            for (int f0 = 0; f0 < 256; f0 += 4) {
                float4 a4[2], b4[4];
#pragma unroll
                for (int u = 0; u < 2; u++) a4[u] = *(const float4*)(X2r + (ty2*2+u)*256 + f0);
#pragma unroll
                for (int d = 0; d < 4; d++) b4[d] = *(const float4*)(W2r + (f0+d)*64 + tx2*4);
#pragma unroll
                for (int u = 0; u < 2; u++) {
                    acc[u][0] += a4[u].x*b4[0].x + a4[u].y*b4[1].x + a4[u].z*b4[2].x + a4[u].w*b4[3].x;
                    acc[u][1] += a4[u].x*b4[0].y + a4[u].y*b4[1].y + a4[u].z*b4[2].y + a4[u].w*b4[3].y;
                    acc[u][2] += a4[u].x*b4[0].z + a4[u].y*b4[1].z + a4[u].z*b4[2].z + a4[u].w*b4[3].z;
                    acc[u][3] += a4[u].x*b4[0].w + a4[u].y*b4[1].w + a4[u].z*b4[2].w + a4[u].w*b4[3].w;
                }
            }
#pragma unroll
            for (int u = 0; u < 2; u++)
#pragma unroll
                for (int v = 0; v < 4; v++) ssc[(ty2*2+u)*PS + tx2*4+v] = acc[u][v];
        }
        __syncthreads();

        // C: gZ2 = ln_l2_bwd(Z2, xv-xk)
        for (int i = w; i < 64; i += 16) {
            float z0 = ssc[i*PS + l], z1 = ssc[i*PS + l + 32];
            float mu = warpsum(z0 + z1) * (1.f/64.f);
            float d0 = z0 - mu, d1 = z1 - mu;
            float var = warpsum(d0*d0 + d1*d1) * (1.f/64.f);
            float rstd = rsqrtf(var + EPSc);
            float xh0 = d0 * rstd, xh1 = d1 * rstd;
            float g0 = nwh[l], g1 = nwh[l+32];
            float t0 = sxv[i*TP + l] - sxk[i*TP + l];
            float t1 = sxv[i*TP + l + 32] - sxk[i*TP + l + 32];
            float gh0 = (g0*xh0 + nbh[l]    - t0) * g0;
            float gh1 = (g1*xh1 + nbh[l+32] - t1) * g1;
            float sgh = warpsum(gh0 + gh1);
            float sgx = warpsum(gh0*xh0 + gh1*xh1);
            float cc = rstd * (1.f/64.f);
            sgZ2[i*PS + l]      = (64.f*gh0 - sgh - xh0*sgx) * cc;
            sgZ2[i*PS + l + 32] = (64.f*gh1 - sgh - xh1*sgx) * cc;
        }
        __syncthreads();

        // D: gZ1 = (gZ2 @ W2^T) * gb
        {
            u64 acc2[4][4];
#pragma unroll
            for (int u = 0; u < 4; u++)
#pragma unroll
                for (int p = 0; p < 4; p++) acc2[u][p] = 0ULL;
#pragma unroll 4
            for (int e = 0; e < 64; e++) {
                float4 w0 = *(const float4*)(W2Tr + e*256 + l*8);
                float4 w1 = *(const float4*)(W2Tr + e*256 + l*8 + 4);
                u64 w2[4];
                f4tou2(w0, w2[0], w2[1]); f4tou2(w1, w2[2], w2[3]);
#pragma unroll
                for (int u = 0; u < 4; u++) {
                    float a = sgZ2[(w*4+u)*PS + e];
                    u64 a2 = f2pack(a, a);
#pragma unroll
                    for (int p = 0; p < 4; p++) acc2[u][p] = ffma2(a2, w2[p], acc2[u][p]);
                }
            }
#pragma unroll
            for (int u = 0; u < 4; u++) {
                int row = w * 4 + u;
                float av[8];
#pragma unroll
                for (int p = 0; p < 4; p++) f2unpack(acc2[u][p], av[2*p], av[2*p+1]);
                float4* gp = (float4*)(gZ1r + row * 256 + l * 8);
                float4 g0 = gp[0], g1 = gp[1];
                gp[0] = make_float4(av[0]*g0.x, av[1]*g0.y, av[2]*g0.z, av[3]*g0.w);
                gp[1] = make_float4(av[4]*g1.x, av[5]*g1.y, av[6]*g1.z, av[7]*g1.w);
            }
        }
        __syncthreads();

        // E: coef1 = eta[k]*(tril(xq@xk^T)+1) -> ssc
        {
            float acc[2][4];
#pragma unroll
            for (int u = 0; u < 2; u++)
#pragma unroll
                for (int v = 0; v < 4; v++) acc[u][v] = 0.f;
            if (tx2 * 4 <= ty2 * 2 + 1) {
#pragma unroll 4
                for (int e = 0; e < 64; e++) {
                    float a[2], bb[4];
#pragma unroll
                    for (int u = 0; u < 2; u++) a[u]  = sxq[(ty2*2+u)*TP + e];
#pragma unroll
                    for (int v = 0; v < 4; v++) bb[v] = sxk[(tx2*4+v)*TP + e];
#pragma unroll
                    for (int u = 0; u < 2; u++)
#pragma unroll
                        for (int v = 0; v < 4; v++) acc[u][v] += a[u] * bb[v];
                }
            }
#pragma unroll
            for (int u = 0; u < 2; u++) {
                int i = ty2 * 2 + u;
#pragma unroll
                for (int v = 0; v < 4; v++) {
                    int kk = tx2 * 4 + v;
                    ssc[i*PS + kk] = (kk <= i) ? seta[kk] * (acc[u][v] + 1.f) : 0.f;
                }
            }
        }
        __syncthreads();

        // F: Z1b = Z1q - coef1@gZ1 ; X2b = gelu  (Z1q preloaded in X2br)
        {
            u64 acc2[4][4];
#pragma unroll
            for (int u = 0; u < 4; u++) {
                float4 q0 = *(const float4*)(X2br + (w*4+u)*256 + l*8);
                float4 q1 = *(const float4*)(X2br + (w*4+u)*256 + l*8 + 4);
                f4tou2(q0, acc2[u][0], acc2[u][1]);
                f4tou2(q1, acc2[u][2], acc2[u][3]);
            }
#pragma unroll 4
            for (int k2 = 0; k2 < 64; k2++) {
                float4 g0 = *(const float4*)(gZ1r + k2*256 + l*8);
                float4 g1 = *(const float4*)(gZ1r + k2*256 + l*8 + 4);
                u64 gv2[4];
                f4tou2(g0, gv2[0], gv2[1]); f4tou2(g1, gv2[2], gv2[3]);
#pragma unroll
                for (int u = 0; u < 4; u++) {
                    float c = -ssc[(w*4+u)*PS + k2];
                    u64 c2 = f2pack(c, c);
#pragma unroll
                    for (int p = 0; p < 4; p++) acc2[u][p] = ffma2(c2, gv2[p], acc2[u][p]);
                }
            }
#pragma unroll
            for (int u = 0; u < 4; u++) {
                int row = w * 4 + u;
                float zz[8], xv2[8];
#pragma unroll
                for (int p = 0; p < 4; p++) f2unpack(acc2[u][p], zz[2*p], zz[2*p+1]);
#pragma unroll
                for (int v = 0; v < 8; v++) {
                    float z = zz[v];
                    float t = tanh_fast(0.79788456f * (z + 0.044715f * z * z * z));
                    xv2[v] = 0.5f * z * (1.f + t);
                }
                float4* xp = (float4*)(X2br + row * 256 + l * 8);
                xp[0] = make_float4(xv2[0],xv2[1],xv2[2],xv2[3]);
                xp[1] = make_float4(xv2[4],xv2[5],xv2[6],xv2[7]);
            }
        }
        __syncthreads();

        // G: coef2 = eta[j]*(tril(X2b@X2^T)+1) -> ssc
        {
            float acc[2][4];
#pragma unroll
            for (int u = 0; u < 2; u++)
#pragma unroll
                for (int v = 0; v < 4; v++) acc[u][v] = 0.f;
            if (tx2 * 4 <= ty2 * 2 + 1) {
#pragma unroll 2
                for (int f0 = 0; f0 < 256; f0 += 4) {
                    float4 a4[2], b4[4];
#pragma unroll
                    for (int u = 0; u < 2; u++) a4[u] = *(const float4*)(X2br + (ty2*2+u)*256 + f0);
#pragma unroll
                    for (int v = 0; v < 4; v++) b4[v] = *(const float4*)(X2r + (tx2*4+v)*256 + f0);
#pragma unroll
                    for (int u = 0; u < 2; u++)
#pragma unroll
                        for (int v = 0; v < 4; v++)
                            acc[u][v] += a4[u].x*b4[v].x + a4[u].y*b4[v].y
                                       + a4[u].z*b4[v].z + a4[u].w*b4[v].w;
                }
            }
#pragma unroll
            for (int u = 0; u < 2; u++) {
                int i = ty2 * 2 + u;
#pragma unroll
                for (int v = 0; v < 4; v++) {
                    int j = tx2 * 4 + v;
                    ssc[i*PS + j] = (j <= i) ? seta[j] * (acc[u][v] + 1.f) : 0.f;
                }
            }
        }
        __syncthreads();

        // H: Z2b = X2b@W2 + b2 - coef2@gZ2 -> sxv
        {
            float acc[2][4];
#pragma unroll
            for (int u = 0; u < 2; u++)
#pragma unroll
                for (int v = 0; v < 4; v++) acc[u][v] = b2sm[tx2 * 4 + v];
#pragma unroll 4
            for (int f0 = 0; f0 < 256; f0 += 4) {
                float4 a4[2], b4[4];
#pragma unroll
                for (int u = 0; u < 2; u++) a4[u] = *(const float4*)(X2br + (ty2*2+u)*256 + f0);
#pragma unroll
                for (int d = 0; d < 4; d++) b4[d] = *(const float4*)(W2r + (f0+d)*64 + tx2*4);
#pragma unroll
                for (int u = 0; u < 2; u++) {
                    acc[u][0] += a4[u].x*b4[0].x + a4[u].y*b4[1].x + a4[u].z*b4[2].x + a4[u].w*b4[3].x;
                    acc[u][1] += a4[u].x*b4[0].y + a4[u].y*b4[1].y + a4[u].z*b4[2].y + a4[u].w*b4[3].y;
                    acc[u][2] += a4[u].x*b4[0].z + a4[u].y*b4[1].z + a4[u].z*b4[2].z + a4[u].w*b4[3].z;
                    acc[u][3] += a4[u].x*b4[0].w + a4[u].y*b4[1].w + a4[u].z*b4[2].w + a4[u].w*b4[3].w;
                }
            }
#pragma unroll 4
            for (int k2 = 0; k2 < 64; k2++) {
                float c[2];
                c[0] = ssc[(ty2*2)*PS + k2];
                c[1] = ssc[(ty2*2+1)*PS + k2];
                float4 gv4 = *(const float4*)(sgZ2 + k2*PS + tx2*4);
                float gv[4] = {gv4.x, gv4.y, gv4.z, gv4.w};
#pragma unroll
                for (int u = 0; u < 2; u++)
#pragma unroll
                    for (int v = 0; v < 4; v++) acc[u][v] -= c[u] * gv[v];
            }
#pragma unroll
            for (int u = 0; u < 2; u++)
#pragma unroll
                for (int v = 0; v < 4; v++) sxv[(ty2*2+u)*TP + tx2*4+v] = acc[u][v];
        }
        __syncthreads();

        // I: out = xq + LN(Z2b)
        for (int i = w; i < 64; i += 16) {
            float z0 = sxv[i*TP + l], z1 = sxv[i*TP + l + 32];
            float mu = warpsum(z0 + z1) * (1.f/64.f);
            float d0 = z0 - mu, d1 = z1 - mu;
            float var = warpsum(d0*d0 + d1*d1) * (1.f/64.f);
            float rstd = rsqrtf(var + EPSc);
            size_t g = (tokbase + i) * Dn + h * 64;
            outp[g + l]      = sxq[i*TP + l]      + nwh[l]    * d0 * rstd + nbh[l];
            outp[g + l + 32] = sxq[i*TP + l + 32] + nwh[l+32] * d1 * rstd + nbh[l+32];
        }

        // J1: W1 -= (eta*xk)^T @ gZ1
        {
            u64 acc2[4][4];
#pragma unroll
            for (int u = 0; u < 4; u++)
#pragma unroll
                for (int p = 0; p < 4; p++) acc2[u][p] = 0ULL;
#pragma unroll 4
            for (int i = 0; i < 64; i++) {
                float et = seta[i];
                float4 g0 = *(const float4*)(gZ1r + i*256 + l*8);
                float4 g1 = *(const float4*)(gZ1r + i*256 + l*8 + 4);
                u64 gv2[4];
                f4tou2(g0, gv2[0], gv2[1]); f4tou2(g1, gv2[2], gv2[3]);
#pragma unroll
                for (int u = 0; u < 4; u++) {
                    float a = et * sxk[i*TP + w*4+u];
                    u64 a2 = f2pack(a, a);
#pragma unroll
                    for (int p = 0; p < 4; p++) acc2[u][p] = ffma2(a2, gv2[p], acc2[u][p]);
                }
            }
#pragma unroll
            for (int u = 0; u < 4; u++) {
                int e = w * 4 + u;
                float av[8];
#pragma unroll
                for (int p = 0; p < 4; p++) f2unpack(acc2[u][p], av[2*p], av[2*p+1]);
                float4* wp = (float4*)(W1r + e*256 + l*8);
                float4 o0 = wp[0], o1 = wp[1];
                wp[0] = make_float4(o0.x-av[0], o0.y-av[1], o0.z-av[2], o0.w-av[3]);
                wp[1] = make_float4(o1.x-av[4], o1.y-av[5], o1.z-av[6], o1.w-av[7]);
            }
        }
        // J2: b1
        if (tid < 256) {
            float acc = 0.f;
#pragma unroll 8
            for (int i = 0; i < 64; i++) acc += seta[i] * gZ1r[i*256 + tid];
            b1sm[tid] -= acc;
        }
        // J3: W2 and W2T
        {
            u64 acc2[4][4];
#pragma unroll
            for (int u = 0; u < 4; u++)
#pragma unroll
                for (int p = 0; p < 4; p++) acc2[u][p] = 0ULL;
#pragma unroll 4
            for (int i = 0; i < 64; i++) {
                float et = seta[i];
                float4 x0 = *(const float4*)(X2r + i*256 + ft*4);
                float4 gv0 = *(const float4*)(sgZ2 + i*PS + jt*8);
                float4 gv1 = *(const float4*)(sgZ2 + i*PS + jt*8 + 4);
                u64 gv2[4];
                f4tou2(gv0, gv2[0], gv2[1]); f4tou2(gv1, gv2[2], gv2[3]);
                float a[4] = {et*x0.x, et*x0.y, et*x0.z, et*x0.w};
#pragma unroll
                for (int u = 0; u < 4; u++) {
                    u64 a2 = f2pack(a[u], a[u]);
#pragma unroll
                    for (int p = 0; p < 4; p++) acc2[u][p] = ffma2(a2, gv2[p], acc2[u][p]);
                }
            }
#pragma unroll
            for (int u = 0; u < 4; u++) {
                int f = ft * 4 + u;
                float av[8];
#pragma unroll
                for (int p = 0; p < 4; p++) f2unpack(acc2[u][p], av[2*p], av[2*p+1]);
                float4* wp0 = (float4*)(W2r + f*64 + jt*8);
                float4* wp1 = (float4*)(W2r + f*64 + jt*8 + 4);
                float4 o0 = wp0[0], o1 = wp1[0];
                wp0[0] = make_float4(o0.x-av[0], o0.y-av[1], o0.z-av[2], o0.w-av[3]);
                wp1[0] = make_float4(o1.x-av[4], o1.y-av[5], o1.z-av[6], o1.w-av[7]);
#pragma unroll
                for (int v = 0; v < 8; v++)
                    W2Tr[(jt*8+v)*256 + f] -= av[v];
            }
        }
        // J4: b2
        if (tid < 64) {
            float acc = 0.f;
#pragma unroll 8
            for (int i = 0; i < 64; i++) acc += seta[i] * sgZ2[i*PS + tid];
            b2sm[tid] -= acc;
        }
        __syncthreads();
    }
}

// ---------------- Launch ----------------
extern "C" void kernel_launch(void* const* d_in, const int* in_sizes, int n_in,
                              void* d_out, int out_size)
{
    const float* x       = (const float*)d_in[0];
    const float* ln1_w   = (const float*)d_in[1];
    const float* ln1_b   = (const float*)d_in[2];
    const float* attn_wq = (const float*)d_in[3];
    const float* attn_wk = (const float*)d_in[4];
    const float* attn_wv = (const float*)d_in[5];
    const float* attn_wo = (const float*)d_in[6];
    const float* wq_w    = (const float*)d_in[7];
    const float* wq_b    = (const float*)d_in[8];
    const float* wk_w    = (const float*)d_in[9];
    const float* wk_b    = (const float*)d_in[10];
    const float* wv_w    = (const float*)d_in[11];
    const float* wv_b    = (const float*)d_in[12];
    const float* wo_w    = (const float*)d_in[13];
    const float* wo_b    = (const float*)d_in[14];
    const float* W1      = (const float*)d_in[15];
    const float* b1      = (const float*)d_in[16];
    const float* W2      = (const float*)d_in[17];
    const float* b2      = (const float*)d_in[18];
    const float* ttt_nw  = (const float*)d_in[19];
    const float* ttt_nb  = (const float*)d_in[20];
    const float* lr_w    = (const float*)d_in[21];
    const float* lr_b    = (const float*)d_in[22];
    const float* pn_w    = (const float*)d_in[23];
    const float* pn_b    = (const float*)d_in[24];
    const float* gate_a  = (const float*)d_in[25];
    float* out = (float*)d_out;

    float *p_h,*p_q,*p_k,*p_v,*p_o,*p_x1,*p_lr,*p_W1,*p_W2,*p_W2T,*p_X2,*p_gZ1,*p_X2b;
    cudaGetSymbolAddress((void**)&p_h,  g_h);
    cudaGetSymbolAddress((void**)&p_q,  g_q);
    cudaGetSymbolAddress((void**)&p_k,  g_k);
    cudaGetSymbolAddress((void**)&p_v,  g_v);
    cudaGetSymbolAddress((void**)&p_o,  g_o);
    cudaGetSymbolAddress((void**)&p_x1, g_x1);
    cudaGetSymbolAddress((void**)&p_lr, g_lr);
    cudaGetSymbolAddress((void**)&p_W1, g_W1s);
    cudaGetSymbolAddress((void**)&p_W2, g_W2s);
    cudaGetSymbolAddress((void**)&p_W2T,g_W2Ts);
    cudaGetSymbolAddress((void**)&p_X2, g_X2);
    cudaGetSymbolAddress((void**)&p_gZ1,g_gZ1);
    cudaGetSymbolAddress((void**)&p_X2b,g_X2b);

    cudaFuncSetAttribute(ttt_scan_kernel,   cudaFuncAttributeMaxDynamicSharedMemorySize, SCAN_SMEM);
    cudaFuncSetAttribute(attn_flash_kernel, cudaFuncAttributeMaxDynamicSharedMemorySize, ATT_SMEM);

    const int M = Bn * Sn;
    dim3 ggrid(Dn / 128, M / 128);
    dim3 ggrid3(Dn / 128, M / 128, 3);
    int nwarp_grid = (Bn * Sn * Hn) / 8;

    ln_kernel<<<M, 256>>>(x, ln1_w, ln1_b, p_h);
    gemm3_nt_kernel<<<ggrid3, 256>>>(p_h, attn_wq, attn_wk, attn_wv,
                                     p_q, p_k, p_v, nullptr, nullptr, nullptr);
    attn_flash_kernel<<<dim3(16, 64), 256, ATT_SMEM>>>(p_q, p_k, p_v, p_o);
    gemm_nt_kernel<<<ggrid, 256>>>(p_o, attn_wo, p_x1, nullptr, x, nullptr);
    gemm3_nt_kernel<<<ggrid3, 256>>>(p_x1, wq_w, wk_w, wv_w,
                                     p_q, p_k, p_v, wq_b, wk_b, wv_b);
    prep_kernel<<<nwarp_grid, 256>>>(p_q, p_k, p_v, ttt_nw, ttt_nb);
    lr_kernel<<<nwarp_grid, 256>>>(p_x1, lr_w, lr_b, p_lr);
    ttt_scan_kernel<<<Bn * Hn, 512, SCAN_SMEM>>>(
        p_q, p_k, p_v, p_lr, W1, b1, W2, b2, ttt_nw, ttt_nb,
        p_W1, p_W2, p_W2T, p_X2, p_gZ1, p_X2b, p_o);
    ln_kernel<<<M, 256>>>(p_o, pn_w, pn_b, p_h);
    gemm_nt_kernel<<<ggrid, 256>>>(p_h, wo_w, out, wo_b, p_x1, gate_a);
}

// round 10
// speedup vs baseline: 1.4517x; 1.0475x over previous
#include <cuda_runtime.h>
#include <math.h>

#define Bn 4
#define Sn 1024
#define Dn 1024
#define Hn 16
#define HDn 64
#define Cn 64
#define NCn 16
#define DFFn 256
#define EPSc 1e-6f
#define BSD (Bn*Sn*Dn)

typedef unsigned long long u64;
__device__ __forceinline__ u64 f2pack(float lo, float hi) {
    u64 r; asm("mov.b64 %0, {%1, %2};" : "=l"(r) : "f"(lo), "f"(hi)); return r;
}
__device__ __forceinline__ void f2unpack(u64 p, float& lo, float& hi) {
    asm("mov.b64 {%0, %1}, %2;" : "=f"(lo), "=f"(hi) : "l"(p));
}
__device__ __forceinline__ u64 ffma2(u64 a, u64 b, u64 c) {
    u64 d; asm("fma.rn.f32x2 %0, %1, %2, %3;" : "=l"(d) : "l"(a), "l"(b), "l"(c)); return d;
}
__device__ __forceinline__ void f4tou2(float4 f, u64& p0, u64& p1) {
    p0 = f2pack(f.x, f.y); p1 = f2pack(f.z, f.w);
}
__device__ __forceinline__ unsigned f2tf32(float f) {
    unsigned r; asm("cvt.rna.tf32.f32 %0, %1;" : "=r"(r) : "f"(f)); return r;
}
__device__ __forceinline__ void mma_tf32(float* c, const unsigned* a, const unsigned* b) {
    asm volatile("mma.sync.aligned.m16n8k8.row.col.f32.tf32.tf32.f32 "
        "{%0,%1,%2,%3}, {%4,%5,%6,%7}, {%8,%9}, {%0,%1,%2,%3};"
        : "+f"(c[0]), "+f"(c[1]), "+f"(c[2]), "+f"(c[3])
        : "r"(a[0]), "r"(a[1]), "r"(a[2]), "r"(a[3]), "r"(b[0]), "r"(b[1]));
}

__device__ float g_h [BSD];
__device__ float g_q [BSD];
__device__ float g_k [BSD];
__device__ float g_v [BSD];
__device__ float g_o [BSD];
__device__ float g_x1[BSD];
__device__ float g_lr[Bn*Hn*Sn];
__device__ float g_W2Ts[Bn*Hn*16384];
__device__ float g_X2  [Bn*Hn*16384];
__device__ float g_gZ1 [Bn*Hn*16384];
__device__ float g_X2b [Bn*Hn*16384];

__device__ __forceinline__ float warpsum(float v) {
#pragma unroll
    for (int o = 16; o > 0; o >>= 1) v += __shfl_xor_sync(0xffffffffu, v, o);
    return v;
}
__device__ __forceinline__ float hsum16(float v) {
#pragma unroll
    for (int o = 8; o > 0; o >>= 1) v += __shfl_xor_sync(0xffffffffu, v, o);
    return v;
}
__device__ __forceinline__ float hmax16(float v) {
#pragma unroll
    for (int o = 8; o > 0; o >>= 1) v = fmaxf(v, __shfl_xor_sync(0xffffffffu, v, o));
    return v;
}
__device__ __forceinline__ float blocksum256(float v) {
    __shared__ float red[8];
    int lane = threadIdx.x & 31, w = threadIdx.x >> 5;
    v = warpsum(v);
    if (lane == 0) red[w] = v;
    __syncthreads();
    float r = (lane < 8) ? red[lane] : 0.f;
    r = warpsum(r);
    __syncthreads();
    return r;
}
__device__ __forceinline__ float tanh_fast(float x) {
    float e = __expf(2.f * x);
    return 1.f - __fdividef(2.f, e + 1.f);
}

// ---------------- LayerNorm rows of 1024 ----------------
__global__ __launch_bounds__(256) void ln_kernel(
    const float* __restrict__ x, const float* __restrict__ g,
    const float* __restrict__ b, float* __restrict__ y)
{
    int row = blockIdx.x, tid = threadIdx.x;
    const float* xr = x + (size_t)row * Dn;
    float v[4]; float s = 0.f;
#pragma unroll
    for (int i = 0; i < 4; i++) { v[i] = xr[tid + 256 * i]; s += v[i]; }
    s = blocksum256(s);
    float mu = s * (1.f / Dn), ss = 0.f;
#pragma unroll
    for (int i = 0; i < 4; i++) { float d = v[i] - mu; ss += d * d; }
    ss = blocksum256(ss);
    float rstd = rsqrtf(ss * (1.f / Dn) + EPSc);
    float* yr = y + (size_t)row * Dn;
#pragma unroll
    for (int i = 0; i < 4; i++) {
        int c = tid + 256 * i;
        yr[c] = (v[i] - mu) * rstd * g[c] + b[c];
    }
}

// ---------------- tf32 tensor-core GEMM ----------------
#define GSTR 136
__device__ __forceinline__ void gemm_core(
    const float* __restrict__ A, const float* __restrict__ B, float* __restrict__ C,
    const float* __restrict__ bias, const float* __restrict__ res,
    const float* __restrict__ gate, int bm, int bn)
{
    const int N = 1024, K = 1024, BK = 16;
    __shared__ unsigned As[BK][GSTR];
    __shared__ unsigned Bs[BK][GSTR];
    int t = threadIdx.x;
    int warp = t >> 5, lane = t & 31;
    int wm = warp >> 1, wn = warp & 1;
    int g = lane >> 2, tg = lane & 3;

    float acc[2][8][4];
#pragma unroll
    for (int mt = 0; mt < 2; mt++)
#pragma unroll
        for (int nt = 0; nt < 8; nt++)
#pragma unroll
            for (int r = 0; r < 4; r++) acc[mt][nt][r] = 0.f;

    int r128 = t >> 1, kc = (t & 1) * 8;
    const float* Ab = A + (size_t)(bm + r128) * K + kc;
    const float* Bb = B + (size_t)(bn + r128) * K + kc;
    float4 a0 = *(const float4*)(Ab);
    float4 a1 = *(const float4*)(Ab + 4);
    float4 b0 = *(const float4*)(Bb);
    float4 b1 = *(const float4*)(Bb + 4);

    for (int k0 = 0; k0 < K; k0 += BK) {
        As[kc+0][r128]=f2tf32(a0.x); As[kc+1][r128]=f2tf32(a0.y);
        As[kc+2][r128]=f2tf32(a0.z); As[kc+3][r128]=f2tf32(a0.w);
        As[kc+4][r128]=f2tf32(a1.x); As[kc+5][r128]=f2tf32(a1.y);
        As[kc+6][r128]=f2tf32(a1.z); As[kc+7][r128]=f2tf32(a1.w);
        Bs[kc+0][r128]=f2tf32(b0.x); Bs[kc+1][r128]=f2tf32(b0.y);
        Bs[kc+2][r128]=f2tf32(b0.z); Bs[kc+3][r128]=f2tf32(b0.w);
        Bs[kc+4][r128]=f2tf32(b1.x); Bs[kc+5][r128]=f2tf32(b1.y);
        Bs[kc+6][r128]=f2tf32(b1.z); Bs[kc+7][r128]=f2tf32(b1.w);
        __syncthreads();
        if (k0 + BK < K) {
            a0 = *(const float4*)(Ab + k0 + BK);
            a1 = *(const float4*)(Ab + k0 + BK + 4);
            b0 = *(const float4*)(Bb + k0 + BK);
            b1 = *(const float4*)(Bb + k0 + BK + 4);
        }
#pragma unroll
        for (int ks = 0; ks < 2; ks++) {
            int kb = ks * 8;
            unsigned af[2][4], bf[8][2];
#pragma unroll
            for (int mt = 0; mt < 2; mt++) {
                int mb = wm * 32 + mt * 16 + g;
                af[mt][0] = As[kb+tg  ][mb];
                af[mt][1] = As[kb+tg  ][mb+8];
                af[mt][2] = As[kb+tg+4][mb];
                af[mt][3] = As[kb+tg+4][mb+8];
            }
#pragma unroll
            for (int nt = 0; nt < 8; nt++) {
                int nb = wn * 64 + nt * 8 + g;
                bf[nt][0] = Bs[kb+tg  ][nb];
                bf[nt][1] = Bs[kb+tg+4][nb];
            }
#pragma unroll
            for (int mt = 0; mt < 2; mt++)
#pragma unroll
                for (int nt = 0; nt < 8; nt++)
                    mma_tf32(acc[mt][nt], af[mt], bf[nt]);
        }
        __syncthreads();
    }

    float bs2[8][2], gv2[8][2];
#pragma unroll
    for (int nt = 0; nt < 8; nt++) {
        int col = bn + wn * 64 + nt * 8 + tg * 2;
        if (bias) { bs2[nt][0] = bias[col]; bs2[nt][1] = bias[col+1]; }
        else      { bs2[nt][0] = 0.f;       bs2[nt][1] = 0.f; }
        if (gate) { gv2[nt][0] = tanhf(gate[col]); gv2[nt][1] = tanhf(gate[col+1]); }
    }
#pragma unroll
    for (int mt = 0; mt < 2; mt++) {
        int row0 = bm + wm * 32 + mt * 16 + g;
#pragma unroll
        for (int nt = 0; nt < 8; nt++) {
            int col = bn + wn * 64 + nt * 8 + tg * 2;
            float v0 = acc[mt][nt][0] + bs2[nt][0];
            float v1 = acc[mt][nt][1] + bs2[nt][1];
            float v2 = acc[mt][nt][2] + bs2[nt][0];
            float v3 = acc[mt][nt][3] + bs2[nt][1];
            if (gate) {
                float2 r0 = *(const float2*)(res + (size_t)row0 * N + col);
                float2 r1 = *(const float2*)(res + (size_t)(row0+8) * N + col);
                v0 = r0.x + gv2[nt][0] * v0; v1 = r0.y + gv2[nt][1] * v1;
                v2 = r1.x + gv2[nt][0] * v2; v3 = r1.y + gv2[nt][1] * v3;
            } else if (res) {
                float2 r0 = *(const float2*)(res + (size_t)row0 * N + col);
                float2 r1 = *(const float2*)(res + (size_t)(row0+8) * N + col);
                v0 += r0.x; v1 += r0.y; v2 += r1.x; v3 += r1.y;
            }
            *(float2*)(C + (size_t)row0 * N + col)     = make_float2(v0, v1);
            *(float2*)(C + (size_t)(row0+8) * N + col) = make_float2(v2, v3);
        }
    }
}

__global__ __launch_bounds__(256, 2) void gemm_nt_kernel(
    const float* __restrict__ A, const float* __restrict__ B, float* __restrict__ C,
    const float* __restrict__ bias, const float* __restrict__ res,
    const float* __restrict__ gate)
{
    gemm_core(A, B, C, bias, res, gate, blockIdx.y * 128, blockIdx.x * 128);
}

__global__ __launch_bounds__(256, 2) void gemm3_nt_kernel(
    const float* __restrict__ A,
    const float* __restrict__ B0, const float* __restrict__ B1, const float* __restrict__ B2,
    float* __restrict__ C0, float* __restrict__ C1, float* __restrict__ C2,
    const float* __restrict__ b0, const float* __restrict__ b1, const float* __restrict__ b2)
{
    const float* B; float* C; const float* bias;
    if (blockIdx.z == 0)      { B = B0; C = C0; bias = b0; }
    else if (blockIdx.z == 1) { B = B1; C = C1; bias = b1; }
    else                      { B = B2; C = C2; bias = b2; }
    gemm_core(A, B, C, bias, nullptr, nullptr, blockIdx.y * 128, blockIdx.x * 128);
}

// ---------------- Flash attention (FFMA2) ----------------
#define AQ 68
#define AK 68
#define AP 65
#define ATT_SMEM ((64*AQ + 64*AK + 64*64 + 64*AP) * 4)

__global__ __launch_bounds__(256) void attn_flash_kernel(
    const float* __restrict__ q, const float* __restrict__ k,
    const float* __restrict__ v, float* __restrict__ o)
{
    extern __shared__ float sm[];
    float* Qs = sm;
    float* Ks = Qs + 64 * AQ;
    float* Vs = Ks + 64 * AK;
    float* Ps = Vs + 64 * 64;

    int qt = blockIdx.x, bh = blockIdx.y;
    int b = bh >> 4, h = bh & 15;
    int tid = threadIdx.x, tx = tid & 15, ty = tid >> 4;
    size_t base = ((size_t)b * Sn) * Dn + h * HDn;

    for (int idx = tid; idx < 4096; idx += 256) {
        int r = idx >> 6, e = idx & 63;
        Qs[r * AQ + e] = q[base + (size_t)(qt * 64 + r) * Dn + e] * 0.125f;
    }
    float m[4], l[4];
    u64 oa2[4][2];
#pragma unroll
    for (int u = 0; u < 4; u++) {
        m[u] = -1e30f; l[u] = 0.f;
        oa2[u][0] = 0ULL; oa2[u][1] = 0ULL;
    }
    __syncthreads();

    for (int kt = 0; kt <= qt; kt++) {
        for (int idx = tid; idx < 4096; idx += 256) {
            int r = idx >> 6, e = idx & 63;
            size_t g = base + (size_t)(kt * 64 + r) * Dn + e;
            Ks[r * AK + e] = k[g];
            Vs[r * 64 + e] = v[g];
        }
        __syncthreads();

        u64 s2[4][4];
#pragma unroll
        for (int u = 0; u < 4; u++)
#pragma unroll
            for (int vv = 0; vv < 4; vv++) s2[u][vv] = 0ULL;
#pragma unroll 2
        for (int e0 = 0; e0 < 64; e0 += 4) {
            u64 qa2[4][2], ka2[4][2];
#pragma unroll
            for (int u = 0; u < 4; u++) {
                float4 f = *(const float4*)(Qs + (ty*4+u)*AQ + e0);
                f4tou2(f, qa2[u][0], qa2[u][1]);
            }
#pragma unroll
            for (int vv = 0; vv < 4; vv++) {
                float4 f = *(const float4*)(Ks + (tx*4+vv)*AK + e0);
                f4tou2(f, ka2[vv][0], ka2[vv][1]);
            }
#pragma unroll
            for (int u = 0; u < 4; u++)
#pragma unroll
                for (int vv = 0; vv < 4; vv++) {
                    s2[u][vv] = ffma2(qa2[u][0], ka2[vv][0], s2[u][vv]);
                    s2[u][vv] = ffma2(qa2[u][1], ka2[vv][1], s2[u][vv]);
                }
        }
        float acc[4][4];
#pragma unroll
        for (int u = 0; u < 4; u++)
#pragma unroll
            for (int vv = 0; vv < 4; vv++) {
                float lo, hi; f2unpack(s2[u][vv], lo, hi);
                acc[u][vv] = lo + hi;
            }
        bool diag = (kt == qt);
#pragma unroll
        for (int u = 0; u < 4; u++) {
            int r = ty * 4 + u;
            float mx = -1e30f;
#pragma unroll
            for (int vv = 0; vv < 4; vv++) {
                int c = tx * 4 + vv;
                if (diag && c > r) acc[u][vv] = -1e30f;
                mx = fmaxf(mx, acc[u][vv]);
            }
            mx = hmax16(mx);
            float nm = fmaxf(m[u], mx);
            float corr = __expf(m[u] - nm);
            float ps = 0.f;
#pragma unroll
            for (int vv = 0; vv < 4; vv++) {
                float p = __expf(acc[u][vv] - nm);
                Ps[r * AP + tx * 4 + vv] = p;
                ps += p;
            }
            ps = hsum16(ps);
            l[u] = l[u] * corr + ps;
            m[u] = nm;
            u64 c2 = f2pack(corr, corr);
            u64 z = 0ULL;
            oa2[u][0] = ffma2(oa2[u][0], c2, z);
            oa2[u][1] = ffma2(oa2[u][1], c2, z);
        }
        __syncthreads();
#pragma unroll 4
        for (int kc = 0; kc < 64; kc++) {
            float4 v4 = *(const float4*)(Vs + kc * 64 + tx * 4);
            u64 v2[2];
            f4tou2(v4, v2[0], v2[1]);
#pragma unroll
            for (int u = 0; u < 4; u++) {
                float p = Ps[(ty * 4 + u) * AP + kc];
                u64 p2 = f2pack(p, p);
                oa2[u][0] = ffma2(p2, v2[0], oa2[u][0]);
                oa2[u][1] = ffma2(p2, v2[1], oa2[u][1]);
            }
        }
        __syncthreads();
    }
#pragma unroll
    for (int u = 0; u < 4; u++) {
        float inv = __fdividef(1.f, l[u]);
        float o0, o1, o2, o3;
        f2unpack(oa2[u][0], o0, o1);
        f2unpack(oa2[u][1], o2, o3);
        size_t g = base + (size_t)(qt * 64 + ty * 4 + u) * Dn + tx * 4;
        *(float4*)(o + g) = make_float4(o0*inv, o1*inv, o2*inv, o3*inv);
    }
}

// ---------------- prep & lr ----------------
__global__ __launch_bounds__(256) void prep_kernel(
    float* __restrict__ XQ, float* __restrict__ XK, float* __restrict__ XV,
    const float* __restrict__ nw, const float* __restrict__ nb)
{
    int w = (blockIdx.x * blockDim.x + threadIdx.x) >> 5;
    if (w >= Bn * Sn * Hn) return;
    int lane = threadIdx.x & 31;
    int h = w & 15, bs = w >> 4;
    size_t base = (size_t)bs * Dn + h * HDn;
    float q0 = XQ[base + lane], q1 = XQ[base + lane + 32];
    float qi = 1.f / fmaxf(sqrtf(warpsum(q0*q0 + q1*q1)), 1e-12f);
    XQ[base + lane] = q0 * qi; XQ[base + lane + 32] = q1 * qi;
    float k0 = XK[base + lane], k1 = XK[base + lane + 32];
    float ki = 1.f / fmaxf(sqrtf(warpsum(k0*k0 + k1*k1)), 1e-12f);
    k0 *= ki; k1 *= ki;
    XK[base + lane] = k0; XK[base + lane + 32] = k1;
    float v0 = XV[base + lane], v1 = XV[base + lane + 32];
    float mu = warpsum(v0 + v1) * (1.f / 64.f);
    float d0 = v0 - mu, d1 = v1 - mu;
    float var = warpsum(d0*d0 + d1*d1) * (1.f / 64.f);
    float rstd = rsqrtf(var + EPSc);
    XV[base + lane]      = nw[h*64+lane]    * d0 * rstd + nb[h*64+lane]    + k0;
    XV[base + lane + 32] = nw[h*64+lane+32] * d1 * rstd + nb[h*64+lane+32] + k1;
}

__global__ __launch_bounds__(256) void lr_kernel(
    const float* __restrict__ x1, const float* __restrict__ lrw,
    const float* __restrict__ lrb, float* __restrict__ lro)
{
    int w = (blockIdx.x * blockDim.x + threadIdx.x) >> 5;
    if (w >= Bn * Sn * Hn) return;
    int lane = threadIdx.x & 31;
    int h = w & 15, bs = w >> 4;
    int b = bs >> 10, s = bs & (Sn - 1);
    const float* xr = x1 + (size_t)bs * Dn;
    const float* wr = lrw + h * Dn;
    float acc = 0.f;
    for (int c = lane; c < Dn; c += 32) acc += xr[c] * wr[c];
    acc = warpsum(acc);
    if (lane == 0)
        lro[(size_t)(b * Hn + h) * Sn + s] = 1.f / (1.f + __expf(-(acc + lrb[h])));
}

// ---------------- TTT scan, 512 threads, W1+W2 resident in smem ----------
#define TP 65
#define PS 68
#define SCAN_SMEM ((3*64*TP + 2*64*PS + 256 + 64 + 64 + 2*16384) * 4)

__global__ __launch_bounds__(512) void ttt_scan_kernel(
    const float* __restrict__ XQ, const float* __restrict__ XK, const float* __restrict__ XV,
    const float* __restrict__ lr,
    const float* __restrict__ W1i, const float* __restrict__ b1i,
    const float* __restrict__ W2i, const float* __restrict__ b2i,
    const float* __restrict__ nw,  const float* __restrict__ nb,
    float* __restrict__ W2TG,
    float* __restrict__ X2G, float* __restrict__ gZ1G, float* __restrict__ X2bG,
    float* __restrict__ outp)
{
    extern __shared__ float sm[];
    float* sxq  = sm;
    float* sxk  = sxq + 64 * TP;
    float* sxv  = sxk + 64 * TP;
    float* ssc  = sxv + 64 * TP;
    float* sgZ2 = ssc + 64 * PS;
    float* b1sm = sgZ2 + 64 * PS;
    float* b2sm = b1sm + 256;
    float* seta = b2sm + 64;
    float* sW1  = seta + 64;        // 16384 floats
    float* sW2  = sW1 + 16384;      // 16384 floats

    int bh = blockIdx.x, b = bh >> 4, h = bh & 15;
    int tid = threadIdx.x, w = tid >> 5, l = tid & 31;
    int ty2 = tid >> 4, tx2 = tid & 15;
    int ft = tid >> 3, jt = tid & 7;
    float* W2Tr = W2TG + (size_t)bh * 16384;
    float* X2r  = X2G  + (size_t)bh * 16384;
    float* gZ1r = gZ1G + (size_t)bh * 16384;
    float* X2br = X2bG + (size_t)bh * 16384;
    const float* nwh = nw + h * 64;
    const float* nbh = nb + h * 64;

    for (int idx = tid; idx < 16384; idx += 512) {
        sW1[idx] = W1i[(size_t)h * 16384 + idx];
        sW2[idx] = W2i[(size_t)h * 16384 + idx];
        int e = idx >> 8, f = idx & 255;
        W2Tr[idx] = W2i[(size_t)h * 16384 + f * 64 + e];
    }
    if (tid < 256) b1sm[tid] = b1i[h * 256 + tid];
    if (tid < 64)  b2sm[tid] = b2i[h * 64 + tid];
    __syncthreads();

    for (int n = 0; n < NCn; n++) {
        size_t tokbase = (size_t)b * Sn + n * Cn;
        for (int idx = tid; idx < 4096; idx += 512) {
            int i = idx >> 6, e = idx & 63;
            size_t g = (tokbase + i) * Dn + h * 64 + e;
            sxq[i * TP + e] = XQ[g];
            sxk[i * TP + e] = XK[g];
            sxv[i * TP + e] = XV[g];
        }
        if (tid < 64) seta[tid] = lr[(size_t)bh * Sn + n * 64 + tid] * (1.f / 64.f);
        __syncthreads();

        // A (fused): one pass over sW1 computes BOTH Z1=xk@W1+b1 (-> X2, gb)
        // and Z1q=xq@W1+b1 (-> raw into X2br for phase F).
        {
            u64 acc2[4][4], accq[4][4];
            {
                float4 bb0 = *(const float4*)(b1sm + l * 8);
                float4 bb1 = *(const float4*)(b1sm + l * 8 + 4);
                u64 p0, p1, p2, p3;
                f4tou2(bb0, p0, p1); f4tou2(bb1, p2, p3);
#pragma unroll
                for (int u = 0; u < 4; u++) {
                    acc2[u][0] = p0; acc2[u][1] = p1; acc2[u][2] = p2; acc2[u][3] = p3;
                    accq[u][0] = p0; accq[u][1] = p1; accq[u][2] = p2; accq[u][3] = p3;
                }
            }
#pragma unroll 2
            for (int e = 0; e < 64; e++) {
                float4 w0 = *(const float4*)(sW1 + e * 256 + l * 8);
                float4 w1 = *(const float4*)(sW1 + e * 256 + l * 8 + 4);
                u64 w2[4];
                f4tou2(w0, w2[0], w2[1]); f4tou2(w1, w2[2], w2[3]);
#pragma unroll
                for (int u = 0; u < 4; u++) {
                    float ak = sxk[(w * 4 + u) * TP + e];
                    float aq = sxq[(w * 4 + u) * TP + e];
                    u64 ak2 = f2pack(ak, ak);
                    u64 aq2 = f2pack(aq, aq);
#pragma unroll
                    for (int p = 0; p < 4; p++) {
                        acc2[u][p] = ffma2(ak2, w2[p], acc2[u][p]);
                        accq[u][p] = ffma2(aq2, w2[p], accq[u][p]);
                    }
                }
            }
#pragma unroll
            for (int u = 0; u < 4; u++) {
                int row = w * 4 + u;
                float zz[8], x2v[8], gbv[8], zq[8];
#pragma unroll
                for (int p = 0; p < 4; p++) {
                    f2unpack(acc2[u][p], zz[2*p], zz[2*p+1]);
                    f2unpack(accq[u][p], zq[2*p], zq[2*p+1]);
                }
#pragma unroll
                for (int v = 0; v < 8; v++) {
                    float z = zz[v];
                    float t = tanh_fast(0.79788456f * (z + 0.044715f * z * z * z));
                    x2v[v] = 0.5f * z * (1.f + t);
                    gbv[v] = 0.5f * z * (1.f - t * t) * (0.79788456f + 0.1070322243f * z * z)
                           + 0.5f * (1.f + t);
                }
                float4* xp = (float4*)(X2r + row * 256 + l * 8);
                xp[0] = make_float4(x2v[0],x2v[1],x2v[2],x2v[3]);
                xp[1] = make_float4(x2v[4],x2v[5],x2v[6],x2v[7]);
                float4* gp = (float4*)(gZ1r + row * 256 + l * 8);
                gp[0] = make_float4(gbv[0],gbv[1],gbv[2],gbv[3]);
                gp[1] = make_float4(gbv[4],gbv[5],gbv[6],gbv[7]);
                float4* qp = (float4*)(X2br + row * 256 + l * 8);
                qp[0] = make_float4(zq[0],zq[1],zq[2],zq[3]);
                qp[1] = make_float4(zq[4],zq[5],zq[6],zq[7]);
            }
        }
        __syncthreads();

        // B: Z2 = X2@W2 + b2 -> ssc
        {
            float acc[2][4];
#pragma unroll
            for (int u = 0; u < 2; u++)
#pragma unroll
                for (int v = 0; v < 4; v++) acc[u][v] = b2sm[tx2 * 4 + v];
#pragma unroll 4
            for (int f0 = 0; f0 < 256; f0 += 4) {
                float4 a4[2], b4[4];
#pragma unroll
                for (int u = 0; u < 2; u++) a4[u] = *(const float4*)(X2r + (ty2*2+u)*256 + f0);
#pragma unroll
                for (int d = 0; d < 4; d++) b4[d] = *(const float4*)(sW2 + (f0+d)*64 + tx2*4);
#pragma unroll
                for (int u = 0; u < 2; u++) {
                    acc[u][0] += a4[u].x*b4[0].x + a4[u].y*b4[1].x + a4[u].z*b4[2].x + a4[u].w*b4[3].x;
                    acc[u][1] += a4[u].x*b4[0].y + a4[u].y*b4[1].y + a4[u].z*b4[2].y + a4[u].w*b4[3].y;
                    acc[u][2] += a4[u].x*b4[0].z + a4[u].y*b4[1].z + a4[u].z*b4[2].z + a4[u].w*b4[3].z;
                    acc[u][3] += a4[u].x*b4[0].w + a4[u].y*b4[1].w + a4[u].z*b4[2].w + a4[u].w*b4[3].w;
                }
            }
#pragma unroll
            for (int u = 0; u < 2; u++)
#pragma unroll
                for (int v = 0; v < 4; v++) ssc[(ty2*2+u)*PS + tx2*4+v] = acc[u][v];
        }
        __syncthreads();

        // C: gZ2 = ln_l2_bwd(Z2, xv-xk)
        for (int i = w; i < 64; i += 16) {
            float z0 = ssc[i*PS + l], z1 = ssc[i*PS + l + 32];
            float mu = warpsum(z0 + z1) * (1.f/64.f);
            float d0 = z0 - mu, d1 = z1 - mu;
            float var = warpsum(d0*d0 + d1*d1) * (1.f/64.f);
            float rstd = rsqrtf(var + EPSc);
            float xh0 = d0 * rstd, xh1 = d1 * rstd;
            float g0 = nwh[l], g1 = nwh[l+32];
            float t0 = sxv[i*TP + l] - sxk[i*TP + l];
            float t1 = sxv[i*TP + l + 32] - sxk[i*TP + l + 32];
            float gh0 = (g0*xh0 + nbh[l]    - t0) * g0;
            float gh1 = (g1*xh1 + nbh[l+32] - t1) * g1;
            float sgh = warpsum(gh0 + gh1);
            float sgx = warpsum(gh0*xh0 + gh1*xh1);
            float cc = rstd * (1.f/64.f);
            sgZ2[i*PS + l]      = (64.f*gh0 - sgh - xh0*sgx) * cc;
            sgZ2[i*PS + l + 32] = (64.f*gh1 - sgh - xh1*sgx) * cc;
        }
        __syncthreads();

        // D: gZ1 = (gZ2 @ W2^T) * gb
        {
            u64 acc2[4][4];
#pragma unroll
            for (int u = 0; u < 4; u++)
#pragma unroll
                for (int p = 0; p < 4; p++) acc2[u][p] = 0ULL;
#pragma unroll 4
            for (int e = 0; e < 64; e++) {
                float4 w0 = *(const float4*)(W2Tr + e*256 + l*8);
                float4 w1 = *(const float4*)(W2Tr + e*256 + l*8 + 4);
                u64 w2[4];
                f4tou2(w0, w2[0], w2[1]); f4tou2(w1, w2[2], w2[3]);
#pragma unroll
                for (int u = 0; u < 4; u++) {
                    float a = sgZ2[(w*4+u)*PS + e];
                    u64 a2 = f2pack(a, a);
#pragma unroll
                    for (int p = 0; p < 4; p++) acc2[u][p] = ffma2(a2, w2[p], acc2[u][p]);
                }
            }
#pragma unroll
            for (int u = 0; u < 4; u++) {
                int row = w * 4 + u;
                float av[8];
#pragma unroll
                for (int p = 0; p < 4; p++) f2unpack(acc2[u][p], av[2*p], av[2*p+1]);
                float4* gp = (float4*)(gZ1r + row * 256 + l * 8);
                float4 g0 = gp[0], g1 = gp[1];
                gp[0] = make_float4(av[0]*g0.x, av[1]*g0.y, av[2]*g0.z, av[3]*g0.w);
                gp[1] = make_float4(av[4]*g1.x, av[5]*g1.y, av[6]*g1.z, av[7]*g1.w);
            }
        }
        __syncthreads();

        // E: coef1 = eta[k]*(tril(xq@xk^T)+1) -> ssc
        {
            float acc[2][4];
#pragma unroll
            for (int u = 0; u < 2; u++)
#pragma unroll
                for (int v = 0; v < 4; v++) acc[u][v] = 0.f;
            if (tx2 * 4 <= ty2 * 2 + 1) {
#pragma unroll 4
                for (int e = 0; e < 64; e++) {
                    float a[2], bb[4];
#pragma unroll
                    for (int u = 0; u < 2; u++) a[u]  = sxq[(ty2*2+u)*TP + e];
#pragma unroll
                    for (int v = 0; v < 4; v++) bb[v] = sxk[(tx2*4+v)*TP + e];
#pragma unroll
                    for (int u = 0; u < 2; u++)
#pragma unroll
                        for (int v = 0; v < 4; v++) acc[u][v] += a[u] * bb[v];
                }
            }
#pragma unroll
            for (int u = 0; u < 2; u++) {
                int i = ty2 * 2 + u;
#pragma unroll
                for (int v = 0; v < 4; v++) {
                    int kk = tx2 * 4 + v;
                    ssc[i*PS + kk] = (kk <= i) ? seta[kk] * (acc[u][v] + 1.f) : 0.f;
                }
            }
        }
        __syncthreads();

        // F: Z1b = Z1q - coef1@gZ1 ; X2b = gelu  (Z1q preloaded in X2br)
        {
            u64 acc2[4][4];
#pragma unroll
            for (int u = 0; u < 4; u++) {
                float4 q0 = *(const float4*)(X2br + (w*4+u)*256 + l*8);
                float4 q1 = *(const float4*)(X2br + (w*4+u)*256 + l*8 + 4);
                f4tou2(q0, acc2[u][0], acc2[u][1]);
                f4tou2(q1, acc2[u][2], acc2[u][3]);
            }
#pragma unroll 4
            for (int k2 = 0; k2 < 64; k2++) {
                float4 g0 = *(const float4*)(gZ1r + k2*256 + l*8);
                float4 g1 = *(const float4*)(gZ1r + k2*256 + l*8 + 4);
                u64 gv2[4];
                f4tou2(g0, gv2[0], gv2[1]); f4tou2(g1, gv2[2], gv2[3]);
#pragma unroll
                for (int u = 0; u < 4; u++) {
                    float c = -ssc[(w*4+u)*PS + k2];
                    u64 c2 = f2pack(c, c);
#pragma unroll
                    for (int p = 0; p < 4; p++) acc2[u][p] = ffma2(c2, gv2[p], acc2[u][p]);
                }
            }
#pragma unroll
            for (int u = 0; u < 4; u++) {
                int row = w * 4 + u;
                float zz[8], xv2[8];
#pragma unroll
                for (int p = 0; p < 4; p++) f2unpack(acc2[u][p], zz[2*p], zz[2*p+1]);
#pragma unroll
                for (int v = 0; v < 8; v++) {
                    float z = zz[v];
                    float t = tanh_fast(0.79788456f * (z + 0.044715f * z * z * z));
                    xv2[v] = 0.5f * z * (1.f + t);
                }
                float4* xp = (float4*)(X2br + row * 256 + l * 8);
                xp[0] = make_float4(xv2[0],xv2[1],xv2[2],xv2[3]);
                xp[1] = make_float4(xv2[4],xv2[5],xv2[6],xv2[7]);
            }
        }
        __syncthreads();

        // G: coef2 = eta[j]*(tril(X2b@X2^T)+1) -> ssc
        {
            float acc[2][4];
#pragma unroll
            for (int u = 0; u < 2; u++)
#pragma unroll
                for (int v = 0; v < 4; v++) acc[u][v] = 0.f;
            if (tx2 * 4 <= ty2 * 2 + 1) {
#pragma unroll 2
                for (int f0 = 0; f0 < 256; f0 += 4) {
                    float4 a4[2], b4[4];
#pragma unroll
                    for (int u = 0; u < 2; u++) a4[u] = *(const float4*)(X2br + (ty2*2+u)*256 + f0);
#pragma unroll
                    for (int v = 0; v < 4; v++) b4[v] = *(const float4*)(X2r + (tx2*4+v)*256 + f0);
#pragma unroll
                    for (int u = 0; u < 2; u++)
#pragma unroll
                        for (int v = 0; v < 4; v++)
                            acc[u][v] += a4[u].x*b4[v].x + a4[u].y*b4[v].y
                                       + a4[u].z*b4[v].z + a4[u].w*b4[v].w;
                }
            }
#pragma unroll
            for (int u = 0; u < 2; u++) {
                int i = ty2 * 2 + u;
#pragma unroll
                for (int v = 0; v < 4; v++) {
                    int j = tx2 * 4 + v;
                    ssc[i*PS + j] = (j <= i) ? seta[j] * (acc[u][v] + 1.f) : 0.f;
                }
            }
        }
        __syncthreads();

        // H: Z2b = X2b@W2 + b2 - coef2@gZ2 -> sxv
        {
            float acc[2][4];
#pragma unroll
            for (int u = 0; u < 2; u++)
#pragma unroll
                for (int v = 0; v < 4; v++) acc[u][v] = b2sm[tx2 * 4 + v];
#pragma unroll 4
            for (int f0 = 0; f0 < 256; f0 += 4) {
                float4 a4[2], b4[4];
#pragma unroll
                for (int u = 0; u < 2; u++) a4[u] = *(const float4*)(X2br + (ty2*2+u)*256 + f0);
#pragma unroll
                for (int d = 0; d < 4; d++) b4[d] = *(const float4*)(sW2 + (f0+d)*64 + tx2*4);
#pragma unroll
                for (int u = 0; u < 2; u++) {
                    acc[u][0] += a4[u].x*b4[0].x + a4[u].y*b4[1].x + a4[u].z*b4[2].x + a4[u].w*b4[3].x;
                    acc[u][1] += a4[u].x*b4[0].y + a4[u].y*b4[1].y + a4[u].z*b4[2].y + a4[u].w*b4[3].y;
                    acc[u][2] += a4[u].x*b4[0].z + a4[u].y*b4[1].z + a4[u].z*b4[2].z + a4[u].w*b4[3].z;
                    acc[u][3] += a4[u].x*b4[0].w + a4[u].y*b4[1].w + a4[u].z*b4[2].w + a4[u].w*b4[3].w;
                }
            }
#pragma unroll 4
            for (int k2 = 0; k2 < 64; k2++) {
                float c[2];
                c[0] = ssc[(ty2*2)*PS + k2];
                c[1] = ssc[(ty2*2+1)*PS + k2];
                float4 gv4 = *(const float4*)(sgZ2 + k2*PS + tx2*4);
                float gv[4] = {gv4.x, gv4.y, gv4.z, gv4.w};
#pragma unroll
                for (int u = 0; u < 2; u++)
#pragma unroll
                    for (int v = 0; v < 4; v++) acc[u][v] -= c[u] * gv[v];
            }
#pragma unroll
            for (int u = 0; u < 2; u++)
#pragma unroll
                for (int v = 0; v < 4; v++) sxv[(ty2*2+u)*TP + tx2*4+v] = acc[u][v];
        }
        __syncthreads();

        // I: out = xq + LN(Z2b)
        for (int i = w; i < 64; i += 16) {
            float z0 = sxv[i*TP + l], z1 = sxv[i*TP + l + 32];
            float mu = warpsum(z0 + z1) * (1.f/64.f);
            float d0 = z0 - mu, d1 = z1 - mu;
            float var = warpsum(d0*d0 + d1*d1) * (1.f/64.f);
            float rstd = rsqrtf(var + EPSc);
            size_t g = (tokbase + i) * Dn + h * 64;
            outp[g + l]      = sxq[i*TP + l]      + nwh[l]    * d0 * rstd + nbh[l];
            outp[g + l + 32] = sxq[i*TP + l + 32] + nwh[l+32] * d1 * rstd + nbh[l+32];
        }

        // J1: W1 -= (eta*xk)^T @ gZ1  (update sW1 in smem)
        {
            u64 acc2[4][4];
#pragma unroll
            for (int u = 0; u < 4; u++)
#pragma unroll
                for (int p = 0; p < 4; p++) acc2[u][p] = 0ULL;
#pragma unroll 4
            for (int i = 0; i < 64; i++) {
                float et = seta[i];
                float4 g0 = *(const float4*)(gZ1r + i*256 + l*8);
                float4 g1 = *(const float4*)(gZ1r + i*256 + l*8 + 4);
                u64 gv2[4];
                f4tou2(g0, gv2[0], gv2[1]); f4tou2(g1, gv2[2], gv2[3]);
#pragma unroll
                for (int u = 0; u < 4; u++) {
                    float a = et * sxk[i*TP + w*4+u];
                    u64 a2 = f2pack(a, a);
#pragma unroll
                    for (int p = 0; p < 4; p++) acc2[u][p] = ffma2(a2, gv2[p], acc2[u][p]);
                }
            }
#pragma unroll
            for (int u = 0; u < 4; u++) {
                int e = w * 4 + u;
                float av[8];
#pragma unroll
                for (int p = 0; p < 4; p++) f2unpack(acc2[u][p], av[2*p], av[2*p+1]);
                float4* wp = (float4*)(sW1 + e*256 + l*8);
                float4 o0 = wp[0], o1 = wp[1];
                wp[0] = make_float4(o0.x-av[0], o0.y-av[1], o0.z-av[2], o0.w-av[3]);
                wp[1] = make_float4(o1.x-av[4], o1.y-av[5], o1.z-av[6], o1.w-av[7]);
            }
        }
        // J2: b1
        if (tid < 256) {
            float acc = 0.f;
#pragma unroll 8
            for (int i = 0; i < 64; i++) acc += seta[i] * gZ1r[i*256 + tid];
            b1sm[tid] -= acc;
        }
        // J3: W2 (smem) and W2T (global)
        {
            u64 acc2[4][4];
#pragma unroll
            for (int u = 0; u < 4; u++)
#pragma unroll
                for (int p = 0; p < 4; p++) acc2[u][p] = 0ULL;
#pragma unroll 4
            for (int i = 0; i < 64; i++) {
                float et = seta[i];
                float4 x0 = *(const float4*)(X2r + i*256 + ft*4);
                float4 gv0 = *(const float4*)(sgZ2 + i*PS + jt*8);
                float4 gv1 = *(const float4*)(sgZ2 + i*PS + jt*8 + 4);
                u64 gv2[4];
                f4tou2(gv0, gv2[0], gv2[1]); f4tou2(gv1, gv2[2], gv2[3]);
                float a[4] = {et*x0.x, et*x0.y, et*x0.z, et*x0.w};
#pragma unroll
                for (int u = 0; u < 4; u++) {
                    u64 a2 = f2pack(a[u], a[u]);
#pragma unroll
                    for (int p = 0; p < 4; p++) acc2[u][p] = ffma2(a2, gv2[p], acc2[u][p]);
                }
            }
#pragma unroll
            for (int u = 0; u < 4; u++) {
                int f = ft * 4 + u;
                float av[8];
#pragma unroll
                for (int p = 0; p < 4; p++) f2unpack(acc2[u][p], av[2*p], av[2*p+1]);
                float4* wp0 = (float4*)(sW2 + f*64 + jt*8);
                float4* wp1 = (float4*)(sW2 + f*64 + jt*8 + 4);
                float4 o0 = wp0[0], o1 = wp1[0];
                wp0[0] = make_float4(o0.x-av[0], o0.y-av[1], o0.z-av[2], o0.w-av[3]);
                wp1[0] = make_float4(o1.x-av[4], o1.y-av[5], o1.z-av[6], o1.w-av[7]);
#pragma unroll
                for (int v = 0; v < 8; v++)
                    W2Tr[(jt*8+v)*256 + f] -= av[v];
            }
        }
        // J4: b2
        if (tid < 64) {
            float acc = 0.f;
#pragma unroll 8
            for (int i = 0; i < 64; i++) acc += seta[i] * sgZ2[i*PS + tid];
            b2sm[tid] -= acc;
        }
        __syncthreads();
    }
}

// ---------------- Launch ----------------
extern "C" void kernel_launch(void* const* d_in, const int* in_sizes, int n_in,
                              void* d_out, int out_size)
{
    const float* x       = (const float*)d_in[0];
    const float* ln1_w   = (const float*)d_in[1];
    const float* ln1_b   = (const float*)d_in[2];
    const float* attn_wq = (const float*)d_in[3];
    const float* attn_wk = (const float*)d_in[4];
    const float* attn_wv = (const float*)d_in[5];
    const float* attn_wo = (const float*)d_in[6];
    const float* wq_w    = (const float*)d_in[7];
    const float* wq_b    = (const float*)d_in[8];
    const float* wk_w    = (const float*)d_in[9];
    const float* wk_b    = (const float*)d_in[10];
    const float* wv_w    = (const float*)d_in[11];
    const float* wv_b    = (const float*)d_in[12];
    const float* wo_w    = (const float*)d_in[13];
    const float* wo_b    = (const float*)d_in[14];
    const float* W1      = (const float*)d_in[15];
    const float* b1      = (const float*)d_in[16];
    const float* W2      = (const float*)d_in[17];
    const float* b2      = (const float*)d_in[18];
    const float* ttt_nw  = (const float*)d_in[19];
    const float* ttt_nb  = (const float*)d_in[20];
    const float* lr_w    = (const float*)d_in[21];
    const float* lr_b    = (const float*)d_in[22];
    const float* pn_w    = (const float*)d_in[23];
    const float* pn_b    = (const float*)d_in[24];
    const float* gate_a  = (const float*)d_in[25];
    float* out = (float*)d_out;

    float *p_h,*p_q,*p_k,*p_v,*p_o,*p_x1,*p_lr,*p_W2T,*p_X2,*p_gZ1,*p_X2b;
    cudaGetSymbolAddress((void**)&p_h,  g_h);
    cudaGetSymbolAddress((void**)&p_q,  g_q);
    cudaGetSymbolAddress((void**)&p_k,  g_k);
    cudaGetSymbolAddress((void**)&p_v,  g_v);
    cudaGetSymbolAddress((void**)&p_o,  g_o);
    cudaGetSymbolAddress((void**)&p_x1, g_x1);
    cudaGetSymbolAddress((void**)&p_lr, g_lr);
    cudaGetSymbolAddress((void**)&p_W2T,g_W2Ts);
    cudaGetSymbolAddress((void**)&p_X2, g_X2);
    cudaGetSymbolAddress((void**)&p_gZ1,g_gZ1);
    cudaGetSymbolAddress((void**)&p_X2b,g_X2b);

    cudaFuncSetAttribute(ttt_scan_kernel,   cudaFuncAttributeMaxDynamicSharedMemorySize, SCAN_SMEM);
    cudaFuncSetAttribute(attn_flash_kernel, cudaFuncAttributeMaxDynamicSharedMemorySize, ATT_SMEM);

    const int M = Bn * Sn;
    dim3 ggrid(Dn / 128, M / 128);
    dim3 ggrid3(Dn / 128, M / 128, 3);
    int nwarp_grid = (Bn * Sn * Hn) / 8;

    ln_kernel<<<M, 256>>>(x, ln1_w, ln1_b, p_h);
    gemm3_nt_kernel<<<ggrid3, 256>>>(p_h, attn_wq, attn_wk, attn_wv,
                                     p_q, p_k, p_v, nullptr, nullptr, nullptr);
    attn_flash_kernel<<<dim3(16, 64), 256, ATT_SMEM>>>(p_q, p_k, p_v, p_o);
    gemm_nt_kernel<<<ggrid, 256>>>(p_o, attn_wo, p_x1, nullptr, x, nullptr);
    gemm3_nt_kernel<<<ggrid3, 256>>>(p_x1, wq_w, wk_w, wv_w,
                                     p_q, p_k, p_v, wq_b, wk_b, wv_b);
    prep_kernel<<<nwarp_grid, 256>>>(p_q, p_k, p_v, ttt_nw, ttt_nb);
    lr_kernel<<<nwarp_grid, 256>>>(p_x1, lr_w, lr_b, p_lr);
    ttt_scan_kernel<<<Bn * Hn, 512, SCAN_SMEM>>>(
        p_q, p_k, p_v, p_lr, W1, b1, W2, b2, ttt_nw, ttt_nb,
        p_W2T, p_X2, p_gZ1, p_X2b, p_o);
    ln_kernel<<<M, 256>>>(p_o, pn_w, pn_b, p_h);
    gemm_nt_kernel<<<ggrid, 256>>>(p_h, wo_w, out, wo_b, p_x1, gate_a);
}

// round 11
// speedup vs baseline: 1.4667x; 1.0103x over previous
#include <cuda_runtime.h>
#include <math.h>

#define Bn 4
#define Sn 1024
#define Dn 1024
#define Hn 16
#define HDn 64
#define Cn 64
#define NCn 16
#define DFFn 256
#define EPSc 1e-6f
#define BSD (Bn*Sn*Dn)

typedef unsigned long long u64;
__device__ __forceinline__ u64 f2pack(float lo, float hi) {
    u64 r; asm("mov.b64 %0, {%1, %2};" : "=l"(r) : "f"(lo), "f"(hi)); return r;
}
__device__ __forceinline__ void f2unpack(u64 p, float& lo, float& hi) {
    asm("mov.b64 {%0, %1}, %2;" : "=f"(lo), "=f"(hi) : "l"(p));
}
__device__ __forceinline__ u64 ffma2(u64 a, u64 b, u64 c) {
    u64 d; asm("fma.rn.f32x2 %0, %1, %2, %3;" : "=l"(d) : "l"(a), "l"(b), "l"(c)); return d;
}
__device__ __forceinline__ void f4tou2(float4 f, u64& p0, u64& p1) {
    p0 = f2pack(f.x, f.y); p1 = f2pack(f.z, f.w);
}
__device__ __forceinline__ unsigned f2tf32(float f) {
    unsigned r; asm("cvt.rna.tf32.f32 %0, %1;" : "=r"(r) : "f"(f)); return r;
}
__device__ __forceinline__ void mma_tf32(float* c, const unsigned* a, const unsigned* b) {
    asm volatile("mma.sync.aligned.m16n8k8.row.col.f32.tf32.tf32.f32 "
        "{%0,%1,%2,%3}, {%4,%5,%6,%7}, {%8,%9}, {%0,%1,%2,%3};"
        : "+f"(c[0]), "+f"(c[1]), "+f"(c[2]), "+f"(c[3])
        : "r"(a[0]), "r"(a[1]), "r"(a[2]), "r"(a[3]), "r"(b[0]), "r"(b[1]));
}

__device__ float g_h [BSD];
__device__ float g_q [BSD];
__device__ float g_k [BSD];
__device__ float g_v [BSD];
__device__ float g_o [BSD];
__device__ float g_x1[BSD];
__device__ float g_lr[Bn*Hn*Sn];
__device__ float g_W2s [Bn*Hn*16384];
__device__ float g_W2Ts[Bn*Hn*16384];
__device__ float g_X2  [Bn*Hn*16384];
__device__ float g_gZ1 [Bn*Hn*16384];
__device__ float g_X2b [Bn*Hn*16384];

__device__ __forceinline__ float warpsum(float v) {
#pragma unroll
    for (int o = 16; o > 0; o >>= 1) v += __shfl_xor_sync(0xffffffffu, v, o);
    return v;
}
__device__ __forceinline__ float hsum16(float v) {
#pragma unroll
    for (int o = 8; o > 0; o >>= 1) v += __shfl_xor_sync(0xffffffffu, v, o);
    return v;
}
__device__ __forceinline__ float hmax16(float v) {
#pragma unroll
    for (int o = 8; o > 0; o >>= 1) v = fmaxf(v, __shfl_xor_sync(0xffffffffu, v, o));
    return v;
}
__device__ __forceinline__ float blocksum256(float v) {
    __shared__ float red[8];
    int lane = threadIdx.x & 31, w = threadIdx.x >> 5;
    v = warpsum(v);
    if (lane == 0) red[w] = v;
    __syncthreads();
    float r = (lane < 8) ? red[lane] : 0.f;
    r = warpsum(r);
    __syncthreads();
    return r;
}
__device__ __forceinline__ float tanh_fast(float x) {
    float e = __expf(2.f * x);
    return 1.f - __fdividef(2.f, e + 1.f);
}

// ---------------- LayerNorm rows of 1024 ----------------
__global__ __launch_bounds__(256) void ln_kernel(
    const float* __restrict__ x, const float* __restrict__ g,
    const float* __restrict__ b, float* __restrict__ y)
{
    int row = blockIdx.x, tid = threadIdx.x;
    const float* xr = x + (size_t)row * Dn;
    float v[4]; float s = 0.f;
#pragma unroll
    for (int i = 0; i < 4; i++) { v[i] = xr[tid + 256 * i]; s += v[i]; }
    s = blocksum256(s);
    float mu = s * (1.f / Dn), ss = 0.f;
#pragma unroll
    for (int i = 0; i < 4; i++) { float d = v[i] - mu; ss += d * d; }
    ss = blocksum256(ss);
    float rstd = rsqrtf(ss * (1.f / Dn) + EPSc);
    float* yr = y + (size_t)row * Dn;
#pragma unroll
    for (int i = 0; i < 4; i++) {
        int c = tid + 256 * i;
        yr[c] = (v[i] - mu) * rstd * g[c] + b[c];
    }
}

// ---------------- tf32 tensor-core GEMM ----------------
#define GSTR 136
__device__ __forceinline__ void gemm_core(
    const float* __restrict__ A, const float* __restrict__ B, float* __restrict__ C,
    const float* __restrict__ bias, const float* __restrict__ res,
    const float* __restrict__ gate, int bm, int bn)
{
    const int N = 1024, K = 1024, BK = 16;
    __shared__ unsigned As[BK][GSTR];
    __shared__ unsigned Bs[BK][GSTR];
    int t = threadIdx.x;
    int warp = t >> 5, lane = t & 31;
    int wm = warp >> 1, wn = warp & 1;
    int g = lane >> 2, tg = lane & 3;

    float acc[2][8][4];
#pragma unroll
    for (int mt = 0; mt < 2; mt++)
#pragma unroll
        for (int nt = 0; nt < 8; nt++)
#pragma unroll
            for (int r = 0; r < 4; r++) acc[mt][nt][r] = 0.f;

    int r128 = t >> 1, kc = (t & 1) * 8;
    const float* Ab = A + (size_t)(bm + r128) * K + kc;
    const float* Bb = B + (size_t)(bn + r128) * K + kc;
    float4 a0 = *(const float4*)(Ab);
    float4 a1 = *(const float4*)(Ab + 4);
    float4 b0 = *(const float4*)(Bb);
    float4 b1 = *(const float4*)(Bb + 4);

    for (int k0 = 0; k0 < K; k0 += BK) {
        As[kc+0][r128]=f2tf32(a0.x); As[kc+1][r128]=f2tf32(a0.y);
        As[kc+2][r128]=f2tf32(a0.z); As[kc+3][r128]=f2tf32(a0.w);
        As[kc+4][r128]=f2tf32(a1.x); As[kc+5][r128]=f2tf32(a1.y);
        As[kc+6][r128]=f2tf32(a1.z); As[kc+7][r128]=f2tf32(a1.w);
        Bs[kc+0][r128]=f2tf32(b0.x); Bs[kc+1][r128]=f2tf32(b0.y);
        Bs[kc+2][r128]=f2tf32(b0.z); Bs[kc+3][r128]=f2tf32(b0.w);
        Bs[kc+4][r128]=f2tf32(b1.x); Bs[kc+5][r128]=f2tf32(b1.y);
        Bs[kc+6][r128]=f2tf32(b1.z); Bs[kc+7][r128]=f2tf32(b1.w);
        __syncthreads();
        if (k0 + BK < K) {
            a0 = *(const float4*)(Ab + k0 + BK);
            a1 = *(const float4*)(Ab + k0 + BK + 4);
            b0 = *(const float4*)(Bb + k0 + BK);
            b1 = *(const float4*)(Bb + k0 + BK + 4);
        }
#pragma unroll
        for (int ks = 0; ks < 2; ks++) {
            int kb = ks * 8;
            unsigned af[2][4], bf[8][2];
#pragma unroll
            for (int mt = 0; mt < 2; mt++) {
                int mb = wm * 32 + mt * 16 + g;
                af[mt][0] = As[kb+tg  ][mb];
                af[mt][1] = As[kb+tg  ][mb+8];
                af[mt][2] = As[kb+tg+4][mb];
                af[mt][3] = As[kb+tg+4][mb+8];
            }
#pragma unroll
            for (int nt = 0; nt < 8; nt++) {
                int nb = wn * 64 + nt * 8 + g;
                bf[nt][0] = Bs[kb+tg  ][nb];
                bf[nt][1] = Bs[kb+tg+4][nb];
            }
#pragma unroll
            for (int mt = 0; mt < 2; mt++)
#pragma unroll
                for (int nt = 0; nt < 8; nt++)
                    mma_tf32(acc[mt][nt], af[mt], bf[nt]);
        }
        __syncthreads();
    }

    float bs2[8][2], gv2[8][2];
#pragma unroll
    for (int nt = 0; nt < 8; nt++) {
        int col = bn + wn * 64 + nt * 8 + tg * 2;
        if (bias) { bs2[nt][0] = bias[col]; bs2[nt][1] = bias[col+1]; }
        else      { bs2[nt][0] = 0.f;       bs2[nt][1] = 0.f; }
        if (gate) { gv2[nt][0] = tanhf(gate[col]); gv2[nt][1] = tanhf(gate[col+1]); }
    }
#pragma unroll
    for (int mt = 0; mt < 2; mt++) {
        int row0 = bm + wm * 32 + mt * 16 + g;
#pragma unroll
        for (int nt = 0; nt < 8; nt++) {
            int col = bn + wn * 64 + nt * 8 + tg * 2;
            float v0 = acc[mt][nt][0] + bs2[nt][0];
            float v1 = acc[mt][nt][1] + bs2[nt][1];
            float v2 = acc[mt][nt][2] + bs2[nt][0];
            float v3 = acc[mt][nt][3] + bs2[nt][1];
            if (gate) {
                float2 r0 = *(const float2*)(res + (size_t)row0 * N + col);
                float2 r1 = *(const float2*)(res + (size_t)(row0+8) * N + col);
                v0 = r0.x + gv2[nt][0] * v0; v1 = r0.y + gv2[nt][1] * v1;
                v2 = r1.x + gv2[nt][0] * v2; v3 = r1.y + gv2[nt][1] * v3;
            } else if (res) {
                float2 r0 = *(const float2*)(res + (size_t)row0 * N + col);
                float2 r1 = *(const float2*)(res + (size_t)(row0+8) * N + col);
                v0 += r0.x; v1 += r0.y; v2 += r1.x; v3 += r1.y;
            }
            *(float2*)(C + (size_t)row0 * N + col)     = make_float2(v0, v1);
            *(float2*)(C + (size_t)(row0+8) * N + col) = make_float2(v2, v3);
        }
    }
}

__global__ __launch_bounds__(256, 2) void gemm_nt_kernel(
    const float* __restrict__ A, const float* __restrict__ B, float* __restrict__ C,
    const float* __restrict__ bias, const float* __restrict__ res,
    const float* __restrict__ gate)
{
    gemm_core(A, B, C, bias, res, gate, blockIdx.y * 128, blockIdx.x * 128);
}

__global__ __launch_bounds__(256, 2) void gemm3_nt_kernel(
    const float* __restrict__ A,
    const float* __restrict__ B0, const float* __restrict__ B1, const float* __restrict__ B2,
    float* __restrict__ C0, float* __restrict__ C1, float* __restrict__ C2,
    const float* __restrict__ b0, const float* __restrict__ b1, const float* __restrict__ b2)
{
    const float* B; float* C; const float* bias;
    if (blockIdx.z == 0)      { B = B0; C = C0; bias = b0; }
    else if (blockIdx.z == 1) { B = B1; C = C1; bias = b1; }
    else                      { B = B2; C = C2; bias = b2; }
    gemm_core(A, B, C, bias, nullptr, nullptr, blockIdx.y * 128, blockIdx.x * 128);
}

// ---------------- Flash attention (FFMA2) ----------------
#define AQ 68
#define AK 68
#define AP 65
#define ATT_SMEM ((64*AQ + 64*AK + 64*64 + 64*AP) * 4)

__global__ __launch_bounds__(256) void attn_flash_kernel(
    const float* __restrict__ q, const float* __restrict__ k,
    const float* __restrict__ v, float* __restrict__ o)
{
    extern __shared__ float sm[];
    float* Qs = sm;
    float* Ks = Qs + 64 * AQ;
    float* Vs = Ks + 64 * AK;
    float* Ps = Vs + 64 * 64;

    int qt = blockIdx.x, bh = blockIdx.y;
    int b = bh >> 4, h = bh & 15;
    int tid = threadIdx.x, tx = tid & 15, ty = tid >> 4;
    size_t base = ((size_t)b * Sn) * Dn + h * HDn;

    for (int idx = tid; idx < 4096; idx += 256) {
        int r = idx >> 6, e = idx & 63;
        Qs[r * AQ + e] = q[base + (size_t)(qt * 64 + r) * Dn + e] * 0.125f;
    }
    float m[4], l[4];
    u64 oa2[4][2];
#pragma unroll
    for (int u = 0; u < 4; u++) {
        m[u] = -1e30f; l[u] = 0.f;
        oa2[u][0] = 0ULL; oa2[u][1] = 0ULL;
    }
    __syncthreads();

    for (int kt = 0; kt <= qt; kt++) {
        for (int idx = tid; idx < 4096; idx += 256) {
            int r = idx >> 6, e = idx & 63;
            size_t g = base + (size_t)(kt * 64 + r) * Dn + e;
            Ks[r * AK + e] = k[g];
            Vs[r * 64 + e] = v[g];
        }
        __syncthreads();

        u64 s2[4][4];
#pragma unroll
        for (int u = 0; u < 4; u++)
#pragma unroll
            for (int vv = 0; vv < 4; vv++) s2[u][vv] = 0ULL;
#pragma unroll 2
        for (int e0 = 0; e0 < 64; e0 += 4) {
            u64 qa2[4][2], ka2[4][2];
#pragma unroll
            for (int u = 0; u < 4; u++) {
                float4 f = *(const float4*)(Qs + (ty*4+u)*AQ + e0);
                f4tou2(f, qa2[u][0], qa2[u][1]);
            }
#pragma unroll
            for (int vv = 0; vv < 4; vv++) {
                float4 f = *(const float4*)(Ks + (tx*4+vv)*AK + e0);
                f4tou2(f, ka2[vv][0], ka2[vv][1]);
            }
#pragma unroll
            for (int u = 0; u < 4; u++)
#pragma unroll
                for (int vv = 0; vv < 4; vv++) {
                    s2[u][vv] = ffma2(qa2[u][0], ka2[vv][0], s2[u][vv]);
                    s2[u][vv] = ffma2(qa2[u][1], ka2[vv][1], s2[u][vv]);
                }
        }
        float acc[4][4];
#pragma unroll
        for (int u = 0; u < 4; u++)
#pragma unroll
            for (int vv = 0; vv < 4; vv++) {
                float lo, hi; f2unpack(s2[u][vv], lo, hi);
                acc[u][vv] = lo + hi;
            }
        bool diag = (kt == qt);
#pragma unroll
        for (int u = 0; u < 4; u++) {
            int r = ty * 4 + u;
            float mx = -1e30f;
#pragma unroll
            for (int vv = 0; vv < 4; vv++) {
                int c = tx * 4 + vv;
                if (diag && c > r) acc[u][vv] = -1e30f;
                mx = fmaxf(mx, acc[u][vv]);
            }
            mx = hmax16(mx);
            float nm = fmaxf(m[u], mx);
            float corr = __expf(m[u] - nm);
            float ps = 0.f;
#pragma unroll
            for (int vv = 0; vv < 4; vv++) {
                float p = __expf(acc[u][vv] - nm);
                Ps[r * AP + tx * 4 + vv] = p;
                ps += p;
            }
            ps = hsum16(ps);
            l[u] = l[u] * corr + ps;
            m[u] = nm;
            u64 c2 = f2pack(corr, corr);
            u64 z = 0ULL;
            oa2[u][0] = ffma2(oa2[u][0], c2, z);
            oa2[u][1] = ffma2(oa2[u][1], c2, z);
        }
        __syncthreads();
#pragma unroll 4
        for (int kc = 0; kc < 64; kc++) {
            float4 v4 = *(const float4*)(Vs + kc * 64 + tx * 4);
            u64 v2[2];
            f4tou2(v4, v2[0], v2[1]);
#pragma unroll
            for (int u = 0; u < 4; u++) {
                float p = Ps[(ty * 4 + u) * AP + kc];
                u64 p2 = f2pack(p, p);
                oa2[u][0] = ffma2(p2, v2[0], oa2[u][0]);
                oa2[u][1] = ffma2(p2, v2[1], oa2[u][1]);
            }
        }
        __syncthreads();
    }
#pragma unroll
    for (int u = 0; u < 4; u++) {
        float inv = __fdividef(1.f, l[u]);
        float o0, o1, o2, o3;
        f2unpack(oa2[u][0], o0, o1);
        f2unpack(oa2[u][1], o2, o3);
        size_t g = base + (size_t)(qt * 64 + ty * 4 + u) * Dn + tx * 4;
        *(float4*)(o + g) = make_float4(o0*inv, o1*inv, o2*inv, o3*inv);
    }
}

// ---------------- prep & lr ----------------
__global__ __launch_bounds__(256) void prep_kernel(
    float* __restrict__ XQ, float* __restrict__ XK, float* __restrict__ XV,
    const float* __restrict__ nw, const float* __restrict__ nb)
{
    int w = (blockIdx.x * blockDim.x + threadIdx.x) >> 5;
    if (w >= Bn * Sn * Hn) return;
    int lane = threadIdx.x & 31;
    int h = w & 15, bs = w >> 4;
    size_t base = (size_t)bs * Dn + h * HDn;
    float q0 = XQ[base + lane], q1 = XQ[base + lane + 32];
    float qi = 1.f / fmaxf(sqrtf(warpsum(q0*q0 + q1*q1)), 1e-12f);
    XQ[base + lane] = q0 * qi; XQ[base + lane + 32] = q1 * qi;
    float k0 = XK[base + lane], k1 = XK[base + lane + 32];
    float ki = 1.f / fmaxf(sqrtf(warpsum(k0*k0 + k1*k1)), 1e-12f);
    k0 *= ki; k1 *= ki;
    XK[base + lane] = k0; XK[base + lane + 32] = k1;
    float v0 = XV[base + lane], v1 = XV[base + lane + 32];
    float mu = warpsum(v0 + v1) * (1.f / 64.f);
    float d0 = v0 - mu, d1 = v1 - mu;
    float var = warpsum(d0*d0 + d1*d1) * (1.f / 64.f);
    float rstd = rsqrtf(var + EPSc);
    XV[base + lane]      = nw[h*64+lane]    * d0 * rstd + nb[h*64+lane]    + k0;
    XV[base + lane + 32] = nw[h*64+lane+32] * d1 * rstd + nb[h*64+lane+32] + k1;
}

__global__ __launch_bounds__(256) void lr_kernel(
    const float* __restrict__ x1, const float* __restrict__ lrw,
    const float* __restrict__ lrb, float* __restrict__ lro)
{
    int w = (blockIdx.x * blockDim.x + threadIdx.x) >> 5;
    if (w >= Bn * Sn * Hn) return;
    int lane = threadIdx.x & 31;
    int h = w & 15, bs = w >> 4;
    int b = bs >> 10, s = bs & (Sn - 1);
    const float* xr = x1 + (size_t)bs * Dn;
    const float* wr = lrw + h * Dn;
    float acc = 0.f;
    for (int c = lane; c < Dn; c += 32) acc += xr[c] * wr[c];
    acc = warpsum(acc);
    if (lane == 0)
        lro[(size_t)(b * Hn + h) * Sn + s] = 1.f / (1.f + __expf(-(acc + lrb[h])));
}

// ---------------- TTT scan: 512 thr, tensor-core phases A/D/E/Fcorr ------
// smem strides: sxv 65, ssc/sgZ2 68, transposed tiles 72, sW1 264, stage 264
#define SV 65
#define PS 68
#define TS 72
#define WS 264
#define SCAN_FLOATS (64*SV + 2*64*PS + 4*64*TS + 8*WS + 64*WS + 256 + 64 + 64)
#define SCAN_SMEM (SCAN_FLOATS * 4)

__global__ __launch_bounds__(512) void ttt_scan_kernel(
    const float* __restrict__ XQ, const float* __restrict__ XK, const float* __restrict__ XV,
    const float* __restrict__ lr,
    const float* __restrict__ W1i, const float* __restrict__ b1i,
    const float* __restrict__ W2i, const float* __restrict__ b2i,
    const float* __restrict__ nw,  const float* __restrict__ nb,
    float* __restrict__ W2G, float* __restrict__ W2TG,
    float* __restrict__ X2G, float* __restrict__ gZ1G, float* __restrict__ X2bG,
    float* __restrict__ outp)
{
    extern __shared__ float sm[];
    float* sxv   = sm;                 // [64][SV]
    float* ssc   = sxv  + 64 * SV;     // [64][PS]  Z2 / coef2 (natural)
    float* sgZ2  = ssc  + 64 * PS;     // [64][PS]  natural
    float* sxqT  = sgZ2 + 64 * PS;     // [e][TS]
    float* sxkT  = sxqT + 64 * TS;
    float* sscT  = sxkT + 64 * TS;     // coef1 negated, [k2][TS]
    float* sgZ2T = sscT + 64 * TS;     // [j][TS]
    float* sstg  = sgZ2T+ 64 * TS;     // [8][WS] staging
    float* sW1   = sstg + 8 * WS;      // [64][WS]
    float* b1sm  = sW1  + 64 * WS;     // 256
    float* b2sm  = b1sm + 256;         // 64
    float* seta  = b2sm + 64;          // 64

    int bh = blockIdx.x, b = bh >> 4, h = bh & 15;
    int tid = threadIdx.x, w = tid >> 5, l = tid & 31;
    int g = l >> 2, tg = l & 3;
    int ty2 = tid >> 4, tx2 = tid & 15;
    int ft = tid >> 3, jt = tid & 7;
    int mi = (w & 3) * 16, ng = (w >> 2) * 64;
    float* W2r  = W2G  + (size_t)bh * 16384;
    float* W2Tr = W2TG + (size_t)bh * 16384;
    float* X2r  = X2G  + (size_t)bh * 16384;
    float* gZ1r = gZ1G + (size_t)bh * 16384;
    float* X2br = X2bG + (size_t)bh * 16384;
    const float* nwh = nw + h * 64;
    const float* nbh = nb + h * 64;

    for (int idx = tid; idx < 16384; idx += 512) {
        int e = idx >> 8, f = idx & 255;
        sW1[e * WS + f] = W1i[(size_t)h * 16384 + idx];
        W2r[idx]  = W2i[(size_t)h * 16384 + idx];
        W2Tr[idx] = W2i[(size_t)h * 16384 + f * 64 + e];
    }
    if (tid < 256) b1sm[tid] = b1i[h * 256 + tid];
    if (tid < 64)  b2sm[tid] = b2i[h * 64 + tid];
    __syncthreads();

    for (int n = 0; n < NCn; n++) {
        size_t tokbase = (size_t)b * Sn + n * Cn;
        for (int idx = tid; idx < 4096; idx += 512) {
            int i = idx >> 6, e = idx & 63;
            size_t gg = (tokbase + i) * Dn + h * 64 + e;
            sxqT[e * TS + i] = XQ[gg];
            sxkT[e * TS + i] = XK[gg];
            sxv [i * SV + e] = XV[gg];
        }
        if (tid < 64) seta[tid] = lr[(size_t)bh * Sn + n * 64 + tid] * (1.f / 64.f);
        __syncthreads();

        // ---- A (mma, 2 passes): Z1=xk@W1+b1 -> X2,gb ; Z1q=xq@W1+b1 -> X2br
#pragma unroll
        for (int p = 0; p < 2; p++) {
            const float* T = p ? sxqT : sxkT;
            float c[8][4];
#pragma unroll
            for (int nt = 0; nt < 8; nt++) {
                int col = ng + nt * 8 + tg * 2;
                c[nt][0] = b1sm[col];   c[nt][1] = b1sm[col+1];
                c[nt][2] = b1sm[col];   c[nt][3] = b1sm[col+1];
            }
#pragma unroll
            for (int kb = 0; kb < 64; kb += 8) {
                unsigned a[4];
                a[0] = f2tf32(T[(kb+tg  )*TS + mi+g]);
                a[1] = f2tf32(T[(kb+tg  )*TS + mi+g+8]);
                a[2] = f2tf32(T[(kb+tg+4)*TS + mi+g]);
                a[3] = f2tf32(T[(kb+tg+4)*TS + mi+g+8]);
#pragma unroll
                for (int nt = 0; nt < 8; nt++) {
                    unsigned bb[2];
                    bb[0] = f2tf32(sW1[(kb+tg  )*WS + ng + nt*8 + g]);
                    bb[1] = f2tf32(sW1[(kb+tg+4)*WS + ng + nt*8 + g]);
                    mma_tf32(c[nt], a, bb);
                }
            }
#pragma unroll
            for (int nt = 0; nt < 8; nt++) {
                int col = ng + nt * 8 + tg * 2;
                int r0 = mi + g;
                if (p == 0) {
                    float x2o[4], gbo[4];
#pragma unroll
                    for (int r = 0; r < 4; r++) {
                        float z = c[nt][r];
                        float t = tanh_fast(0.79788456f * (z + 0.044715f * z * z * z));
                        x2o[r] = 0.5f * z * (1.f + t);
                        gbo[r] = 0.5f * z * (1.f - t * t) * (0.79788456f + 0.1070322243f * z * z)
                               + 0.5f * (1.f + t);
                    }
                    *(float2*)(X2r  + r0*256 + col)     = make_float2(x2o[0], x2o[1]);
                    *(float2*)(X2r  + (r0+8)*256 + col) = make_float2(x2o[2], x2o[3]);
                    *(float2*)(gZ1r + r0*256 + col)     = make_float2(gbo[0], gbo[1]);
                    *(float2*)(gZ1r + (r0+8)*256 + col) = make_float2(gbo[2], gbo[3]);
                } else {
                    *(float2*)(X2br + r0*256 + col)     = make_float2(c[nt][0], c[nt][1]);
                    *(float2*)(X2br + (r0+8)*256 + col) = make_float2(c[nt][2], c[nt][3]);
                }
            }
        }
        __syncthreads();

        // ---- B: Z2 = X2@W2 + b2 -> ssc (FFMA, W2 global)
        {
            float acc[2][4];
#pragma unroll
            for (int u = 0; u < 2; u++)
#pragma unroll
                for (int v = 0; v < 4; v++) acc[u][v] = b2sm[tx2 * 4 + v];
#pragma unroll 4
            for (int f0 = 0; f0 < 256; f0 += 4) {
                float4 a4[2], b4[4];
#pragma unroll
                for (int u = 0; u < 2; u++) a4[u] = *(const float4*)(X2r + (ty2*2+u)*256 + f0);
#pragma unroll
                for (int d = 0; d < 4; d++) b4[d] = *(const float4*)(W2r + (f0+d)*64 + tx2*4);
#pragma unroll
                for (int u = 0; u < 2; u++) {
                    acc[u][0] += a4[u].x*b4[0].x + a4[u].y*b4[1].x + a4[u].z*b4[2].x + a4[u].w*b4[3].x;
                    acc[u][1] += a4[u].x*b4[0].y + a4[u].y*b4[1].y + a4[u].z*b4[2].y + a4[u].w*b4[3].y;
                    acc[u][2] += a4[u].x*b4[0].z + a4[u].y*b4[1].z + a4[u].z*b4[2].z + a4[u].w*b4[3].z;
                    acc[u][3] += a4[u].x*b4[0].w + a4[u].y*b4[1].w + a4[u].z*b4[2].w + a4[u].w*b4[3].w;
                }
            }
#pragma unroll
            for (int u = 0; u < 2; u++)
#pragma unroll
                for (int v = 0; v < 4; v++) ssc[(ty2*2+u)*PS + tx2*4+v] = acc[u][v];
        }
        __syncthreads();

        // ---- C: gZ2 = ln_l2_bwd(Z2, xv-xk) -> sgZ2 + sgZ2T
        for (int i = w; i < 64; i += 16) {
            float z0 = ssc[i*PS + l], z1 = ssc[i*PS + l + 32];
            float mu = warpsum(z0 + z1) * (1.f/64.f);
            float d0 = z0 - mu, d1 = z1 - mu;
            float var = warpsum(d0*d0 + d1*d1) * (1.f/64.f);
            float rstd = rsqrtf(var + EPSc);
            float xh0 = d0 * rstd, xh1 = d1 * rstd;
            float g0 = nwh[l], g1 = nwh[l+32];
            float t0 = sxv[i*SV + l]      - sxkT[l*TS + i];
            float t1 = sxv[i*SV + l + 32] - sxkT[(l+32)*TS + i];
            float gh0 = (g0*xh0 + nbh[l]    - t0) * g0;
            float gh1 = (g1*xh1 + nbh[l+32] - t1) * g1;
            float sgh = warpsum(gh0 + gh1);
            float sgx = warpsum(gh0*xh0 + gh1*xh1);
            float cc = rstd * (1.f/64.f);
            float o0 = (64.f*gh0 - sgh - xh0*sgx) * cc;
            float o1 = (64.f*gh1 - sgh - xh1*sgx) * cc;
            sgZ2[i*PS + l]        = o0;
            sgZ2[i*PS + l + 32]   = o1;
            sgZ2T[l*TS + i]       = o0;
            sgZ2T[(l+32)*TS + i]  = o1;
        }
        __syncthreads();

        // ---- D (mma): gZ1 = (gZ2 @ W2^T) * gb
        {
            float c[8][4];
#pragma unroll
            for (int nt = 0; nt < 8; nt++)
#pragma unroll
                for (int r = 0; r < 4; r++) c[nt][r] = 0.f;
#pragma unroll
            for (int kb = 0; kb < 64; kb += 8) {
                __syncthreads();
                for (int idx = tid; idx < 2048; idx += 512) {
                    int rr = idx >> 8, cf = idx & 255;
                    sstg[rr*WS + cf] = W2Tr[(kb+rr)*256 + cf];
                }
                __syncthreads();
                unsigned a[4];
                a[0] = f2tf32(sgZ2T[(kb+tg  )*TS + mi+g]);
                a[1] = f2tf32(sgZ2T[(kb+tg  )*TS + mi+g+8]);
                a[2] = f2tf32(sgZ2T[(kb+tg+4)*TS + mi+g]);
                a[3] = f2tf32(sgZ2T[(kb+tg+4)*TS + mi+g+8]);
#pragma unroll
                for (int nt = 0; nt < 8; nt++) {
                    unsigned bb[2];
                    bb[0] = f2tf32(sstg[(tg  )*WS + ng + nt*8 + g]);
                    bb[1] = f2tf32(sstg[(tg+4)*WS + ng + nt*8 + g]);
                    mma_tf32(c[nt], a, bb);
                }
            }
#pragma unroll
            for (int nt = 0; nt < 8; nt++) {
                int col = ng + nt * 8 + tg * 2;
                int r0 = mi + g;
                float2 gb0 = *(const float2*)(gZ1r + r0*256 + col);
                float2 gb1 = *(const float2*)(gZ1r + (r0+8)*256 + col);
                *(float2*)(gZ1r + r0*256 + col)     = make_float2(c[nt][0]*gb0.x, c[nt][1]*gb0.y);
                *(float2*)(gZ1r + (r0+8)*256 + col) = make_float2(c[nt][2]*gb1.x, c[nt][3]*gb1.y);
            }
        }
        __syncthreads();

        // ---- E (mma): coef1 = -eta[k2]*(tril(xq@xk^T)+1) -> sscT [k2][i]
#pragma unroll
        for (int sub = 0; sub < 2; sub++) {
            int ncol = ((w >> 2) * 2 + sub) * 8;
            float c[4] = {0.f, 0.f, 0.f, 0.f};
#pragma unroll
            for (int kb = 0; kb < 64; kb += 8) {
                unsigned a[4], bb[2];
                a[0] = f2tf32(sxqT[(kb+tg  )*TS + mi+g]);
                a[1] = f2tf32(sxqT[(kb+tg  )*TS + mi+g+8]);
                a[2] = f2tf32(sxqT[(kb+tg+4)*TS + mi+g]);
                a[3] = f2tf32(sxqT[(kb+tg+4)*TS + mi+g+8]);
                bb[0] = f2tf32(sxkT[(kb+tg  )*TS + ncol + g]);
                bb[1] = f2tf32(sxkT[(kb+tg+4)*TS + ncol + g]);
                mma_tf32(c, a, bb);
            }
            int r0 = mi + g, k2 = ncol + tg * 2;
            sscT[k2*TS + r0]       = (k2   <= r0)   ? -seta[k2]  *(c[0]+1.f) : 0.f;
            sscT[(k2+1)*TS + r0]   = (k2+1 <= r0)   ? -seta[k2+1]*(c[1]+1.f) : 0.f;
            sscT[k2*TS + r0+8]     = (k2   <= r0+8) ? -seta[k2]  *(c[2]+1.f) : 0.f;
            sscT[(k2+1)*TS + r0+8] = (k2+1 <= r0+8) ? -seta[k2+1]*(c[3]+1.f) : 0.f;
        }
        __syncthreads();

        // ---- F (mma): Z1b = Z1q + coef1neg@gZ1 ; X2b = gelu
        {
            float c[8][4];
#pragma unroll
            for (int nt = 0; nt < 8; nt++) {
                int col = ng + nt * 8 + tg * 2;
                int r0 = mi + g;
                float2 q0 = *(const float2*)(X2br + r0*256 + col);
                float2 q1 = *(const float2*)(X2br + (r0+8)*256 + col);
                c[nt][0] = q0.x; c[nt][1] = q0.y; c[nt][2] = q1.x; c[nt][3] = q1.y;
            }
#pragma unroll
            for (int kb = 0; kb < 64; kb += 8) {
                __syncthreads();
                for (int idx = tid; idx < 2048; idx += 512) {
                    int rr = idx >> 8, cf = idx & 255;
                    sstg[rr*WS + cf] = gZ1r[(kb+rr)*256 + cf];
                }
                __syncthreads();
                unsigned a[4];
                a[0] = f2tf32(sscT[(kb+tg  )*TS + mi+g]);
                a[1] = f2tf32(sscT[(kb+tg  )*TS + mi+g+8]);
                a[2] = f2tf32(sscT[(kb+tg+4)*TS + mi+g]);
                a[3] = f2tf32(sscT[(kb+tg+4)*TS + mi+g+8]);
#pragma unroll
                for (int nt = 0; nt < 8; nt++) {
                    unsigned bb[2];
                    bb[0] = f2tf32(sstg[(tg  )*WS + ng + nt*8 + g]);
                    bb[1] = f2tf32(sstg[(tg+4)*WS + ng + nt*8 + g]);
                    mma_tf32(c[nt], a, bb);
                }
            }
#pragma unroll
            for (int nt = 0; nt < 8; nt++) {
                int col = ng + nt * 8 + tg * 2;
                int r0 = mi + g;
                float xo[4];
#pragma unroll
                for (int r = 0; r < 4; r++) {
                    float z = c[nt][r];
                    float t = tanh_fast(0.79788456f * (z + 0.044715f * z * z * z));
                    xo[r] = 0.5f * z * (1.f + t);
                }
                *(float2*)(X2br + r0*256 + col)     = make_float2(xo[0], xo[1]);
                *(float2*)(X2br + (r0+8)*256 + col) = make_float2(xo[2], xo[3]);
            }
        }
        __syncthreads();

        // ---- G: coef2 = eta[j]*(tril(X2b@X2^T)+1) -> ssc (FFMA)
        {
            float acc[2][4];
#pragma unroll
            for (int u = 0; u < 2; u++)
#pragma unroll
                for (int v = 0; v < 4; v++) acc[u][v] = 0.f;
            if (tx2 * 4 <= ty2 * 2 + 1) {
#pragma unroll 2
                for (int f0 = 0; f0 < 256; f0 += 4) {
                    float4 a4[2], b4[4];
#pragma unroll
                    for (int u = 0; u < 2; u++) a4[u] = *(const float4*)(X2br + (ty2*2+u)*256 + f0);
#pragma unroll
                    for (int v = 0; v < 4; v++) b4[v] = *(const float4*)(X2r + (tx2*4+v)*256 + f0);
#pragma unroll
                    for (int u = 0; u < 2; u++)
#pragma unroll
                        for (int v = 0; v < 4; v++)
                            acc[u][v] += a4[u].x*b4[v].x + a4[u].y*b4[v].y
                                       + a4[u].z*b4[v].z + a4[u].w*b4[v].w;
                }
            }
#pragma unroll
            for (int u = 0; u < 2; u++) {
                int i = ty2 * 2 + u;
#pragma unroll
                for (int v = 0; v < 4; v++) {
                    int j = tx2 * 4 + v;
                    ssc[i*PS + j] = (j <= i) ? seta[j] * (acc[u][v] + 1.f) : 0.f;
                }
            }
        }
        __syncthreads();

        // ---- H: Z2b = X2b@W2 + b2 - coef2@gZ2 -> sxv (FFMA, W2 global)
        {
            float acc[2][4];
#pragma unroll
            for (int u = 0; u < 2; u++)
#pragma unroll
                for (int v = 0; v < 4; v++) acc[u][v] = b2sm[tx2 * 4 + v];
#pragma unroll 4
            for (int f0 = 0; f0 < 256; f0 += 4) {
                float4 a4[2], b4[4];
#pragma unroll
                for (int u = 0; u < 2; u++) a4[u] = *(const float4*)(X2br + (ty2*2+u)*256 + f0);
#pragma unroll
                for (int d = 0; d < 4; d++) b4[d] = *(const float4*)(W2r + (f0+d)*64 + tx2*4);
#pragma unroll
                for (int u = 0; u < 2; u++) {
                    acc[u][0] += a4[u].x*b4[0].x + a4[u].y*b4[1].x + a4[u].z*b4[2].x + a4[u].w*b4[3].x;
                    acc[u][1] += a4[u].x*b4[0].y + a4[u].y*b4[1].y + a4[u].z*b4[2].y + a4[u].w*b4[3].y;
                    acc[u][2] += a4[u].x*b4[0].z + a4[u].y*b4[1].z + a4[u].z*b4[2].z + a4[u].w*b4[3].z;
                    acc[u][3] += a4[u].x*b4[0].w + a4[u].y*b4[1].w + a4[u].z*b4[2].w + a4[u].w*b4[3].w;
                }
            }
#pragma unroll 4
            for (int k2 = 0; k2 < 64; k2++) {
                float cc0 = ssc[(ty2*2)*PS + k2];
                float cc1 = ssc[(ty2*2+1)*PS + k2];
                float4 gv4 = *(const float4*)(sgZ2 + k2*PS + tx2*4);
                acc[0][0] -= cc0*gv4.x; acc[0][1] -= cc0*gv4.y; acc[0][2] -= cc0*gv4.z; acc[0][3] -= cc0*gv4.w;
                acc[1][0] -= cc1*gv4.x; acc[1][1] -= cc1*gv4.y; acc[1][2] -= cc1*gv4.z; acc[1][3] -= cc1*gv4.w;
            }
#pragma unroll
            for (int u = 0; u < 2; u++)
#pragma unroll
                for (int v = 0; v < 4; v++) sxv[(ty2*2+u)*SV + tx2*4+v] = acc[u][v];
        }
        __syncthreads();

        // ---- I: out = xq + LN(Z2b)
        for (int i = w; i < 64; i += 16) {
            float z0 = sxv[i*SV + l], z1 = sxv[i*SV + l + 32];
            float mu = warpsum(z0 + z1) * (1.f/64.f);
            float d0 = z0 - mu, d1 = z1 - mu;
            float var = warpsum(d0*d0 + d1*d1) * (1.f/64.f);
            float rstd = rsqrtf(var + EPSc);
            size_t gg = (tokbase + i) * Dn + h * 64;
            outp[gg + l]      = sxqT[l*TS + i]      + nwh[l]    * d0 * rstd + nbh[l];
            outp[gg + l + 32] = sxqT[(l+32)*TS + i] + nwh[l+32] * d1 * rstd + nbh[l+32];
        }

        // ---- J1: W1 -= (eta*xk)^T @ gZ1  (sW1 smem, FFMA2)
        {
            u64 acc2[4][4];
#pragma unroll
            for (int u = 0; u < 4; u++)
#pragma unroll
                for (int p = 0; p < 4; p++) acc2[u][p] = 0ULL;
#pragma unroll 4
            for (int i = 0; i < 64; i++) {
                float et = seta[i];
                float4 g0 = *(const float4*)(gZ1r + i*256 + l*8);
                float4 g1 = *(const float4*)(gZ1r + i*256 + l*8 + 4);
                u64 gv2[4];
                f4tou2(g0, gv2[0], gv2[1]); f4tou2(g1, gv2[2], gv2[3]);
#pragma unroll
                for (int u = 0; u < 4; u++) {
                    float a = et * sxkT[(w*4+u)*TS + i];
                    u64 a2 = f2pack(a, a);
#pragma unroll
                    for (int p = 0; p < 4; p++) acc2[u][p] = ffma2(a2, gv2[p], acc2[u][p]);
                }
            }
#pragma unroll
            for (int u = 0; u < 4; u++) {
                int e = w * 4 + u;
                float av[8];
#pragma unroll
                for (int p = 0; p < 4; p++) f2unpack(acc2[u][p], av[2*p], av[2*p+1]);
                float4* wp = (float4*)(sW1 + e*WS + l*8);
                float4 o0 = wp[0], o1 = wp[1];
                wp[0] = make_float4(o0.x-av[0], o0.y-av[1], o0.z-av[2], o0.w-av[3]);
                wp[1] = make_float4(o1.x-av[4], o1.y-av[5], o1.z-av[6], o1.w-av[7]);
            }
        }
        // J2: b1
        if (tid < 256) {
            float acc = 0.f;
#pragma unroll 8
            for (int i = 0; i < 64; i++) acc += seta[i] * gZ1r[i*256 + tid];
            b1sm[tid] -= acc;
        }
        // J3: W2 (global) and W2T (global)
        {
            u64 acc2[4][4];
#pragma unroll
            for (int u = 0; u < 4; u++)
#pragma unroll
                for (int p = 0; p < 4; p++) acc2[u][p] = 0ULL;
#pragma unroll 4
            for (int i = 0; i < 64; i++) {
                float et = seta[i];
                float4 x0 = *(const float4*)(X2r + i*256 + ft*4);
                float4 gv0 = *(const float4*)(sgZ2 + i*PS + jt*8);
                float4 gv1 = *(const float4*)(sgZ2 + i*PS + jt*8 + 4);
                u64 gv2[4];
                f4tou2(gv0, gv2[0], gv2[1]); f4tou2(gv1, gv2[2], gv2[3]);
                float a[4] = {et*x0.x, et*x0.y, et*x0.z, et*x0.w};
#pragma unroll
                for (int u = 0; u < 4; u++) {
                    u64 a2 = f2pack(a[u], a[u]);
#pragma unroll
                    for (int p = 0; p < 4; p++) acc2[u][p] = ffma2(a2, gv2[p], acc2[u][p]);
                }
            }
#pragma unroll
            for (int u = 0; u < 4; u++) {
                int f = ft * 4 + u;
                float av[8];
#pragma unroll
                for (int p = 0; p < 4; p++) f2unpack(acc2[u][p], av[2*p], av[2*p+1]);
                float4* wp0 = (float4*)(W2r + f*64 + jt*8);
                float4* wp1 = (float4*)(W2r + f*64 + jt*8 + 4);
                float4 o0 = wp0[0], o1 = wp1[0];
                wp0[0] = make_float4(o0.x-av[0], o0.y-av[1], o0.z-av[2], o0.w-av[3]);
                wp1[0] = make_float4(o1.x-av[4], o1.y-av[5], o1.z-av[6], o1.w-av[7]);
#pragma unroll
                for (int v = 0; v < 8; v++)
                    W2Tr[(jt*8+v)*256 + f] -= av[v];
            }
        }
        // J4: b2
        if (tid < 64) {
            float acc = 0.f;
#pragma unroll 8
            for (int i = 0; i < 64; i++) acc += seta[i] * sgZ2[i*PS + tid];
            b2sm[tid] -= acc;
        }
        __syncthreads();
    }
}

// ---------------- Launch ----------------
extern "C" void kernel_launch(void* const* d_in, const int* in_sizes, int n_in,
                              void* d_out, int out_size)
{
    const float* x       = (const float*)d_in[0];
    const float* ln1_w   = (const float*)d_in[1];
    const float* ln1_b   = (const float*)d_in[2];
    const float* attn_wq = (const float*)d_in[3];
    const float* attn_wk = (const float*)d_in[4];
    const float* attn_wv = (const float*)d_in[5];
    const float* attn_wo = (const float*)d_in[6];
    const float* wq_w    = (const float*)d_in[7];
    const float* wq_b    = (const float*)d_in[8];
    const float* wk_w    = (const float*)d_in[9];
    const float* wk_b    = (const float*)d_in[10];
    const float* wv_w    = (const float*)d_in[11];
    const float* wv_b    = (const float*)d_in[12];
    const float* wo_w    = (const float*)d_in[13];
    const float* wo_b    = (const float*)d_in[14];
    const float* W1      = (const float*)d_in[15];
    const float* b1      = (const float*)d_in[16];
    const float* W2      = (const float*)d_in[17];
    const float* b2      = (const float*)d_in[18];
    const float* ttt_nw  = (const float*)d_in[19];
    const float* ttt_nb  = (const float*)d_in[20];
    const float* lr_w    = (const float*)d_in[21];
    const float* lr_b    = (const float*)d_in[22];
    const float* pn_w    = (const float*)d_in[23];
    const float* pn_b    = (const float*)d_in[24];
    const float* gate_a  = (const float*)d_in[25];
    float* out = (float*)d_out;

    float *p_h,*p_q,*p_k,*p_v,*p_o,*p_x1,*p_lr,*p_W2,*p_W2T,*p_X2,*p_gZ1,*p_X2b;
    cudaGetSymbolAddress((void**)&p_h,  g_h);
    cudaGetSymbolAddress((void**)&p_q,  g_q);
    cudaGetSymbolAddress((void**)&p_k,  g_k);
    cudaGetSymbolAddress((void**)&p_v,  g_v);
    cudaGetSymbolAddress((void**)&p_o,  g_o);
    cudaGetSymbolAddress((void**)&p_x1, g_x1);
    cudaGetSymbolAddress((void**)&p_lr, g_lr);
    cudaGetSymbolAddress((void**)&p_W2, g_W2s);
    cudaGetSymbolAddress((void**)&p_W2T,g_W2Ts);
    cudaGetSymbolAddress((void**)&p_X2, g_X2);
    cudaGetSymbolAddress((void**)&p_gZ1,g_gZ1);
    cudaGetSymbolAddress((void**)&p_X2b,g_X2b);

    cudaFuncSetAttribute(ttt_scan_kernel,   cudaFuncAttributeMaxDynamicSharedMemorySize, SCAN_SMEM);
    cudaFuncSetAttribute(attn_flash_kernel, cudaFuncAttributeMaxDynamicSharedMemorySize, ATT_SMEM);

    const int M = Bn * Sn;
    dim3 ggrid(Dn / 128, M / 128);
    dim3 ggrid3(Dn / 128, M / 128, 3);
    int nwarp_grid = (Bn * Sn * Hn) / 8;

    ln_kernel<<<M, 256>>>(x, ln1_w, ln1_b, p_h);
    gemm3_nt_kernel<<<ggrid3, 256>>>(p_h, attn_wq, attn_wk, attn_wv,
                                     p_q, p_k, p_v, nullptr, nullptr, nullptr);
    attn_flash_kernel<<<dim3(16, 64), 256, ATT_SMEM>>>(p_q, p_k, p_v, p_o);
    gemm_nt_kernel<<<ggrid, 256>>>(p_o, attn_wo, p_x1, nullptr, x, nullptr);
    gemm3_nt_kernel<<<ggrid3, 256>>>(p_x1, wq_w, wk_w, wv_w,
                                     p_q, p_k, p_v, wq_b, wk_b, wv_b);
    prep_kernel<<<nwarp_grid, 256>>>(p_q, p_k, p_v, ttt_nw, ttt_nb);
    lr_kernel<<<nwarp_grid, 256>>>(p_x1, lr_w, lr_b, p_lr);
    ttt_scan_kernel<<<Bn * Hn, 512, SCAN_SMEM>>>(
        p_q, p_k, p_v, p_lr, W1, b1, W2, b2, ttt_nw, ttt_nb,
        p_W2, p_W2T, p_X2, p_gZ1, p_X2b, p_o);
    ln_kernel<<<M, 256>>>(p_o, pn_w, pn_b, p_h);
    gemm_nt_kernel<<<ggrid, 256>>>(p_h, wo_w, out, wo_b, p_x1, gate_a);
}

// round 12
// speedup vs baseline: 1.6073x; 1.0959x over previous
#include <cuda_runtime.h>
#include <math.h>

#define Bn 4
#define Sn 1024
#define Dn 1024
#define Hn 16
#define HDn 64
#define Cn 64
#define NCn 16
#define DFFn 256
#define EPSc 1e-6f
#define BSD (Bn*Sn*Dn)

typedef unsigned long long u64;
__device__ __forceinline__ u64 f2pack(float lo, float hi) {
    u64 r; asm("mov.b64 %0, {%1, %2};" : "=l"(r) : "f"(lo), "f"(hi)); return r;
}
__device__ __forceinline__ void f2unpack(u64 p, float& lo, float& hi) {
    asm("mov.b64 {%0, %1}, %2;" : "=f"(lo), "=f"(hi) : "l"(p));
}
__device__ __forceinline__ u64 ffma2(u64 a, u64 b, u64 c) {
    u64 d; asm("fma.rn.f32x2 %0, %1, %2, %3;" : "=l"(d) : "l"(a), "l"(b), "l"(c)); return d;
}
__device__ __forceinline__ void f4tou2(float4 f, u64& p0, u64& p1) {
    p0 = f2pack(f.x, f.y); p1 = f2pack(f.z, f.w);
}
__device__ __forceinline__ unsigned f2tf32(float f) {
    unsigned r; asm("cvt.rna.tf32.f32 %0, %1;" : "=r"(r) : "f"(f)); return r;
}
__device__ __forceinline__ void mma_tf32(float* c, const unsigned* a, const unsigned* b) {
    asm volatile("mma.sync.aligned.m16n8k8.row.col.f32.tf32.tf32.f32 "
        "{%0,%1,%2,%3}, {%4,%5,%6,%7}, {%8,%9}, {%0,%1,%2,%3};"
        : "+f"(c[0]), "+f"(c[1]), "+f"(c[2]), "+f"(c[3])
        : "r"(a[0]), "r"(a[1]), "r"(a[2]), "r"(a[3]), "r"(b[0]), "r"(b[1]));
}

__device__ float g_h [BSD];
__device__ float g_q [BSD];
__device__ float g_k [BSD];
__device__ float g_v [BSD];
__device__ float g_o [BSD];
__device__ float g_x1[BSD];
__device__ float g_lr[Bn*Hn*Sn];
__device__ float g_W2s [Bn*Hn*16384];
__device__ float g_W2Ts[Bn*Hn*16384];
__device__ float g_X2  [Bn*Hn*16384];
__device__ float g_gZ1 [Bn*Hn*16384];
__device__ float g_X2b [Bn*Hn*16384];

__device__ __forceinline__ float warpsum(float v) {
#pragma unroll
    for (int o = 16; o > 0; o >>= 1) v += __shfl_xor_sync(0xffffffffu, v, o);
    return v;
}
__device__ __forceinline__ float warpmax(float v) {
#pragma unroll
    for (int o = 16; o > 0; o >>= 1) v = fmaxf(v, __shfl_xor_sync(0xffffffffu, v, o));
    return v;
}
__device__ __forceinline__ float blocksum256(float v) {
    __shared__ float red[8];
    int lane = threadIdx.x & 31, w = threadIdx.x >> 5;
    v = warpsum(v);
    if (lane == 0) red[w] = v;
    __syncthreads();
    float r = (lane < 8) ? red[lane] : 0.f;
    r = warpsum(r);
    __syncthreads();
    return r;
}
__device__ __forceinline__ float tanh_fast(float x) {
    float e = __expf(2.f * x);
    return 1.f - __fdividef(2.f, e + 1.f);
}

// ---------------- LayerNorm rows of 1024 ----------------
__global__ __launch_bounds__(256) void ln_kernel(
    const float* __restrict__ x, const float* __restrict__ g,
    const float* __restrict__ b, float* __restrict__ y)
{
    int row = blockIdx.x, tid = threadIdx.x;
    const float* xr = x + (size_t)row * Dn;
    float v[4]; float s = 0.f;
#pragma unroll
    for (int i = 0; i < 4; i++) { v[i] = xr[tid + 256 * i]; s += v[i]; }
    s = blocksum256(s);
    float mu = s * (1.f / Dn), ss = 0.f;
#pragma unroll
    for (int i = 0; i < 4; i++) { float d = v[i] - mu; ss += d * d; }
    ss = blocksum256(ss);
    float rstd = rsqrtf(ss * (1.f / Dn) + EPSc);
    float* yr = y + (size_t)row * Dn;
#pragma unroll
    for (int i = 0; i < 4; i++) {
        int c = tid + 256 * i;
        yr[c] = (v[i] - mu) * rstd * g[c] + b[c];
    }
}

// ---------------- tf32 tensor-core GEMM ----------------
#define GSTR 136
__device__ __forceinline__ void gemm_core(
    const float* __restrict__ A, const float* __restrict__ B, float* __restrict__ C,
    const float* __restrict__ bias, const float* __restrict__ res,
    const float* __restrict__ gate, int bm, int bn)
{
    const int N = 1024, K = 1024, BK = 16;
    __shared__ unsigned As[BK][GSTR];
    __shared__ unsigned Bs[BK][GSTR];
    int t = threadIdx.x;
    int warp = t >> 5, lane = t & 31;
    int wm = warp >> 1, wn = warp & 1;
    int g = lane >> 2, tg = lane & 3;

    float acc[2][8][4];
#pragma unroll
    for (int mt = 0; mt < 2; mt++)
#pragma unroll
        for (int nt = 0; nt < 8; nt++)
#pragma unroll
            for (int r = 0; r < 4; r++) acc[mt][nt][r] = 0.f;

    int r128 = t >> 1, kc = (t & 1) * 8;
    const float* Ab = A + (size_t)(bm + r128) * K + kc;
    const float* Bb = B + (size_t)(bn + r128) * K + kc;
    float4 a0 = *(const float4*)(Ab);
    float4 a1 = *(const float4*)(Ab + 4);
    float4 b0 = *(const float4*)(Bb);
    float4 b1 = *(const float4*)(Bb + 4);

    for (int k0 = 0; k0 < K; k0 += BK) {
        As[kc+0][r128]=f2tf32(a0.x); As[kc+1][r128]=f2tf32(a0.y);
        As[kc+2][r128]=f2tf32(a0.z); As[kc+3][r128]=f2tf32(a0.w);
        As[kc+4][r128]=f2tf32(a1.x); As[kc+5][r128]=f2tf32(a1.y);
        As[kc+6][r128]=f2tf32(a1.z); As[kc+7][r128]=f2tf32(a1.w);
        Bs[kc+0][r128]=f2tf32(b0.x); Bs[kc+1][r128]=f2tf32(b0.y);
        Bs[kc+2][r128]=f2tf32(b0.z); Bs[kc+3][r128]=f2tf32(b0.w);
        Bs[kc+4][r128]=f2tf32(b1.x); Bs[kc+5][r128]=f2tf32(b1.y);
        Bs[kc+6][r128]=f2tf32(b1.z); Bs[kc+7][r128]=f2tf32(b1.w);
        __syncthreads();
        if (k0 + BK < K) {
            a0 = *(const float4*)(Ab + k0 + BK);
            a1 = *(const float4*)(Ab + k0 + BK + 4);
            b0 = *(const float4*)(Bb + k0 + BK);
            b1 = *(const float4*)(Bb + k0 + BK + 4);
        }
#pragma unroll
        for (int ks = 0; ks < 2; ks++) {
            int kb = ks * 8;
            unsigned af[2][4], bf[8][2];
#pragma unroll
            for (int mt = 0; mt < 2; mt++) {
                int mb = wm * 32 + mt * 16 + g;
                af[mt][0] = As[kb+tg  ][mb];
                af[mt][1] = As[kb+tg  ][mb+8];
                af[mt][2] = As[kb+tg+4][mb];
                af[mt][3] = As[kb+tg+4][mb+8];
            }
#pragma unroll
            for (int nt = 0; nt < 8; nt++) {
                int nb = wn * 64 + nt * 8 + g;
                bf[nt][0] = Bs[kb+tg  ][nb];
                bf[nt][1] = Bs[kb+tg+4][nb];
            }
#pragma unroll
            for (int mt = 0; mt < 2; mt++)
#pragma unroll
                for (int nt = 0; nt < 8; nt++)
                    mma_tf32(acc[mt][nt], af[mt], bf[nt]);
        }
        __syncthreads();
    }

    float bs2[8][2], gv2[8][2];
#pragma unroll
    for (int nt = 0; nt < 8; nt++) {
        int col = bn + wn * 64 + nt * 8 + tg * 2;
        if (bias) { bs2[nt][0] = bias[col]; bs2[nt][1] = bias[col+1]; }
        else      { bs2[nt][0] = 0.f;       bs2[nt][1] = 0.f; }
        if (gate) { gv2[nt][0] = tanhf(gate[col]); gv2[nt][1] = tanhf(gate[col+1]); }
    }
#pragma unroll
    for (int mt = 0; mt < 2; mt++) {
        int row0 = bm + wm * 32 + mt * 16 + g;
#pragma unroll
        for (int nt = 0; nt < 8; nt++) {
            int col = bn + wn * 64 + nt * 8 + tg * 2;
            float v0 = acc[mt][nt][0] + bs2[nt][0];
            float v1 = acc[mt][nt][1] + bs2[nt][1];
            float v2 = acc[mt][nt][2] + bs2[nt][0];
            float v3 = acc[mt][nt][3] + bs2[nt][1];
            if (gate) {
                float2 r0 = *(const float2*)(res + (size_t)row0 * N + col);
                float2 r1 = *(const float2*)(res + (size_t)(row0+8) * N + col);
                v0 = r0.x + gv2[nt][0] * v0; v1 = r0.y + gv2[nt][1] * v1;
                v2 = r1.x + gv2[nt][0] * v2; v3 = r1.y + gv2[nt][1] * v3;
            } else if (res) {
                float2 r0 = *(const float2*)(res + (size_t)row0 * N + col);
                float2 r1 = *(const float2*)(res + (size_t)(row0+8) * N + col);
                v0 += r0.x; v1 += r0.y; v2 += r1.x; v3 += r1.y;
            }
            *(float2*)(C + (size_t)row0 * N + col)     = make_float2(v0, v1);
            *(float2*)(C + (size_t)(row0+8) * N + col) = make_float2(v2, v3);
        }
    }
}

__global__ __launch_bounds__(256, 2) void gemm_nt_kernel(
    const float* __restrict__ A, const float* __restrict__ B, float* __restrict__ C,
    const float* __restrict__ bias, const float* __restrict__ res,
    const float* __restrict__ gate)
{
    gemm_core(A, B, C, bias, res, gate, blockIdx.y * 128, blockIdx.x * 128);
}

__global__ __launch_bounds__(256, 2) void gemm3_nt_kernel(
    const float* __restrict__ A,
    const float* __restrict__ B0, const float* __restrict__ B1, const float* __restrict__ B2,
    float* __restrict__ C0, float* __restrict__ C1, float* __restrict__ C2,
    const float* __restrict__ b0, const float* __restrict__ b1, const float* __restrict__ b2)
{
    const float* B; float* C; const float* bias;
    if (blockIdx.z == 0)      { B = B0; C = C0; bias = b0; }
    else if (blockIdx.z == 1) { B = B1; C = C1; bias = b1; }
    else                      { B = B2; C = C2; bias = b2; }
    gemm_core(A, B, C, bias, nullptr, nullptr, blockIdx.y * 128, blockIdx.x * 128);
}

// ---------------- Flash attention: tf32 mma ----------------
#define ATS 72
#define APS 65
#define ASS 68
#define ATT_SMEM ((3*64*ATS + 64*APS + 64*ASS + 192) * 4)

__global__ __launch_bounds__(256) void attn_flash_kernel(
    const float* __restrict__ q, const float* __restrict__ k,
    const float* __restrict__ v, float* __restrict__ o)
{
    extern __shared__ float sm[];
    unsigned* QsT = (unsigned*)sm;          // [e][ATS] tf32
    unsigned* KsT = QsT + 64 * ATS;         // [e][ATS]
    unsigned* Vs  = KsT + 64 * ATS;         // [j][ATS]
    unsigned* PsT = Vs  + 64 * ATS;         // [j][APS]
    float* Ss   = (float*)(PsT + 64 * APS); // [i][ASS]
    float* smm  = Ss + 64 * ASS;            // 64
    float* sml  = smm + 64;                 // 64
    float* scor = sml + 64;                 // 64

    int qt = blockIdx.x, bh = blockIdx.y;
    int b = bh >> 4, h = bh & 15;
    int tid = threadIdx.x, warp = tid >> 5, lane = tid & 31;
    int wm = warp >> 1, wn = warp & 1;
    int mi = wm * 16, ng = wn * 32;
    int g = lane >> 2, tg = lane & 3;
    size_t base = ((size_t)b * Sn) * Dn + h * HDn;

    for (int idx = tid; idx < 4096; idx += 256) {
        int r = idx >> 6, e = idx & 63;
        QsT[e * ATS + r] = f2tf32(q[base + (size_t)(qt * 64 + r) * Dn + e] * 0.125f);
    }
    if (tid < 64) { smm[tid] = -1e30f; sml[tid] = 0.f; }
    float co[4][4];
#pragma unroll
    for (int nt = 0; nt < 4; nt++)
#pragma unroll
        for (int r = 0; r < 4; r++) co[nt][r] = 0.f;
    __syncthreads();

    for (int kt = 0; kt <= qt; kt++) {
        for (int idx = tid; idx < 4096; idx += 256) {
            int r = idx >> 6, e = idx & 63;
            size_t gg = base + (size_t)(kt * 64 + r) * Dn + e;
            KsT[e * ATS + r] = f2tf32(k[gg]);
            Vs [r * ATS + e] = f2tf32(v[gg]);
        }
        __syncthreads();

        // S = Q K^T (mma)
        float c[4][4];
#pragma unroll
        for (int nt = 0; nt < 4; nt++)
#pragma unroll
            for (int r = 0; r < 4; r++) c[nt][r] = 0.f;
#pragma unroll
        for (int kb = 0; kb < 64; kb += 8) {
            unsigned a[4];
            a[0] = QsT[(kb+tg  )*ATS + mi+g];
            a[1] = QsT[(kb+tg  )*ATS + mi+g+8];
            a[2] = QsT[(kb+tg+4)*ATS + mi+g];
            a[3] = QsT[(kb+tg+4)*ATS + mi+g+8];
#pragma unroll
            for (int nt = 0; nt < 4; nt++) {
                unsigned bb[2];
                bb[0] = KsT[(kb+tg  )*ATS + ng + nt*8 + g];
                bb[1] = KsT[(kb+tg+4)*ATS + ng + nt*8 + g];
                mma_tf32(c[nt], a, bb);
            }
        }
        bool diag = (kt == qt);
        int r0 = mi + g, r1 = mi + g + 8;
#pragma unroll
        for (int nt = 0; nt < 4; nt++) {
            int col = ng + nt * 8 + tg * 2;
            if (diag) {
                if (col   > r0) c[nt][0] = -1e30f;
                if (col+1 > r0) c[nt][1] = -1e30f;
                if (col   > r1) c[nt][2] = -1e30f;
                if (col+1 > r1) c[nt][3] = -1e30f;
            }
            Ss[r0*ASS + col]   = c[nt][0];
            Ss[r0*ASS + col+1] = c[nt][1];
            Ss[r1*ASS + col]   = c[nt][2];
            Ss[r1*ASS + col+1] = c[nt][3];
        }
        __syncthreads();

        // online softmax rows (warp per 8 rows)
        for (int i = warp; i < 64; i += 8) {
            float s0 = Ss[i*ASS + lane], s1 = Ss[i*ASS + lane + 32];
            float mx = warpmax(fmaxf(s0, s1));
            float nm = fmaxf(smm[i], mx);
            float corr = __expf(smm[i] - nm);
            float p0 = __expf(s0 - nm), p1 = __expf(s1 - nm);
            float ps = warpsum(p0 + p1);
            if (lane == 0) { sml[i] = sml[i] * corr + ps; smm[i] = nm; scor[i] = corr; }
            PsT[lane*APS + i]      = f2tf32(p0);
            PsT[(lane+32)*APS + i] = f2tf32(p1);
        }
        __syncthreads();

        // O = O*corr + P V (mma)
        float cr0 = scor[r0], cr1 = scor[r1];
#pragma unroll
        for (int nt = 0; nt < 4; nt++) {
            co[nt][0] *= cr0; co[nt][1] *= cr0;
            co[nt][2] *= cr1; co[nt][3] *= cr1;
        }
#pragma unroll
        for (int kb = 0; kb < 64; kb += 8) {
            unsigned a[4];
            a[0] = PsT[(kb+tg  )*APS + mi+g];
            a[1] = PsT[(kb+tg  )*APS + mi+g+8];
            a[2] = PsT[(kb+tg+4)*APS + mi+g];
            a[3] = PsT[(kb+tg+4)*APS + mi+g+8];
#pragma unroll
            for (int nt = 0; nt < 4; nt++) {
                unsigned bb[2];
                bb[0] = Vs[(kb+tg  )*ATS + ng + nt*8 + g];
                bb[1] = Vs[(kb+tg+4)*ATS + ng + nt*8 + g];
                mma_tf32(co[nt], a, bb);
            }
        }
        __syncthreads();
    }

    int r0 = mi + g, r1 = mi + g + 8;
    float inv0 = __fdividef(1.f, sml[r0]);
    float inv1 = __fdividef(1.f, sml[r1]);
#pragma unroll
    for (int nt = 0; nt < 4; nt++) {
        int col = ng + nt * 8 + tg * 2;
        *(float2*)(o + base + (size_t)(qt*64 + r0) * Dn + col) =
            make_float2(co[nt][0]*inv0, co[nt][1]*inv0);
        *(float2*)(o + base + (size_t)(qt*64 + r1) * Dn + col) =
            make_float2(co[nt][2]*inv1, co[nt][3]*inv1);
    }
}

// ---------------- prep & lr ----------------
__global__ __launch_bounds__(256) void prep_kernel(
    float* __restrict__ XQ, float* __restrict__ XK, float* __restrict__ XV,
    const float* __restrict__ nw, const float* __restrict__ nb)
{
    int w = (blockIdx.x * blockDim.x + threadIdx.x) >> 5;
    if (w >= Bn * Sn * Hn) return;
    int lane = threadIdx.x & 31;
    int h = w & 15, bs = w >> 4;
    size_t base = (size_t)bs * Dn + h * HDn;
    float q0 = XQ[base + lane], q1 = XQ[base + lane + 32];
    float qi = 1.f / fmaxf(sqrtf(warpsum(q0*q0 + q1*q1)), 1e-12f);
    XQ[base + lane] = q0 * qi; XQ[base + lane + 32] = q1 * qi;
    float k0 = XK[base + lane], k1 = XK[base + lane + 32];
    float ki = 1.f / fmaxf(sqrtf(warpsum(k0*k0 + k1*k1)), 1e-12f);
    k0 *= ki; k1 *= ki;
    XK[base + lane] = k0; XK[base + lane + 32] = k1;
    float v0 = XV[base + lane], v1 = XV[base + lane + 32];
    float mu = warpsum(v0 + v1) * (1.f / 64.f);
    float d0 = v0 - mu, d1 = v1 - mu;
    float var = warpsum(d0*d0 + d1*d1) * (1.f / 64.f);
    float rstd = rsqrtf(var + EPSc);
    XV[base + lane]      = nw[h*64+lane]    * d0 * rstd + nb[h*64+lane]    + k0;
    XV[base + lane + 32] = nw[h*64+lane+32] * d1 * rstd + nb[h*64+lane+32] + k1;
}

__global__ __launch_bounds__(256) void lr_kernel(
    const float* __restrict__ x1, const float* __restrict__ lrw,
    const float* __restrict__ lrb, float* __restrict__ lro)
{
    int w = (blockIdx.x * blockDim.x + threadIdx.x) >> 5;
    if (w >= Bn * Sn * Hn) return;
    int lane = threadIdx.x & 31;
    int h = w & 15, bs = w >> 4;
    int b = bs >> 10, s = bs & (Sn - 1);
    const float* xr = x1 + (size_t)bs * Dn;
    const float* wr = lrw + h * Dn;
    float acc = 0.f;
    for (int c = lane; c < Dn; c += 32) acc += xr[c] * wr[c];
    acc = warpsum(acc);
    if (lane == 0)
        lro[(size_t)(b * Hn + h) * Sn + s] = 1.f / (1.f + __expf(-(acc + lrb[h])));
}

// ---------------- TTT scan: 512 thr, tensor-core A/D/E/Fcorr -------------
#define SV 65
#define PS 68
#define TS 72
#define WS 264
#define SCAN_FLOATS (64*SV + 2*64*PS + 4*64*TS + 16*WS + 64*WS + 256 + 64 + 64)
#define SCAN_SMEM (SCAN_FLOATS * 4)

__global__ __launch_bounds__(512) void ttt_scan_kernel(
    const float* __restrict__ XQ, const float* __restrict__ XK, const float* __restrict__ XV,
    const float* __restrict__ lr,
    const float* __restrict__ W1i, const float* __restrict__ b1i,
    const float* __restrict__ W2i, const float* __restrict__ b2i,
    const float* __restrict__ nw,  const float* __restrict__ nb,
    float* __restrict__ W2G, float* __restrict__ W2TG,
    float* __restrict__ X2G, float* __restrict__ gZ1G, float* __restrict__ X2bG,
    float* __restrict__ outp)
{
    extern __shared__ float sm[];
    float* sxv   = sm;                 // [64][SV]
    float* ssc   = sxv  + 64 * SV;     // [64][PS]
    float* sgZ2  = ssc  + 64 * PS;     // [64][PS]
    float* sxqT  = sgZ2 + 64 * PS;     // [e][TS]
    float* sxkT  = sxqT + 64 * TS;
    float* sscT  = sxkT + 64 * TS;     // coef1 negated [k2][TS]
    float* sgZ2T = sscT + 64 * TS;     // [j][TS]
    float* sstg  = sgZ2T+ 64 * TS;     // [16][WS] staging
    float* sW1   = sstg + 16 * WS;     // [64][WS]
    float* b1sm  = sW1  + 64 * WS;
    float* b2sm  = b1sm + 256;
    float* seta  = b2sm + 64;

    int bh = blockIdx.x, b = bh >> 4, h = bh & 15;
    int tid = threadIdx.x, w = tid >> 5, l = tid & 31;
    int g = l >> 2, tg = l & 3;
    int ty2 = tid >> 4, tx2 = tid & 15;
    int ft = tid >> 3, jt = tid & 7;
    int mi = (w & 3) * 16, ng = (w >> 2) * 64;
    float* W2r  = W2G  + (size_t)bh * 16384;
    float* W2Tr = W2TG + (size_t)bh * 16384;
    float* X2r  = X2G  + (size_t)bh * 16384;
    float* gZ1r = gZ1G + (size_t)bh * 16384;
    float* X2br = X2bG + (size_t)bh * 16384;
    const float* nwh = nw + h * 64;
    const float* nbh = nb + h * 64;

    for (int idx = tid; idx < 16384; idx += 512) {
        int e = idx >> 8, f = idx & 255;
        sW1[e * WS + f] = W1i[(size_t)h * 16384 + idx];
        W2r[idx]  = W2i[(size_t)h * 16384 + idx];
        W2Tr[idx] = W2i[(size_t)h * 16384 + f * 64 + e];
    }
    if (tid < 256) b1sm[tid] = b1i[h * 256 + tid];
    if (tid < 64)  b2sm[tid] = b2i[h * 64 + tid];
    __syncthreads();

    for (int n = 0; n < NCn; n++) {
        size_t tokbase = (size_t)b * Sn + n * Cn;
        for (int idx = tid; idx < 4096; idx += 512) {
            int i = idx >> 6, e = idx & 63;
            size_t gg = (tokbase + i) * Dn + h * 64 + e;
            sxqT[e * TS + i] = XQ[gg];
            sxkT[e * TS + i] = XK[gg];
            sxv [i * SV + e] = XV[gg];
        }
        if (tid < 64) seta[tid] = lr[(size_t)bh * Sn + n * 64 + tid] * (1.f / 64.f);
        __syncthreads();

        // ---- A (mma, 2 passes): Z1=xk@W1+b1 ; Z1q=xq@W1+b1
#pragma unroll
        for (int p = 0; p < 2; p++) {
            const float* T = p ? sxqT : sxkT;
            float c[8][4];
#pragma unroll
            for (int nt = 0; nt < 8; nt++) {
                int col = ng + nt * 8 + tg * 2;
                c[nt][0] = b1sm[col];   c[nt][1] = b1sm[col+1];
                c[nt][2] = b1sm[col];   c[nt][3] = b1sm[col+1];
            }
#pragma unroll
            for (int kb = 0; kb < 64; kb += 8) {
                unsigned a[4];
                a[0] = f2tf32(T[(kb+tg  )*TS + mi+g]);
                a[1] = f2tf32(T[(kb+tg  )*TS + mi+g+8]);
                a[2] = f2tf32(T[(kb+tg+4)*TS + mi+g]);
                a[3] = f2tf32(T[(kb+tg+4)*TS + mi+g+8]);
#pragma unroll
                for (int nt = 0; nt < 8; nt++) {
                    unsigned bb[2];
                    bb[0] = f2tf32(sW1[(kb+tg  )*WS + ng + nt*8 + g]);
                    bb[1] = f2tf32(sW1[(kb+tg+4)*WS + ng + nt*8 + g]);
                    mma_tf32(c[nt], a, bb);
                }
            }
#pragma unroll
            for (int nt = 0; nt < 8; nt++) {
                int col = ng + nt * 8 + tg * 2;
                int r0 = mi + g;
                if (p == 0) {
                    float x2o[4], gbo[4];
#pragma unroll
                    for (int r = 0; r < 4; r++) {
                        float z = c[nt][r];
                        float t = tanh_fast(0.79788456f * (z + 0.044715f * z * z * z));
                        x2o[r] = 0.5f * z * (1.f + t);
                        gbo[r] = 0.5f * z * (1.f - t * t) * (0.79788456f + 0.1070322243f * z * z)
                               + 0.5f * (1.f + t);
                    }
                    *(float2*)(X2r  + r0*256 + col)     = make_float2(x2o[0], x2o[1]);
                    *(float2*)(X2r  + (r0+8)*256 + col) = make_float2(x2o[2], x2o[3]);
                    *(float2*)(gZ1r + r0*256 + col)     = make_float2(gbo[0], gbo[1]);
                    *(float2*)(gZ1r + (r0+8)*256 + col) = make_float2(gbo[2], gbo[3]);
                } else {
                    *(float2*)(X2br + r0*256 + col)     = make_float2(c[nt][0], c[nt][1]);
                    *(float2*)(X2br + (r0+8)*256 + col) = make_float2(c[nt][2], c[nt][3]);
                }
            }
        }
        __syncthreads();

        // ---- B: Z2 = X2@W2 + b2 -> ssc (FFMA)
        {
            float acc[2][4];
#pragma unroll
            for (int u = 0; u < 2; u++)
#pragma unroll
                for (int v = 0; v < 4; v++) acc[u][v] = b2sm[tx2 * 4 + v];
#pragma unroll 4
            for (int f0 = 0; f0 < 256; f0 += 4) {
                float4 a4[2], b4[4];
#pragma unroll
                for (int u = 0; u < 2; u++) a4[u] = *(const float4*)(X2r + (ty2*2+u)*256 + f0);
#pragma unroll
                for (int d = 0; d < 4; d++) b4[d] = *(const float4*)(W2r + (f0+d)*64 + tx2*4);
#pragma unroll
                for (int u = 0; u < 2; u++) {
                    acc[u][0] += a4[u].x*b4[0].x + a4[u].y*b4[1].x + a4[u].z*b4[2].x + a4[u].w*b4[3].x;
                    acc[u][1] += a4[u].x*b4[0].y + a4[u].y*b4[1].y + a4[u].z*b4[2].y + a4[u].w*b4[3].y;
                    acc[u][2] += a4[u].x*b4[0].z + a4[u].y*b4[1].z + a4[u].z*b4[2].z + a4[u].w*b4[3].z;
                    acc[u][3] += a4[u].x*b4[0].w + a4[u].y*b4[1].w + a4[u].z*b4[2].w + a4[u].w*b4[3].w;
                }
            }
#pragma unroll
            for (int u = 0; u < 2; u++)
#pragma unroll
                for (int v = 0; v < 4; v++) ssc[(ty2*2+u)*PS + tx2*4+v] = acc[u][v];
        }
        __syncthreads();

        // ---- C: gZ2 = ln_l2_bwd -> sgZ2 + sgZ2T
        for (int i = w; i < 64; i += 16) {
            float z0 = ssc[i*PS + l], z1 = ssc[i*PS + l + 32];
            float mu = warpsum(z0 + z1) * (1.f/64.f);
            float d0 = z0 - mu, d1 = z1 - mu;
            float var = warpsum(d0*d0 + d1*d1) * (1.f/64.f);
            float rstd = rsqrtf(var + EPSc);
            float xh0 = d0 * rstd, xh1 = d1 * rstd;
            float g0 = nwh[l], g1 = nwh[l+32];
            float t0 = sxv[i*SV + l]      - sxkT[l*TS + i];
            float t1 = sxv[i*SV + l + 32] - sxkT[(l+32)*TS + i];
            float gh0 = (g0*xh0 + nbh[l]    - t0) * g0;
            float gh1 = (g1*xh1 + nbh[l+32] - t1) * g1;
            float sgh = warpsum(gh0 + gh1);
            float sgx = warpsum(gh0*xh0 + gh1*xh1);
            float cc = rstd * (1.f/64.f);
            float o0 = (64.f*gh0 - sgh - xh0*sgx) * cc;
            float o1 = (64.f*gh1 - sgh - xh1*sgx) * cc;
            sgZ2[i*PS + l]        = o0;
            sgZ2[i*PS + l + 32]   = o1;
            sgZ2T[l*TS + i]       = o0;
            sgZ2T[(l+32)*TS + i]  = o1;
        }
        __syncthreads();

        // ---- D (mma): gZ1 = (gZ2 @ W2^T) * gb   (16-row staging)
        {
            float c[8][4];
#pragma unroll
            for (int nt = 0; nt < 8; nt++)
#pragma unroll
                for (int r = 0; r < 4; r++) c[nt][r] = 0.f;
#pragma unroll
            for (int kbb = 0; kbb < 64; kbb += 16) {
                __syncthreads();
                for (int idx = tid; idx < 4096; idx += 512) {
                    int rr = idx >> 8, cf = idx & 255;
                    sstg[rr*WS + cf] = W2Tr[(kbb+rr)*256 + cf];
                }
                __syncthreads();
#pragma unroll
                for (int kk = 0; kk < 2; kk++) {
                    int kb = kk * 8;
                    unsigned a[4];
                    a[0] = f2tf32(sgZ2T[(kbb+kb+tg  )*TS + mi+g]);
                    a[1] = f2tf32(sgZ2T[(kbb+kb+tg  )*TS + mi+g+8]);
                    a[2] = f2tf32(sgZ2T[(kbb+kb+tg+4)*TS + mi+g]);
                    a[3] = f2tf32(sgZ2T[(kbb+kb+tg+4)*TS + mi+g+8]);
#pragma unroll
                    for (int nt = 0; nt < 8; nt++) {
                        unsigned bb[2];
                        bb[0] = f2tf32(sstg[(kb+tg  )*WS + ng + nt*8 + g]);
                        bb[1] = f2tf32(sstg[(kb+tg+4)*WS + ng + nt*8 + g]);
                        mma_tf32(c[nt], a, bb);
                    }
                }
            }
#pragma unroll
            for (int nt = 0; nt < 8; nt++) {
                int col = ng + nt * 8 + tg * 2;
                int r0 = mi + g;
                float2 gb0 = *(const float2*)(gZ1r + r0*256 + col);
                float2 gb1 = *(const float2*)(gZ1r + (r0+8)*256 + col);
                *(float2*)(gZ1r + r0*256 + col)     = make_float2(c[nt][0]*gb0.x, c[nt][1]*gb0.y);
                *(float2*)(gZ1r + (r0+8)*256 + col) = make_float2(c[nt][2]*gb1.x, c[nt][3]*gb1.y);
            }
        }
        __syncthreads();

        // ---- E (mma): coef1 = -eta[k2]*(tril(xq@xk^T)+1) -> sscT
#pragma unroll
        for (int sub = 0; sub < 2; sub++) {
            int ncol = ((w >> 2) * 2 + sub) * 8;
            float c[4] = {0.f, 0.f, 0.f, 0.f};
#pragma unroll
            for (int kb = 0; kb < 64; kb += 8) {
                unsigned a[4], bb[2];
                a[0] = f2tf32(sxqT[(kb+tg  )*TS + mi+g]);
                a[1] = f2tf32(sxqT[(kb+tg  )*TS + mi+g+8]);
                a[2] = f2tf32(sxqT[(kb+tg+4)*TS + mi+g]);
                a[3] = f2tf32(sxqT[(kb+tg+4)*TS + mi+g+8]);
                bb[0] = f2tf32(sxkT[(kb+tg  )*TS + ncol + g]);
                bb[1] = f2tf32(sxkT[(kb+tg+4)*TS + ncol + g]);
                mma_tf32(c, a, bb);
            }
            int r0 = mi + g, k2 = ncol + tg * 2;
            sscT[k2*TS + r0]       = (k2   <= r0)   ? -seta[k2]  *(c[0]+1.f) : 0.f;
            sscT[(k2+1)*TS + r0]   = (k2+1 <= r0)   ? -seta[k2+1]*(c[1]+1.f) : 0.f;
            sscT[k2*TS + r0+8]     = (k2   <= r0+8) ? -seta[k2]  *(c[2]+1.f) : 0.f;
            sscT[(k2+1)*TS + r0+8] = (k2+1 <= r0+8) ? -seta[k2+1]*(c[3]+1.f) : 0.f;
        }
        __syncthreads();

        // ---- F (mma): Z1b = Z1q + coef1neg@gZ1 ; X2b = gelu (16-row staging)
        {
            float c[8][4];
#pragma unroll
            for (int nt = 0; nt < 8; nt++) {
                int col = ng + nt * 8 + tg * 2;
                int r0 = mi + g;
                float2 q0 = *(const float2*)(X2br + r0*256 + col);
                float2 q1 = *(const float2*)(X2br + (r0+8)*256 + col);
                c[nt][0] = q0.x; c[nt][1] = q0.y; c[nt][2] = q1.x; c[nt][3] = q1.y;
            }
#pragma unroll
            for (int kbb = 0; kbb < 64; kbb += 16) {
                __syncthreads();
                for (int idx = tid; idx < 4096; idx += 512) {
                    int rr = idx >> 8, cf = idx & 255;
                    sstg[rr*WS + cf] = gZ1r[(kbb+rr)*256 + cf];
                }
                __syncthreads();
#pragma unroll
                for (int kk = 0; kk < 2; kk++) {
                    int kb = kk * 8;
                    unsigned a[4];
                    a[0] = f2tf32(sscT[(kbb+kb+tg  )*TS + mi+g]);
                    a[1] = f2tf32(sscT[(kbb+kb+tg  )*TS + mi+g+8]);
                    a[2] = f2tf32(sscT[(kbb+kb+tg+4)*TS + mi+g]);
                    a[3] = f2tf32(sscT[(kbb+kb+tg+4)*TS + mi+g+8]);
#pragma unroll
                    for (int nt = 0; nt < 8; nt++) {
                        unsigned bb[2];
                        bb[0] = f2tf32(sstg[(kb+tg  )*WS + ng + nt*8 + g]);
                        bb[1] = f2tf32(sstg[(kb+tg+4)*WS + ng + nt*8 + g]);
                        mma_tf32(c[nt], a, bb);
                    }
                }
            }
#pragma unroll
            for (int nt = 0; nt < 8; nt++) {
                int col = ng + nt * 8 + tg * 2;
                int r0 = mi + g;
                float xo[4];
#pragma unroll
                for (int r = 0; r < 4; r++) {
                    float z = c[nt][r];
                    float t = tanh_fast(0.79788456f * (z + 0.044715f * z * z * z));
                    xo[r] = 0.5f * z * (1.f + t);
                }
                *(float2*)(X2br + r0*256 + col)     = make_float2(xo[0], xo[1]);
                *(float2*)(X2br + (r0+8)*256 + col) = make_float2(xo[2], xo[3]);
            }
        }
        __syncthreads();

        // ---- G: coef2 (FFMA)
        {
            float acc[2][4];
#pragma unroll
            for (int u = 0; u < 2; u++)
#pragma unroll
                for (int v = 0; v < 4; v++) acc[u][v] = 0.f;
            if (tx2 * 4 <= ty2 * 2 + 1) {
#pragma unroll 2
                for (int f0 = 0; f0 < 256; f0 += 4) {
                    float4 a4[2], b4[4];
#pragma unroll
                    for (int u = 0; u < 2; u++) a4[u] = *(const float4*)(X2br + (ty2*2+u)*256 + f0);
#pragma unroll
                    for (int v = 0; v < 4; v++) b4[v] = *(const float4*)(X2r + (tx2*4+v)*256 + f0);
#pragma unroll
                    for (int u = 0; u < 2; u++)
#pragma unroll
                        for (int v = 0; v < 4; v++)
                            acc[u][v] += a4[u].x*b4[v].x + a4[u].y*b4[v].y
                                       + a4[u].z*b4[v].z + a4[u].w*b4[v].w;
                }
            }
#pragma unroll
            for (int u = 0; u < 2; u++) {
                int i = ty2 * 2 + u;
#pragma unroll
                for (int v = 0; v < 4; v++) {
                    int j = tx2 * 4 + v;
                    ssc[i*PS + j] = (j <= i) ? seta[j] * (acc[u][v] + 1.f) : 0.f;
                }
            }
        }
        __syncthreads();

        // ---- H: Z2b (FFMA)
        {
            float acc[2][4];
#pragma unroll
            for (int u = 0; u < 2; u++)
#pragma unroll
                for (int v = 0; v < 4; v++) acc[u][v] = b2sm[tx2 * 4 + v];
#pragma unroll 4
            for (int f0 = 0; f0 < 256; f0 += 4) {
                float4 a4[2], b4[4];
#pragma unroll
                for (int u = 0; u < 2; u++) a4[u] = *(const float4*)(X2br + (ty2*2+u)*256 + f0);
#pragma unroll
                for (int d = 0; d < 4; d++) b4[d] = *(const float4*)(W2r + (f0+d)*64 + tx2*4);
#pragma unroll
                for (int u = 0; u < 2; u++) {
                    acc[u][0] += a4[u].x*b4[0].x + a4[u].y*b4[1].x + a4[u].z*b4[2].x + a4[u].w*b4[3].x;
                    acc[u][1] += a4[u].x*b4[0].y + a4[u].y*b4[1].y + a4[u].z*b4[2].y + a4[u].w*b4[3].y;
                    acc[u][2] += a4[u].x*b4[0].z + a4[u].y*b4[1].z + a4[u].z*b4[2].z + a4[u].w*b4[3].z;
                    acc[u][3] += a4[u].x*b4[0].w + a4[u].y*b4[1].w + a4[u].z*b4[2].w + a4[u].w*b4[3].w;
                }
            }
#pragma unroll 4
            for (int k2 = 0; k2 < 64; k2++) {
                float cc0 = ssc[(ty2*2)*PS + k2];
                float cc1 = ssc[(ty2*2+1)*PS + k2];
                float4 gv4 = *(const float4*)(sgZ2 + k2*PS + tx2*4);
                acc[0][0] -= cc0*gv4.x; acc[0][1] -= cc0*gv4.y; acc[0][2] -= cc0*gv4.z; acc[0][3] -= cc0*gv4.w;
                acc[1][0] -= cc1*gv4.x; acc[1][1] -= cc1*gv4.y; acc[1][2] -= cc1*gv4.z; acc[1][3] -= cc1*gv4.w;
            }
#pragma unroll
            for (int u = 0; u < 2; u++)
#pragma unroll
                for (int v = 0; v < 4; v++) sxv[(ty2*2+u)*SV + tx2*4+v] = acc[u][v];
        }
        __syncthreads();

        // ---- I: out = xq + LN(Z2b)
        for (int i = w; i < 64; i += 16) {
            float z0 = sxv[i*SV + l], z1 = sxv[i*SV + l + 32];
            float mu = warpsum(z0 + z1) * (1.f/64.f);
            float d0 = z0 - mu, d1 = z1 - mu;
            float var = warpsum(d0*d0 + d1*d1) * (1.f/64.f);
            float rstd = rsqrtf(var + EPSc);
            size_t gg = (tokbase + i) * Dn + h * 64;
            outp[gg + l]      = sxqT[l*TS + i]      + nwh[l]    * d0 * rstd + nbh[l];
            outp[gg + l + 32] = sxqT[(l+32)*TS + i] + nwh[l+32] * d1 * rstd + nbh[l+32];
        }

        // ---- J1: W1 -= (eta*xk)^T @ gZ1  (sW1 smem)
        {
            u64 acc2[4][4];
#pragma unroll
            for (int u = 0; u < 4; u++)
#pragma unroll
                for (int p = 0; p < 4; p++) acc2[u][p] = 0ULL;
#pragma unroll 4
            for (int i = 0; i < 64; i++) {
                float et = seta[i];
                float4 g0 = *(const float4*)(gZ1r + i*256 + l*8);
                float4 g1 = *(const float4*)(gZ1r + i*256 + l*8 + 4);
                u64 gv2[4];
                f4tou2(g0, gv2[0], gv2[1]); f4tou2(g1, gv2[2], gv2[3]);
#pragma unroll
                for (int u = 0; u < 4; u++) {
                    float a = et * sxkT[(w*4+u)*TS + i];
                    u64 a2 = f2pack(a, a);
#pragma unroll
                    for (int p = 0; p < 4; p++) acc2[u][p] = ffma2(a2, gv2[p], acc2[u][p]);
                }
            }
#pragma unroll
            for (int u = 0; u < 4; u++) {
                int e = w * 4 + u;
                float av[8];
#pragma unroll
                for (int p = 0; p < 4; p++) f2unpack(acc2[u][p], av[2*p], av[2*p+1]);
                float4* wp = (float4*)(sW1 + e*WS + l*8);
                float4 o0 = wp[0], o1 = wp[1];
                wp[0] = make_float4(o0.x-av[0], o0.y-av[1], o0.z-av[2], o0.w-av[3]);
                wp[1] = make_float4(o1.x-av[4], o1.y-av[5], o1.z-av[6], o1.w-av[7]);
            }
        }
        // J2: b1
        if (tid < 256) {
            float acc = 0.f;
#pragma unroll 8
            for (int i = 0; i < 64; i++) acc += seta[i] * gZ1r[i*256 + tid];
            b1sm[tid] -= acc;
        }
        // J3: W2 + W2T (global)
        {
            u64 acc2[4][4];
#pragma unroll
            for (int u = 0; u < 4; u++)
#pragma unroll
                for (int p = 0; p < 4; p++) acc2[u][p] = 0ULL;
#pragma unroll 4
            for (int i = 0; i < 64; i++) {
                float et = seta[i];
                float4 x0 = *(const float4*)(X2r + i*256 + ft*4);
                float4 gv0 = *(const float4*)(sgZ2 + i*PS + jt*8);
                float4 gv1 = *(const float4*)(sgZ2 + i*PS + jt*8 + 4);
                u64 gv2[4];
                f4tou2(gv0, gv2[0], gv2[1]); f4tou2(gv1, gv2[2], gv2[3]);
                float a[4] = {et*x0.x, et*x0.y, et*x0.z, et*x0.w};
#pragma unroll
                for (int u = 0; u < 4; u++) {
                    u64 a2 = f2pack(a[u], a[u]);
#pragma unroll
                    for (int p = 0; p < 4; p++) acc2[u][p] = ffma2(a2, gv2[p], acc2[u][p]);
                }
            }
#pragma unroll
            for (int u = 0; u < 4; u++) {
                int f = ft * 4 + u;
                float av[8];
#pragma unroll
                for (int p = 0; p < 4; p++) f2unpack(acc2[u][p], av[2*p], av[2*p+1]);
                float4* wp0 = (float4*)(W2r + f*64 + jt*8);
                float4* wp1 = (float4*)(W2r + f*64 + jt*8 + 4);
                float4 o0 = wp0[0], o1 = wp1[0];
                wp0[0] = make_float4(o0.x-av[0], o0.y-av[1], o0.z-av[2], o0.w-av[3]);
                wp1[0] = make_float4(o1.x-av[4], o1.y-av[5], o1.z-av[6], o1.w-av[7]);
#pragma unroll
                for (int v = 0; v < 8; v++)
                    W2Tr[(jt*8+v)*256 + f] -= av[v];
            }
        }
        // J4: b2
        if (tid < 64) {
            float acc = 0.f;
#pragma unroll 8
            for (int i = 0; i < 64; i++) acc += seta[i] * sgZ2[i*PS + tid];
            b2sm[tid] -= acc;
        }
        __syncthreads();
    }
}

// ---------------- Launch ----------------
extern "C" void kernel_launch(void* const* d_in, const int* in_sizes, int n_in,
                              void* d_out, int out_size)
{
    const float* x       = (const float*)d_in[0];
    const float* ln1_w   = (const float*)d_in[1];
    const float* ln1_b   = (const float*)d_in[2];
    const float* attn_wq = (const float*)d_in[3];
    const float* attn_wk = (const float*)d_in[4];
    const float* attn_wv = (const float*)d_in[5];
    const float* attn_wo = (const float*)d_in[6];
    const float* wq_w    = (const float*)d_in[7];
    const float* wq_b    = (const float*)d_in[8];
    const float* wk_w    = (const float*)d_in[9];
    const float* wk_b    = (const float*)d_in[10];
    const float* wv_w    = (const float*)d_in[11];
    const float* wv_b    = (const float*)d_in[12];
    const float* wo_w    = (const float*)d_in[13];
    const float* wo_b    = (const float*)d_in[14];
    const float* W1      = (const float*)d_in[15];
    const float* b1      = (const float*)d_in[16];
    const float* W2      = (const float*)d_in[17];
    const float* b2      = (const float*)d_in[18];
    const float* ttt_nw  = (const float*)d_in[19];
    const float* ttt_nb  = (const float*)d_in[20];
    const float* lr_w    = (const float*)d_in[21];
    const float* lr_b    = (const float*)d_in[22];
    const float* pn_w    = (const float*)d_in[23];
    const float* pn_b    = (const float*)d_in[24];
    const float* gate_a  = (const float*)d_in[25];
    float* out = (float*)d_out;

    float *p_h,*p_q,*p_k,*p_v,*p_o,*p_x1,*p_lr,*p_W2,*p_W2T,*p_X2,*p_gZ1,*p_X2b;
    cudaGetSymbolAddress((void**)&p_h,  g_h);
    cudaGetSymbolAddress((void**)&p_q,  g_q);
    cudaGetSymbolAddress((void**)&p_k,  g_k);
    cudaGetSymbolAddress((void**)&p_v,  g_v);
    cudaGetSymbolAddress((void**)&p_o,  g_o);
    cudaGetSymbolAddress((void**)&p_x1, g_x1);
    cudaGetSymbolAddress((void**)&p_lr, g_lr);
    cudaGetSymbolAddress((void**)&p_W2, g_W2s);
    cudaGetSymbolAddress((void**)&p_W2T,g_W2Ts);
    cudaGetSymbolAddress((void**)&p_X2, g_X2);
    cudaGetSymbolAddress((void**)&p_gZ1,g_gZ1);
    cudaGetSymbolAddress((void**)&p_X2b,g_X2b);

    cudaFuncSetAttribute(ttt_scan_kernel,   cudaFuncAttributeMaxDynamicSharedMemorySize, SCAN_SMEM);
    cudaFuncSetAttribute(attn_flash_kernel, cudaFuncAttributeMaxDynamicSharedMemorySize, ATT_SMEM);

    const int M = Bn * Sn;
    dim3 ggrid(Dn / 128, M / 128);
    dim3 ggrid3(Dn / 128, M / 128, 3);
    int nwarp_grid = (Bn * Sn * Hn) / 8;

    ln_kernel<<<M, 256>>>(x, ln1_w, ln1_b, p_h);
    gemm3_nt_kernel<<<ggrid3, 256>>>(p_h, attn_wq, attn_wk, attn_wv,
                                     p_q, p_k, p_v, nullptr, nullptr, nullptr);
    attn_flash_kernel<<<dim3(16, 64), 256, ATT_SMEM>>>(p_q, p_k, p_v, p_o);
    gemm_nt_kernel<<<ggrid, 256>>>(p_o, attn_wo, p_x1, nullptr, x, nullptr);
    gemm3_nt_kernel<<<ggrid3, 256>>>(p_x1, wq_w, wk_w, wv_w,
                                     p_q, p_k, p_v, wq_b, wk_b, wv_b);
    prep_kernel<<<nwarp_grid, 256>>>(p_q, p_k, p_v, ttt_nw, ttt_nb);
    lr_kernel<<<nwarp_grid, 256>>>(p_x1, lr_w, lr_b, p_lr);
    ttt_scan_kernel<<<Bn * Hn, 512, SCAN_SMEM>>>(
        p_q, p_k, p_v, p_lr, W1, b1, W2, b2, ttt_nw, ttt_nb,
        p_W2, p_W2T, p_X2, p_gZ1, p_X2b, p_o);
    ln_kernel<<<M, 256>>>(p_o, pn_w, pn_b, p_h);
    gemm_nt_kernel<<<ggrid, 256>>>(p_h, wo_w, out, wo_b, p_x1, gate_a);
}

// round 13
// speedup vs baseline: 1.6570x; 1.0309x over previous
#include <cuda_runtime.h>
#include <math.h>

#define Bn 4
#define Sn 1024
#define Dn 1024
#define Hn 16
#define HDn 64
#define Cn 64
#define NCn 16
#define DFFn 256
#define EPSc 1e-6f
#define BSD (Bn*Sn*Dn)

typedef unsigned long long u64;
__device__ __forceinline__ u64 f2pack(float lo, float hi) {
    u64 r; asm("mov.b64 %0, {%1, %2};" : "=l"(r) : "f"(lo), "f"(hi)); return r;
}
__device__ __forceinline__ void f2unpack(u64 p, float& lo, float& hi) {
    asm("mov.b64 {%0, %1}, %2;" : "=f"(lo), "=f"(hi) : "l"(p));
}
__device__ __forceinline__ u64 ffma2(u64 a, u64 b, u64 c) {
    u64 d; asm("fma.rn.f32x2 %0, %1, %2, %3;" : "=l"(d) : "l"(a), "l"(b), "l"(c)); return d;
}
__device__ __forceinline__ void f4tou2(float4 f, u64& p0, u64& p1) {
    p0 = f2pack(f.x, f.y); p1 = f2pack(f.z, f.w);
}
__device__ __forceinline__ unsigned f2tf32(float f) {
    unsigned r; asm("cvt.rna.tf32.f32 %0, %1;" : "=r"(r) : "f"(f)); return r;
}
__device__ __forceinline__ void mma_tf32(float* c, const unsigned* a, const unsigned* b) {
    asm volatile("mma.sync.aligned.m16n8k8.row.col.f32.tf32.tf32.f32 "
        "{%0,%1,%2,%3}, {%4,%5,%6,%7}, {%8,%9}, {%0,%1,%2,%3};"
        : "+f"(c[0]), "+f"(c[1]), "+f"(c[2]), "+f"(c[3])
        : "r"(a[0]), "r"(a[1]), "r"(a[2]), "r"(a[3]), "r"(b[0]), "r"(b[1]));
}

__device__ float g_h [BSD];
__device__ float g_q [BSD];
__device__ float g_k [BSD];
__device__ float g_v [BSD];
__device__ float g_o [BSD];
__device__ float g_x1[BSD];
__device__ float g_lr[Bn*Hn*Sn];
__device__ float g_W2s [Bn*Hn*16384];
__device__ float g_W2Ts[Bn*Hn*16384];
__device__ float g_X2  [Bn*Hn*16384];
__device__ float g_gZ1 [Bn*Hn*16384];
__device__ float g_X2b [Bn*Hn*16384];

__device__ __forceinline__ float warpsum(float v) {
#pragma unroll
    for (int o = 16; o > 0; o >>= 1) v += __shfl_xor_sync(0xffffffffu, v, o);
    return v;
}
__device__ __forceinline__ float warpmax(float v) {
#pragma unroll
    for (int o = 16; o > 0; o >>= 1) v = fmaxf(v, __shfl_xor_sync(0xffffffffu, v, o));
    return v;
}
__device__ __forceinline__ float blocksum256(float v) {
    __shared__ float red[8];
    int lane = threadIdx.x & 31, w = threadIdx.x >> 5;
    v = warpsum(v);
    if (lane == 0) red[w] = v;
    __syncthreads();
    float r = (lane < 8) ? red[lane] : 0.f;
    r = warpsum(r);
    __syncthreads();
    return r;
}
__device__ __forceinline__ float tanh_fast(float x) {
    float e = __expf(2.f * x);
    return 1.f - __fdividef(2.f, e + 1.f);
}

// ---------------- LayerNorm rows of 1024 ----------------
__global__ __launch_bounds__(256) void ln_kernel(
    const float* __restrict__ x, const float* __restrict__ g,
    const float* __restrict__ b, float* __restrict__ y)
{
    int row = blockIdx.x, tid = threadIdx.x;
    const float* xr = x + (size_t)row * Dn;
    float v[4]; float s = 0.f;
#pragma unroll
    for (int i = 0; i < 4; i++) { v[i] = xr[tid + 256 * i]; s += v[i]; }
    s = blocksum256(s);
    float mu = s * (1.f / Dn), ss = 0.f;
#pragma unroll
    for (int i = 0; i < 4; i++) { float d = v[i] - mu; ss += d * d; }
    ss = blocksum256(ss);
    float rstd = rsqrtf(ss * (1.f / Dn) + EPSc);
    float* yr = y + (size_t)row * Dn;
#pragma unroll
    for (int i = 0; i < 4; i++) {
        int c = tid + 256 * i;
        yr[c] = (v[i] - mu) * rstd * g[c] + b[c];
    }
}

// ---------------- tf32 tensor-core GEMM, double-buffered smem ------------
#define GSTR 136
__device__ __forceinline__ void gemm_core(
    const float* __restrict__ A, const float* __restrict__ B, float* __restrict__ C,
    const float* __restrict__ bias, const float* __restrict__ res,
    const float* __restrict__ gate, int bm, int bn)
{
    const int N = 1024, K = 1024, BK = 16;
    __shared__ unsigned As[2][BK][GSTR];
    __shared__ unsigned Bs[2][BK][GSTR];
    int t = threadIdx.x;
    int warp = t >> 5, lane = t & 31;
    int wm = warp >> 1, wn = warp & 1;
    int g = lane >> 2, tg = lane & 3;

    float acc[2][8][4];
#pragma unroll
    for (int mt = 0; mt < 2; mt++)
#pragma unroll
        for (int nt = 0; nt < 8; nt++)
#pragma unroll
            for (int r = 0; r < 4; r++) acc[mt][nt][r] = 0.f;

    int r128 = t >> 1, kc = (t & 1) * 8;
    const float* Ab = A + (size_t)(bm + r128) * K + kc;
    const float* Bb = B + (size_t)(bn + r128) * K + kc;
    float4 a0 = *(const float4*)(Ab);
    float4 a1 = *(const float4*)(Ab + 4);
    float4 b0 = *(const float4*)(Bb);
    float4 b1 = *(const float4*)(Bb + 4);

    // store tile 0 into buffer 0
    As[0][kc+0][r128]=f2tf32(a0.x); As[0][kc+1][r128]=f2tf32(a0.y);
    As[0][kc+2][r128]=f2tf32(a0.z); As[0][kc+3][r128]=f2tf32(a0.w);
    As[0][kc+4][r128]=f2tf32(a1.x); As[0][kc+5][r128]=f2tf32(a1.y);
    As[0][kc+6][r128]=f2tf32(a1.z); As[0][kc+7][r128]=f2tf32(a1.w);
    Bs[0][kc+0][r128]=f2tf32(b0.x); Bs[0][kc+1][r128]=f2tf32(b0.y);
    Bs[0][kc+2][r128]=f2tf32(b0.z); Bs[0][kc+3][r128]=f2tf32(b0.w);
    Bs[0][kc+4][r128]=f2tf32(b1.x); Bs[0][kc+5][r128]=f2tf32(b1.y);
    Bs[0][kc+6][r128]=f2tf32(b1.z); Bs[0][kc+7][r128]=f2tf32(b1.w);
    __syncthreads();

    int cur = 0;
    for (int k0 = 0; k0 < K; k0 += BK) {
        bool more = (k0 + BK < K);
        if (more) {
            a0 = *(const float4*)(Ab + k0 + BK);
            a1 = *(const float4*)(Ab + k0 + BK + 4);
            b0 = *(const float4*)(Bb + k0 + BK);
            b1 = *(const float4*)(Bb + k0 + BK + 4);
        }
#pragma unroll
        for (int ks = 0; ks < 2; ks++) {
            int kb = ks * 8;
            unsigned af[2][4], bf[8][2];
#pragma unroll
            for (int mt = 0; mt < 2; mt++) {
                int mb = wm * 32 + mt * 16 + g;
                af[mt][0] = As[cur][kb+tg  ][mb];
                af[mt][1] = As[cur][kb+tg  ][mb+8];
                af[mt][2] = As[cur][kb+tg+4][mb];
                af[mt][3] = As[cur][kb+tg+4][mb+8];
            }
#pragma unroll
            for (int nt = 0; nt < 8; nt++) {
                int nb = wn * 64 + nt * 8 + g;
                bf[nt][0] = Bs[cur][kb+tg  ][nb];
                bf[nt][1] = Bs[cur][kb+tg+4][nb];
            }
#pragma unroll
            for (int mt = 0; mt < 2; mt++)
#pragma unroll
                for (int nt = 0; nt < 8; nt++)
                    mma_tf32(acc[mt][nt], af[mt], bf[nt]);
        }
        if (more) {
            int nxt = cur ^ 1;
            As[nxt][kc+0][r128]=f2tf32(a0.x); As[nxt][kc+1][r128]=f2tf32(a0.y);
            As[nxt][kc+2][r128]=f2tf32(a0.z); As[nxt][kc+3][r128]=f2tf32(a0.w);
            As[nxt][kc+4][r128]=f2tf32(a1.x); As[nxt][kc+5][r128]=f2tf32(a1.y);
            As[nxt][kc+6][r128]=f2tf32(a1.z); As[nxt][kc+7][r128]=f2tf32(a1.w);
            Bs[nxt][kc+0][r128]=f2tf32(b0.x); Bs[nxt][kc+1][r128]=f2tf32(b0.y);
            Bs[nxt][kc+2][r128]=f2tf32(b0.z); Bs[nxt][kc+3][r128]=f2tf32(b0.w);
            Bs[nxt][kc+4][r128]=f2tf32(b1.x); Bs[nxt][kc+5][r128]=f2tf32(b1.y);
            Bs[nxt][kc+6][r128]=f2tf32(b1.z); Bs[nxt][kc+7][r128]=f2tf32(b1.w);
            __syncthreads();
            cur = nxt;
        }
    }

    float bs2[8][2], gv2[8][2];
#pragma unroll
    for (int nt = 0; nt < 8; nt++) {
        int col = bn + wn * 64 + nt * 8 + tg * 2;
        if (bias) { bs2[nt][0] = bias[col]; bs2[nt][1] = bias[col+1]; }
        else      { bs2[nt][0] = 0.f;       bs2[nt][1] = 0.f; }
        if (gate) { gv2[nt][0] = tanhf(gate[col]); gv2[nt][1] = tanhf(gate[col+1]); }
    }
#pragma unroll
    for (int mt = 0; mt < 2; mt++) {
        int row0 = bm + wm * 32 + mt * 16 + g;
#pragma unroll
        for (int nt = 0; nt < 8; nt++) {
            int col = bn + wn * 64 + nt * 8 + tg * 2;
            float v0 = acc[mt][nt][0] + bs2[nt][0];
            float v1 = acc[mt][nt][1] + bs2[nt][1];
            float v2 = acc[mt][nt][2] + bs2[nt][0];
            float v3 = acc[mt][nt][3] + bs2[nt][1];
            if (gate) {
                float2 r0 = *(const float2*)(res + (size_t)row0 * N + col);
                float2 r1 = *(const float2*)(res + (size_t)(row0+8) * N + col);
                v0 = r0.x + gv2[nt][0] * v0; v1 = r0.y + gv2[nt][1] * v1;
                v2 = r1.x + gv2[nt][0] * v2; v3 = r1.y + gv2[nt][1] * v3;
            } else if (res) {
                float2 r0 = *(const float2*)(res + (size_t)row0 * N + col);
                float2 r1 = *(const float2*)(res + (size_t)(row0+8) * N + col);
                v0 += r0.x; v1 += r0.y; v2 += r1.x; v3 += r1.y;
            }
            *(float2*)(C + (size_t)row0 * N + col)     = make_float2(v0, v1);
            *(float2*)(C + (size_t)(row0+8) * N + col) = make_float2(v2, v3);
        }
    }
}

__global__ __launch_bounds__(256, 2) void gemm_nt_kernel(
    const float* __restrict__ A, const float* __restrict__ B, float* __restrict__ C,
    const float* __restrict__ bias, const float* __restrict__ res,
    const float* __restrict__ gate)
{
    gemm_core(A, B, C, bias, res, gate, blockIdx.y * 128, blockIdx.x * 128);
}

__global__ __launch_bounds__(256, 2) void gemm3_nt_kernel(
    const float* __restrict__ A,
    const float* __restrict__ B0, const float* __restrict__ B1, const float* __restrict__ B2,
    float* __restrict__ C0, float* __restrict__ C1, float* __restrict__ C2,
    const float* __restrict__ b0, const float* __restrict__ b1, const float* __restrict__ b2)
{
    const float* B; float* C; const float* bias;
    if (blockIdx.z == 0)      { B = B0; C = C0; bias = b0; }
    else if (blockIdx.z == 1) { B = B1; C = C1; bias = b1; }
    else                      { B = B2; C = C2; bias = b2; }
    gemm_core(A, B, C, bias, nullptr, nullptr, blockIdx.y * 128, blockIdx.x * 128);
}

// ---------------- Flash attention: tf32 mma ----------------
#define ATS 72
#define APS 65
#define ASS 68
#define ATT_SMEM ((3*64*ATS + 64*APS + 64*ASS + 192) * 4)

__global__ __launch_bounds__(256) void attn_flash_kernel(
    const float* __restrict__ q, const float* __restrict__ k,
    const float* __restrict__ v, float* __restrict__ o)
{
    extern __shared__ float sm[];
    unsigned* QsT = (unsigned*)sm;
    unsigned* KsT = QsT + 64 * ATS;
    unsigned* Vs  = KsT + 64 * ATS;
    unsigned* PsT = Vs  + 64 * ATS;
    float* Ss   = (float*)(PsT + 64 * APS);
    float* smm  = Ss + 64 * ASS;
    float* sml  = smm + 64;
    float* scor = sml + 64;

    int qt = blockIdx.x, bh = blockIdx.y;
    int b = bh >> 4, h = bh & 15;
    int tid = threadIdx.x, warp = tid >> 5, lane = tid & 31;
    int wm = warp >> 1, wn = warp & 1;
    int mi = wm * 16, ng = wn * 32;
    int g = lane >> 2, tg = lane & 3;
    size_t base = ((size_t)b * Sn) * Dn + h * HDn;

    for (int idx = tid; idx < 4096; idx += 256) {
        int r = idx >> 6, e = idx & 63;
        QsT[e * ATS + r] = f2tf32(q[base + (size_t)(qt * 64 + r) * Dn + e] * 0.125f);
    }
    if (tid < 64) { smm[tid] = -1e30f; sml[tid] = 0.f; }
    float co[4][4];
#pragma unroll
    for (int nt = 0; nt < 4; nt++)
#pragma unroll
        for (int r = 0; r < 4; r++) co[nt][r] = 0.f;
    __syncthreads();

    for (int kt = 0; kt <= qt; kt++) {
        for (int idx = tid; idx < 4096; idx += 256) {
            int r = idx >> 6, e = idx & 63;
            size_t gg = base + (size_t)(kt * 64 + r) * Dn + e;
            KsT[e * ATS + r] = f2tf32(k[gg]);
            Vs [r * ATS + e] = f2tf32(v[gg]);
        }
        __syncthreads();

        float c[4][4];
#pragma unroll
        for (int nt = 0; nt < 4; nt++)
#pragma unroll
            for (int r = 0; r < 4; r++) c[nt][r] = 0.f;
#pragma unroll
        for (int kb = 0; kb < 64; kb += 8) {
            unsigned a[4];
            a[0] = QsT[(kb+tg  )*ATS + mi+g];
            a[1] = QsT[(kb+tg  )*ATS + mi+g+8];
            a[2] = QsT[(kb+tg+4)*ATS + mi+g];
            a[3] = QsT[(kb+tg+4)*ATS + mi+g+8];
#pragma unroll
            for (int nt = 0; nt < 4; nt++) {
                unsigned bb[2];
                bb[0] = KsT[(kb+tg  )*ATS + ng + nt*8 + g];
                bb[1] = KsT[(kb+tg+4)*ATS + ng + nt*8 + g];
                mma_tf32(c[nt], a, bb);
            }
        }
        bool diag = (kt == qt);
        int r0 = mi + g, r1 = mi + g + 8;
#pragma unroll
        for (int nt = 0; nt < 4; nt++) {
            int col = ng + nt * 8 + tg * 2;
            if (diag) {
                if (col   > r0) c[nt][0] = -1e30f;
                if (col+1 > r0) c[nt][1] = -1e30f;
                if (col   > r1) c[nt][2] = -1e30f;
                if (col+1 > r1) c[nt][3] = -1e30f;
            }
            Ss[r0*ASS + col]   = c[nt][0];
            Ss[r0*ASS + col+1] = c[nt][1];
            Ss[r1*ASS + col]   = c[nt][2];
            Ss[r1*ASS + col+1] = c[nt][3];
        }
        __syncthreads();

        for (int i = warp; i < 64; i += 8) {
            float s0 = Ss[i*ASS + lane], s1 = Ss[i*ASS + lane + 32];
            float mx = warpmax(fmaxf(s0, s1));
            float nm = fmaxf(smm[i], mx);
            float corr = __expf(smm[i] - nm);
            float p0 = __expf(s0 - nm), p1 = __expf(s1 - nm);
            float ps = warpsum(p0 + p1);
            if (lane == 0) { sml[i] = sml[i] * corr + ps; smm[i] = nm; scor[i] = corr; }
            PsT[lane*APS + i]      = f2tf32(p0);
            PsT[(lane+32)*APS + i] = f2tf32(p1);
        }
        __syncthreads();

        float cr0 = scor[r0], cr1 = scor[r1];
#pragma unroll
        for (int nt = 0; nt < 4; nt++) {
            co[nt][0] *= cr0; co[nt][1] *= cr0;
            co[nt][2] *= cr1; co[nt][3] *= cr1;
        }
#pragma unroll
        for (int kb = 0; kb < 64; kb += 8) {
            unsigned a[4];
            a[0] = PsT[(kb+tg  )*APS + mi+g];
            a[1] = PsT[(kb+tg  )*APS + mi+g+8];
            a[2] = PsT[(kb+tg+4)*APS + mi+g];
            a[3] = PsT[(kb+tg+4)*APS + mi+g+8];
#pragma unroll
            for (int nt = 0; nt < 4; nt++) {
                unsigned bb[2];
                bb[0] = Vs[(kb+tg  )*ATS + ng + nt*8 + g];
                bb[1] = Vs[(kb+tg+4)*ATS + ng + nt*8 + g];
                mma_tf32(co[nt], a, bb);
            }
        }
        __syncthreads();
    }

    int r0 = mi + g, r1 = mi + g + 8;
    float inv0 = __fdividef(1.f, sml[r0]);
    float inv1 = __fdividef(1.f, sml[r1]);
#pragma unroll
    for (int nt = 0; nt < 4; nt++) {
        int col = ng + nt * 8 + tg * 2;
        *(float2*)(o + base + (size_t)(qt*64 + r0) * Dn + col) =
            make_float2(co[nt][0]*inv0, co[nt][1]*inv0);
        *(float2*)(o + base + (size_t)(qt*64 + r1) * Dn + col) =
            make_float2(co[nt][2]*inv1, co[nt][3]*inv1);
    }
}

// ---------------- prep & lr ----------------
__global__ __launch_bounds__(256) void prep_kernel(
    float* __restrict__ XQ, float* __restrict__ XK, float* __restrict__ XV,
    const float* __restrict__ nw, const float* __restrict__ nb)
{
    int w = (blockIdx.x * blockDim.x + threadIdx.x) >> 5;
    if (w >= Bn * Sn * Hn) return;
    int lane = threadIdx.x & 31;
    int h = w & 15, bs = w >> 4;
    size_t base = (size_t)bs * Dn + h * HDn;
    float q0 = XQ[base + lane], q1 = XQ[base + lane + 32];
    float qi = 1.f / fmaxf(sqrtf(warpsum(q0*q0 + q1*q1)), 1e-12f);
    XQ[base + lane] = q0 * qi; XQ[base + lane + 32] = q1 * qi;
    float k0 = XK[base + lane], k1 = XK[base + lane + 32];
    float ki = 1.f / fmaxf(sqrtf(warpsum(k0*k0 + k1*k1)), 1e-12f);
    k0 *= ki; k1 *= ki;
    XK[base + lane] = k0; XK[base + lane + 32] = k1;
    float v0 = XV[base + lane], v1 = XV[base + lane + 32];
    float mu = warpsum(v0 + v1) * (1.f / 64.f);
    float d0 = v0 - mu, d1 = v1 - mu;
    float var = warpsum(d0*d0 + d1*d1) * (1.f / 64.f);
    float rstd = rsqrtf(var + EPSc);
    XV[base + lane]      = nw[h*64+lane]    * d0 * rstd + nb[h*64+lane]    + k0;
    XV[base + lane + 32] = nw[h*64+lane+32] * d1 * rstd + nb[h*64+lane+32] + k1;
}

__global__ __launch_bounds__(256) void lr_kernel(
    const float* __restrict__ x1, const float* __restrict__ lrw,
    const float* __restrict__ lrb, float* __restrict__ lro)
{
    int w = (blockIdx.x * blockDim.x + threadIdx.x) >> 5;
    if (w >= Bn * Sn * Hn) return;
    int lane = threadIdx.x & 31;
    int h = w & 15, bs = w >> 4;
    int b = bs >> 10, s = bs & (Sn - 1);
    const float* xr = x1 + (size_t)bs * Dn;
    const float* wr = lrw + h * Dn;
    float acc = 0.f;
    for (int c = lane; c < Dn; c += 32) acc += xr[c] * wr[c];
    acc = warpsum(acc);
    if (lane == 0)
        lro[(size_t)(b * Hn + h) * Sn + s] = 1.f / (1.f + __expf(-(acc + lrb[h])));
}

// ---------------- TTT scan: 512 thr, mma A/D/E/Fcorr, W2 staged B/H ------
#define SV 65
#define PS 68
#define TS 72
#define WS 264
#define SCAN_FLOATS (64*SV + 2*64*PS + 4*64*TS + 16*WS + 64*WS + 256 + 64 + 64)
#define SCAN_SMEM (SCAN_FLOATS * 4)

__global__ __launch_bounds__(512) void ttt_scan_kernel(
    const float* __restrict__ XQ, const float* __restrict__ XK, const float* __restrict__ XV,
    const float* __restrict__ lr,
    const float* __restrict__ W1i, const float* __restrict__ b1i,
    const float* __restrict__ W2i, const float* __restrict__ b2i,
    const float* __restrict__ nw,  const float* __restrict__ nb,
    float* __restrict__ W2G, float* __restrict__ W2TG,
    float* __restrict__ X2G, float* __restrict__ gZ1G, float* __restrict__ X2bG,
    float* __restrict__ outp)
{
    extern __shared__ float sm[];
    float* sxv   = sm;
    float* ssc   = sxv  + 64 * SV;
    float* sgZ2  = ssc  + 64 * PS;
    float* sxqT  = sgZ2 + 64 * PS;
    float* sxkT  = sxqT + 64 * TS;
    float* sscT  = sxkT + 64 * TS;
    float* sgZ2T = sscT + 64 * TS;
    float* sstg  = sgZ2T+ 64 * TS;     // 16*WS = 4224 floats
    float* sW1   = sstg + 16 * WS;
    float* b1sm  = sW1  + 64 * WS;
    float* b2sm  = b1sm + 256;
    float* seta  = b2sm + 64;

    int bh = blockIdx.x, b = bh >> 4, h = bh & 15;
    int tid = threadIdx.x, w = tid >> 5, l = tid & 31;
    int g = l >> 2, tg = l & 3;
    int ty2 = tid >> 4, tx2 = tid & 15;
    int ft = tid >> 3, jt = tid & 7;
    int mi = (w & 3) * 16, ng = (w >> 2) * 64;
    float* W2r  = W2G  + (size_t)bh * 16384;
    float* W2Tr = W2TG + (size_t)bh * 16384;
    float* X2r  = X2G  + (size_t)bh * 16384;
    float* gZ1r = gZ1G + (size_t)bh * 16384;
    float* X2br = X2bG + (size_t)bh * 16384;
    const float* nwh = nw + h * 64;
    const float* nbh = nb + h * 64;

    for (int idx = tid; idx < 16384; idx += 512) {
        int e = idx >> 8, f = idx & 255;
        sW1[e * WS + f] = W1i[(size_t)h * 16384 + idx];
        W2r[idx]  = W2i[(size_t)h * 16384 + idx];
        W2Tr[idx] = W2i[(size_t)h * 16384 + f * 64 + e];
    }
    if (tid < 256) b1sm[tid] = b1i[h * 256 + tid];
    if (tid < 64)  b2sm[tid] = b2i[h * 64 + tid];
    __syncthreads();

    for (int n = 0; n < NCn; n++) {
        size_t tokbase = (size_t)b * Sn + n * Cn;
        for (int idx = tid; idx < 4096; idx += 512) {
            int i = idx >> 6, e = idx & 63;
            size_t gg = (tokbase + i) * Dn + h * 64 + e;
            sxqT[e * TS + i] = XQ[gg];
            sxkT[e * TS + i] = XK[gg];
            sxv [i * SV + e] = XV[gg];
        }
        if (tid < 64) seta[tid] = lr[(size_t)bh * Sn + n * 64 + tid] * (1.f / 64.f);
        __syncthreads();

        // ---- A (mma, 2 passes): Z1=xk@W1+b1 ; Z1q=xq@W1+b1
#pragma unroll
        for (int p = 0; p < 2; p++) {
            const float* T = p ? sxqT : sxkT;
            float c[8][4];
#pragma unroll
            for (int nt = 0; nt < 8; nt++) {
                int col = ng + nt * 8 + tg * 2;
                c[nt][0] = b1sm[col];   c[nt][1] = b1sm[col+1];
                c[nt][2] = b1sm[col];   c[nt][3] = b1sm[col+1];
            }
#pragma unroll
            for (int kb = 0; kb < 64; kb += 8) {
                unsigned a[4];
                a[0] = f2tf32(T[(kb+tg  )*TS + mi+g]);
                a[1] = f2tf32(T[(kb+tg  )*TS + mi+g+8]);
                a[2] = f2tf32(T[(kb+tg+4)*TS + mi+g]);
                a[3] = f2tf32(T[(kb+tg+4)*TS + mi+g+8]);
#pragma unroll
                for (int nt = 0; nt < 8; nt++) {
                    unsigned bb[2];
                    bb[0] = f2tf32(sW1[(kb+tg  )*WS + ng + nt*8 + g]);
                    bb[1] = f2tf32(sW1[(kb+tg+4)*WS + ng + nt*8 + g]);
                    mma_tf32(c[nt], a, bb);
                }
            }
#pragma unroll
            for (int nt = 0; nt < 8; nt++) {
                int col = ng + nt * 8 + tg * 2;
                int r0 = mi + g;
                if (p == 0) {
                    float x2o[4], gbo[4];
#pragma unroll
                    for (int r = 0; r < 4; r++) {
                        float z = c[nt][r];
                        float t = tanh_fast(0.79788456f * (z + 0.044715f * z * z * z));
                        x2o[r] = 0.5f * z * (1.f + t);
                        gbo[r] = 0.5f * z * (1.f - t * t) * (0.79788456f + 0.1070322243f * z * z)
                               + 0.5f * (1.f + t);
                    }
                    *(float2*)(X2r  + r0*256 + col)     = make_float2(x2o[0], x2o[1]);
                    *(float2*)(X2r  + (r0+8)*256 + col) = make_float2(x2o[2], x2o[3]);
                    *(float2*)(gZ1r + r0*256 + col)     = make_float2(gbo[0], gbo[1]);
                    *(float2*)(gZ1r + (r0+8)*256 + col) = make_float2(gbo[2], gbo[3]);
                } else {
                    *(float2*)(X2br + r0*256 + col)     = make_float2(c[nt][0], c[nt][1]);
                    *(float2*)(X2br + (r0+8)*256 + col) = make_float2(c[nt][2], c[nt][3]);
                }
            }
        }
        __syncthreads();

        // ---- B: Z2 = X2@W2 + b2 -> ssc (FFMA, W2 staged 64 rows at a time)
        {
            float acc[2][4];
#pragma unroll
            for (int u = 0; u < 2; u++)
#pragma unroll
                for (int v = 0; v < 4; v++) acc[u][v] = b2sm[tx2 * 4 + v];
            for (int kbb = 0; kbb < 256; kbb += 64) {
                __syncthreads();
                for (int idx = tid; idx < 4096; idx += 512) {
                    int rr = idx >> 6, cf = idx & 63;
                    sstg[rr*64 + cf] = W2r[(size_t)(kbb+rr)*64 + cf];
                }
                __syncthreads();
#pragma unroll 4
                for (int f0 = 0; f0 < 64; f0 += 4) {
                    float4 a4[2], b4[4];
#pragma unroll
                    for (int u = 0; u < 2; u++)
                        a4[u] = *(const float4*)(X2r + (ty2*2+u)*256 + kbb + f0);
#pragma unroll
                    for (int d = 0; d < 4; d++)
                        b4[d] = *(const float4*)(sstg + (f0+d)*64 + tx2*4);
#pragma unroll
                    for (int u = 0; u < 2; u++) {
                        acc[u][0] += a4[u].x*b4[0].x + a4[u].y*b4[1].x + a4[u].z*b4[2].x + a4[u].w*b4[3].x;
                        acc[u][1] += a4[u].x*b4[0].y + a4[u].y*b4[1].y + a4[u].z*b4[2].y + a4[u].w*b4[3].y;
                        acc[u][2] += a4[u].x*b4[0].z + a4[u].y*b4[1].z + a4[u].z*b4[2].z + a4[u].w*b4[3].z;
                        acc[u][3] += a4[u].x*b4[0].w + a4[u].y*b4[1].w + a4[u].z*b4[2].w + a4[u].w*b4[3].w;
                    }
                }
            }
#pragma unroll
            for (int u = 0; u < 2; u++)
#pragma unroll
                for (int v = 0; v < 4; v++) ssc[(ty2*2+u)*PS + tx2*4+v] = acc[u][v];
        }
        __syncthreads();

        // ---- C: gZ2 = ln_l2_bwd -> sgZ2 + sgZ2T
        for (int i = w; i < 64; i += 16) {
            float z0 = ssc[i*PS + l], z1 = ssc[i*PS + l + 32];
            float mu = warpsum(z0 + z1) * (1.f/64.f);
            float d0 = z0 - mu, d1 = z1 - mu;
            float var = warpsum(d0*d0 + d1*d1) * (1.f/64.f);
            float rstd = rsqrtf(var + EPSc);
            float xh0 = d0 * rstd, xh1 = d1 * rstd;
            float g0 = nwh[l], g1 = nwh[l+32];
            float t0 = sxv[i*SV + l]      - sxkT[l*TS + i];
            float t1 = sxv[i*SV + l + 32] - sxkT[(l+32)*TS + i];
            float gh0 = (g0*xh0 + nbh[l]    - t0) * g0;
            float gh1 = (g1*xh1 + nbh[l+32] - t1) * g1;
            float sgh = warpsum(gh0 + gh1);
            float sgx = warpsum(gh0*xh0 + gh1*xh1);
            float cc = rstd * (1.f/64.f);
            float o0 = (64.f*gh0 - sgh - xh0*sgx) * cc;
            float o1 = (64.f*gh1 - sgh - xh1*sgx) * cc;
            sgZ2[i*PS + l]        = o0;
            sgZ2[i*PS + l + 32]   = o1;
            sgZ2T[l*TS + i]       = o0;
            sgZ2T[(l+32)*TS + i]  = o1;
        }
        __syncthreads();

        // ---- D (mma): gZ1 = (gZ2 @ W2^T) * gb   (16-row staging)
        {
            float c[8][4];
#pragma unroll
            for (int nt = 0; nt < 8; nt++)
#pragma unroll
                for (int r = 0; r < 4; r++) c[nt][r] = 0.f;
#pragma unroll
            for (int kbb = 0; kbb < 64; kbb += 16) {
                __syncthreads();
                for (int idx = tid; idx < 4096; idx += 512) {
                    int rr = idx >> 8, cf = idx & 255;
                    sstg[rr*WS + cf] = W2Tr[(kbb+rr)*256 + cf];
                }
                __syncthreads();
#pragma unroll
                for (int kk = 0; kk < 2; kk++) {
                    int kb = kk * 8;
                    unsigned a[4];
                    a[0] = f2tf32(sgZ2T[(kbb+kb+tg  )*TS + mi+g]);
                    a[1] = f2tf32(sgZ2T[(kbb+kb+tg  )*TS + mi+g+8]);
                    a[2] = f2tf32(sgZ2T[(kbb+kb+tg+4)*TS + mi+g]);
                    a[3] = f2tf32(sgZ2T[(kbb+kb+tg+4)*TS + mi+g+8]);
#pragma unroll
                    for (int nt = 0; nt < 8; nt++) {
                        unsigned bb[2];
                        bb[0] = f2tf32(sstg[(kb+tg  )*WS + ng + nt*8 + g]);
                        bb[1] = f2tf32(sstg[(kb+tg+4)*WS + ng + nt*8 + g]);
                        mma_tf32(c[nt], a, bb);
                    }
                }
            }
#pragma unroll
            for (int nt = 0; nt < 8; nt++) {
                int col = ng + nt * 8 + tg * 2;
                int r0 = mi + g;
                float2 gb0 = *(const float2*)(gZ1r + r0*256 + col);
                float2 gb1 = *(const float2*)(gZ1r + (r0+8)*256 + col);
                *(float2*)(gZ1r + r0*256 + col)     = make_float2(c[nt][0]*gb0.x, c[nt][1]*gb0.y);
                *(float2*)(gZ1r + (r0+8)*256 + col) = make_float2(c[nt][2]*gb1.x, c[nt][3]*gb1.y);
            }
        }
        __syncthreads();

        // ---- E (mma): coef1 = -eta[k2]*(tril(xq@xk^T)+1) -> sscT
#pragma unroll
        for (int sub = 0; sub < 2; sub++) {
            int ncol = ((w >> 2) * 2 + sub) * 8;
            float c[4] = {0.f, 0.f, 0.f, 0.f};
#pragma unroll
            for (int kb = 0; kb < 64; kb += 8) {
                unsigned a[4], bb[2];
                a[0] = f2tf32(sxqT[(kb+tg  )*TS + mi+g]);
                a[1] = f2tf32(sxqT[(kb+tg  )*TS + mi+g+8]);
                a[2] = f2tf32(sxqT[(kb+tg+4)*TS + mi+g]);
                a[3] = f2tf32(sxqT[(kb+tg+4)*TS + mi+g+8]);
                bb[0] = f2tf32(sxkT[(kb+tg  )*TS + ncol + g]);
                bb[1] = f2tf32(sxkT[(kb+tg+4)*TS + ncol + g]);
                mma_tf32(c, a, bb);
            }
            int r0 = mi + g, k2 = ncol + tg * 2;
            sscT[k2*TS + r0]       = (k2   <= r0)   ? -seta[k2]  *(c[0]+1.f) : 0.f;
            sscT[(k2+1)*TS + r0]   = (k2+1 <= r0)   ? -seta[k2+1]*(c[1]+1.f) : 0.f;
            sscT[k2*TS + r0+8]     = (k2   <= r0+8) ? -seta[k2]  *(c[2]+1.f) : 0.f;
            sscT[(k2+1)*TS + r0+8] = (k2+1 <= r0+8) ? -seta[k2+1]*(c[3]+1.f) : 0.f;
        }
        __syncthreads();

        // ---- F (mma): Z1b = Z1q + coef1neg@gZ1 ; X2b = gelu (16-row staging)
        {
            float c[8][4];
#pragma unroll
            for (int nt = 0; nt < 8; nt++) {
                int col = ng + nt * 8 + tg * 2;
                int r0 = mi + g;
                float2 q0 = *(const float2*)(X2br + r0*256 + col);
                float2 q1 = *(const float2*)(X2br + (r0+8)*256 + col);
                c[nt][0] = q0.x; c[nt][1] = q0.y; c[nt][2] = q1.x; c[nt][3] = q1.y;
            }
#pragma unroll
            for (int kbb = 0; kbb < 64; kbb += 16) {
                __syncthreads();
                for (int idx = tid; idx < 4096; idx += 512) {
                    int rr = idx >> 8, cf = idx & 255;
                    sstg[rr*WS + cf] = gZ1r[(kbb+rr)*256 + cf];
                }
                __syncthreads();
#pragma unroll
                for (int kk = 0; kk < 2; kk++) {
                    int kb = kk * 8;
                    unsigned a[4];
                    a[0] = f2tf32(sscT[(kbb+kb+tg  )*TS + mi+g]);
                    a[1] = f2tf32(sscT[(kbb+kb+tg  )*TS + mi+g+8]);
                    a[2] = f2tf32(sscT[(kbb+kb+tg+4)*TS + mi+g]);
                    a[3] = f2tf32(sscT[(kbb+kb+tg+4)*TS + mi+g+8]);
#pragma unroll
                    for (int nt = 0; nt < 8; nt++) {
                        unsigned bb[2];
                        bb[0] = f2tf32(sstg[(kb+tg  )*WS + ng + nt*8 + g]);
                        bb[1] = f2tf32(sstg[(kb+tg+4)*WS + ng + nt*8 + g]);
                        mma_tf32(c[nt], a, bb);
                    }
                }
            }
#pragma unroll
            for (int nt = 0; nt < 8; nt++) {
                int col = ng + nt * 8 + tg * 2;
                int r0 = mi + g;
                float xo[4];
#pragma unroll
                for (int r = 0; r < 4; r++) {
                    float z = c[nt][r];
                    float t = tanh_fast(0.79788456f * (z + 0.044715f * z * z * z));
                    xo[r] = 0.5f * z * (1.f + t);
                }
                *(float2*)(X2br + r0*256 + col)     = make_float2(xo[0], xo[1]);
                *(float2*)(X2br + (r0+8)*256 + col) = make_float2(xo[2], xo[3]);
            }
        }
        __syncthreads();

        // ---- G: coef2 (FFMA)
        {
            float acc[2][4];
#pragma unroll
            for (int u = 0; u < 2; u++)
#pragma unroll
                for (int v = 0; v < 4; v++) acc[u][v] = 0.f;
            if (tx2 * 4 <= ty2 * 2 + 1) {
#pragma unroll 2
                for (int f0 = 0; f0 < 256; f0 += 4) {
                    float4 a4[2], b4[4];
#pragma unroll
                    for (int u = 0; u < 2; u++) a4[u] = *(const float4*)(X2br + (ty2*2+u)*256 + f0);
#pragma unroll
                    for (int v = 0; v < 4; v++) b4[v] = *(const float4*)(X2r + (tx2*4+v)*256 + f0);
#pragma unroll
                    for (int u = 0; u < 2; u++)
#pragma unroll
                        for (int v = 0; v < 4; v++)
                            acc[u][v] += a4[u].x*b4[v].x + a4[u].y*b4[v].y
                                       + a4[u].z*b4[v].z + a4[u].w*b4[v].w;
                }
            }
#pragma unroll
            for (int u = 0; u < 2; u++) {
                int i = ty2 * 2 + u;
#pragma unroll
                for (int v = 0; v < 4; v++) {
                    int j = tx2 * 4 + v;
                    ssc[i*PS + j] = (j <= i) ? seta[j] * (acc[u][v] + 1.f) : 0.f;
                }
            }
        }
        __syncthreads();

        // ---- H: Z2b = X2b@W2 + b2 - coef2@gZ2 -> sxv (W2 staged)
        {
            float acc[2][4];
#pragma unroll
            for (int u = 0; u < 2; u++)
#pragma unroll
                for (int v = 0; v < 4; v++) acc[u][v] = b2sm[tx2 * 4 + v];
            for (int kbb = 0; kbb < 256; kbb += 64) {
                __syncthreads();
                for (int idx = tid; idx < 4096; idx += 512) {
                    int rr = idx >> 6, cf = idx & 63;
                    sstg[rr*64 + cf] = W2r[(size_t)(kbb+rr)*64 + cf];
                }
                __syncthreads();
#pragma unroll 4
                for (int f0 = 0; f0 < 64; f0 += 4) {
                    float4 a4[2], b4[4];
#pragma unroll
                    for (int u = 0; u < 2; u++)
                        a4[u] = *(const float4*)(X2br + (ty2*2+u)*256 + kbb + f0);
#pragma unroll
                    for (int d = 0; d < 4; d++)
                        b4[d] = *(const float4*)(sstg + (f0+d)*64 + tx2*4);
#pragma unroll
                    for (int u = 0; u < 2; u++) {
                        acc[u][0] += a4[u].x*b4[0].x + a4[u].y*b4[1].x + a4[u].z*b4[2].x + a4[u].w*b4[3].x;
                        acc[u][1] += a4[u].x*b4[0].y + a4[u].y*b4[1].y + a4[u].z*b4[2].y + a4[u].w*b4[3].y;
                        acc[u][2] += a4[u].x*b4[0].z + a4[u].y*b4[1].z + a4[u].z*b4[2].z + a4[u].w*b4[3].z;
                        acc[u][3] += a4[u].x*b4[0].w + a4[u].y*b4[1].w + a4[u].z*b4[2].w + a4[u].w*b4[3].w;
                    }
                }
            }
#pragma unroll 4
            for (int k2 = 0; k2 < 64; k2++) {
                float cc0 = ssc[(ty2*2)*PS + k2];
                float cc1 = ssc[(ty2*2+1)*PS + k2];
                float4 gv4 = *(const float4*)(sgZ2 + k2*PS + tx2*4);
                acc[0][0] -= cc0*gv4.x; acc[0][1] -= cc0*gv4.y; acc[0][2] -= cc0*gv4.z; acc[0][3] -= cc0*gv4.w;
                acc[1][0] -= cc1*gv4.x; acc[1][1] -= cc1*gv4.y; acc[1][2] -= cc1*gv4.z; acc[1][3] -= cc1*gv4.w;
            }
#pragma unroll
            for (int u = 0; u < 2; u++)
#pragma unroll
                for (int v = 0; v < 4; v++) sxv[(ty2*2+u)*SV + tx2*4+v] = acc[u][v];
        }
        __syncthreads();

        // ---- I: out = xq + LN(Z2b)
        for (int i = w; i < 64; i += 16) {
            float z0 = sxv[i*SV + l], z1 = sxv[i*SV + l + 32];
            float mu = warpsum(z0 + z1) * (1.f/64.f);
            float d0 = z0 - mu, d1 = z1 - mu;
            float var = warpsum(d0*d0 + d1*d1) * (1.f/64.f);
            float rstd = rsqrtf(var + EPSc);
            size_t gg = (tokbase + i) * Dn + h * 64;
            outp[gg + l]      = sxqT[l*TS + i]      + nwh[l]    * d0 * rstd + nbh[l];
            outp[gg + l + 32] = sxqT[(l+32)*TS + i] + nwh[l+32] * d1 * rstd + nbh[l+32];
        }

        // ---- J1: W1 -= (eta*xk)^T @ gZ1  (sW1 smem)
        {
            u64 acc2[4][4];
#pragma unroll
            for (int u = 0; u < 4; u++)
#pragma unroll
                for (int p = 0; p < 4; p++) acc2[u][p] = 0ULL;
#pragma unroll 4
            for (int i = 0; i < 64; i++) {
                float et = seta[i];
                float4 g0 = *(const float4*)(gZ1r + i*256 + l*8);
                float4 g1 = *(const float4*)(gZ1r + i*256 + l*8 + 4);
                u64 gv2[4];
                f4tou2(g0, gv2[0], gv2[1]); f4tou2(g1, gv2[2], gv2[3]);
#pragma unroll
                for (int u = 0; u < 4; u++) {
                    float a = et * sxkT[(w*4+u)*TS + i];
                    u64 a2 = f2pack(a, a);
#pragma unroll
                    for (int p = 0; p < 4; p++) acc2[u][p] = ffma2(a2, gv2[p], acc2[u][p]);
                }
            }
#pragma unroll
            for (int u = 0; u < 4; u++) {
                int e = w * 4 + u;
                float av[8];
#pragma unroll
                for (int p = 0; p < 4; p++) f2unpack(acc2[u][p], av[2*p], av[2*p+1]);
                float4* wp = (float4*)(sW1 + e*WS + l*8);
                float4 o0 = wp[0], o1 = wp[1];
                wp[0] = make_float4(o0.x-av[0], o0.y-av[1], o0.z-av[2], o0.w-av[3]);
                wp[1] = make_float4(o1.x-av[4], o1.y-av[5], o1.z-av[6], o1.w-av[7]);
            }
        }
        // J2: b1
        if (tid < 256) {
            float acc = 0.f;
#pragma unroll 8
            for (int i = 0; i < 64; i++) acc += seta[i] * gZ1r[i*256 + tid];
            b1sm[tid] -= acc;
        }
        // J3: W2 + W2T (global)
        {
            u64 acc2[4][4];
#pragma unroll
            for (int u = 0; u < 4; u++)
#pragma unroll
                for (int p = 0; p < 4; p++) acc2[u][p] = 0ULL;
#pragma unroll 4
            for (int i = 0; i < 64; i++) {
                float et = seta[i];
                float4 x0 = *(const float4*)(X2r + i*256 + ft*4);
                float4 gv0 = *(const float4*)(sgZ2 + i*PS + jt*8);
                float4 gv1 = *(const float4*)(sgZ2 + i*PS + jt*8 + 4);
                u64 gv2[4];
                f4tou2(gv0, gv2[0], gv2[1]); f4tou2(gv1, gv2[2], gv2[3]);
                float a[4] = {et*x0.x, et*x0.y, et*x0.z, et*x0.w};
#pragma unroll
                for (int u = 0; u < 4; u++) {
                    u64 a2 = f2pack(a[u], a[u]);
#pragma unroll
                    for (int p = 0; p < 4; p++) acc2[u][p] = ffma2(a2, gv2[p], acc2[u][p]);
                }
            }
#pragma unroll
            for (int u = 0; u < 4; u++) {
                int f = ft * 4 + u;
                float av[8];
#pragma unroll
                for (int p = 0; p < 4; p++) f2unpack(acc2[u][p], av[2*p], av[2*p+1]);
                float4* wp0 = (float4*)(W2r + f*64 + jt*8);
                float4* wp1 = (float4*)(W2r + f*64 + jt*8 + 4);
                float4 o0 = wp0[0], o1 = wp1[0];
                wp0[0] = make_float4(o0.x-av[0], o0.y-av[1], o0.z-av[2], o0.w-av[3]);
                wp1[0] = make_float4(o1.x-av[4], o1.y-av[5], o1.z-av[6], o1.w-av[7]);
#pragma unroll
                for (int v = 0; v < 8; v++)
                    W2Tr[(jt*8+v)*256 + f] -= av[v];
            }
        }
        // J4: b2
        if (tid < 64) {
            float acc = 0.f;
#pragma unroll 8
            for (int i = 0; i < 64; i++) acc += seta[i] * sgZ2[i*PS + tid];
            b2sm[tid] -= acc;
        }
        __syncthreads();
    }
}

// ---------------- Launch ----------------
extern "C" void kernel_launch(void* const* d_in, const int* in_sizes, int n_in,
                              void* d_out, int out_size)
{
    const float* x       = (const float*)d_in[0];
    const float* ln1_w   = (const float*)d_in[1];
    const float* ln1_b   = (const float*)d_in[2];
    const float* attn_wq = (const float*)d_in[3];
    const float* attn_wk = (const float*)d_in[4];
    const float* attn_wv = (const float*)d_in[5];
    const float* attn_wo = (const float*)d_in[6];
    const float* wq_w    = (const float*)d_in[7];
    const float* wq_b    = (const float*)d_in[8];
    const float* wk_w    = (const float*)d_in[9];
    const float* wk_b    = (const float*)d_in[10];
    const float* wv_w    = (const float*)d_in[11];
    const float* wv_b    = (const float*)d_in[12];
    const float* wo_w    = (const float*)d_in[13];
    const float* wo_b    = (const float*)d_in[14];
    const float* W1      = (const float*)d_in[15];
    const float* b1      = (const float*)d_in[16];
    const float* W2      = (const float*)d_in[17];
    const float* b2      = (const float*)d_in[18];
    const float* ttt_nw  = (const float*)d_in[19];
    const float* ttt_nb  = (const float*)d_in[20];
    const float* lr_w    = (const float*)d_in[21];
    const float* lr_b    = (const float*)d_in[22];
    const float* pn_w    = (const float*)d_in[23];
    const float* pn_b    = (const float*)d_in[24];
    const float* gate_a  = (const float*)d_in[25];
    float* out = (float*)d_out;

    float *p_h,*p_q,*p_k,*p_v,*p_o,*p_x1,*p_lr,*p_W2,*p_W2T,*p_X2,*p_gZ1,*p_X2b;
    cudaGetSymbolAddress((void**)&p_h,  g_h);
    cudaGetSymbolAddress((void**)&p_q,  g_q);
    cudaGetSymbolAddress((void**)&p_k,  g_k);
    cudaGetSymbolAddress((void**)&p_v,  g_v);
    cudaGetSymbolAddress((void**)&p_o,  g_o);
    cudaGetSymbolAddress((void**)&p_x1, g_x1);
    cudaGetSymbolAddress((void**)&p_lr, g_lr);
    cudaGetSymbolAddress((void**)&p_W2, g_W2s);
    cudaGetSymbolAddress((void**)&p_W2T,g_W2Ts);
    cudaGetSymbolAddress((void**)&p_X2, g_X2);
    cudaGetSymbolAddress((void**)&p_gZ1,g_gZ1);
    cudaGetSymbolAddress((void**)&p_X2b,g_X2b);

    cudaFuncSetAttribute(ttt_scan_kernel,   cudaFuncAttributeMaxDynamicSharedMemorySize, SCAN_SMEM);
    cudaFuncSetAttribute(attn_flash_kernel, cudaFuncAttributeMaxDynamicSharedMemorySize, ATT_SMEM);

    const int M = Bn * Sn;
    dim3 ggrid(Dn / 128, M / 128);
    dim3 ggrid3(Dn / 128, M / 128, 3);
    int nwarp_grid = (Bn * Sn * Hn) / 8;

    ln_kernel<<<M, 256>>>(x, ln1_w, ln1_b, p_h);
    gemm3_nt_kernel<<<ggrid3, 256>>>(p_h, attn_wq, attn_wk, attn_wv,
                                     p_q, p_k, p_v, nullptr, nullptr, nullptr);
    attn_flash_kernel<<<dim3(16, 64), 256, ATT_SMEM>>>(p_q, p_k, p_v, p_o);
    gemm_nt_kernel<<<ggrid, 256>>>(p_o, attn_wo, p_x1, nullptr, x, nullptr);
    gemm3_nt_kernel<<<ggrid3, 256>>>(p_x1, wq_w, wk_w, wv_w,
                                     p_q, p_k, p_v, wq_b, wk_b, wv_b);
    prep_kernel<<<nwarp_grid, 256>>>(p_q, p_k, p_v, ttt_nw, ttt_nb);
    lr_kernel<<<nwarp_grid, 256>>>(p_x1, lr_w, lr_b, p_lr);
    ttt_scan_kernel<<<Bn * Hn, 512, SCAN_SMEM>>>(
        p_q, p_k, p_v, p_lr, W1, b1, W2, b2, ttt_nw, ttt_nb,
        p_W2, p_W2T, p_X2, p_gZ1, p_X2b, p_o);
    ln_kernel<<<M, 256>>>(p_o, pn_w, pn_b, p_h);
    gemm_nt_kernel<<<ggrid, 256>>>(p_h, wo_w, out, wo_b, p_x1, gate_a);
}

// round 14
// speedup vs baseline: 1.7877x; 1.0789x over previous
#include <cuda_runtime.h>
#include <math.h>

#define Bn 4
#define Sn 1024
#define Dn 1024
#define Hn 16
#define HDn 64
#define Cn 64
#define NCn 16
#define DFFn 256
#define EPSc 1e-6f
#define BSD (Bn*Sn*Dn)

typedef unsigned long long u64;
__device__ __forceinline__ u64 f2pack(float lo, float hi) {
    u64 r; asm("mov.b64 %0, {%1, %2};" : "=l"(r) : "f"(lo), "f"(hi)); return r;
}
__device__ __forceinline__ void f2unpack(u64 p, float& lo, float& hi) {
    asm("mov.b64 {%0, %1}, %2;" : "=f"(lo), "=f"(hi) : "l"(p));
}
__device__ __forceinline__ u64 ffma2(u64 a, u64 b, u64 c) {
    u64 d; asm("fma.rn.f32x2 %0, %1, %2, %3;" : "=l"(d) : "l"(a), "l"(b), "l"(c)); return d;
}
__device__ __forceinline__ void f4tou2(float4 f, u64& p0, u64& p1) {
    p0 = f2pack(f.x, f.y); p1 = f2pack(f.z, f.w);
}
__device__ __forceinline__ unsigned f2tf32(float f) {
    unsigned r; asm("cvt.rna.tf32.f32 %0, %1;" : "=r"(r) : "f"(f)); return r;
}
__device__ __forceinline__ unsigned bf2pack(float lo, float hi) {
    unsigned r; asm("cvt.rn.bf16x2.f32 %0, %1, %2;" : "=r"(r) : "f"(hi), "f"(lo)); return r;
}
__device__ __forceinline__ void mma_tf32(float* c, const unsigned* a, const unsigned* b) {
    asm volatile("mma.sync.aligned.m16n8k8.row.col.f32.tf32.tf32.f32 "
        "{%0,%1,%2,%3}, {%4,%5,%6,%7}, {%8,%9}, {%0,%1,%2,%3};"
        : "+f"(c[0]), "+f"(c[1]), "+f"(c[2]), "+f"(c[3])
        : "r"(a[0]), "r"(a[1]), "r"(a[2]), "r"(a[3]), "r"(b[0]), "r"(b[1]));
}
__device__ __forceinline__ void mma_bf16(float* c, const unsigned* a, const unsigned* b) {
    asm volatile("mma.sync.aligned.m16n8k16.row.col.f32.bf16.bf16.f32 "
        "{%0,%1,%2,%3}, {%4,%5,%6,%7}, {%8,%9}, {%0,%1,%2,%3};"
        : "+f"(c[0]), "+f"(c[1]), "+f"(c[2]), "+f"(c[3])
        : "r"(a[0]), "r"(a[1]), "r"(a[2]), "r"(a[3]), "r"(b[0]), "r"(b[1]));
}

__device__ float g_h [BSD];
__device__ float g_q [BSD];
__device__ float g_k [BSD];
__device__ float g_v [BSD];
__device__ float g_o [BSD];
__device__ float g_x1[BSD];
__device__ float g_lr[Bn*Hn*Sn];
__device__ float g_W2s [Bn*Hn*16384];
__device__ float g_W2Ts[Bn*Hn*16384];
__device__ float g_X2  [Bn*Hn*16384];
__device__ float g_gZ1 [Bn*Hn*16384];
__device__ float g_X2b [Bn*Hn*16384];

__device__ __forceinline__ float warpsum(float v) {
#pragma unroll
    for (int o = 16; o > 0; o >>= 1) v += __shfl_xor_sync(0xffffffffu, v, o);
    return v;
}
__device__ __forceinline__ float warpmax(float v) {
#pragma unroll
    for (int o = 16; o > 0; o >>= 1) v = fmaxf(v, __shfl_xor_sync(0xffffffffu, v, o));
    return v;
}
__device__ __forceinline__ float blocksum256(float v) {
    __shared__ float red[8];
    int lane = threadIdx.x & 31, w = threadIdx.x >> 5;
    v = warpsum(v);
    if (lane == 0) red[w] = v;
    __syncthreads();
    float r = (lane < 8) ? red[lane] : 0.f;
    r = warpsum(r);
    __syncthreads();
    return r;
}
__device__ __forceinline__ float tanh_fast(float x) {
    float e = __expf(2.f * x);
    return 1.f - __fdividef(2.f, e + 1.f);
}

// ---------------- LayerNorm rows of 1024 ----------------
__global__ __launch_bounds__(256) void ln_kernel(
    const float* __restrict__ x, const float* __restrict__ g,
    const float* __restrict__ b, float* __restrict__ y)
{
    int row = blockIdx.x, tid = threadIdx.x;
    const float* xr = x + (size_t)row * Dn;
    float v[4]; float s = 0.f;
#pragma unroll
    for (int i = 0; i < 4; i++) { v[i] = xr[tid + 256 * i]; s += v[i]; }
    s = blocksum256(s);
    float mu = s * (1.f / Dn), ss = 0.f;
#pragma unroll
    for (int i = 0; i < 4; i++) { float d = v[i] - mu; ss += d * d; }
    ss = blocksum256(ss);
    float rstd = rsqrtf(ss * (1.f / Dn) + EPSc);
    float* yr = y + (size_t)row * Dn;
#pragma unroll
    for (int i = 0; i < 4; i++) {
        int c = tid + 256 * i;
        yr[c] = (v[i] - mu) * rstd * g[c] + b[c];
    }
}

// ---------------- bf16 tensor-core GEMM, double-buffered ----------------
// C = A@B^T, fp32 accum. BK=16, bf16x2-packed k-pairs: As[kp][m], Bs[kp][n].
#define GSTR 136
__device__ __forceinline__ void gemm_core(
    const float* __restrict__ A, const float* __restrict__ B, float* __restrict__ C,
    const float* __restrict__ bias, const float* __restrict__ res,
    const float* __restrict__ gate, int bm, int bn)
{
    const int N = 1024, K = 1024, BK = 16;
    __shared__ unsigned As[2][8][GSTR];
    __shared__ unsigned Bs[2][8][GSTR];
    int t = threadIdx.x;
    int warp = t >> 5, lane = t & 31;
    int wm = warp >> 1, wn = warp & 1;
    int g = lane >> 2, tg = lane & 3;

    float acc[2][8][4];
#pragma unroll
    for (int mt = 0; mt < 2; mt++)
#pragma unroll
        for (int nt = 0; nt < 8; nt++)
#pragma unroll
            for (int r = 0; r < 4; r++) acc[mt][nt][r] = 0.f;

    int r128 = t >> 1, kc = (t & 1) * 8, kp0 = (t & 1) * 4;
    const float* Ab = A + (size_t)(bm + r128) * K + kc;
    const float* Bb = B + (size_t)(bn + r128) * K + kc;
    float4 a0 = *(const float4*)(Ab);
    float4 a1 = *(const float4*)(Ab + 4);
    float4 b0 = *(const float4*)(Bb);
    float4 b1 = *(const float4*)(Bb + 4);

    As[0][kp0+0][r128] = bf2pack(a0.x, a0.y);
    As[0][kp0+1][r128] = bf2pack(a0.z, a0.w);
    As[0][kp0+2][r128] = bf2pack(a1.x, a1.y);
    As[0][kp0+3][r128] = bf2pack(a1.z, a1.w);
    Bs[0][kp0+0][r128] = bf2pack(b0.x, b0.y);
    Bs[0][kp0+1][r128] = bf2pack(b0.z, b0.w);
    Bs[0][kp0+2][r128] = bf2pack(b1.x, b1.y);
    Bs[0][kp0+3][r128] = bf2pack(b1.z, b1.w);
    __syncthreads();

    int cur = 0;
    for (int k0 = 0; k0 < K; k0 += BK) {
        bool more = (k0 + BK < K);
        if (more) {
            a0 = *(const float4*)(Ab + k0 + BK);
            a1 = *(const float4*)(Ab + k0 + BK + 4);
            b0 = *(const float4*)(Bb + k0 + BK);
            b1 = *(const float4*)(Bb + k0 + BK + 4);
        }
        {
            unsigned af[2][4], bf[8][2];
#pragma unroll
            for (int mt = 0; mt < 2; mt++) {
                int mb = wm * 32 + mt * 16 + g;
                af[mt][0] = As[cur][tg  ][mb];
                af[mt][1] = As[cur][tg  ][mb+8];
                af[mt][2] = As[cur][tg+4][mb];
                af[mt][3] = As[cur][tg+4][mb+8];
            }
#pragma unroll
            for (int nt = 0; nt < 8; nt++) {
                int nb = wn * 64 + nt * 8 + g;
                bf[nt][0] = Bs[cur][tg  ][nb];
                bf[nt][1] = Bs[cur][tg+4][nb];
            }
#pragma unroll
            for (int mt = 0; mt < 2; mt++)
#pragma unroll
                for (int nt = 0; nt < 8; nt++)
                    mma_bf16(acc[mt][nt], af[mt], bf[nt]);
        }
        if (more) {
            int nxt = cur ^ 1;
            As[nxt][kp0+0][r128] = bf2pack(a0.x, a0.y);
            As[nxt][kp0+1][r128] = bf2pack(a0.z, a0.w);
            As[nxt][kp0+2][r128] = bf2pack(a1.x, a1.y);
            As[nxt][kp0+3][r128] = bf2pack(a1.z, a1.w);
            Bs[nxt][kp0+0][r128] = bf2pack(b0.x, b0.y);
            Bs[nxt][kp0+1][r128] = bf2pack(b0.z, b0.w);
            Bs[nxt][kp0+2][r128] = bf2pack(b1.x, b1.y);
            Bs[nxt][kp0+3][r128] = bf2pack(b1.z, b1.w);
            __syncthreads();
            cur = nxt;
        }
    }

    float bs2[8][2], gv2[8][2];
#pragma unroll
    for (int nt = 0; nt < 8; nt++) {
        int col = bn + wn * 64 + nt * 8 + tg * 2;
        if (bias) { bs2[nt][0] = bias[col]; bs2[nt][1] = bias[col+1]; }
        else      { bs2[nt][0] = 0.f;       bs2[nt][1] = 0.f; }
        if (gate) { gv2[nt][0] = tanhf(gate[col]); gv2[nt][1] = tanhf(gate[col+1]); }
    }
#pragma unroll
    for (int mt = 0; mt < 2; mt++) {
        int row0 = bm + wm * 32 + mt * 16 + g;
#pragma unroll
        for (int nt = 0; nt < 8; nt++) {
            int col = bn + wn * 64 + nt * 8 + tg * 2;
            float v0 = acc[mt][nt][0] + bs2[nt][0];
            float v1 = acc[mt][nt][1] + bs2[nt][1];
            float v2 = acc[mt][nt][2] + bs2[nt][0];
            float v3 = acc[mt][nt][3] + bs2[nt][1];
            if (gate) {
                float2 r0 = *(const float2*)(res + (size_t)row0 * N + col);
                float2 r1 = *(const float2*)(res + (size_t)(row0+8) * N + col);
                v0 = r0.x + gv2[nt][0] * v0; v1 = r0.y + gv2[nt][1] * v1;
                v2 = r1.x + gv2[nt][0] * v2; v3 = r1.y + gv2[nt][1] * v3;
            } else if (res) {
                float2 r0 = *(const float2*)(res + (size_t)row0 * N + col);
                float2 r1 = *(const float2*)(res + (size_t)(row0+8) * N + col);
                v0 += r0.x; v1 += r0.y; v2 += r1.x; v3 += r1.y;
            }
            *(float2*)(C + (size_t)row0 * N + col)     = make_float2(v0, v1);
            *(float2*)(C + (size_t)(row0+8) * N + col) = make_float2(v2, v3);
        }
    }
}

__global__ __launch_bounds__(256, 2) void gemm_nt_kernel(
    const float* __restrict__ A, const float* __restrict__ B, float* __restrict__ C,
    const float* __restrict__ bias, const float* __restrict__ res,
    const float* __restrict__ gate)
{
    gemm_core(A, B, C, bias, res, gate, blockIdx.y * 128, blockIdx.x * 128);
}

__global__ __launch_bounds__(256, 2) void gemm3_nt_kernel(
    const float* __restrict__ A,
    const float* __restrict__ B0, const float* __restrict__ B1, const float* __restrict__ B2,
    float* __restrict__ C0, float* __restrict__ C1, float* __restrict__ C2,
    const float* __restrict__ b0, const float* __restrict__ b1, const float* __restrict__ b2)
{
    const float* B; float* C; const float* bias;
    if (blockIdx.z == 0)      { B = B0; C = C0; bias = b0; }
    else if (blockIdx.z == 1) { B = B1; C = C1; bias = b1; }
    else                      { B = B2; C = C2; bias = b2; }
    gemm_core(A, B, C, bias, nullptr, nullptr, blockIdx.y * 128, blockIdx.x * 128);
}

// ---------------- Flash attention: tf32 mma ----------------
#define ATS 72
#define APS 65
#define ASS 68
#define ATT_SMEM ((3*64*ATS + 64*APS + 64*ASS + 192) * 4)

__global__ __launch_bounds__(256) void attn_flash_kernel(
    const float* __restrict__ q, const float* __restrict__ k,
    const float* __restrict__ v, float* __restrict__ o)
{
    extern __shared__ float sm[];
    unsigned* QsT = (unsigned*)sm;
    unsigned* KsT = QsT + 64 * ATS;
    unsigned* Vs  = KsT + 64 * ATS;
    unsigned* PsT = Vs  + 64 * ATS;
    float* Ss   = (float*)(PsT + 64 * APS);
    float* smm  = Ss + 64 * ASS;
    float* sml  = smm + 64;
    float* scor = sml + 64;

    int qt = blockIdx.x, bh = blockIdx.y;
    int b = bh >> 4, h = bh & 15;
    int tid = threadIdx.x, warp = tid >> 5, lane = tid & 31;
    int wm = warp >> 1, wn = warp & 1;
    int mi = wm * 16, ng = wn * 32;
    int g = lane >> 2, tg = lane & 3;
    size_t base = ((size_t)b * Sn) * Dn + h * HDn;

    for (int idx = tid; idx < 4096; idx += 256) {
        int r = idx >> 6, e = idx & 63;
        QsT[e * ATS + r] = f2tf32(q[base + (size_t)(qt * 64 + r) * Dn + e] * 0.125f);
    }
    if (tid < 64) { smm[tid] = -1e30f; sml[tid] = 0.f; }
    float co[4][4];
#pragma unroll
    for (int nt = 0; nt < 4; nt++)
#pragma unroll
        for (int r = 0; r < 4; r++) co[nt][r] = 0.f;
    __syncthreads();

    for (int kt = 0; kt <= qt; kt++) {
        for (int idx = tid; idx < 4096; idx += 256) {
            int r = idx >> 6, e = idx & 63;
            size_t gg = base + (size_t)(kt * 64 + r) * Dn + e;
            KsT[e * ATS + r] = f2tf32(k[gg]);
            Vs [r * ATS + e] = f2tf32(v[gg]);
        }
        __syncthreads();

        float c[4][4];
#pragma unroll
        for (int nt = 0; nt < 4; nt++)
#pragma unroll
            for (int r = 0; r < 4; r++) c[nt][r] = 0.f;
#pragma unroll
        for (int kb = 0; kb < 64; kb += 8) {
            unsigned a[4];
            a[0] = QsT[(kb+tg  )*ATS + mi+g];
            a[1] = QsT[(kb+tg  )*ATS + mi+g+8];
            a[2] = QsT[(kb+tg+4)*ATS + mi+g];
            a[3] = QsT[(kb+tg+4)*ATS + mi+g+8];
#pragma unroll
            for (int nt = 0; nt < 4; nt++) {
                unsigned bb[2];
                bb[0] = KsT[(kb+tg  )*ATS + ng + nt*8 + g];
                bb[1] = KsT[(kb+tg+4)*ATS + ng + nt*8 + g];
                mma_tf32(c[nt], a, bb);
            }
        }
        bool diag = (kt == qt);
        int r0 = mi + g, r1 = mi + g + 8;
#pragma unroll
        for (int nt = 0; nt < 4; nt++) {
            int col = ng + nt * 8 + tg * 2;
            if (diag) {
                if (col   > r0) c[nt][0] = -1e30f;
                if (col+1 > r0) c[nt][1] = -1e30f;
                if (col   > r1) c[nt][2] = -1e30f;
                if (col+1 > r1) c[nt][3] = -1e30f;
            }
            Ss[r0*ASS + col]   = c[nt][0];
            Ss[r0*ASS + col+1] = c[nt][1];
            Ss[r1*ASS + col]   = c[nt][2];
            Ss[r1*ASS + col+1] = c[nt][3];
        }
        __syncthreads();

        for (int i = warp; i < 64; i += 8) {
            float s0 = Ss[i*ASS + lane], s1 = Ss[i*ASS + lane + 32];
            float mx = warpmax(fmaxf(s0, s1));
            float nm = fmaxf(smm[i], mx);
            float corr = __expf(smm[i] - nm);
            float p0 = __expf(s0 - nm), p1 = __expf(s1 - nm);
            float ps = warpsum(p0 + p1);
            if (lane == 0) { sml[i] = sml[i] * corr + ps; smm[i] = nm; scor[i] = corr; }
            PsT[lane*APS + i]      = f2tf32(p0);
            PsT[(lane+32)*APS + i] = f2tf32(p1);
        }
        __syncthreads();

        float cr0 = scor[r0], cr1 = scor[r1];
#pragma unroll
        for (int nt = 0; nt < 4; nt++) {
            co[nt][0] *= cr0; co[nt][1] *= cr0;
            co[nt][2] *= cr1; co[nt][3] *= cr1;
        }
#pragma unroll
        for (int kb = 0; kb < 64; kb += 8) {
            unsigned a[4];
            a[0] = PsT[(kb+tg  )*APS + mi+g];
            a[1] = PsT[(kb+tg  )*APS + mi+g+8];
            a[2] = PsT[(kb+tg+4)*APS + mi+g];
            a[3] = PsT[(kb+tg+4)*APS + mi+g+8];
#pragma unroll
            for (int nt = 0; nt < 4; nt++) {
                unsigned bb[2];
                bb[0] = Vs[(kb+tg  )*ATS + ng + nt*8 + g];
                bb[1] = Vs[(kb+tg+4)*ATS + ng + nt*8 + g];
                mma_tf32(co[nt], a, bb);
            }
        }
        __syncthreads();
    }

    int r0 = mi + g, r1 = mi + g + 8;
    float inv0 = __fdividef(1.f, sml[r0]);
    float inv1 = __fdividef(1.f, sml[r1]);
#pragma unroll
    for (int nt = 0; nt < 4; nt++) {
        int col = ng + nt * 8 + tg * 2;
        *(float2*)(o + base + (size_t)(qt*64 + r0) * Dn + col) =
            make_float2(co[nt][0]*inv0, co[nt][1]*inv0);
        *(float2*)(o + base + (size_t)(qt*64 + r1) * Dn + col) =
            make_float2(co[nt][2]*inv1, co[nt][3]*inv1);
    }
}

// ---------------- prep & lr ----------------
__global__ __launch_bounds__(256) void prep_kernel(
    float* __restrict__ XQ, float* __restrict__ XK, float* __restrict__ XV,
    const float* __restrict__ nw, const float* __restrict__ nb)
{
    int w = (blockIdx.x * blockDim.x + threadIdx.x) >> 5;
    if (w >= Bn * Sn * Hn) return;
    int lane = threadIdx.x & 31;
    int h = w & 15, bs = w >> 4;
    size_t base = (size_t)bs * Dn + h * HDn;
    float q0 = XQ[base + lane], q1 = XQ[base + lane + 32];
    float qi = 1.f / fmaxf(sqrtf(warpsum(q0*q0 + q1*q1)), 1e-12f);
    XQ[base + lane] = q0 * qi; XQ[base + lane + 32] = q1 * qi;
    float k0 = XK[base + lane], k1 = XK[base + lane + 32];
    float ki = 1.f / fmaxf(sqrtf(warpsum(k0*k0 + k1*k1)), 1e-12f);
    k0 *= ki; k1 *= ki;
    XK[base + lane] = k0; XK[base + lane + 32] = k1;
    float v0 = XV[base + lane], v1 = XV[base + lane + 32];
    float mu = warpsum(v0 + v1) * (1.f / 64.f);
    float d0 = v0 - mu, d1 = v1 - mu;
    float var = warpsum(d0*d0 + d1*d1) * (1.f / 64.f);
    float rstd = rsqrtf(var + EPSc);
    XV[base + lane]      = nw[h*64+lane]    * d0 * rstd + nb[h*64+lane]    + k0;
    XV[base + lane + 32] = nw[h*64+lane+32] * d1 * rstd + nb[h*64+lane+32] + k1;
}

__global__ __launch_bounds__(256) void lr_kernel(
    const float* __restrict__ x1, const float* __restrict__ lrw,
    const float* __restrict__ lrb, float* __restrict__ lro)
{
    int w = (blockIdx.x * blockDim.x + threadIdx.x) >> 5;
    if (w >= Bn * Sn * Hn) return;
    int lane = threadIdx.x & 31;
    int h = w & 15, bs = w >> 4;
    int b = bs >> 10, s = bs & (Sn - 1);
    const float* xr = x1 + (size_t)bs * Dn;
    const float* wr = lrw + h * Dn;
    float acc = 0.f;
    for (int c = lane; c < Dn; c += 32) acc += xr[c] * wr[c];
    acc = warpsum(acc);
    if (lane == 0)
        lro[(size_t)(b * Hn + h) * Sn + s] = 1.f / (1.f + __expf(-(acc + lrb[h])));
}

// ---------------- TTT scan: 512 thr, mma A/D/E/Fcorr, W2 staged B/H ------
#define SV 65
#define PS 68
#define TS 72
#define WS 264
#define SCAN_FLOATS (64*SV + 2*64*PS + 4*64*TS + 16*WS + 64*WS + 256 + 64 + 64)
#define SCAN_SMEM (SCAN_FLOATS * 4)

__global__ __launch_bounds__(512) void ttt_scan_kernel(
    const float* __restrict__ XQ, const float* __restrict__ XK, const float* __restrict__ XV,
    const float* __restrict__ lr,
    const float* __restrict__ W1i, const float* __restrict__ b1i,
    const float* __restrict__ W2i, const float* __restrict__ b2i,
    const float* __restrict__ nw,  const float* __restrict__ nb,
    float* __restrict__ W2G, float* __restrict__ W2TG,
    float* __restrict__ X2G, float* __restrict__ gZ1G, float* __restrict__ X2bG,
    float* __restrict__ outp)
{
    extern __shared__ float sm[];
    float* sxv   = sm;
    float* ssc   = sxv  + 64 * SV;
    float* sgZ2  = ssc  + 64 * PS;
    float* sxqT  = sgZ2 + 64 * PS;
    float* sxkT  = sxqT + 64 * TS;
    float* sscT  = sxkT + 64 * TS;
    float* sgZ2T = sscT + 64 * TS;
    float* sstg  = sgZ2T+ 64 * TS;
    float* sW1   = sstg + 16 * WS;
    float* b1sm  = sW1  + 64 * WS;
    float* b2sm  = b1sm + 256;
    float* seta  = b2sm + 64;

    int bh = blockIdx.x, b = bh >> 4, h = bh & 15;
    int tid = threadIdx.x, w = tid >> 5, l = tid & 31;
    int g = l >> 2, tg = l & 3;
    int ty2 = tid >> 4, tx2 = tid & 15;
    int ft = tid >> 3, jt = tid & 7;
    int mi = (w & 3) * 16, ng = (w >> 2) * 64;
    float* W2r  = W2G  + (size_t)bh * 16384;
    float* W2Tr = W2TG + (size_t)bh * 16384;
    float* X2r  = X2G  + (size_t)bh * 16384;
    float* gZ1r = gZ1G + (size_t)bh * 16384;
    float* X2br = X2bG + (size_t)bh * 16384;
    const float* nwh = nw + h * 64;
    const float* nbh = nb + h * 64;

    for (int idx = tid; idx < 16384; idx += 512) {
        int e = idx >> 8, f = idx & 255;
        sW1[e * WS + f] = W1i[(size_t)h * 16384 + idx];
        W2r[idx]  = W2i[(size_t)h * 16384 + idx];
        W2Tr[idx] = W2i[(size_t)h * 16384 + f * 64 + e];
    }
    if (tid < 256) b1sm[tid] = b1i[h * 256 + tid];
    if (tid < 64)  b2sm[tid] = b2i[h * 64 + tid];
    __syncthreads();

    for (int n = 0; n < NCn; n++) {
        size_t tokbase = (size_t)b * Sn + n * Cn;
        for (int idx = tid; idx < 4096; idx += 512) {
            int i = idx >> 6, e = idx & 63;
            size_t gg = (tokbase + i) * Dn + h * 64 + e;
            sxqT[e * TS + i] = XQ[gg];
            sxkT[e * TS + i] = XK[gg];
            sxv [i * SV + e] = XV[gg];
        }
        if (tid < 64) seta[tid] = lr[(size_t)bh * Sn + n * 64 + tid] * (1.f / 64.f);
        __syncthreads();

        // ---- A (mma, 2 passes): Z1=xk@W1+b1 ; Z1q=xq@W1+b1
#pragma unroll
        for (int p = 0; p < 2; p++) {
            const float* T = p ? sxqT : sxkT;
            float c[8][4];
#pragma unroll
            for (int nt = 0; nt < 8; nt++) {
                int col = ng + nt * 8 + tg * 2;
                c[nt][0] = b1sm[col];   c[nt][1] = b1sm[col+1];
                c[nt][2] = b1sm[col];   c[nt][3] = b1sm[col+1];
            }
#pragma unroll
            for (int kb = 0; kb < 64; kb += 8) {
                unsigned a[4];
                a[0] = f2tf32(T[(kb+tg  )*TS + mi+g]);
                a[1] = f2tf32(T[(kb+tg  )*TS + mi+g+8]);
                a[2] = f2tf32(T[(kb+tg+4)*TS + mi+g]);
                a[3] = f2tf32(T[(kb+tg+4)*TS + mi+g+8]);
#pragma unroll
                for (int nt = 0; nt < 8; nt++) {
                    unsigned bb[2];
                    bb[0] = f2tf32(sW1[(kb+tg  )*WS + ng + nt*8 + g]);
                    bb[1] = f2tf32(sW1[(kb+tg+4)*WS + ng + nt*8 + g]);
                    mma_tf32(c[nt], a, bb);
                }
            }
#pragma unroll
            for (int nt = 0; nt < 8; nt++) {
                int col = ng + nt * 8 + tg * 2;
                int r0 = mi + g;
                if (p == 0) {
                    float x2o[4], gbo[4];
#pragma unroll
                    for (int r = 0; r < 4; r++) {
                        float z = c[nt][r];
                        float t = tanh_fast(0.79788456f * (z + 0.044715f * z * z * z));
                        x2o[r] = 0.5f * z * (1.f + t);
                        gbo[r] = 0.5f * z * (1.f - t * t) * (0.79788456f + 0.1070322243f * z * z)
                               + 0.5f * (1.f + t);
                    }
                    *(float2*)(X2r  + r0*256 + col)     = make_float2(x2o[0], x2o[1]);
                    *(float2*)(X2r  + (r0+8)*256 + col) = make_float2(x2o[2], x2o[3]);
                    *(float2*)(gZ1r + r0*256 + col)     = make_float2(gbo[0], gbo[1]);
                    *(float2*)(gZ1r + (r0+8)*256 + col) = make_float2(gbo[2], gbo[3]);
                } else {
                    *(float2*)(X2br + r0*256 + col)     = make_float2(c[nt][0], c[nt][1]);
                    *(float2*)(X2br + (r0+8)*256 + col) = make_float2(c[nt][2], c[nt][3]);
                }
            }
        }
        __syncthreads();

        // ---- B: Z2 = X2@W2 + b2 -> ssc (FFMA, W2 staged 64 rows at a time)
        {
            float acc[2][4];
#pragma unroll
            for (int u = 0; u < 2; u++)
#pragma unroll
                for (int v = 0; v < 4; v++) acc[u][v] = b2sm[tx2 * 4 + v];
            for (int kbb = 0; kbb < 256; kbb += 64) {
                __syncthreads();
                for (int idx = tid; idx < 4096; idx += 512) {
                    int rr = idx >> 6, cf = idx & 63;
                    sstg[rr*64 + cf] = W2r[(size_t)(kbb+rr)*64 + cf];
                }
                __syncthreads();
#pragma unroll 4
                for (int f0 = 0; f0 < 64; f0 += 4) {
                    float4 a4[2], b4[4];
#pragma unroll
                    for (int u = 0; u < 2; u++)
                        a4[u] = *(const float4*)(X2r + (ty2*2+u)*256 + kbb + f0);
#pragma unroll
                    for (int d = 0; d < 4; d++)
                        b4[d] = *(const float4*)(sstg + (f0+d)*64 + tx2*4);
#pragma unroll
                    for (int u = 0; u < 2; u++) {
                        acc[u][0] += a4[u].x*b4[0].x + a4[u].y*b4[1].x + a4[u].z*b4[2].x + a4[u].w*b4[3].x;
                        acc[u][1] += a4[u].x*b4[0].y + a4[u].y*b4[1].y + a4[u].z*b4[2].y + a4[u].w*b4[3].y;
                        acc[u][2] += a4[u].x*b4[0].z + a4[u].y*b4[1].z + a4[u].z*b4[2].z + a4[u].w*b4[3].z;
                        acc[u][3] += a4[u].x*b4[0].w + a4[u].y*b4[1].w + a4[u].z*b4[2].w + a4[u].w*b4[3].w;
                    }
                }
            }
#pragma unroll
            for (int u = 0; u < 2; u++)
#pragma unroll
                for (int v = 0; v < 4; v++) ssc[(ty2*2+u)*PS + tx2*4+v] = acc[u][v];
        }
        __syncthreads();

        // ---- C: gZ2 = ln_l2_bwd -> sgZ2 + sgZ2T
        for (int i = w; i < 64; i += 16) {
            float z0 = ssc[i*PS + l], z1 = ssc[i*PS + l + 32];
            float mu = warpsum(z0 + z1) * (1.f/64.f);
            float d0 = z0 - mu, d1 = z1 - mu;
            float var = warpsum(d0*d0 + d1*d1) * (1.f/64.f);
            float rstd = rsqrtf(var + EPSc);
            float xh0 = d0 * rstd, xh1 = d1 * rstd;
            float g0 = nwh[l], g1 = nwh[l+32];
            float t0 = sxv[i*SV + l]      - sxkT[l*TS + i];
            float t1 = sxv[i*SV + l + 32] - sxkT[(l+32)*TS + i];
            float gh0 = (g0*xh0 + nbh[l]    - t0) * g0;
            float gh1 = (g1*xh1 + nbh[l+32] - t1) * g1;
            float sgh = warpsum(gh0 + gh1);
            float sgx = warpsum(gh0*xh0 + gh1*xh1);
            float cc = rstd * (1.f/64.f);
            float o0 = (64.f*gh0 - sgh - xh0*sgx) * cc;
            float o1 = (64.f*gh1 - sgh - xh1*sgx) * cc;
            sgZ2[i*PS + l]        = o0;
            sgZ2[i*PS + l + 32]   = o1;
            sgZ2T[l*TS + i]       = o0;
            sgZ2T[(l+32)*TS + i]  = o1;
        }
        __syncthreads();

        // ---- D (mma): gZ1 = (gZ2 @ W2^T) * gb   (16-row staging)
        {
            float c[8][4];
#pragma unroll
            for (int nt = 0; nt < 8; nt++)
#pragma unroll
                for (int r = 0; r < 4; r++) c[nt][r] = 0.f;
#pragma unroll
            for (int kbb = 0; kbb < 64; kbb += 16) {
                __syncthreads();
                for (int idx = tid; idx < 4096; idx += 512) {
                    int rr = idx >> 8, cf = idx & 255;
                    sstg[rr*WS + cf] = W2Tr[(kbb+rr)*256 + cf];
                }
                __syncthreads();
#pragma unroll
                for (int kk = 0; kk < 2; kk++) {
                    int kb = kk * 8;
                    unsigned a[4];
                    a[0] = f2tf32(sgZ2T[(kbb+kb+tg  )*TS + mi+g]);
                    a[1] = f2tf32(sgZ2T[(kbb+kb+tg  )*TS + mi+g+8]);
                    a[2] = f2tf32(sgZ2T[(kbb+kb+tg+4)*TS + mi+g]);
                    a[3] = f2tf32(sgZ2T[(kbb+kb+tg+4)*TS + mi+g+8]);
#pragma unroll
                    for (int nt = 0; nt < 8; nt++) {
                        unsigned bb[2];
                        bb[0] = f2tf32(sstg[(kb+tg  )*WS + ng + nt*8 + g]);
                        bb[1] = f2tf32(sstg[(kb+tg+4)*WS + ng + nt*8 + g]);
                        mma_tf32(c[nt], a, bb);
                    }
                }
            }
#pragma unroll
            for (int nt = 0; nt < 8; nt++) {
                int col = ng + nt * 8 + tg * 2;
                int r0 = mi + g;
                float2 gb0 = *(const float2*)(gZ1r + r0*256 + col);
                float2 gb1 = *(const float2*)(gZ1r + (r0+8)*256 + col);
                *(float2*)(gZ1r + r0*256 + col)     = make_float2(c[nt][0]*gb0.x, c[nt][1]*gb0.y);
                *(float2*)(gZ1r + (r0+8)*256 + col) = make_float2(c[nt][2]*gb1.x, c[nt][3]*gb1.y);
            }
        }
        __syncthreads();

        // ---- E (mma): coef1 = -eta[k2]*(tril(xq@xk^T)+1) -> sscT
#pragma unroll
        for (int sub = 0; sub < 2; sub++) {
            int ncol = ((w >> 2) * 2 + sub) * 8;
            float c[4] = {0.f, 0.f, 0.f, 0.f};
#pragma unroll
            for (int kb = 0; kb < 64; kb += 8) {
                unsigned a[4], bb[2];
                a[0] = f2tf32(sxqT[(kb+tg  )*TS + mi+g]);
                a[1] = f2tf32(sxqT[(kb+tg  )*TS + mi+g+8]);
                a[2] = f2tf32(sxqT[(kb+tg+4)*TS + mi+g]);
                a[3] = f2tf32(sxqT[(kb+tg+4)*TS + mi+g+8]);
                bb[0] = f2tf32(sxkT[(kb+tg  )*TS + ncol + g]);
                bb[1] = f2tf32(sxkT[(kb+tg+4)*TS + ncol + g]);
                mma_tf32(c, a, bb);
            }
            int r0 = mi + g, k2 = ncol + tg * 2;
            sscT[k2*TS + r0]       = (k2   <= r0)   ? -seta[k2]  *(c[0]+1.f) : 0.f;
            sscT[(k2+1)*TS + r0]   = (k2+1 <= r0)   ? -seta[k2+1]*(c[1]+1.f) : 0.f;
            sscT[k2*TS + r0+8]     = (k2   <= r0+8) ? -seta[k2]  *(c[2]+1.f) : 0.f;
            sscT[(k2+1)*TS + r0+8] = (k2+1 <= r0+8) ? -seta[k2+1]*(c[3]+1.f) : 0.f;
        }
        __syncthreads();

        // ---- F (mma): Z1b = Z1q + coef1neg@gZ1 ; X2b = gelu (16-row staging)
        {
            float c[8][4];
#pragma unroll
            for (int nt = 0; nt < 8; nt++) {
                int col = ng + nt * 8 + tg * 2;
                int r0 = mi + g;
                float2 q0 = *(const float2*)(X2br + r0*256 + col);
                float2 q1 = *(const float2*)(X2br + (r0+8)*256 + col);
                c[nt][0] = q0.x; c[nt][1] = q0.y; c[nt][2] = q1.x; c[nt][3] = q1.y;
            }
#pragma unroll
            for (int kbb = 0; kbb < 64; kbb += 16) {
                __syncthreads();
                for (int idx = tid; idx < 4096; idx += 512) {
                    int rr = idx >> 8, cf = idx & 255;
                    sstg[rr*WS + cf] = gZ1r[(kbb+rr)*256 + cf];
                }
                __syncthreads();
#pragma unroll
                for (int kk = 0; kk < 2; kk++) {
                    int kb = kk * 8;
                    unsigned a[4];
                    a[0] = f2tf32(sscT[(kbb+kb+tg  )*TS + mi+g]);
                    a[1] = f2tf32(sscT[(kbb+kb+tg  )*TS + mi+g+8]);
                    a[2] = f2tf32(sscT[(kbb+kb+tg+4)*TS + mi+g]);
                    a[3] = f2tf32(sscT[(kbb+kb+tg+4)*TS + mi+g+8]);
#pragma unroll
                    for (int nt = 0; nt < 8; nt++) {
                        unsigned bb[2];
                        bb[0] = f2tf32(sstg[(kb+tg  )*WS + ng + nt*8 + g]);
                        bb[1] = f2tf32(sstg[(kb+tg+4)*WS + ng + nt*8 + g]);
                        mma_tf32(c[nt], a, bb);
                    }
                }
            }
#pragma unroll
            for (int nt = 0; nt < 8; nt++) {
                int col = ng + nt * 8 + tg * 2;
                int r0 = mi + g;
                float xo[4];
#pragma unroll
                for (int r = 0; r < 4; r++) {
                    float z = c[nt][r];
                    float t = tanh_fast(0.79788456f * (z + 0.044715f * z * z * z));
                    xo[r] = 0.5f * z * (1.f + t);
                }
                *(float2*)(X2br + r0*256 + col)     = make_float2(xo[0], xo[1]);
                *(float2*)(X2br + (r0+8)*256 + col) = make_float2(xo[2], xo[3]);
            }
        }
        __syncthreads();

        // ---- G: coef2 (FFMA)
        {
            float acc[2][4];
#pragma unroll
            for (int u = 0; u < 2; u++)
#pragma unroll
                for (int v = 0; v < 4; v++) acc[u][v] = 0.f;
            if (tx2 * 4 <= ty2 * 2 + 1) {
#pragma unroll 2
                for (int f0 = 0; f0 < 256; f0 += 4) {
                    float4 a4[2], b4[4];
#pragma unroll
                    for (int u = 0; u < 2; u++) a4[u] = *(const float4*)(X2br + (ty2*2+u)*256 + f0);
#pragma unroll
                    for (int v = 0; v < 4; v++) b4[v] = *(const float4*)(X2r + (tx2*4+v)*256 + f0);
#pragma unroll
                    for (int u = 0; u < 2; u++)
#pragma unroll
                        for (int v = 0; v < 4; v++)
                            acc[u][v] += a4[u].x*b4[v].x + a4[u].y*b4[v].y
                                       + a4[u].z*b4[v].z + a4[u].w*b4[v].w;
                }
            }
#pragma unroll
            for (int u = 0; u < 2; u++) {
                int i = ty2 * 2 + u;
#pragma unroll
                for (int v = 0; v < 4; v++) {
                    int j = tx2 * 4 + v;
                    ssc[i*PS + j] = (j <= i) ? seta[j] * (acc[u][v] + 1.f) : 0.f;
                }
            }
        }
        __syncthreads();

        // ---- H: Z2b = X2b@W2 + b2 - coef2@gZ2 -> sxv (W2 staged)
        {
            float acc[2][4];
#pragma unroll
            for (int u = 0; u < 2; u++)
#pragma unroll
                for (int v = 0; v < 4; v++) acc[u][v] = b2sm[tx2 * 4 + v];
            for (int kbb = 0; kbb < 256; kbb += 64) {
                __syncthreads();
                for (int idx = tid; idx < 4096; idx += 512) {
                    int rr = idx >> 6, cf = idx & 63;
                    sstg[rr*64 + cf] = W2r[(size_t)(kbb+rr)*64 + cf];
                }
                __syncthreads();
#pragma unroll 4
                for (int f0 = 0; f0 < 64; f0 += 4) {
                    float4 a4[2], b4[4];
#pragma unroll
                    for (int u = 0; u < 2; u++)
                        a4[u] = *(const float4*)(X2br + (ty2*2+u)*256 + kbb + f0);
#pragma unroll
                    for (int d = 0; d < 4; d++)
                        b4[d] = *(const float4*)(sstg + (f0+d)*64 + tx2*4);
#pragma unroll
                    for (int u = 0; u < 2; u++) {
                        acc[u][0] += a4[u].x*b4[0].x + a4[u].y*b4[1].x + a4[u].z*b4[2].x + a4[u].w*b4[3].x;
                        acc[u][1] += a4[u].x*b4[0].y + a4[u].y*b4[1].y + a4[u].z*b4[2].y + a4[u].w*b4[3].y;
                        acc[u][2] += a4[u].x*b4[0].z + a4[u].y*b4[1].z + a4[u].z*b4[2].z + a4[u].w*b4[3].z;
                        acc[u][3] += a4[u].x*b4[0].w + a4[u].y*b4[1].w + a4[u].z*b4[2].w + a4[u].w*b4[3].w;
                    }
                }
            }
#pragma unroll 4
            for (int k2 = 0; k2 < 64; k2++) {
                float cc0 = ssc[(ty2*2)*PS + k2];
                float cc1 = ssc[(ty2*2+1)*PS + k2];
                float4 gv4 = *(const float4*)(sgZ2 + k2*PS + tx2*4);
                acc[0][0] -= cc0*gv4.x; acc[0][1] -= cc0*gv4.y; acc[0][2] -= cc0*gv4.z; acc[0][3] -= cc0*gv4.w;
                acc[1][0] -= cc1*gv4.x; acc[1][1] -= cc1*gv4.y; acc[1][2] -= cc1*gv4.z; acc[1][3] -= cc1*gv4.w;
            }
#pragma unroll
            for (int u = 0; u < 2; u++)
#pragma unroll
                for (int v = 0; v < 4; v++) sxv[(ty2*2+u)*SV + tx2*4+v] = acc[u][v];
        }
        __syncthreads();

        // ---- I: out = xq + LN(Z2b)
        for (int i = w; i < 64; i += 16) {
            float z0 = sxv[i*SV + l], z1 = sxv[i*SV + l + 32];
            float mu = warpsum(z0 + z1) * (1.f/64.f);
            float d0 = z0 - mu, d1 = z1 - mu;
            float var = warpsum(d0*d0 + d1*d1) * (1.f/64.f);
            float rstd = rsqrtf(var + EPSc);
            size_t gg = (tokbase + i) * Dn + h * 64;
            outp[gg + l]      = sxqT[l*TS + i]      + nwh[l]    * d0 * rstd + nbh[l];
            outp[gg + l + 32] = sxqT[(l+32)*TS + i] + nwh[l+32] * d1 * rstd + nbh[l+32];
        }

        // ---- J1: W1 -= (eta*xk)^T @ gZ1  (sW1 smem)
        {
            u64 acc2[4][4];
#pragma unroll
            for (int u = 0; u < 4; u++)
#pragma unroll
                for (int p = 0; p < 4; p++) acc2[u][p] = 0ULL;
#pragma unroll 4
            for (int i = 0; i < 64; i++) {
                float et = seta[i];
                float4 g0 = *(const float4*)(gZ1r + i*256 + l*8);
                float4 g1 = *(const float4*)(gZ1r + i*256 + l*8 + 4);
                u64 gv2[4];
                f4tou2(g0, gv2[0], gv2[1]); f4tou2(g1, gv2[2], gv2[3]);
#pragma unroll
                for (int u = 0; u < 4; u++) {
                    float a = et * sxkT[(w*4+u)*TS + i];
                    u64 a2 = f2pack(a, a);
#pragma unroll
                    for (int p = 0; p < 4; p++) acc2[u][p] = ffma2(a2, gv2[p], acc2[u][p]);
                }
            }
#pragma unroll
            for (int u = 0; u < 4; u++) {
                int e = w * 4 + u;
                float av[8];
#pragma unroll
                for (int p = 0; p < 4; p++) f2unpack(acc2[u][p], av[2*p], av[2*p+1]);
                float4* wp = (float4*)(sW1 + e*WS + l*8);
                float4 o0 = wp[0], o1 = wp[1];
                wp[0] = make_float4(o0.x-av[0], o0.y-av[1], o0.z-av[2], o0.w-av[3]);
                wp[1] = make_float4(o1.x-av[4], o1.y-av[5], o1.z-av[6], o1.w-av[7]);
            }
        }
        // J2: b1
        if (tid < 256) {
            float acc = 0.f;
#pragma unroll 8
            for (int i = 0; i < 64; i++) acc += seta[i] * gZ1r[i*256 + tid];
            b1sm[tid] -= acc;
        }
        // J3: W2 + W2T (global)
        {
            u64 acc2[4][4];
#pragma unroll
            for (int u = 0; u < 4; u++)
#pragma unroll
                for (int p = 0; p < 4; p++) acc2[u][p] = 0ULL;
#pragma unroll 4
            for (int i = 0; i < 64; i++) {
                float et = seta[i];
                float4 x0 = *(const float4*)(X2r + i*256 + ft*4);
                float4 gv0 = *(const float4*)(sgZ2 + i*PS + jt*8);
                float4 gv1 = *(const float4*)(sgZ2 + i*PS + jt*8 + 4);
                u64 gv2[4];
                f4tou2(gv0, gv2[0], gv2[1]); f4tou2(gv1, gv2[2], gv2[3]);
                float a[4] = {et*x0.x, et*x0.y, et*x0.z, et*x0.w};
#pragma unroll
                for (int u = 0; u < 4; u++) {
                    u64 a2 = f2pack(a[u], a[u]);
#pragma unroll
                    for (int p = 0; p < 4; p++) acc2[u][p] = ffma2(a2, gv2[p], acc2[u][p]);
                }
            }
#pragma unroll
            for (int u = 0; u < 4; u++) {
                int f = ft * 4 + u;
                float av[8];
#pragma unroll
                for (int p = 0; p < 4; p++) f2unpack(acc2[u][p], av[2*p], av[2*p+1]);
                float4* wp0 = (float4*)(W2r + f*64 + jt*8);
                float4* wp1 = (float4*)(W2r + f*64 + jt*8 + 4);
                float4 o0 = wp0[0], o1 = wp1[0];
                wp0[0] = make_float4(o0.x-av[0], o0.y-av[1], o0.z-av[2], o0.w-av[3]);
                wp1[0] = make_float4(o1.x-av[4], o1.y-av[5], o1.z-av[6], o1.w-av[7]);
#pragma unroll
                for (int v = 0; v < 8; v++)
                    W2Tr[(jt*8+v)*256 + f] -= av[v];
            }
        }
        // J4: b2
        if (tid < 64) {
            float acc = 0.f;
#pragma unroll 8
            for (int i = 0; i < 64; i++) acc += seta[i] * sgZ2[i*PS + tid];
            b2sm[tid] -= acc;
        }
        __syncthreads();
    }
}

// ---------------- Launch ----------------
extern "C" void kernel_launch(void* const* d_in, const int* in_sizes, int n_in,
                              void* d_out, int out_size)
{
    const float* x       = (const float*)d_in[0];
    const float* ln1_w   = (const float*)d_in[1];
    const float* ln1_b   = (const float*)d_in[2];
    const float* attn_wq = (const float*)d_in[3];
    const float* attn_wk = (const float*)d_in[4];
    const float* attn_wv = (const float*)d_in[5];
    const float* attn_wo = (const float*)d_in[6];
    const float* wq_w    = (const float*)d_in[7];
    const float* wq_b    = (const float*)d_in[8];
    const float* wk_w    = (const float*)d_in[9];
    const float* wk_b    = (const float*)d_in[10];
    const float* wv_w    = (const float*)d_in[11];
    const float* wv_b    = (const float*)d_in[12];
    const float* wo_w    = (const float*)d_in[13];
    const float* wo_b    = (const float*)d_in[14];
    const float* W1      = (const float*)d_in[15];
    const float* b1      = (const float*)d_in[16];
    const float* W2      = (const float*)d_in[17];
    const float* b2      = (const float*)d_in[18];
    const float* ttt_nw  = (const float*)d_in[19];
    const float* ttt_nb  = (const float*)d_in[20];
    const float* lr_w    = (const float*)d_in[21];
    const float* lr_b    = (const float*)d_in[22];
    const float* pn_w    = (const float*)d_in[23];
    const float* pn_b    = (const float*)d_in[24];
    const float* gate_a  = (const float*)d_in[25];
    float* out = (float*)d_out;

    float *p_h,*p_q,*p_k,*p_v,*p_o,*p_x1,*p_lr,*p_W2,*p_W2T,*p_X2,*p_gZ1,*p_X2b;
    cudaGetSymbolAddress((void**)&p_h,  g_h);
    cudaGetSymbolAddress((void**)&p_q,  g_q);
    cudaGetSymbolAddress((void**)&p_k,  g_k);
    cudaGetSymbolAddress((void**)&p_v,  g_v);
    cudaGetSymbolAddress((void**)&p_o,  g_o);
    cudaGetSymbolAddress((void**)&p_x1, g_x1);
    cudaGetSymbolAddress((void**)&p_lr, g_lr);
    cudaGetSymbolAddress((void**)&p_W2, g_W2s);
    cudaGetSymbolAddress((void**)&p_W2T,g_W2Ts);
    cudaGetSymbolAddress((void**)&p_X2, g_X2);
    cudaGetSymbolAddress((void**)&p_gZ1,g_gZ1);
    cudaGetSymbolAddress((void**)&p_X2b,g_X2b);

    cudaFuncSetAttribute(ttt_scan_kernel,   cudaFuncAttributeMaxDynamicSharedMemorySize, SCAN_SMEM);
    cudaFuncSetAttribute(attn_flash_kernel, cudaFuncAttributeMaxDynamicSharedMemorySize, ATT_SMEM);

    const int M = Bn * Sn;
    dim3 ggrid(Dn / 128, M / 128);
    dim3 ggrid3(Dn / 128, M / 128, 3);
    int nwarp_grid = (Bn * Sn * Hn) / 8;

    ln_kernel<<<M, 256>>>(x, ln1_w, ln1_b, p_h);
    gemm3_nt_kernel<<<ggrid3, 256>>>(p_h, attn_wq, attn_wk, attn_wv,
                                     p_q, p_k, p_v, nullptr, nullptr, nullptr);
    attn_flash_kernel<<<dim3(16, 64), 256, ATT_SMEM>>>(p_q, p_k, p_v, p_o);
    gemm_nt_kernel<<<ggrid, 256>>>(p_o, attn_wo, p_x1, nullptr, x, nullptr);
    gemm3_nt_kernel<<<ggrid3, 256>>>(p_x1, wq_w, wk_w, wv_w,
                                     p_q, p_k, p_v, wq_b, wk_b, wv_b);
    prep_kernel<<<nwarp_grid, 256>>>(p_q, p_k, p_v, ttt_nw, ttt_nb);
    lr_kernel<<<nwarp_grid, 256>>>(p_x1, lr_w, lr_b, p_lr);
    ttt_scan_kernel<<<Bn * Hn, 512, SCAN_SMEM>>>(
        p_q, p_k, p_v, p_lr, W1, b1, W2, b2, ttt_nw, ttt_nb,
        p_W2, p_W2T, p_X2, p_gZ1, p_X2b, p_o);
    ln_kernel<<<M, 256>>>(p_o, pn_w, pn_b, p_h);
    gemm_nt_kernel<<<ggrid, 256>>>(p_h, wo_w, out, wo_b, p_x1, gate_a);
}

// round 15
// speedup vs baseline: 1.8749x; 1.0488x over previous
#include <cuda_runtime.h>
#include <math.h>

#define Bn 4
#define Sn 1024
#define Dn 1024
#define Hn 16
#define HDn 64
#define Cn 64
#define NCn 16
#define DFFn 256
#define EPSc 1e-6f
#define BSD (Bn*Sn*Dn)

typedef unsigned long long u64;
__device__ __forceinline__ u64 f2pack(float lo, float hi) {
    u64 r; asm("mov.b64 %0, {%1, %2};" : "=l"(r) : "f"(lo), "f"(hi)); return r;
}
__device__ __forceinline__ void f2unpack(u64 p, float& lo, float& hi) {
    asm("mov.b64 {%0, %1}, %2;" : "=f"(lo), "=f"(hi) : "l"(p));
}
__device__ __forceinline__ u64 ffma2(u64 a, u64 b, u64 c) {
    u64 d; asm("fma.rn.f32x2 %0, %1, %2, %3;" : "=l"(d) : "l"(a), "l"(b), "l"(c)); return d;
}
__device__ __forceinline__ void f4tou2(float4 f, u64& p0, u64& p1) {
    p0 = f2pack(f.x, f.y); p1 = f2pack(f.z, f.w);
}
__device__ __forceinline__ unsigned f2tf32(float f) {
    unsigned r; asm("cvt.rna.tf32.f32 %0, %1;" : "=r"(r) : "f"(f)); return r;
}
__device__ __forceinline__ unsigned bf2pack(float lo, float hi) {
    unsigned r; asm("cvt.rn.bf16x2.f32 %0, %1, %2;" : "=r"(r) : "f"(hi), "f"(lo)); return r;
}
__device__ __forceinline__ void mma_tf32(float* c, const unsigned* a, const unsigned* b) {
    asm volatile("mma.sync.aligned.m16n8k8.row.col.f32.tf32.tf32.f32 "
        "{%0,%1,%2,%3}, {%4,%5,%6,%7}, {%8,%9}, {%0,%1,%2,%3};"
        : "+f"(c[0]), "+f"(c[1]), "+f"(c[2]), "+f"(c[3])
        : "r"(a[0]), "r"(a[1]), "r"(a[2]), "r"(a[3]), "r"(b[0]), "r"(b[1]));
}
__device__ __forceinline__ void mma_bf16(float* c, const unsigned* a, const unsigned* b) {
    asm volatile("mma.sync.aligned.m16n8k16.row.col.f32.bf16.bf16.f32 "
        "{%0,%1,%2,%3}, {%4,%5,%6,%7}, {%8,%9}, {%0,%1,%2,%3};"
        : "+f"(c[0]), "+f"(c[1]), "+f"(c[2]), "+f"(c[3])
        : "r"(a[0]), "r"(a[1]), "r"(a[2]), "r"(a[3]), "r"(b[0]), "r"(b[1]));
}

__device__ float g_h [BSD];
__device__ float g_q [BSD];
__device__ float g_k [BSD];
__device__ float g_v [BSD];
__device__ float g_o [BSD];
__device__ float g_x1[BSD];
__device__ float g_lr[Bn*Hn*Sn];
__device__ float g_W2s [Bn*Hn*16384];
__device__ float g_W2Ts[Bn*Hn*16384];
__device__ float g_X2  [Bn*Hn*16384];
__device__ float g_gZ1 [Bn*Hn*16384];
__device__ float g_X2b [Bn*Hn*16384];

__device__ __forceinline__ float warpsum(float v) {
#pragma unroll
    for (int o = 16; o > 0; o >>= 1) v += __shfl_xor_sync(0xffffffffu, v, o);
    return v;
}
__device__ __forceinline__ float warpmax(float v) {
#pragma unroll
    for (int o = 16; o > 0; o >>= 1) v = fmaxf(v, __shfl_xor_sync(0xffffffffu, v, o));
    return v;
}
__device__ __forceinline__ float blocksum256(float v) {
    __shared__ float red[8];
    int lane = threadIdx.x & 31, w = threadIdx.x >> 5;
    v = warpsum(v);
    if (lane == 0) red[w] = v;
    __syncthreads();
    float r = (lane < 8) ? red[lane] : 0.f;
    r = warpsum(r);
    __syncthreads();
    return r;
}
__device__ __forceinline__ float tanh_fast(float x) {
    float e = __expf(2.f * x);
    return 1.f - __fdividef(2.f, e + 1.f);
}

// ---------------- LayerNorm rows of 1024 ----------------
__global__ __launch_bounds__(256) void ln_kernel(
    const float* __restrict__ x, const float* __restrict__ g,
    const float* __restrict__ b, float* __restrict__ y)
{
    int row = blockIdx.x, tid = threadIdx.x;
    const float* xr = x + (size_t)row * Dn;
    float v[4]; float s = 0.f;
#pragma unroll
    for (int i = 0; i < 4; i++) { v[i] = xr[tid + 256 * i]; s += v[i]; }
    s = blocksum256(s);
    float mu = s * (1.f / Dn), ss = 0.f;
#pragma unroll
    for (int i = 0; i < 4; i++) { float d = v[i] - mu; ss += d * d; }
    ss = blocksum256(ss);
    float rstd = rsqrtf(ss * (1.f / Dn) + EPSc);
    float* yr = y + (size_t)row * Dn;
#pragma unroll
    for (int i = 0; i < 4; i++) {
        int c = tid + 256 * i;
        yr[c] = (v[i] - mu) * rstd * g[c] + b[c];
    }
}

// ---------------- bf16 tensor-core GEMM, double-buffered ----------------
#define GSTR 136
__device__ __forceinline__ void gemm_core(
    const float* __restrict__ A, const float* __restrict__ B, float* __restrict__ C,
    const float* __restrict__ bias, const float* __restrict__ res,
    const float* __restrict__ gate, int bm, int bn)
{
    const int N = 1024, K = 1024, BK = 16;
    __shared__ unsigned As[2][8][GSTR];
    __shared__ unsigned Bs[2][8][GSTR];
    int t = threadIdx.x;
    int warp = t >> 5, lane = t & 31;
    int wm = warp >> 1, wn = warp & 1;
    int g = lane >> 2, tg = lane & 3;

    float acc[2][8][4];
#pragma unroll
    for (int mt = 0; mt < 2; mt++)
#pragma unroll
        for (int nt = 0; nt < 8; nt++)
#pragma unroll
            for (int r = 0; r < 4; r++) acc[mt][nt][r] = 0.f;

    int r128 = t >> 1, kc = (t & 1) * 8, kp0 = (t & 1) * 4;
    const float* Ab = A + (size_t)(bm + r128) * K + kc;
    const float* Bb = B + (size_t)(bn + r128) * K + kc;
    float4 a0 = *(const float4*)(Ab);
    float4 a1 = *(const float4*)(Ab + 4);
    float4 b0 = *(const float4*)(Bb);
    float4 b1 = *(const float4*)(Bb + 4);

    As[0][kp0+0][r128] = bf2pack(a0.x, a0.y);
    As[0][kp0+1][r128] = bf2pack(a0.z, a0.w);
    As[0][kp0+2][r128] = bf2pack(a1.x, a1.y);
    As[0][kp0+3][r128] = bf2pack(a1.z, a1.w);
    Bs[0][kp0+0][r128] = bf2pack(b0.x, b0.y);
    Bs[0][kp0+1][r128] = bf2pack(b0.z, b0.w);
    Bs[0][kp0+2][r128] = bf2pack(b1.x, b1.y);
    Bs[0][kp0+3][r128] = bf2pack(b1.z, b1.w);
    __syncthreads();

    int cur = 0;
    for (int k0 = 0; k0 < K; k0 += BK) {
        bool more = (k0 + BK < K);
        if (more) {
            a0 = *(const float4*)(Ab + k0 + BK);
            a1 = *(const float4*)(Ab + k0 + BK + 4);
            b0 = *(const float4*)(Bb + k0 + BK);
            b1 = *(const float4*)(Bb + k0 + BK + 4);
        }
        {
            unsigned af[2][4], bf[8][2];
#pragma unroll
            for (int mt = 0; mt < 2; mt++) {
                int mb = wm * 32 + mt * 16 + g;
                af[mt][0] = As[cur][tg  ][mb];
                af[mt][1] = As[cur][tg  ][mb+8];
                af[mt][2] = As[cur][tg+4][mb];
                af[mt][3] = As[cur][tg+4][mb+8];
            }
#pragma unroll
            for (int nt = 0; nt < 8; nt++) {
                int nb = wn * 64 + nt * 8 + g;
                bf[nt][0] = Bs[cur][tg  ][nb];
                bf[nt][1] = Bs[cur][tg+4][nb];
            }
#pragma unroll
            for (int mt = 0; mt < 2; mt++)
#pragma unroll
                for (int nt = 0; nt < 8; nt++)
                    mma_bf16(acc[mt][nt], af[mt], bf[nt]);
        }
        if (more) {
            int nxt = cur ^ 1;
            As[nxt][kp0+0][r128] = bf2pack(a0.x, a0.y);
            As[nxt][kp0+1][r128] = bf2pack(a0.z, a0.w);
            As[nxt][kp0+2][r128] = bf2pack(a1.x, a1.y);
            As[nxt][kp0+3][r128] = bf2pack(a1.z, a1.w);
            Bs[nxt][kp0+0][r128] = bf2pack(b0.x, b0.y);
            Bs[nxt][kp0+1][r128] = bf2pack(b0.z, b0.w);
            Bs[nxt][kp0+2][r128] = bf2pack(b1.x, b1.y);
            Bs[nxt][kp0+3][r128] = bf2pack(b1.z, b1.w);
            __syncthreads();
            cur = nxt;
        }
    }

    float bs2[8][2], gv2[8][2];
#pragma unroll
    for (int nt = 0; nt < 8; nt++) {
        int col = bn + wn * 64 + nt * 8 + tg * 2;
        if (bias) { bs2[nt][0] = bias[col]; bs2[nt][1] = bias[col+1]; }
        else      { bs2[nt][0] = 0.f;       bs2[nt][1] = 0.f; }
        if (gate) { gv2[nt][0] = tanhf(gate[col]); gv2[nt][1] = tanhf(gate[col+1]); }
    }
#pragma unroll
    for (int mt = 0; mt < 2; mt++) {
        int row0 = bm + wm * 32 + mt * 16 + g;
#pragma unroll
        for (int nt = 0; nt < 8; nt++) {
            int col = bn + wn * 64 + nt * 8 + tg * 2;
            float v0 = acc[mt][nt][0] + bs2[nt][0];
            float v1 = acc[mt][nt][1] + bs2[nt][1];
            float v2 = acc[mt][nt][2] + bs2[nt][0];
            float v3 = acc[mt][nt][3] + bs2[nt][1];
            if (gate) {
                float2 r0 = *(const float2*)(res + (size_t)row0 * N + col);
                float2 r1 = *(const float2*)(res + (size_t)(row0+8) * N + col);
                v0 = r0.x + gv2[nt][0] * v0; v1 = r0.y + gv2[nt][1] * v1;
                v2 = r1.x + gv2[nt][0] * v2; v3 = r1.y + gv2[nt][1] * v3;
            } else if (res) {
                float2 r0 = *(const float2*)(res + (size_t)row0 * N + col);
                float2 r1 = *(const float2*)(res + (size_t)(row0+8) * N + col);
                v0 += r0.x; v1 += r0.y; v2 += r1.x; v3 += r1.y;
            }
            *(float2*)(C + (size_t)row0 * N + col)     = make_float2(v0, v1);
            *(float2*)(C + (size_t)(row0+8) * N + col) = make_float2(v2, v3);
        }
    }
}

__global__ __launch_bounds__(256, 2) void gemm_nt_kernel(
    const float* __restrict__ A, const float* __restrict__ B, float* __restrict__ C,
    const float* __restrict__ bias, const float* __restrict__ res,
    const float* __restrict__ gate)
{
    gemm_core(A, B, C, bias, res, gate, blockIdx.y * 128, blockIdx.x * 128);
}

__global__ __launch_bounds__(256, 2) void gemm3_nt_kernel(
    const float* __restrict__ A,
    const float* __restrict__ B0, const float* __restrict__ B1, const float* __restrict__ B2,
    float* __restrict__ C0, float* __restrict__ C1, float* __restrict__ C2,
    const float* __restrict__ b0, const float* __restrict__ b1, const float* __restrict__ b2)
{
    const float* B; float* C; const float* bias;
    if (blockIdx.z == 0)      { B = B0; C = C0; bias = b0; }
    else if (blockIdx.z == 1) { B = B1; C = C1; bias = b1; }
    else                      { B = B2; C = C2; bias = b2; }
    gemm_core(A, B, C, bias, nullptr, nullptr, blockIdx.y * 128, blockIdx.x * 128);
}

// ---------------- Flash attention: tf32 mma ----------------
#define ATS 72
#define APS 65
#define ASS 68
#define ATT_SMEM ((3*64*ATS + 64*APS + 64*ASS + 192) * 4)

__global__ __launch_bounds__(256) void attn_flash_kernel(
    const float* __restrict__ q, const float* __restrict__ k,
    const float* __restrict__ v, float* __restrict__ o)
{
    extern __shared__ float sm[];
    unsigned* QsT = (unsigned*)sm;
    unsigned* KsT = QsT + 64 * ATS;
    unsigned* Vs  = KsT + 64 * ATS;
    unsigned* PsT = Vs  + 64 * ATS;
    float* Ss   = (float*)(PsT + 64 * APS);
    float* smm  = Ss + 64 * ASS;
    float* sml  = smm + 64;
    float* scor = sml + 64;

    int qt = blockIdx.x, bh = blockIdx.y;
    int b = bh >> 4, h = bh & 15;
    int tid = threadIdx.x, warp = tid >> 5, lane = tid & 31;
    int wm = warp >> 1, wn = warp & 1;
    int mi = wm * 16, ng = wn * 32;
    int g = lane >> 2, tg = lane & 3;
    size_t base = ((size_t)b * Sn) * Dn + h * HDn;

    for (int idx = tid; idx < 4096; idx += 256) {
        int r = idx >> 6, e = idx & 63;
        QsT[e * ATS + r] = f2tf32(q[base + (size_t)(qt * 64 + r) * Dn + e] * 0.125f);
    }
    if (tid < 64) { smm[tid] = -1e30f; sml[tid] = 0.f; }
    float co[4][4];
#pragma unroll
    for (int nt = 0; nt < 4; nt++)
#pragma unroll
        for (int r = 0; r < 4; r++) co[nt][r] = 0.f;
    __syncthreads();

    for (int kt = 0; kt <= qt; kt++) {
        for (int idx = tid; idx < 4096; idx += 256) {
            int r = idx >> 6, e = idx & 63;
            size_t gg = base + (size_t)(kt * 64 + r) * Dn + e;
            KsT[e * ATS + r] = f2tf32(k[gg]);
            Vs [r * ATS + e] = f2tf32(v[gg]);
        }
        __syncthreads();

        float c[4][4];
#pragma unroll
        for (int nt = 0; nt < 4; nt++)
#pragma unroll
            for (int r = 0; r < 4; r++) c[nt][r] = 0.f;
#pragma unroll
        for (int kb = 0; kb < 64; kb += 8) {
            unsigned a[4];
            a[0] = QsT[(kb+tg  )*ATS + mi+g];
            a[1] = QsT[(kb+tg  )*ATS + mi+g+8];
            a[2] = QsT[(kb+tg+4)*ATS + mi+g];
            a[3] = QsT[(kb+tg+4)*ATS + mi+g+8];
#pragma unroll
            for (int nt = 0; nt < 4; nt++) {
                unsigned bb[2];
                bb[0] = KsT[(kb+tg  )*ATS + ng + nt*8 + g];
                bb[1] = KsT[(kb+tg+4)*ATS + ng + nt*8 + g];
                mma_tf32(c[nt], a, bb);
            }
        }
        bool diag = (kt == qt);
        int r0 = mi + g, r1 = mi + g + 8;
#pragma unroll
        for (int nt = 0; nt < 4; nt++) {
            int col = ng + nt * 8 + tg * 2;
            if (diag) {
                if (col   > r0) c[nt][0] = -1e30f;
                if (col+1 > r0) c[nt][1] = -1e30f;
                if (col   > r1) c[nt][2] = -1e30f;
                if (col+1 > r1) c[nt][3] = -1e30f;
            }
            Ss[r0*ASS + col]   = c[nt][0];
            Ss[r0*ASS + col+1] = c[nt][1];
            Ss[r1*ASS + col]   = c[nt][2];
            Ss[r1*ASS + col+1] = c[nt][3];
        }
        __syncthreads();

        for (int i = warp; i < 64; i += 8) {
            float s0 = Ss[i*ASS + lane], s1 = Ss[i*ASS + lane + 32];
            float mx = warpmax(fmaxf(s0, s1));
            float nm = fmaxf(smm[i], mx);
            float corr = __expf(smm[i] - nm);
            float p0 = __expf(s0 - nm), p1 = __expf(s1 - nm);
            float ps = warpsum(p0 + p1);
            if (lane == 0) { sml[i] = sml[i] * corr + ps; smm[i] = nm; scor[i] = corr; }
            PsT[lane*APS + i]      = f2tf32(p0);
            PsT[(lane+32)*APS + i] = f2tf32(p1);
        }
        __syncthreads();

        float cr0 = scor[r0], cr1 = scor[r1];
#pragma unroll
        for (int nt = 0; nt < 4; nt++) {
            co[nt][0] *= cr0; co[nt][1] *= cr0;
            co[nt][2] *= cr1; co[nt][3] *= cr1;
        }
#pragma unroll
        for (int kb = 0; kb < 64; kb += 8) {
            unsigned a[4];
            a[0] = PsT[(kb+tg  )*APS + mi+g];
            a[1] = PsT[(kb+tg  )*APS + mi+g+8];
            a[2] = PsT[(kb+tg+4)*APS + mi+g];
            a[3] = PsT[(kb+tg+4)*APS + mi+g+8];
#pragma unroll
            for (int nt = 0; nt < 4; nt++) {
                unsigned bb[2];
                bb[0] = Vs[(kb+tg  )*ATS + ng + nt*8 + g];
                bb[1] = Vs[(kb+tg+4)*ATS + ng + nt*8 + g];
                mma_tf32(co[nt], a, bb);
            }
        }
        __syncthreads();
    }

    int r0 = mi + g, r1 = mi + g + 8;
    float inv0 = __fdividef(1.f, sml[r0]);
    float inv1 = __fdividef(1.f, sml[r1]);
#pragma unroll
    for (int nt = 0; nt < 4; nt++) {
        int col = ng + nt * 8 + tg * 2;
        *(float2*)(o + base + (size_t)(qt*64 + r0) * Dn + col) =
            make_float2(co[nt][0]*inv0, co[nt][1]*inv0);
        *(float2*)(o + base + (size_t)(qt*64 + r1) * Dn + col) =
            make_float2(co[nt][2]*inv1, co[nt][3]*inv1);
    }
}

// ---------------- prep & lr ----------------
__global__ __launch_bounds__(256) void prep_kernel(
    float* __restrict__ XQ, float* __restrict__ XK, float* __restrict__ XV,
    const float* __restrict__ nw, const float* __restrict__ nb)
{
    int w = (blockIdx.x * blockDim.x + threadIdx.x) >> 5;
    if (w >= Bn * Sn * Hn) return;
    int lane = threadIdx.x & 31;
    int h = w & 15, bs = w >> 4;
    size_t base = (size_t)bs * Dn + h * HDn;
    float q0 = XQ[base + lane], q1 = XQ[base + lane + 32];
    float qi = 1.f / fmaxf(sqrtf(warpsum(q0*q0 + q1*q1)), 1e-12f);
    XQ[base + lane] = q0 * qi; XQ[base + lane + 32] = q1 * qi;
    float k0 = XK[base + lane], k1 = XK[base + lane + 32];
    float ki = 1.f / fmaxf(sqrtf(warpsum(k0*k0 + k1*k1)), 1e-12f);
    k0 *= ki; k1 *= ki;
    XK[base + lane] = k0; XK[base + lane + 32] = k1;
    float v0 = XV[base + lane], v1 = XV[base + lane + 32];
    float mu = warpsum(v0 + v1) * (1.f / 64.f);
    float d0 = v0 - mu, d1 = v1 - mu;
    float var = warpsum(d0*d0 + d1*d1) * (1.f / 64.f);
    float rstd = rsqrtf(var + EPSc);
    XV[base + lane]      = nw[h*64+lane]    * d0 * rstd + nb[h*64+lane]    + k0;
    XV[base + lane + 32] = nw[h*64+lane+32] * d1 * rstd + nb[h*64+lane+32] + k1;
}

__global__ __launch_bounds__(256) void lr_kernel(
    const float* __restrict__ x1, const float* __restrict__ lrw,
    const float* __restrict__ lrb, float* __restrict__ lro)
{
    int w = (blockIdx.x * blockDim.x + threadIdx.x) >> 5;
    if (w >= Bn * Sn * Hn) return;
    int lane = threadIdx.x & 31;
    int h = w & 15, bs = w >> 4;
    int b = bs >> 10, s = bs & (Sn - 1);
    const float* xr = x1 + (size_t)bs * Dn;
    const float* wr = lrw + h * Dn;
    float acc = 0.f;
    for (int c = lane; c < Dn; c += 32) acc += xr[c] * wr[c];
    acc = warpsum(acc);
    if (lane == 0)
        lro[(size_t)(b * Hn + h) * Sn + s] = 1.f / (1.f + __expf(-(acc + lrb[h])));
}

// ---------------- TTT scan: bf16 mma A/D/E/F, W2 staged B/H ------------
#define SV 65
#define PS 68
#define TS 68
#define WS 260
#define SCAN_FLOATS (64*SV + 2*64*PS + 4*64*TS + 16*WS + 64*WS + 256 + 64 + 64)
#define SCAN_SMEM (SCAN_FLOATS * 4)

__global__ __launch_bounds__(512) void ttt_scan_kernel(
    const float* __restrict__ XQ, const float* __restrict__ XK, const float* __restrict__ XV,
    const float* __restrict__ lr,
    const float* __restrict__ W1i, const float* __restrict__ b1i,
    const float* __restrict__ W2i, const float* __restrict__ b2i,
    const float* __restrict__ nw,  const float* __restrict__ nb,
    float* __restrict__ W2G, float* __restrict__ W2TG,
    float* __restrict__ X2G, float* __restrict__ gZ1G, float* __restrict__ X2bG,
    float* __restrict__ outp)
{
    extern __shared__ float sm[];
    float* sxv   = sm;
    float* ssc   = sxv  + 64 * SV;
    float* sgZ2  = ssc  + 64 * PS;
    float* sxqT  = sgZ2 + 64 * PS;
    float* sxkT  = sxqT + 64 * TS;
    float* sscT  = sxkT + 64 * TS;
    float* sgZ2T = sscT + 64 * TS;
    float* sstg  = sgZ2T+ 64 * TS;
    float* sW1   = sstg + 16 * WS;
    float* b1sm  = sW1  + 64 * WS;
    float* b2sm  = b1sm + 256;
    float* seta  = b2sm + 64;

    int bh = blockIdx.x, b = bh >> 4, h = bh & 15;
    int tid = threadIdx.x, w = tid >> 5, l = tid & 31;
    int g = l >> 2, tg = l & 3;
    int ty2 = tid >> 4, tx2 = tid & 15;
    int ft = tid >> 3, jt = tid & 7;
    int mi = (w & 3) * 16, ng = (w >> 2) * 64;
    float* W2r  = W2G  + (size_t)bh * 16384;
    float* W2Tr = W2TG + (size_t)bh * 16384;
    float* X2r  = X2G  + (size_t)bh * 16384;
    float* gZ1r = gZ1G + (size_t)bh * 16384;
    float* X2br = X2bG + (size_t)bh * 16384;
    const float* nwh = nw + h * 64;
    const float* nbh = nb + h * 64;

    for (int idx = tid; idx < 16384; idx += 512) {
        int e = idx >> 8, f = idx & 255;
        sW1[e * WS + f] = W1i[(size_t)h * 16384 + idx];
        W2r[idx]  = W2i[(size_t)h * 16384 + idx];
        W2Tr[idx] = W2i[(size_t)h * 16384 + f * 64 + e];
    }
    if (tid < 256) b1sm[tid] = b1i[h * 256 + tid];
    if (tid < 64)  b2sm[tid] = b2i[h * 64 + tid];
    __syncthreads();

    for (int n = 0; n < NCn; n++) {
        size_t tokbase = (size_t)b * Sn + n * Cn;
        for (int idx = tid; idx < 4096; idx += 512) {
            int i = idx >> 6, e = idx & 63;
            size_t gg = (tokbase + i) * Dn + h * 64 + e;
            sxqT[e * TS + i] = XQ[gg];
            sxkT[e * TS + i] = XK[gg];
            sxv [i * SV + e] = XV[gg];
        }
        if (tid < 64) seta[tid] = lr[(size_t)bh * Sn + n * 64 + tid] * (1.f / 64.f);
        __syncthreads();

        // ---- A (bf16 mma, 2 passes): Z1=xk@W1+b1 ; Z1q=xq@W1+b1
#pragma unroll
        for (int p = 0; p < 2; p++) {
            const float* T = p ? sxqT : sxkT;
            float c[8][4];
#pragma unroll
            for (int nt = 0; nt < 8; nt++) {
                int col = ng + nt * 8 + tg * 2;
                c[nt][0] = b1sm[col];   c[nt][1] = b1sm[col+1];
                c[nt][2] = b1sm[col];   c[nt][3] = b1sm[col+1];
            }
#pragma unroll
            for (int kb = 0; kb < 64; kb += 16) {
                int k0 = kb + 2 * tg;
                unsigned a[4];
                a[0] = bf2pack(T[k0*TS + mi+g],       T[(k0+1)*TS + mi+g]);
                a[1] = bf2pack(T[k0*TS + mi+g+8],     T[(k0+1)*TS + mi+g+8]);
                a[2] = bf2pack(T[(k0+8)*TS + mi+g],   T[(k0+9)*TS + mi+g]);
                a[3] = bf2pack(T[(k0+8)*TS + mi+g+8], T[(k0+9)*TS + mi+g+8]);
#pragma unroll
                for (int nt = 0; nt < 8; nt++) {
                    int col = ng + nt * 8 + g;
                    unsigned bb[2];
                    bb[0] = bf2pack(sW1[k0*WS + col],     sW1[(k0+1)*WS + col]);
                    bb[1] = bf2pack(sW1[(k0+8)*WS + col], sW1[(k0+9)*WS + col]);
                    mma_bf16(c[nt], a, bb);
                }
            }
#pragma unroll
            for (int nt = 0; nt < 8; nt++) {
                int col = ng + nt * 8 + tg * 2;
                int r0 = mi + g;
                if (p == 0) {
                    float x2o[4], gbo[4];
#pragma unroll
                    for (int r = 0; r < 4; r++) {
                        float z = c[nt][r];
                        float t = tanh_fast(0.79788456f * (z + 0.044715f * z * z * z));
                        x2o[r] = 0.5f * z * (1.f + t);
                        gbo[r] = 0.5f * z * (1.f - t * t) * (0.79788456f + 0.1070322243f * z * z)
                               + 0.5f * (1.f + t);
                    }
                    *(float2*)(X2r  + r0*256 + col)     = make_float2(x2o[0], x2o[1]);
                    *(float2*)(X2r  + (r0+8)*256 + col) = make_float2(x2o[2], x2o[3]);
                    *(float2*)(gZ1r + r0*256 + col)     = make_float2(gbo[0], gbo[1]);
                    *(float2*)(gZ1r + (r0+8)*256 + col) = make_float2(gbo[2], gbo[3]);
                } else {
                    *(float2*)(X2br + r0*256 + col)     = make_float2(c[nt][0], c[nt][1]);
                    *(float2*)(X2br + (r0+8)*256 + col) = make_float2(c[nt][2], c[nt][3]);
                }
            }
        }
        __syncthreads();

        // ---- B: Z2 = X2@W2 + b2 -> ssc (FFMA, W2 staged 64 rows at a time)
        {
            float acc[2][4];
#pragma unroll
            for (int u = 0; u < 2; u++)
#pragma unroll
                for (int v = 0; v < 4; v++) acc[u][v] = b2sm[tx2 * 4 + v];
            for (int kbb = 0; kbb < 256; kbb += 64) {
                __syncthreads();
                for (int idx = tid; idx < 4096; idx += 512) {
                    int rr = idx >> 6, cf = idx & 63;
                    sstg[rr*64 + cf] = W2r[(size_t)(kbb+rr)*64 + cf];
                }
                __syncthreads();
#pragma unroll 4
                for (int f0 = 0; f0 < 64; f0 += 4) {
                    float4 a4[2], b4[4];
#pragma unroll
                    for (int u = 0; u < 2; u++)
                        a4[u] = *(const float4*)(X2r + (ty2*2+u)*256 + kbb + f0);
#pragma unroll
                    for (int d = 0; d < 4; d++)
                        b4[d] = *(const float4*)(sstg + (f0+d)*64 + tx2*4);
#pragma unroll
                    for (int u = 0; u < 2; u++) {
                        acc[u][0] += a4[u].x*b4[0].x + a4[u].y*b4[1].x + a4[u].z*b4[2].x + a4[u].w*b4[3].x;
                        acc[u][1] += a4[u].x*b4[0].y + a4[u].y*b4[1].y + a4[u].z*b4[2].y + a4[u].w*b4[3].y;
                        acc[u][2] += a4[u].x*b4[0].z + a4[u].y*b4[1].z + a4[u].z*b4[2].z + a4[u].w*b4[3].z;
                        acc[u][3] += a4[u].x*b4[0].w + a4[u].y*b4[1].w + a4[u].z*b4[2].w + a4[u].w*b4[3].w;
                    }
                }
            }
#pragma unroll
            for (int u = 0; u < 2; u++)
#pragma unroll
                for (int v = 0; v < 4; v++) ssc[(ty2*2+u)*PS + tx2*4+v] = acc[u][v];
        }
        __syncthreads();

        // ---- C: gZ2 = ln_l2_bwd -> sgZ2 + sgZ2T
        for (int i = w; i < 64; i += 16) {
            float z0 = ssc[i*PS + l], z1 = ssc[i*PS + l + 32];
            float mu = warpsum(z0 + z1) * (1.f/64.f);
            float d0 = z0 - mu, d1 = z1 - mu;
            float var = warpsum(d0*d0 + d1*d1) * (1.f/64.f);
            float rstd = rsqrtf(var + EPSc);
            float xh0 = d0 * rstd, xh1 = d1 * rstd;
            float g0 = nwh[l], g1 = nwh[l+32];
            float t0 = sxv[i*SV + l]      - sxkT[l*TS + i];
            float t1 = sxv[i*SV + l + 32] - sxkT[(l+32)*TS + i];
            float gh0 = (g0*xh0 + nbh[l]    - t0) * g0;
            float gh1 = (g1*xh1 + nbh[l+32] - t1) * g1;
            float sgh = warpsum(gh0 + gh1);
            float sgx = warpsum(gh0*xh0 + gh1*xh1);
            float cc = rstd * (1.f/64.f);
            float o0 = (64.f*gh0 - sgh - xh0*sgx) * cc;
            float o1 = (64.f*gh1 - sgh - xh1*sgx) * cc;
            sgZ2[i*PS + l]        = o0;
            sgZ2[i*PS + l + 32]   = o1;
            sgZ2T[l*TS + i]       = o0;
            sgZ2T[(l+32)*TS + i]  = o1;
        }
        __syncthreads();

        // ---- D (bf16 mma): gZ1 = (gZ2 @ W2^T) * gb   (16-row staging)
        {
            float c[8][4];
#pragma unroll
            for (int nt = 0; nt < 8; nt++)
#pragma unroll
                for (int r = 0; r < 4; r++) c[nt][r] = 0.f;
#pragma unroll
            for (int kbb = 0; kbb < 64; kbb += 16) {
                __syncthreads();
                for (int idx = tid; idx < 4096; idx += 512) {
                    int rr = idx >> 8, cf = idx & 255;
                    sstg[rr*WS + cf] = W2Tr[(kbb+rr)*256 + cf];
                }
                __syncthreads();
                int k0 = 2 * tg;
                unsigned a[4];
                a[0] = bf2pack(sgZ2T[(kbb+k0)*TS + mi+g],     sgZ2T[(kbb+k0+1)*TS + mi+g]);
                a[1] = bf2pack(sgZ2T[(kbb+k0)*TS + mi+g+8],   sgZ2T[(kbb+k0+1)*TS + mi+g+8]);
                a[2] = bf2pack(sgZ2T[(kbb+k0+8)*TS + mi+g],   sgZ2T[(kbb+k0+9)*TS + mi+g]);
                a[3] = bf2pack(sgZ2T[(kbb+k0+8)*TS + mi+g+8], sgZ2T[(kbb+k0+9)*TS + mi+g+8]);
#pragma unroll
                for (int nt = 0; nt < 8; nt++) {
                    int col = ng + nt * 8 + g;
                    unsigned bb[2];
                    bb[0] = bf2pack(sstg[k0*WS + col],     sstg[(k0+1)*WS + col]);
                    bb[1] = bf2pack(sstg[(k0+8)*WS + col], sstg[(k0+9)*WS + col]);
                    mma_bf16(c[nt], a, bb);
                }
            }
#pragma unroll
            for (int nt = 0; nt < 8; nt++) {
                int col = ng + nt * 8 + tg * 2;
                int r0 = mi + g;
                float2 gb0 = *(const float2*)(gZ1r + r0*256 + col);
                float2 gb1 = *(const float2*)(gZ1r + (r0+8)*256 + col);
                *(float2*)(gZ1r + r0*256 + col)     = make_float2(c[nt][0]*gb0.x, c[nt][1]*gb0.y);
                *(float2*)(gZ1r + (r0+8)*256 + col) = make_float2(c[nt][2]*gb1.x, c[nt][3]*gb1.y);
            }
        }
        __syncthreads();

        // ---- E (bf16 mma): coef1 = -eta[k2]*(tril(xq@xk^T)+1) -> sscT
#pragma unroll
        for (int sub = 0; sub < 2; sub++) {
            int ncol = ((w >> 2) * 2 + sub) * 8;
            float c[4] = {0.f, 0.f, 0.f, 0.f};
#pragma unroll
            for (int kb = 0; kb < 64; kb += 16) {
                int k0 = kb + 2 * tg;
                unsigned a[4], bb[2];
                a[0] = bf2pack(sxqT[k0*TS + mi+g],       sxqT[(k0+1)*TS + mi+g]);
                a[1] = bf2pack(sxqT[k0*TS + mi+g+8],     sxqT[(k0+1)*TS + mi+g+8]);
                a[2] = bf2pack(sxqT[(k0+8)*TS + mi+g],   sxqT[(k0+9)*TS + mi+g]);
                a[3] = bf2pack(sxqT[(k0+8)*TS + mi+g+8], sxqT[(k0+9)*TS + mi+g+8]);
                bb[0] = bf2pack(sxkT[k0*TS + ncol+g],     sxkT[(k0+1)*TS + ncol+g]);
                bb[1] = bf2pack(sxkT[(k0+8)*TS + ncol+g], sxkT[(k0+9)*TS + ncol+g]);
                mma_bf16(c, a, bb);
            }
            int r0 = mi + g, k2 = ncol + tg * 2;
            sscT[k2*TS + r0]       = (k2   <= r0)   ? -seta[k2]  *(c[0]+1.f) : 0.f;
            sscT[(k2+1)*TS + r0]   = (k2+1 <= r0)   ? -seta[k2+1]*(c[1]+1.f) : 0.f;
            sscT[k2*TS + r0+8]     = (k2   <= r0+8) ? -seta[k2]  *(c[2]+1.f) : 0.f;
            sscT[(k2+1)*TS + r0+8] = (k2+1 <= r0+8) ? -seta[k2+1]*(c[3]+1.f) : 0.f;
        }
        __syncthreads();

        // ---- F (bf16 mma): Z1b = Z1q + coef1neg@gZ1 ; X2b = gelu
        {
            float c[8][4];
#pragma unroll
            for (int nt = 0; nt < 8; nt++) {
                int col = ng + nt * 8 + tg * 2;
                int r0 = mi + g;
                float2 q0 = *(const float2*)(X2br + r0*256 + col);
                float2 q1 = *(const float2*)(X2br + (r0+8)*256 + col);
                c[nt][0] = q0.x; c[nt][1] = q0.y; c[nt][2] = q1.x; c[nt][3] = q1.y;
            }
#pragma unroll
            for (int kbb = 0; kbb < 64; kbb += 16) {
                __syncthreads();
                for (int idx = tid; idx < 4096; idx += 512) {
                    int rr = idx >> 8, cf = idx & 255;
                    sstg[rr*WS + cf] = gZ1r[(kbb+rr)*256 + cf];
                }
                __syncthreads();
                int k0 = 2 * tg;
                unsigned a[4];
                a[0] = bf2pack(sscT[(kbb+k0)*TS + mi+g],     sscT[(kbb+k0+1)*TS + mi+g]);
                a[1] = bf2pack(sscT[(kbb+k0)*TS + mi+g+8],   sscT[(kbb+k0+1)*TS + mi+g+8]);
                a[2] = bf2pack(sscT[(kbb+k0+8)*TS + mi+g],   sscT[(kbb+k0+9)*TS + mi+g]);
                a[3] = bf2pack(sscT[(kbb+k0+8)*TS + mi+g+8], sscT[(kbb+k0+9)*TS + mi+g+8]);
#pragma unroll
                for (int nt = 0; nt < 8; nt++) {
                    int col = ng + nt * 8 + g;
                    unsigned bb[2];
                    bb[0] = bf2pack(sstg[k0*WS + col],     sstg[(k0+1)*WS + col]);
                    bb[1] = bf2pack(sstg[(k0+8)*WS + col], sstg[(k0+9)*WS + col]);
                    mma_bf16(c[nt], a, bb);
                }
            }
#pragma unroll
            for (int nt = 0; nt < 8; nt++) {
                int col = ng + nt * 8 + tg * 2;
                int r0 = mi + g;
                float xo[4];
#pragma unroll
                for (int r = 0; r < 4; r++) {
                    float z = c[nt][r];
                    float t = tanh_fast(0.79788456f * (z + 0.044715f * z * z * z));
                    xo[r] = 0.5f * z * (1.f + t);
                }
                *(float2*)(X2br + r0*256 + col)     = make_float2(xo[0], xo[1]);
                *(float2*)(X2br + (r0+8)*256 + col) = make_float2(xo[2], xo[3]);
            }
        }
        __syncthreads();

        // ---- G: coef2 (FFMA)
        {
            float acc[2][4];
#pragma unroll
            for (int u = 0; u < 2; u++)
#pragma unroll
                for (int v = 0; v < 4; v++) acc[u][v] = 0.f;
            if (tx2 * 4 <= ty2 * 2 + 1) {
#pragma unroll 2
                for (int f0 = 0; f0 < 256; f0 += 4) {
                    float4 a4[2], b4[4];
#pragma unroll
                    for (int u = 0; u < 2; u++) a4[u] = *(const float4*)(X2br + (ty2*2+u)*256 + f0);
#pragma unroll
                    for (int v = 0; v < 4; v++) b4[v] = *(const float4*)(X2r + (tx2*4+v)*256 + f0);
#pragma unroll
                    for (int u = 0; u < 2; u++)
#pragma unroll
                        for (int v = 0; v < 4; v++)
                            acc[u][v] += a4[u].x*b4[v].x + a4[u].y*b4[v].y
                                       + a4[u].z*b4[v].z + a4[u].w*b4[v].w;
                }
            }
#pragma unroll
            for (int u = 0; u < 2; u++) {
                int i = ty2 * 2 + u;
#pragma unroll
                for (int v = 0; v < 4; v++) {
                    int j = tx2 * 4 + v;
                    ssc[i*PS + j] = (j <= i) ? seta[j] * (acc[u][v] + 1.f) : 0.f;
                }
            }
        }
        __syncthreads();

        // ---- H: Z2b = X2b@W2 + b2 - coef2@gZ2 -> sxv (W2 staged)
        {
            float acc[2][4];
#pragma unroll
            for (int u = 0; u < 2; u++)
#pragma unroll
                for (int v = 0; v < 4; v++) acc[u][v] = b2sm[tx2 * 4 + v];
            for (int kbb = 0; kbb < 256; kbb += 64) {
                __syncthreads();
                for (int idx = tid; idx < 4096; idx += 512) {
                    int rr = idx >> 6, cf = idx & 63;
                    sstg[rr*64 + cf] = W2r[(size_t)(kbb+rr)*64 + cf];
                }
                __syncthreads();
#pragma unroll 4
                for (int f0 = 0; f0 < 64; f0 += 4) {
                    float4 a4[2], b4[4];
#pragma unroll
                    for (int u = 0; u < 2; u++)
                        a4[u] = *(const float4*)(X2br + (ty2*2+u)*256 + kbb + f0);
#pragma unroll
                    for (int d = 0; d < 4; d++)
                        b4[d] = *(const float4*)(sstg + (f0+d)*64 + tx2*4);
#pragma unroll
                    for (int u = 0; u < 2; u++) {
                        acc[u][0] += a4[u].x*b4[0].x + a4[u].y*b4[1].x + a4[u].z*b4[2].x + a4[u].w*b4[3].x;
                        acc[u][1] += a4[u].x*b4[0].y + a4[u].y*b4[1].y + a4[u].z*b4[2].y + a4[u].w*b4[3].y;
                        acc[u][2] += a4[u].x*b4[0].z + a4[u].y*b4[1].z + a4[u].z*b4[2].z + a4[u].w*b4[3].z;
                        acc[u][3] += a4[u].x*b4[0].w + a4[u].y*b4[1].w + a4[u].z*b4[2].w + a4[u].w*b4[3].w;
                    }
                }
            }
#pragma unroll 4
            for (int k2 = 0; k2 < 64; k2++) {
                float cc0 = ssc[(ty2*2)*PS + k2];
                float cc1 = ssc[(ty2*2+1)*PS + k2];
                float4 gv4 = *(const float4*)(sgZ2 + k2*PS + tx2*4);
                acc[0][0] -= cc0*gv4.x; acc[0][1] -= cc0*gv4.y; acc[0][2] -= cc0*gv4.z; acc[0][3] -= cc0*gv4.w;
                acc[1][0] -= cc1*gv4.x; acc[1][1] -= cc1*gv4.y; acc[1][2] -= cc1*gv4.z; acc[1][3] -= cc1*gv4.w;
            }
#pragma unroll
            for (int u = 0; u < 2; u++)
#pragma unroll
                for (int v = 0; v < 4; v++) sxv[(ty2*2+u)*SV + tx2*4+v] = acc[u][v];
        }
        __syncthreads();

        // ---- I: out = xq + LN(Z2b)
        for (int i = w; i < 64; i += 16) {
            float z0 = sxv[i*SV + l], z1 = sxv[i*SV + l + 32];
            float mu = warpsum(z0 + z1) * (1.f/64.f);
            float d0 = z0 - mu, d1 = z1 - mu;
            float var = warpsum(d0*d0 + d1*d1) * (1.f/64.f);
            float rstd = rsqrtf(var + EPSc);
            size_t gg = (tokbase + i) * Dn + h * 64;
            outp[gg + l]      = sxqT[l*TS + i]      + nwh[l]    * d0 * rstd + nbh[l];
            outp[gg + l + 32] = sxqT[(l+32)*TS + i] + nwh[l+32] * d1 * rstd + nbh[l+32];
        }

        // ---- J1: W1 -= (eta*xk)^T @ gZ1  (sW1 smem)
        {
            u64 acc2[4][4];
#pragma unroll
            for (int u = 0; u < 4; u++)
#pragma unroll
                for (int p = 0; p < 4; p++) acc2[u][p] = 0ULL;
#pragma unroll 4
            for (int i = 0; i < 64; i++) {
                float et = seta[i];
                float4 g0 = *(const float4*)(gZ1r + i*256 + l*8);
                float4 g1 = *(const float4*)(gZ1r + i*256 + l*8 + 4);
                u64 gv2[4];
                f4tou2(g0, gv2[0], gv2[1]); f4tou2(g1, gv2[2], gv2[3]);
#pragma unroll
                for (int u = 0; u < 4; u++) {
                    float a = et * sxkT[(w*4+u)*TS + i];
                    u64 a2 = f2pack(a, a);
#pragma unroll
                    for (int p = 0; p < 4; p++) acc2[u][p] = ffma2(a2, gv2[p], acc2[u][p]);
                }
            }
#pragma unroll
            for (int u = 0; u < 4; u++) {
                int e = w * 4 + u;
                float av[8];
#pragma unroll
                for (int p = 0; p < 4; p++) f2unpack(acc2[u][p], av[2*p], av[2*p+1]);
                float4* wp = (float4*)(sW1 + e*WS + l*8);
                float4 o0 = wp[0], o1 = wp[1];
                wp[0] = make_float4(o0.x-av[0], o0.y-av[1], o0.z-av[2], o0.w-av[3]);
                wp[1] = make_float4(o1.x-av[4], o1.y-av[5], o1.z-av[6], o1.w-av[7]);
            }
        }
        // J2: b1
        if (tid < 256) {
            float acc = 0.f;
#pragma unroll 8
            for (int i = 0; i < 64; i++) acc += seta[i] * gZ1r[i*256 + tid];
            b1sm[tid] -= acc;
        }
        // J3: W2 + W2T (global)
        {
            u64 acc2[4][4];
#pragma unroll
            for (int u = 0; u < 4; u++)
#pragma unroll
                for (int p = 0; p < 4; p++) acc2[u][p] = 0ULL;
#pragma unroll 4
            for (int i = 0; i < 64; i++) {
                float et = seta[i];
                float4 x0 = *(const float4*)(X2r + i*256 + ft*4);
                float4 gv0 = *(const float4*)(sgZ2 + i*PS + jt*8);
                float4 gv1 = *(const float4*)(sgZ2 + i*PS + jt*8 + 4);
                u64 gv2[4];
                f4tou2(gv0, gv2[0], gv2[1]); f4tou2(gv1, gv2[2], gv2[3]);
                float a[4] = {et*x0.x, et*x0.y, et*x0.z, et*x0.w};
#pragma unroll
                for (int u = 0; u < 4; u++) {
                    u64 a2 = f2pack(a[u], a[u]);
#pragma unroll
                    for (int p = 0; p < 4; p++) acc2[u][p] = ffma2(a2, gv2[p], acc2[u][p]);
                }
            }
#pragma unroll
            for (int u = 0; u < 4; u++) {
                int f = ft * 4 + u;
                float av[8];
#pragma unroll
                for (int p = 0; p < 4; p++) f2unpack(acc2[u][p], av[2*p], av[2*p+1]);
                float4* wp0 = (float4*)(W2r + f*64 + jt*8);
                float4* wp1 = (float4*)(W2r + f*64 + jt*8 + 4);
                float4 o0 = wp0[0], o1 = wp1[0];
                wp0[0] = make_float4(o0.x-av[0], o0.y-av[1], o0.z-av[2], o0.w-av[3]);
                wp1[0] = make_float4(o1.x-av[4], o1.y-av[5], o1.z-av[6], o1.w-av[7]);
#pragma unroll
                for (int v = 0; v < 8; v++)
                    W2Tr[(jt*8+v)*256 + f] -= av[v];
            }
        }
        // J4: b2
        if (tid < 64) {
            float acc = 0.f;
#pragma unroll 8
            for (int i = 0; i < 64; i++) acc += seta[i] * sgZ2[i*PS + tid];
            b2sm[tid] -= acc;
        }
        __syncthreads();
    }
}

// ---------------- Launch ----------------
extern "C" void kernel_launch(void* const* d_in, const int* in_sizes, int n_in,
                              void* d_out, int out_size)
{
    const float* x       = (const float*)d_in[0];
    const float* ln1_w   = (const float*)d_in[1];
    const float* ln1_b   = (const float*)d_in[2];
    const float* attn_wq = (const float*)d_in[3];
    const float* attn_wk = (const float*)d_in[4];
    const float* attn_wv = (const float*)d_in[5];
    const float* attn_wo = (const float*)d_in[6];
    const float* wq_w    = (const float*)d_in[7];
    const float* wq_b    = (const float*)d_in[8];
    const float* wk_w    = (const float*)d_in[9];
    const float* wk_b    = (const float*)d_in[10];
    const float* wv_w    = (const float*)d_in[11];
    const float* wv_b    = (const float*)d_in[12];
    const float* wo_w    = (const float*)d_in[13];
    const float* wo_b    = (const float*)d_in[14];
    const float* W1      = (const float*)d_in[15];
    const float* b1      = (const float*)d_in[16];
    const float* W2      = (const float*)d_in[17];
    const float* b2      = (const float*)d_in[18];
    const float* ttt_nw  = (const float*)d_in[19];
    const float* ttt_nb  = (const float*)d_in[20];
    const float* lr_w    = (const float*)d_in[21];
    const float* lr_b    = (const float*)d_in[22];
    const float* pn_w    = (const float*)d_in[23];
    const float* pn_b    = (const float*)d_in[24];
    const float* gate_a  = (const float*)d_in[25];
    float* out = (float*)d_out;

    float *p_h,*p_q,*p_k,*p_v,*p_o,*p_x1,*p_lr,*p_W2,*p_W2T,*p_X2,*p_gZ1,*p_X2b;
    cudaGetSymbolAddress((void**)&p_h,  g_h);
    cudaGetSymbolAddress((void**)&p_q,  g_q);
    cudaGetSymbolAddress((void**)&p_k,  g_k);
    cudaGetSymbolAddress((void**)&p_v,  g_v);
    cudaGetSymbolAddress((void**)&p_o,  g_o);
    cudaGetSymbolAddress((void**)&p_x1, g_x1);
    cudaGetSymbolAddress((void**)&p_lr, g_lr);
    cudaGetSymbolAddress((void**)&p_W2, g_W2s);
    cudaGetSymbolAddress((void**)&p_W2T,g_W2Ts);
    cudaGetSymbolAddress((void**)&p_X2, g_X2);
    cudaGetSymbolAddress((void**)&p_gZ1,g_gZ1);
    cudaGetSymbolAddress((void**)&p_X2b,g_X2b);

    cudaFuncSetAttribute(ttt_scan_kernel,   cudaFuncAttributeMaxDynamicSharedMemorySize, SCAN_SMEM);
    cudaFuncSetAttribute(attn_flash_kernel, cudaFuncAttributeMaxDynamicSharedMemorySize, ATT_SMEM);

    const int M = Bn * Sn;
    dim3 ggrid(Dn / 128, M / 128);
    dim3 ggrid3(Dn / 128, M / 128, 3);
    int nwarp_grid = (Bn * Sn * Hn) / 8;

    ln_kernel<<<M, 256>>>(x, ln1_w, ln1_b, p_h);
    gemm3_nt_kernel<<<ggrid3, 256>>>(p_h, attn_wq, attn_wk, attn_wv,
                                     p_q, p_k, p_v, nullptr, nullptr, nullptr);
    attn_flash_kernel<<<dim3(16, 64), 256, ATT_SMEM>>>(p_q, p_k, p_v, p_o);
    gemm_nt_kernel<<<ggrid, 256>>>(p_o, attn_wo, p_x1, nullptr, x, nullptr);
    gemm3_nt_kernel<<<ggrid3, 256>>>(p_x1, wq_w, wk_w, wv_w,
                                     p_q, p_k, p_v, wq_b, wk_b, wv_b);
    prep_kernel<<<nwarp_grid, 256>>>(p_q, p_k, p_v, ttt_nw, ttt_nb);
    lr_kernel<<<nwarp_grid, 256>>>(p_x1, lr_w, lr_b, p_lr);
    ttt_scan_kernel<<<Bn * Hn, 512, SCAN_SMEM>>>(
        p_q, p_k, p_v, p_lr, W1, b1, W2, b2, ttt_nw, ttt_nb,
        p_W2, p_W2T, p_X2, p_gZ1, p_X2b, p_o);
    ln_kernel<<<M, 256>>>(p_o, pn_w, pn_b, p_h);
    gemm_nt_kernel<<<ggrid, 256>>>(p_h, wo_w, out, wo_b, p_x1, gate_a);
}

// round 16
// speedup vs baseline: 2.5293x; 1.3490x over previous
#include <cuda_runtime.h>
#include <math.h>

#define Bn 4
#define Sn 1024
#define Dn 1024
#define Hn 16
#define HDn 64
#define Cn 64
#define NCn 16
#define DFFn 256
#define EPSc 1e-6f
#define BSD (Bn*Sn*Dn)

typedef unsigned long long u64;
__device__ __forceinline__ u64 f2pack(float lo, float hi) {
    u64 r; asm("mov.b64 %0, {%1, %2};" : "=l"(r) : "f"(lo), "f"(hi)); return r;
}
__device__ __forceinline__ void f2unpack(u64 p, float& lo, float& hi) {
    asm("mov.b64 {%0, %1}, %2;" : "=f"(lo), "=f"(hi) : "l"(p));
}
__device__ __forceinline__ u64 ffma2(u64 a, u64 b, u64 c) {
    u64 d; asm("fma.rn.f32x2 %0, %1, %2, %3;" : "=l"(d) : "l"(a), "l"(b), "l"(c)); return d;
}
__device__ __forceinline__ void f4tou2(float4 f, u64& p0, u64& p1) {
    p0 = f2pack(f.x, f.y); p1 = f2pack(f.z, f.w);
}
__device__ __forceinline__ unsigned f2tf32(float f) {
    unsigned r; asm("cvt.rna.tf32.f32 %0, %1;" : "=r"(r) : "f"(f)); return r;
}
__device__ __forceinline__ unsigned bf2pack(float lo, float hi) {
    unsigned r; asm("cvt.rn.bf16x2.f32 %0, %1, %2;" : "=r"(r) : "f"(hi), "f"(lo)); return r;
}
__device__ __forceinline__ void mma_tf32(float* c, const unsigned* a, const unsigned* b) {
    asm volatile("mma.sync.aligned.m16n8k8.row.col.f32.tf32.tf32.f32 "
        "{%0,%1,%2,%3}, {%4,%5,%6,%7}, {%8,%9}, {%0,%1,%2,%3};"
        : "+f"(c[0]), "+f"(c[1]), "+f"(c[2]), "+f"(c[3])
        : "r"(a[0]), "r"(a[1]), "r"(a[2]), "r"(a[3]), "r"(b[0]), "r"(b[1]));
}
__device__ __forceinline__ void mma_bf16(float* c, const unsigned* a, const unsigned* b) {
    asm volatile("mma.sync.aligned.m16n8k16.row.col.f32.bf16.bf16.f32 "
        "{%0,%1,%2,%3}, {%4,%5,%6,%7}, {%8,%9}, {%0,%1,%2,%3};"
        : "+f"(c[0]), "+f"(c[1]), "+f"(c[2]), "+f"(c[3])
        : "r"(a[0]), "r"(a[1]), "r"(a[2]), "r"(a[3]), "r"(b[0]), "r"(b[1]));
}

__device__ float g_h [BSD];
__device__ float g_q [BSD];
__device__ float g_k [BSD];
__device__ float g_v [BSD];
__device__ float g_o [BSD];
__device__ float g_x1[BSD];
__device__ float g_lr[Bn*Hn*Sn];
__device__ float g_W2Ts[Bn*Hn*16384];
__device__ float g_X2  [Bn*Hn*16384];
__device__ float g_gZ1 [Bn*Hn*16384];
__device__ float g_X2b [Bn*Hn*16384];

__device__ __forceinline__ float warpsum(float v) {
#pragma unroll
    for (int o = 16; o > 0; o >>= 1) v += __shfl_xor_sync(0xffffffffu, v, o);
    return v;
}
__device__ __forceinline__ float warpmax(float v) {
#pragma unroll
    for (int o = 16; o > 0; o >>= 1) v = fmaxf(v, __shfl_xor_sync(0xffffffffu, v, o));
    return v;
}
__device__ __forceinline__ float blocksum256(float v) {
    __shared__ float red[8];
    int lane = threadIdx.x & 31, w = threadIdx.x >> 5;
    v = warpsum(v);
    if (lane == 0) red[w] = v;
    __syncthreads();
    float r = (lane < 8) ? red[lane] : 0.f;
    r = warpsum(r);
    __syncthreads();
    return r;
}
__device__ __forceinline__ float tanh_fast(float x) {
    float e = __expf(2.f * x);
    return 1.f - __fdividef(2.f, e + 1.f);
}

// ---------------- LayerNorm rows of 1024 ----------------
__global__ __launch_bounds__(256) void ln_kernel(
    const float* __restrict__ x, const float* __restrict__ g,
    const float* __restrict__ b, float* __restrict__ y)
{
    int row = blockIdx.x, tid = threadIdx.x;
    const float* xr = x + (size_t)row * Dn;
    float v[4]; float s = 0.f;
#pragma unroll
    for (int i = 0; i < 4; i++) { v[i] = xr[tid + 256 * i]; s += v[i]; }
    s = blocksum256(s);
    float mu = s * (1.f / Dn), ss = 0.f;
#pragma unroll
    for (int i = 0; i < 4; i++) { float d = v[i] - mu; ss += d * d; }
    ss = blocksum256(ss);
    float rstd = rsqrtf(ss * (1.f / Dn) + EPSc);
    float* yr = y + (size_t)row * Dn;
#pragma unroll
    for (int i = 0; i < 4; i++) {
        int c = tid + 256 * i;
        yr[c] = (v[i] - mu) * rstd * g[c] + b[c];
    }
}

// ---------------- bf16 tensor-core GEMM, double-buffered ----------------
#define GSTR 136
__device__ __forceinline__ void gemm_core(
    const float* __restrict__ A, const float* __restrict__ B, float* __restrict__ C,
    const float* __restrict__ bias, const float* __restrict__ res,
    const float* __restrict__ gate, int bm, int bn)
{
    const int N = 1024, K = 1024, BK = 16;
    __shared__ unsigned As[2][8][GSTR];
    __shared__ unsigned Bs[2][8][GSTR];
    int t = threadIdx.x;
    int warp = t >> 5, lane = t & 31;
    int wm = warp >> 1, wn = warp & 1;
    int g = lane >> 2, tg = lane & 3;

    float acc[2][8][4];
#pragma unroll
    for (int mt = 0; mt < 2; mt++)
#pragma unroll
        for (int nt = 0; nt < 8; nt++)
#pragma unroll
            for (int r = 0; r < 4; r++) acc[mt][nt][r] = 0.f;

    int r128 = t >> 1, kc = (t & 1) * 8, kp0 = (t & 1) * 4;
    const float* Ab = A + (size_t)(bm + r128) * K + kc;
    const float* Bb = B + (size_t)(bn + r128) * K + kc;
    float4 a0 = *(const float4*)(Ab);
    float4 a1 = *(const float4*)(Ab + 4);
    float4 b0 = *(const float4*)(Bb);
    float4 b1 = *(const float4*)(Bb + 4);

    As[0][kp0+0][r128] = bf2pack(a0.x, a0.y);
    As[0][kp0+1][r128] = bf2pack(a0.z, a0.w);
    As[0][kp0+2][r128] = bf2pack(a1.x, a1.y);
    As[0][kp0+3][r128] = bf2pack(a1.z, a1.w);
    Bs[0][kp0+0][r128] = bf2pack(b0.x, b0.y);
    Bs[0][kp0+1][r128] = bf2pack(b0.z, b0.w);
    Bs[0][kp0+2][r128] = bf2pack(b1.x, b1.y);
    Bs[0][kp0+3][r128] = bf2pack(b1.z, b1.w);
    __syncthreads();

    int cur = 0;
    for (int k0 = 0; k0 < K; k0 += BK) {
        bool more = (k0 + BK < K);
        if (more) {
            a0 = *(const float4*)(Ab + k0 + BK);
            a1 = *(const float4*)(Ab + k0 + BK + 4);
            b0 = *(const float4*)(Bb + k0 + BK);
            b1 = *(const float4*)(Bb + k0 + BK + 4);
        }
        {
            unsigned af[2][4], bf[8][2];
#pragma unroll
            for (int mt = 0; mt < 2; mt++) {
                int mb = wm * 32 + mt * 16 + g;
                af[mt][0] = As[cur][tg  ][mb];
                af[mt][1] = As[cur][tg  ][mb+8];
                af[mt][2] = As[cur][tg+4][mb];
                af[mt][3] = As[cur][tg+4][mb+8];
            }
#pragma unroll
            for (int nt = 0; nt < 8; nt++) {
                int nb = wn * 64 + nt * 8 + g;
                bf[nt][0] = Bs[cur][tg  ][nb];
                bf[nt][1] = Bs[cur][tg+4][nb];
            }
#pragma unroll
            for (int mt = 0; mt < 2; mt++)
#pragma unroll
                for (int nt = 0; nt < 8; nt++)
                    mma_bf16(acc[mt][nt], af[mt], bf[nt]);
        }
        if (more) {
            int nxt = cur ^ 1;
            As[nxt][kp0+0][r128] = bf2pack(a0.x, a0.y);
            As[nxt][kp0+1][r128] = bf2pack(a0.z, a0.w);
            As[nxt][kp0+2][r128] = bf2pack(a1.x, a1.y);
            As[nxt][kp0+3][r128] = bf2pack(a1.z, a1.w);
            Bs[nxt][kp0+0][r128] = bf2pack(b0.x, b0.y);
            Bs[nxt][kp0+1][r128] = bf2pack(b0.z, b0.w);
            Bs[nxt][kp0+2][r128] = bf2pack(b1.x, b1.y);
            Bs[nxt][kp0+3][r128] = bf2pack(b1.z, b1.w);
            __syncthreads();
            cur = nxt;
        }
    }

    float bs2[8][2], gv2[8][2];
#pragma unroll
    for (int nt = 0; nt < 8; nt++) {
        int col = bn + wn * 64 + nt * 8 + tg * 2;
        if (bias) { bs2[nt][0] = bias[col]; bs2[nt][1] = bias[col+1]; }
        else      { bs2[nt][0] = 0.f;       bs2[nt][1] = 0.f; }
        if (gate) { gv2[nt][0] = tanhf(gate[col]); gv2[nt][1] = tanhf(gate[col+1]); }
    }
#pragma unroll
    for (int mt = 0; mt < 2; mt++) {
        int row0 = bm + wm * 32 + mt * 16 + g;
#pragma unroll
        for (int nt = 0; nt < 8; nt++) {
            int col = bn + wn * 64 + nt * 8 + tg * 2;
            float v0 = acc[mt][nt][0] + bs2[nt][0];
            float v1 = acc[mt][nt][1] + bs2[nt][1];
            float v2 = acc[mt][nt][2] + bs2[nt][0];
            float v3 = acc[mt][nt][3] + bs2[nt][1];
            if (gate) {
                float2 r0 = *(const float2*)(res + (size_t)row0 * N + col);
                float2 r1 = *(const float2*)(res + (size_t)(row0+8) * N + col);
                v0 = r0.x + gv2[nt][0] * v0; v1 = r0.y + gv2[nt][1] * v1;
                v2 = r1.x + gv2[nt][0] * v2; v3 = r1.y + gv2[nt][1] * v3;
            } else if (res) {
                float2 r0 = *(const float2*)(res + (size_t)row0 * N + col);
                float2 r1 = *(const float2*)(res + (size_t)(row0+8) * N + col);
                v0 += r0.x; v1 += r0.y; v2 += r1.x; v3 += r1.y;
            }
            *(float2*)(C + (size_t)row0 * N + col)     = make_float2(v0, v1);
            *(float2*)(C + (size_t)(row0+8) * N + col) = make_float2(v2, v3);
        }
    }
}

__global__ __launch_bounds__(256, 2) void gemm_nt_kernel(
    const float* __restrict__ A, const float* __restrict__ B, float* __restrict__ C,
    const float* __restrict__ bias, const float* __restrict__ res,
    const float* __restrict__ gate)
{
    gemm_core(A, B, C, bias, res, gate, blockIdx.y * 128, blockIdx.x * 128);
}

__global__ __launch_bounds__(256, 2) void gemm3_nt_kernel(
    const float* __restrict__ A,
    const float* __restrict__ B0, const float* __restrict__ B1, const float* __restrict__ B2,
    float* __restrict__ C0, float* __restrict__ C1, float* __restrict__ C2,
    const float* __restrict__ b0, const float* __restrict__ b1, const float* __restrict__ b2)
{
    const float* B; float* C; const float* bias;
    if (blockIdx.z == 0)      { B = B0; C = C0; bias = b0; }
    else if (blockIdx.z == 1) { B = B1; C = C1; bias = b1; }
    else                      { B = B2; C = C2; bias = b2; }
    gemm_core(A, B, C, bias, nullptr, nullptr, blockIdx.y * 128, blockIdx.x * 128);
}

// ---------------- Flash attention: tf32 mma ----------------
#define ATS 72
#define APS 65
#define ASS 68
#define ATT_SMEM ((3*64*ATS + 64*APS + 64*ASS + 192) * 4)

__global__ __launch_bounds__(256) void attn_flash_kernel(
    const float* __restrict__ q, const float* __restrict__ k,
    const float* __restrict__ v, float* __restrict__ o)
{
    extern __shared__ float sm[];
    unsigned* QsT = (unsigned*)sm;
    unsigned* KsT = QsT + 64 * ATS;
    unsigned* Vs  = KsT + 64 * ATS;
    unsigned* PsT = Vs  + 64 * ATS;
    float* Ss   = (float*)(PsT + 64 * APS);
    float* smm  = Ss + 64 * ASS;
    float* sml  = smm + 64;
    float* scor = sml + 64;

    int qt = blockIdx.x, bh = blockIdx.y;
    int b = bh >> 4, h = bh & 15;
    int tid = threadIdx.x, warp = tid >> 5, lane = tid & 31;
    int wm = warp >> 1, wn = warp & 1;
    int mi = wm * 16, ng = wn * 32;
    int g = lane >> 2, tg = lane & 3;
    size_t base = ((size_t)b * Sn) * Dn + h * HDn;

    for (int idx = tid; idx < 4096; idx += 256) {
        int r = idx >> 6, e = idx & 63;
        QsT[e * ATS + r] = f2tf32(q[base + (size_t)(qt * 64 + r) * Dn + e] * 0.125f);
    }
    if (tid < 64) { smm[tid] = -1e30f; sml[tid] = 0.f; }
    float co[4][4];
#pragma unroll
    for (int nt = 0; nt < 4; nt++)
#pragma unroll
        for (int r = 0; r < 4; r++) co[nt][r] = 0.f;
    __syncthreads();

    for (int kt = 0; kt <= qt; kt++) {
        for (int idx = tid; idx < 4096; idx += 256) {
            int r = idx >> 6, e = idx & 63;
            size_t gg = base + (size_t)(kt * 64 + r) * Dn + e;
            KsT[e * ATS + r] = f2tf32(k[gg]);
            Vs [r * ATS + e] = f2tf32(v[gg]);
        }
        __syncthreads();

        float c[4][4];
#pragma unroll
        for (int nt = 0; nt < 4; nt++)
#pragma unroll
            for (int r = 0; r < 4; r++) c[nt][r] = 0.f;
#pragma unroll
        for (int kb = 0; kb < 64; kb += 8) {
            unsigned a[4];
            a[0] = QsT[(kb+tg  )*ATS + mi+g];
            a[1] = QsT[(kb+tg  )*ATS + mi+g+8];
            a[2] = QsT[(kb+tg+4)*ATS + mi+g];
            a[3] = QsT[(kb+tg+4)*ATS + mi+g+8];
#pragma unroll
            for (int nt = 0; nt < 4; nt++) {
                unsigned bb[2];
                bb[0] = KsT[(kb+tg  )*ATS + ng + nt*8 + g];
                bb[1] = KsT[(kb+tg+4)*ATS + ng + nt*8 + g];
                mma_tf32(c[nt], a, bb);
            }
        }
        bool diag = (kt == qt);
        int r0 = mi + g, r1 = mi + g + 8;
#pragma unroll
        for (int nt = 0; nt < 4; nt++) {
            int col = ng + nt * 8 + tg * 2;
            if (diag) {
                if (col   > r0) c[nt][0] = -1e30f;
                if (col+1 > r0) c[nt][1] = -1e30f;
                if (col   > r1) c[nt][2] = -1e30f;
                if (col+1 > r1) c[nt][3] = -1e30f;
            }
            Ss[r0*ASS + col]   = c[nt][0];
            Ss[r0*ASS + col+1] = c[nt][1];
            Ss[r1*ASS + col]   = c[nt][2];
            Ss[r1*ASS + col+1] = c[nt][3];
        }
        __syncthreads();

        for (int i = warp; i < 64; i += 8) {
            float s0 = Ss[i*ASS + lane], s1 = Ss[i*ASS + lane + 32];
            float mx = warpmax(fmaxf(s0, s1));
            float nm = fmaxf(smm[i], mx);
            float corr = __expf(smm[i] - nm);
            float p0 = __expf(s0 - nm), p1 = __expf(s1 - nm);
            float ps = warpsum(p0 + p1);
            if (lane == 0) { sml[i] = sml[i] * corr + ps; smm[i] = nm; scor[i] = corr; }
            PsT[lane*APS + i]      = f2tf32(p0);
            PsT[(lane+32)*APS + i] = f2tf32(p1);
        }
        __syncthreads();

        float cr0 = scor[r0], cr1 = scor[r1];
#pragma unroll
        for (int nt = 0; nt < 4; nt++) {
            co[nt][0] *= cr0; co[nt][1] *= cr0;
            co[nt][2] *= cr1; co[nt][3] *= cr1;
        }
#pragma unroll
        for (int kb = 0; kb < 64; kb += 8) {
            unsigned a[4];
            a[0] = PsT[(kb+tg  )*APS + mi+g];
            a[1] = PsT[(kb+tg  )*APS + mi+g+8];
            a[2] = PsT[(kb+tg+4)*APS + mi+g];
            a[3] = PsT[(kb+tg+4)*APS + mi+g+8];
#pragma unroll
            for (int nt = 0; nt < 4; nt++) {
                unsigned bb[2];
                bb[0] = Vs[(kb+tg  )*ATS + ng + nt*8 + g];
                bb[1] = Vs[(kb+tg+4)*ATS + ng + nt*8 + g];
                mma_tf32(co[nt], a, bb);
            }
        }
        __syncthreads();
    }

    int r0 = mi + g, r1 = mi + g + 8;
    float inv0 = __fdividef(1.f, sml[r0]);
    float inv1 = __fdividef(1.f, sml[r1]);
#pragma unroll
    for (int nt = 0; nt < 4; nt++) {
        int col = ng + nt * 8 + tg * 2;
        *(float2*)(o + base + (size_t)(qt*64 + r0) * Dn + col) =
            make_float2(co[nt][0]*inv0, co[nt][1]*inv0);
        *(float2*)(o + base + (size_t)(qt*64 + r1) * Dn + col) =
            make_float2(co[nt][2]*inv1, co[nt][3]*inv1);
    }
}

// ---------------- prep & lr ----------------
__global__ __launch_bounds__(256) void prep_kernel(
    float* __restrict__ XQ, float* __restrict__ XK, float* __restrict__ XV,
    const float* __restrict__ nw, const float* __restrict__ nb)
{
    int w = (blockIdx.x * blockDim.x + threadIdx.x) >> 5;
    if (w >= Bn * Sn * Hn) return;
    int lane = threadIdx.x & 31;
    int h = w & 15, bs = w >> 4;
    size_t base = (size_t)bs * Dn + h * HDn;
    float q0 = XQ[base + lane], q1 = XQ[base + lane + 32];
    float qi = 1.f / fmaxf(sqrtf(warpsum(q0*q0 + q1*q1)), 1e-12f);
    XQ[base + lane] = q0 * qi; XQ[base + lane + 32] = q1 * qi;
    float k0 = XK[base + lane], k1 = XK[base + lane + 32];
    float ki = 1.f / fmaxf(sqrtf(warpsum(k0*k0 + k1*k1)), 1e-12f);
    k0 *= ki; k1 *= ki;
    XK[base + lane] = k0; XK[base + lane + 32] = k1;
    float v0 = XV[base + lane], v1 = XV[base + lane + 32];
    float mu = warpsum(v0 + v1) * (1.f / 64.f);
    float d0 = v0 - mu, d1 = v1 - mu;
    float var = warpsum(d0*d0 + d1*d1) * (1.f / 64.f);
    float rstd = rsqrtf(var + EPSc);
    XV[base + lane]      = nw[h*64+lane]    * d0 * rstd + nb[h*64+lane]    + k0;
    XV[base + lane + 32] = nw[h*64+lane+32] * d1 * rstd + nb[h*64+lane+32] + k1;
}

__global__ __launch_bounds__(256) void lr_kernel(
    const float* __restrict__ x1, const float* __restrict__ lrw,
    const float* __restrict__ lrb, float* __restrict__ lro)
{
    int w = (blockIdx.x * blockDim.x + threadIdx.x) >> 5;
    if (w >= Bn * Sn * Hn) return;
    int lane = threadIdx.x & 31;
    int h = w & 15, bs = w >> 4;
    int b = bs >> 10, s = bs & (Sn - 1);
    const float* xr = x1 + (size_t)bs * Dn;
    const float* wr = lrw + h * Dn;
    float acc = 0.f;
    for (int c = lane; c < Dn; c += 32) acc += xr[c] * wr[c];
    acc = warpsum(acc);
    if (lane == 0)
        lro[(size_t)(b * Hn + h) * Sn + s] = 1.f / (1.f + __expf(-(acc + lrb[h])));
}

// ---------------- TTT scan: bf16 mma A/B/D/E/F/G/H ------------
#define SV 65
#define PS 68
#define TS 68
#define WS 260
#define SCAN_FLOATS (64*SV + 2*64*PS + 4*64*TS + 16*WS + 64*WS + 256 + 64 + 64)
#define SCAN_SMEM (SCAN_FLOATS * 4)

__global__ __launch_bounds__(512) void ttt_scan_kernel(
    const float* __restrict__ XQ, const float* __restrict__ XK, const float* __restrict__ XV,
    const float* __restrict__ lr,
    const float* __restrict__ W1i, const float* __restrict__ b1i,
    const float* __restrict__ W2i, const float* __restrict__ b2i,
    const float* __restrict__ nw,  const float* __restrict__ nb,
    float* __restrict__ W2TG,
    float* __restrict__ X2G, float* __restrict__ gZ1G, float* __restrict__ X2bG,
    float* __restrict__ outp)
{
    extern __shared__ float sm[];
    float* sxv   = sm;
    float* ssc   = sxv  + 64 * SV;
    float* sgZ2  = ssc  + 64 * PS;
    float* sxqT  = sgZ2 + 64 * PS;
    float* sxkT  = sxqT + 64 * TS;
    float* sscT  = sxkT + 64 * TS;
    float* sgZ2T = sscT + 64 * TS;
    float* sstg  = sgZ2T+ 64 * TS;
    float* sW1   = sstg + 16 * WS;
    float* b1sm  = sW1  + 64 * WS;
    float* b2sm  = b1sm + 256;
    float* seta  = b2sm + 64;

    int bh = blockIdx.x, b = bh >> 4, h = bh & 15;
    int tid = threadIdx.x, w = tid >> 5, l = tid & 31;
    int g = l >> 2, tg = l & 3;
    int ft = tid >> 3, jt = tid & 7;
    int mi = (w & 3) * 16, ng = (w >> 2) * 64;
    int wm3 = w & 3, wn3 = w >> 2;
    int mi3 = wm3 * 16, nb3 = wn3 * 16;
    float* W2Tr = W2TG + (size_t)bh * 16384;
    float* X2r  = X2G  + (size_t)bh * 16384;
    float* gZ1r = gZ1G + (size_t)bh * 16384;
    float* X2br = X2bG + (size_t)bh * 16384;
    const float* nwh = nw + h * 64;
    const float* nbh = nb + h * 64;

    for (int idx = tid; idx < 16384; idx += 512) {
        int e = idx >> 8, f = idx & 255;
        sW1[e * WS + f] = W1i[(size_t)h * 16384 + idx];
        W2Tr[idx] = W2i[(size_t)h * 16384 + f * 64 + e];
    }
    if (tid < 256) b1sm[tid] = b1i[h * 256 + tid];
    if (tid < 64)  b2sm[tid] = b2i[h * 64 + tid];
    __syncthreads();

    for (int n = 0; n < NCn; n++) {
        size_t tokbase = (size_t)b * Sn + n * Cn;
        for (int idx = tid; idx < 4096; idx += 512) {
            int i = idx >> 6, e = idx & 63;
            size_t gg = (tokbase + i) * Dn + h * 64 + e;
            sxqT[e * TS + i] = XQ[gg];
            sxkT[e * TS + i] = XK[gg];
            sxv [i * SV + e] = XV[gg];
        }
        if (tid < 64) seta[tid] = lr[(size_t)bh * Sn + n * 64 + tid] * (1.f / 64.f);
        __syncthreads();

        // ---- A (bf16 mma, 2 passes): Z1=xk@W1+b1 ; Z1q=xq@W1+b1
#pragma unroll
        for (int p = 0; p < 2; p++) {
            const float* T = p ? sxqT : sxkT;
            float c[8][4];
#pragma unroll
            for (int nt = 0; nt < 8; nt++) {
                int col = ng + nt * 8 + tg * 2;
                c[nt][0] = b1sm[col];   c[nt][1] = b1sm[col+1];
                c[nt][2] = b1sm[col];   c[nt][3] = b1sm[col+1];
            }
#pragma unroll
            for (int kb = 0; kb < 64; kb += 16) {
                int k0 = kb + 2 * tg;
                unsigned a[4];
                a[0] = bf2pack(T[k0*TS + mi+g],       T[(k0+1)*TS + mi+g]);
                a[1] = bf2pack(T[k0*TS + mi+g+8],     T[(k0+1)*TS + mi+g+8]);
                a[2] = bf2pack(T[(k0+8)*TS + mi+g],   T[(k0+9)*TS + mi+g]);
                a[3] = bf2pack(T[(k0+8)*TS + mi+g+8], T[(k0+9)*TS + mi+g+8]);
#pragma unroll
                for (int nt = 0; nt < 8; nt++) {
                    int col = ng + nt * 8 + g;
                    unsigned bb[2];
                    bb[0] = bf2pack(sW1[k0*WS + col],     sW1[(k0+1)*WS + col]);
                    bb[1] = bf2pack(sW1[(k0+8)*WS + col], sW1[(k0+9)*WS + col]);
                    mma_bf16(c[nt], a, bb);
                }
            }
#pragma unroll
            for (int nt = 0; nt < 8; nt++) {
                int col = ng + nt * 8 + tg * 2;
                int r0 = mi + g;
                if (p == 0) {
                    float x2o[4], gbo[4];
#pragma unroll
                    for (int r = 0; r < 4; r++) {
                        float z = c[nt][r];
                        float t = tanh_fast(0.79788456f * (z + 0.044715f * z * z * z));
                        x2o[r] = 0.5f * z * (1.f + t);
                        gbo[r] = 0.5f * z * (1.f - t * t) * (0.79788456f + 0.1070322243f * z * z)
                               + 0.5f * (1.f + t);
                    }
                    *(float2*)(X2r  + r0*256 + col)     = make_float2(x2o[0], x2o[1]);
                    *(float2*)(X2r  + (r0+8)*256 + col) = make_float2(x2o[2], x2o[3]);
                    *(float2*)(gZ1r + r0*256 + col)     = make_float2(gbo[0], gbo[1]);
                    *(float2*)(gZ1r + (r0+8)*256 + col) = make_float2(gbo[2], gbo[3]);
                } else {
                    *(float2*)(X2br + r0*256 + col)     = make_float2(c[nt][0], c[nt][1]);
                    *(float2*)(X2br + (r0+8)*256 + col) = make_float2(c[nt][2], c[nt][3]);
                }
            }
        }
        __syncthreads();

        // ---- B (bf16 mma): Z2 = X2@W2 + b2 -> ssc  (A=X2r, B=W2Tr)
        {
            float c[2][4];
#pragma unroll
            for (int nt = 0; nt < 2; nt++) {
                int col = nb3 + nt * 8 + tg * 2;
                c[nt][0] = b2sm[col]; c[nt][1] = b2sm[col+1];
                c[nt][2] = b2sm[col]; c[nt][3] = b2sm[col+1];
            }
#pragma unroll 4
            for (int kb = 0; kb < 256; kb += 16) {
                const float* xa = X2r + (mi3+g)*256 + kb + 2*tg;
                float2 v0 = *(const float2*)(xa);
                float2 v1 = *(const float2*)(xa + 2048);
                float2 v2 = *(const float2*)(xa + 8);
                float2 v3 = *(const float2*)(xa + 2056);
                unsigned a[4] = { bf2pack(v0.x,v0.y), bf2pack(v1.x,v1.y),
                                  bf2pack(v2.x,v2.y), bf2pack(v3.x,v3.y) };
#pragma unroll
                for (int nt = 0; nt < 2; nt++) {
                    int col = nb3 + nt * 8 + g;
                    float2 w0 = *(const float2*)(W2Tr + col*256 + kb + 2*tg);
                    float2 w1 = *(const float2*)(W2Tr + col*256 + kb + 8 + 2*tg);
                    unsigned bb[2] = { bf2pack(w0.x,w0.y), bf2pack(w1.x,w1.y) };
                    mma_bf16(c[nt], a, bb);
                }
            }
#pragma unroll
            for (int nt = 0; nt < 2; nt++) {
                int col = nb3 + nt * 8 + tg * 2;
                int r0 = mi3 + g;
                ssc[r0*PS + col]       = c[nt][0];
                ssc[r0*PS + col+1]     = c[nt][1];
                ssc[(r0+8)*PS + col]   = c[nt][2];
                ssc[(r0+8)*PS + col+1] = c[nt][3];
            }
        }
        __syncthreads();

        // ---- C: gZ2 = ln_l2_bwd -> sgZ2 + sgZ2T
        for (int i = w; i < 64; i += 16) {
            float z0 = ssc[i*PS + l], z1 = ssc[i*PS + l + 32];
            float mu = warpsum(z0 + z1) * (1.f/64.f);
            float d0 = z0 - mu, d1 = z1 - mu;
            float var = warpsum(d0*d0 + d1*d1) * (1.f/64.f);
            float rstd = rsqrtf(var + EPSc);
            float xh0 = d0 * rstd, xh1 = d1 * rstd;
            float g0 = nwh[l], g1 = nwh[l+32];
            float t0 = sxv[i*SV + l]      - sxkT[l*TS + i];
            float t1 = sxv[i*SV + l + 32] - sxkT[(l+32)*TS + i];
            float gh0 = (g0*xh0 + nbh[l]    - t0) * g0;
            float gh1 = (g1*xh1 + nbh[l+32] - t1) * g1;
            float sgh = warpsum(gh0 + gh1);
            float sgx = warpsum(gh0*xh0 + gh1*xh1);
            float cc = rstd * (1.f/64.f);
            float o0 = (64.f*gh0 - sgh - xh0*sgx) * cc;
            float o1 = (64.f*gh1 - sgh - xh1*sgx) * cc;
            sgZ2[i*PS + l]        = o0;
            sgZ2[i*PS + l + 32]   = o1;
            sgZ2T[l*TS + i]       = o0;
            sgZ2T[(l+32)*TS + i]  = o1;
        }
        __syncthreads();

        // ---- D (bf16 mma): gZ1 = (gZ2 @ W2^T) * gb   (16-row staging)
        {
            float c[8][4];
#pragma unroll
            for (int nt = 0; nt < 8; nt++)
#pragma unroll
                for (int r = 0; r < 4; r++) c[nt][r] = 0.f;
#pragma unroll
            for (int kbb = 0; kbb < 64; kbb += 16) {
                __syncthreads();
                for (int idx = tid; idx < 4096; idx += 512) {
                    int rr = idx >> 8, cf = idx & 255;
                    sstg[rr*WS + cf] = W2Tr[(kbb+rr)*256 + cf];
                }
                __syncthreads();
                int k0 = 2 * tg;
                unsigned a[4];
                a[0] = bf2pack(sgZ2T[(kbb+k0)*TS + mi+g],     sgZ2T[(kbb+k0+1)*TS + mi+g]);
                a[1] = bf2pack(sgZ2T[(kbb+k0)*TS + mi+g+8],   sgZ2T[(kbb+k0+1)*TS + mi+g+8]);
                a[2] = bf2pack(sgZ2T[(kbb+k0+8)*TS + mi+g],   sgZ2T[(kbb+k0+9)*TS + mi+g]);
                a[3] = bf2pack(sgZ2T[(kbb+k0+8)*TS + mi+g+8], sgZ2T[(kbb+k0+9)*TS + mi+g+8]);
#pragma unroll
                for (int nt = 0; nt < 8; nt++) {
                    int col = ng + nt * 8 + g;
                    unsigned bb[2];
                    bb[0] = bf2pack(sstg[k0*WS + col],     sstg[(k0+1)*WS + col]);
                    bb[1] = bf2pack(sstg[(k0+8)*WS + col], sstg[(k0+9)*WS + col]);
                    mma_bf16(c[nt], a, bb);
                }
            }
#pragma unroll
            for (int nt = 0; nt < 8; nt++) {
                int col = ng + nt * 8 + tg * 2;
                int r0 = mi + g;
                float2 gb0 = *(const float2*)(gZ1r + r0*256 + col);
                float2 gb1 = *(const float2*)(gZ1r + (r0+8)*256 + col);
                *(float2*)(gZ1r + r0*256 + col)     = make_float2(c[nt][0]*gb0.x, c[nt][1]*gb0.y);
                *(float2*)(gZ1r + (r0+8)*256 + col) = make_float2(c[nt][2]*gb1.x, c[nt][3]*gb1.y);
            }
        }
        __syncthreads();

        // ---- E (bf16 mma): coef1 = -eta[k2]*(tril(xq@xk^T)+1) -> sscT
#pragma unroll
        for (int sub = 0; sub < 2; sub++) {
            int ncol = ((w >> 2) * 2 + sub) * 8;
            float c[4] = {0.f, 0.f, 0.f, 0.f};
#pragma unroll
            for (int kb = 0; kb < 64; kb += 16) {
                int k0 = kb + 2 * tg;
                unsigned a[4], bb[2];
                a[0] = bf2pack(sxqT[k0*TS + mi+g],       sxqT[(k0+1)*TS + mi+g]);
                a[1] = bf2pack(sxqT[k0*TS + mi+g+8],     sxqT[(k0+1)*TS + mi+g+8]);
                a[2] = bf2pack(sxqT[(k0+8)*TS + mi+g],   sxqT[(k0+9)*TS + mi+g]);
                a[3] = bf2pack(sxqT[(k0+8)*TS + mi+g+8], sxqT[(k0+9)*TS + mi+g+8]);
                bb[0] = bf2pack(sxkT[k0*TS + ncol+g],     sxkT[(k0+1)*TS + ncol+g]);
                bb[1] = bf2pack(sxkT[(k0+8)*TS + ncol+g], sxkT[(k0+9)*TS + ncol+g]);
                mma_bf16(c, a, bb);
            }
            int r0 = mi + g, k2 = ncol + tg * 2;
            sscT[k2*TS + r0]       = (k2   <= r0)   ? -seta[k2]  *(c[0]+1.f) : 0.f;
            sscT[(k2+1)*TS + r0]   = (k2+1 <= r0)   ? -seta[k2+1]*(c[1]+1.f) : 0.f;
            sscT[k2*TS + r0+8]     = (k2   <= r0+8) ? -seta[k2]  *(c[2]+1.f) : 0.f;
            sscT[(k2+1)*TS + r0+8] = (k2+1 <= r0+8) ? -seta[k2+1]*(c[3]+1.f) : 0.f;
        }
        __syncthreads();

        // ---- F (bf16 mma): Z1b = Z1q + coef1neg@gZ1 ; X2b = gelu
        {
            float c[8][4];
#pragma unroll
            for (int nt = 0; nt < 8; nt++) {
                int col = ng + nt * 8 + tg * 2;
                int r0 = mi + g;
                float2 q0 = *(const float2*)(X2br + r0*256 + col);
                float2 q1 = *(const float2*)(X2br + (r0+8)*256 + col);
                c[nt][0] = q0.x; c[nt][1] = q0.y; c[nt][2] = q1.x; c[nt][3] = q1.y;
            }
#pragma unroll
            for (int kbb = 0; kbb < 64; kbb += 16) {
                __syncthreads();
                for (int idx = tid; idx < 4096; idx += 512) {
                    int rr = idx >> 8, cf = idx & 255;
                    sstg[rr*WS + cf] = gZ1r[(kbb+rr)*256 + cf];
                }
                __syncthreads();
                int k0 = 2 * tg;
                unsigned a[4];
                a[0] = bf2pack(sscT[(kbb+k0)*TS + mi+g],     sscT[(kbb+k0+1)*TS + mi+g]);
                a[1] = bf2pack(sscT[(kbb+k0)*TS + mi+g+8],   sscT[(kbb+k0+1)*TS + mi+g+8]);
                a[2] = bf2pack(sscT[(kbb+k0+8)*TS + mi+g],   sscT[(kbb+k0+9)*TS + mi+g]);
                a[3] = bf2pack(sscT[(kbb+k0+8)*TS + mi+g+8], sscT[(kbb+k0+9)*TS + mi+g+8]);
#pragma unroll
                for (int nt = 0; nt < 8; nt++) {
                    int col = ng + nt * 8 + g;
                    unsigned bb[2];
                    bb[0] = bf2pack(sstg[k0*WS + col],     sstg[(k0+1)*WS + col]);
                    bb[1] = bf2pack(sstg[(k0+8)*WS + col], sstg[(k0+9)*WS + col]);
                    mma_bf16(c[nt], a, bb);
                }
            }
#pragma unroll
            for (int nt = 0; nt < 8; nt++) {
                int col = ng + nt * 8 + tg * 2;
                int r0 = mi + g;
                float xo[4];
#pragma unroll
                for (int r = 0; r < 4; r++) {
                    float z = c[nt][r];
                    float t = tanh_fast(0.79788456f * (z + 0.044715f * z * z * z));
                    xo[r] = 0.5f * z * (1.f + t);
                }
                *(float2*)(X2br + r0*256 + col)     = make_float2(xo[0], xo[1]);
                *(float2*)(X2br + (r0+8)*256 + col) = make_float2(xo[2], xo[3]);
            }
        }
        __syncthreads();

        // ---- G (bf16 mma): coef2neg = -eta[j]*(tril(X2b@X2^T)+1) -> ssc [i][j]
        {
            float c[2][4] = {{0.f,0.f,0.f,0.f},{0.f,0.f,0.f,0.f}};
            if (nb3 <= mi3) {
#pragma unroll 4
                for (int kb = 0; kb < 256; kb += 16) {
                    const float* xa = X2br + (mi3+g)*256 + kb + 2*tg;
                    float2 v0 = *(const float2*)(xa);
                    float2 v1 = *(const float2*)(xa + 2048);
                    float2 v2 = *(const float2*)(xa + 8);
                    float2 v3 = *(const float2*)(xa + 2056);
                    unsigned a[4] = { bf2pack(v0.x,v0.y), bf2pack(v1.x,v1.y),
                                      bf2pack(v2.x,v2.y), bf2pack(v3.x,v3.y) };
#pragma unroll
                    for (int nt = 0; nt < 2; nt++) {
                        int col = nb3 + nt * 8 + g;
                        const float* xb = X2r + col*256 + kb + 2*tg;
                        float2 w0 = *(const float2*)(xb);
                        float2 w1 = *(const float2*)(xb + 8);
                        unsigned bb[2] = { bf2pack(w0.x,w0.y), bf2pack(w1.x,w1.y) };
                        mma_bf16(c[nt], a, bb);
                    }
                }
            }
#pragma unroll
            for (int nt = 0; nt < 2; nt++) {
                int col = nb3 + nt * 8 + tg * 2;
                int r0 = mi3 + g, r1 = mi3 + g + 8;
                ssc[r0*PS + col]     = (col   <= r0) ? -seta[col]  *(c[nt][0]+1.f) : 0.f;
                ssc[r0*PS + col+1]   = (col+1 <= r0) ? -seta[col+1]*(c[nt][1]+1.f) : 0.f;
                ssc[r1*PS + col]     = (col   <= r1) ? -seta[col]  *(c[nt][2]+1.f) : 0.f;
                ssc[r1*PS + col+1]   = (col+1 <= r1) ? -seta[col+1]*(c[nt][3]+1.f) : 0.f;
            }
        }
        __syncthreads();

        // ---- H (bf16 mma): Z2b = X2b@W2 + b2 + coef2neg@gZ2 -> sxv
        {
            float c[2][4];
#pragma unroll
            for (int nt = 0; nt < 2; nt++) {
                int col = nb3 + nt * 8 + tg * 2;
                c[nt][0] = b2sm[col]; c[nt][1] = b2sm[col+1];
                c[nt][2] = b2sm[col]; c[nt][3] = b2sm[col+1];
            }
#pragma unroll 4
            for (int kb = 0; kb < 256; kb += 16) {
                const float* xa = X2br + (mi3+g)*256 + kb + 2*tg;
                float2 v0 = *(const float2*)(xa);
                float2 v1 = *(const float2*)(xa + 2048);
                float2 v2 = *(const float2*)(xa + 8);
                float2 v3 = *(const float2*)(xa + 2056);
                unsigned a[4] = { bf2pack(v0.x,v0.y), bf2pack(v1.x,v1.y),
                                  bf2pack(v2.x,v2.y), bf2pack(v3.x,v3.y) };
#pragma unroll
                for (int nt = 0; nt < 2; nt++) {
                    int col = nb3 + nt * 8 + g;
                    float2 w0 = *(const float2*)(W2Tr + col*256 + kb + 2*tg);
                    float2 w1 = *(const float2*)(W2Tr + col*256 + kb + 8 + 2*tg);
                    unsigned bb[2] = { bf2pack(w0.x,w0.y), bf2pack(w1.x,w1.y) };
                    mma_bf16(c[nt], a, bb);
                }
            }
#pragma unroll
            for (int kb = 0; kb < 64; kb += 16) {
                int k0 = kb + 2 * tg;
                unsigned a[4];
                a[0] = bf2pack(ssc[(mi3+g)*PS + k0],     ssc[(mi3+g)*PS + k0+1]);
                a[1] = bf2pack(ssc[(mi3+g+8)*PS + k0],   ssc[(mi3+g+8)*PS + k0+1]);
                a[2] = bf2pack(ssc[(mi3+g)*PS + k0+8],   ssc[(mi3+g)*PS + k0+9]);
                a[3] = bf2pack(ssc[(mi3+g+8)*PS + k0+8], ssc[(mi3+g+8)*PS + k0+9]);
#pragma unroll
                for (int nt = 0; nt < 2; nt++) {
                    int col = nb3 + nt * 8 + g;
                    unsigned bb[2];
                    bb[0] = bf2pack(sgZ2T[col*TS + k0],   sgZ2T[col*TS + k0+1]);
                    bb[1] = bf2pack(sgZ2T[col*TS + k0+8], sgZ2T[col*TS + k0+9]);
                    mma_bf16(c[nt], a, bb);
                }
            }
#pragma unroll
            for (int nt = 0; nt < 2; nt++) {
                int col = nb3 + nt * 8 + tg * 2;
                int r0 = mi3 + g;
                sxv[r0*SV + col]       = c[nt][0];
                sxv[r0*SV + col+1]     = c[nt][1];
                sxv[(r0+8)*SV + col]   = c[nt][2];
                sxv[(r0+8)*SV + col+1] = c[nt][3];
            }
        }
        __syncthreads();

        // ---- I: out = xq + LN(Z2b)
        for (int i = w; i < 64; i += 16) {
            float z0 = sxv[i*SV + l], z1 = sxv[i*SV + l + 32];
            float mu = warpsum(z0 + z1) * (1.f/64.f);
            float d0 = z0 - mu, d1 = z1 - mu;
            float var = warpsum(d0*d0 + d1*d1) * (1.f/64.f);
            float rstd = rsqrtf(var + EPSc);
            size_t gg = (tokbase + i) * Dn + h * 64;
            outp[gg + l]      = sxqT[l*TS + i]      + nwh[l]    * d0 * rstd + nbh[l];
            outp[gg + l + 32] = sxqT[(l+32)*TS + i] + nwh[l+32] * d1 * rstd + nbh[l+32];
        }

        // ---- J1: W1 -= (eta*xk)^T @ gZ1  (sW1 smem)
        {
            u64 acc2[4][4];
#pragma unroll
            for (int u = 0; u < 4; u++)
#pragma unroll
                for (int p = 0; p < 4; p++) acc2[u][p] = 0ULL;
#pragma unroll 4
            for (int i = 0; i < 64; i++) {
                float et = seta[i];
                float4 g0 = *(const float4*)(gZ1r + i*256 + l*8);
                float4 g1 = *(const float4*)(gZ1r + i*256 + l*8 + 4);
                u64 gv2[4];
                f4tou2(g0, gv2[0], gv2[1]); f4tou2(g1, gv2[2], gv2[3]);
#pragma unroll
                for (int u = 0; u < 4; u++) {
                    float a = et * sxkT[(w*4+u)*TS + i];
                    u64 a2 = f2pack(a, a);
#pragma unroll
                    for (int p = 0; p < 4; p++) acc2[u][p] = ffma2(a2, gv2[p], acc2[u][p]);
                }
            }
#pragma unroll
            for (int u = 0; u < 4; u++) {
                int e = w * 4 + u;
                float av[8];
#pragma unroll
                for (int p = 0; p < 4; p++) f2unpack(acc2[u][p], av[2*p], av[2*p+1]);
                float4* wp = (float4*)(sW1 + e*WS + l*8);
                float4 o0 = wp[0], o1 = wp[1];
                wp[0] = make_float4(o0.x-av[0], o0.y-av[1], o0.z-av[2], o0.w-av[3]);
                wp[1] = make_float4(o1.x-av[4], o1.y-av[5], o1.z-av[6], o1.w-av[7]);
            }
        }
        // J2: b1
        if (tid < 256) {
            float acc = 0.f;
#pragma unroll 8
            for (int i = 0; i < 64; i++) acc += seta[i] * gZ1r[i*256 + tid];
            b1sm[tid] -= acc;
        }
        // J3: W2T (global)
        {
            u64 acc2[4][4];
#pragma unroll
            for (int u = 0; u < 4; u++)
#pragma unroll
                for (int p = 0; p < 4; p++) acc2[u][p] = 0ULL;
#pragma unroll 4
            for (int i = 0; i < 64; i++) {
                float et = seta[i];
                float4 x0 = *(const float4*)(X2r + i*256 + ft*4);
                float4 gv0 = *(const float4*)(sgZ2 + i*PS + jt*8);
                float4 gv1 = *(const float4*)(sgZ2 + i*PS + jt*8 + 4);
                u64 gv2[4];
                f4tou2(gv0, gv2[0], gv2[1]); f4tou2(gv1, gv2[2], gv2[3]);
                float a[4] = {et*x0.x, et*x0.y, et*x0.z, et*x0.w};
#pragma unroll
                for (int u = 0; u < 4; u++) {
                    u64 a2 = f2pack(a[u], a[u]);
#pragma unroll
                    for (int p = 0; p < 4; p++) acc2[u][p] = ffma2(a2, gv2[p], acc2[u][p]);
                }
            }
#pragma unroll
            for (int u = 0; u < 4; u++) {
                int f = ft * 4 + u;
                float av[8];
#pragma unroll
                for (int p = 0; p < 4; p++) f2unpack(acc2[u][p], av[2*p], av[2*p+1]);
#pragma unroll
                for (int v = 0; v < 8; v++)
                    W2Tr[(jt*8+v)*256 + f] -= av[v];
            }
        }
        // J4: b2
        if (tid < 64) {
            float acc = 0.f;
#pragma unroll 8
            for (int i = 0; i < 64; i++) acc += seta[i] * sgZ2[i*PS + tid];
            b2sm[tid] -= acc;
        }
        __syncthreads();
    }
}

// ---------------- Launch ----------------
extern "C" void kernel_launch(void* const* d_in, const int* in_sizes, int n_in,
                              void* d_out, int out_size)
{
    const float* x       = (const float*)d_in[0];
    const float* ln1_w   = (const float*)d_in[1];
    const float* ln1_b   = (const float*)d_in[2];
    const float* attn_wq = (const float*)d_in[3];
    const float* attn_wk = (const float*)d_in[4];
    const float* attn_wv = (const float*)d_in[5];
    const float* attn_wo = (const float*)d_in[6];
    const float* wq_w    = (const float*)d_in[7];
    const float* wq_b    = (const float*)d_in[8];
    const float* wk_w    = (const float*)d_in[9];
    const float* wk_b    = (const float*)d_in[10];
    const float* wv_w    = (const float*)d_in[11];
    const float* wv_b    = (const float*)d_in[12];
    const float* wo_w    = (const float*)d_in[13];
    const float* wo_b    = (const float*)d_in[14];
    const float* W1      = (const float*)d_in[15];
    const float* b1      = (const float*)d_in[16];
    const float* W2      = (const float*)d_in[17];
    const float* b2      = (const float*)d_in[18];
    const float* ttt_nw  = (const float*)d_in[19];
    const float* ttt_nb  = (const float*)d_in[20];
    const float* lr_w    = (const float*)d_in[21];
    const float* lr_b    = (const float*)d_in[22];
    const float* pn_w    = (const float*)d_in[23];
    const float* pn_b    = (const float*)d_in[24];
    const float* gate_a  = (const float*)d_in[25];
    float* out = (float*)d_out;

    float *p_h,*p_q,*p_k,*p_v,*p_o,*p_x1,*p_lr,*p_W2T,*p_X2,*p_gZ1,*p_X2b;
    cudaGetSymbolAddress((void**)&p_h,  g_h);
    cudaGetSymbolAddress((void**)&p_q,  g_q);
    cudaGetSymbolAddress((void**)&p_k,  g_k);
    cudaGetSymbolAddress((void**)&p_v,  g_v);
    cudaGetSymbolAddress((void**)&p_o,  g_o);
    cudaGetSymbolAddress((void**)&p_x1, g_x1);
    cudaGetSymbolAddress((void**)&p_lr, g_lr);
    cudaGetSymbolAddress((void**)&p_W2T,g_W2Ts);
    cudaGetSymbolAddress((void**)&p_X2, g_X2);
    cudaGetSymbolAddress((void**)&p_gZ1,g_gZ1);
    cudaGetSymbolAddress((void**)&p_X2b,g_X2b);

    cudaFuncSetAttribute(ttt_scan_kernel,   cudaFuncAttributeMaxDynamicSharedMemorySize, SCAN_SMEM);
    cudaFuncSetAttribute(attn_flash_kernel, cudaFuncAttributeMaxDynamicSharedMemorySize, ATT_SMEM);

    const int M = Bn * Sn;
    dim3 ggrid(Dn / 128, M / 128);
    dim3 ggrid3(Dn / 128, M / 128, 3);
    int nwarp_grid = (Bn * Sn * Hn) / 8;

    ln_kernel<<<M, 256>>>(x, ln1_w, ln1_b, p_h);
    gemm3_nt_kernel<<<ggrid3, 256>>>(p_h, attn_wq, attn_wk, attn_wv,
                                     p_q, p_k, p_v, nullptr, nullptr, nullptr);
    attn_flash_kernel<<<dim3(16, 64), 256, ATT_SMEM>>>(p_q, p_k, p_v, p_o);
    gemm_nt_kernel<<<ggrid, 256>>>(p_o, attn_wo, p_x1, nullptr, x, nullptr);
    gemm3_nt_kernel<<<ggrid3, 256>>>(p_x1, wq_w, wk_w, wv_w,
                                     p_q, p_k, p_v, wq_b, wk_b, wv_b);
    prep_kernel<<<nwarp_grid, 256>>>(p_q, p_k, p_v, ttt_nw, ttt_nb);
    lr_kernel<<<nwarp_grid, 256>>>(p_x1, lr_w, lr_b, p_lr);
    ttt_scan_kernel<<<Bn * Hn, 512, SCAN_SMEM>>>(
        p_q, p_k, p_v, p_lr, W1, b1, W2, b2, ttt_nw, ttt_nb,
        p_W2T, p_X2, p_gZ1, p_X2b, p_o);
    ln_kernel<<<M, 256>>>(p_o, pn_w, pn_b, p_h);
    gemm_nt_kernel<<<ggrid, 256>>>(p_h, wo_w, out, wo_b, p_x1, gate_a);
}

// round 17
// speedup vs baseline: 2.5865x; 1.0226x over previous
#include <cuda_runtime.h>
#include <math.h>

#define Bn 4
#define Sn 1024
#define Dn 1024
#define Hn 16
#define HDn 64
#define Cn 64
#define NCn 16
#define DFFn 256
#define EPSc 1e-6f
#define BSD (Bn*Sn*Dn)

typedef unsigned long long u64;
__device__ __forceinline__ u64 f2pack(float lo, float hi) {
    u64 r; asm("mov.b64 %0, {%1, %2};" : "=l"(r) : "f"(lo), "f"(hi)); return r;
}
__device__ __forceinline__ void f2unpack(u64 p, float& lo, float& hi) {
    asm("mov.b64 {%0, %1}, %2;" : "=f"(lo), "=f"(hi) : "l"(p));
}
__device__ __forceinline__ u64 ffma2(u64 a, u64 b, u64 c) {
    u64 d; asm("fma.rn.f32x2 %0, %1, %2, %3;" : "=l"(d) : "l"(a), "l"(b), "l"(c)); return d;
}
__device__ __forceinline__ void f4tou2(float4 f, u64& p0, u64& p1) {
    p0 = f2pack(f.x, f.y); p1 = f2pack(f.z, f.w);
}
__device__ __forceinline__ unsigned bf2pack(float lo, float hi) {
    unsigned r; asm("cvt.rn.bf16x2.f32 %0, %1, %2;" : "=r"(r) : "f"(hi), "f"(lo)); return r;
}
__device__ __forceinline__ void mma_bf16(float* c, const unsigned* a, const unsigned* b) {
    asm volatile("mma.sync.aligned.m16n8k16.row.col.f32.bf16.bf16.f32 "
        "{%0,%1,%2,%3}, {%4,%5,%6,%7}, {%8,%9}, {%0,%1,%2,%3};"
        : "+f"(c[0]), "+f"(c[1]), "+f"(c[2]), "+f"(c[3])
        : "r"(a[0]), "r"(a[1]), "r"(a[2]), "r"(a[3]), "r"(b[0]), "r"(b[1]));
}

__device__ float g_h [BSD];
__device__ float g_q [BSD];
__device__ float g_k [BSD];
__device__ float g_v [BSD];
__device__ float g_o [BSD];
__device__ float g_x1[BSD];
__device__ float g_lr[Bn*Hn*Sn];
__device__ float g_W2Ts[Bn*Hn*16384];
__device__ float g_X2  [Bn*Hn*16384];
__device__ float g_gZ1 [Bn*Hn*16384];
__device__ float g_X2b [Bn*Hn*16384];

__device__ __forceinline__ float warpsum(float v) {
#pragma unroll
    for (int o = 16; o > 0; o >>= 1) v += __shfl_xor_sync(0xffffffffu, v, o);
    return v;
}
__device__ __forceinline__ float warpmax(float v) {
#pragma unroll
    for (int o = 16; o > 0; o >>= 1) v = fmaxf(v, __shfl_xor_sync(0xffffffffu, v, o));
    return v;
}
__device__ __forceinline__ float blocksum256(float v) {
    __shared__ float red[8];
    int lane = threadIdx.x & 31, w = threadIdx.x >> 5;
    v = warpsum(v);
    if (lane == 0) red[w] = v;
    __syncthreads();
    float r = (lane < 8) ? red[lane] : 0.f;
    r = warpsum(r);
    __syncthreads();
    return r;
}
__device__ __forceinline__ float tanh_fast(float x) {
    float e = __expf(2.f * x);
    return 1.f - __fdividef(2.f, e + 1.f);
}

// ---------------- LayerNorm rows of 1024 ----------------
__global__ __launch_bounds__(256) void ln_kernel(
    const float* __restrict__ x, const float* __restrict__ g,
    const float* __restrict__ b, float* __restrict__ y)
{
    int row = blockIdx.x, tid = threadIdx.x;
    const float* xr = x + (size_t)row * Dn;
    float v[4]; float s = 0.f;
#pragma unroll
    for (int i = 0; i < 4; i++) { v[i] = xr[tid + 256 * i]; s += v[i]; }
    s = blocksum256(s);
    float mu = s * (1.f / Dn), ss = 0.f;
#pragma unroll
    for (int i = 0; i < 4; i++) { float d = v[i] - mu; ss += d * d; }
    ss = blocksum256(ss);
    float rstd = rsqrtf(ss * (1.f / Dn) + EPSc);
    float* yr = y + (size_t)row * Dn;
#pragma unroll
    for (int i = 0; i < 4; i++) {
        int c = tid + 256 * i;
        yr[c] = (v[i] - mu) * rstd * g[c] + b[c];
    }
}

// ---------------- bf16 tensor-core GEMM, double-buffered ----------------
#define GSTR 136
__device__ __forceinline__ void gemm_core(
    const float* __restrict__ A, const float* __restrict__ B, float* __restrict__ C,
    const float* __restrict__ bias, const float* __restrict__ res,
    const float* __restrict__ gate, int bm, int bn)
{
    const int N = 1024, K = 1024, BK = 16;
    __shared__ unsigned As[2][8][GSTR];
    __shared__ unsigned Bs[2][8][GSTR];
    int t = threadIdx.x;
    int warp = t >> 5, lane = t & 31;
    int wm = warp >> 1, wn = warp & 1;
    int g = lane >> 2, tg = lane & 3;

    float acc[2][8][4];
#pragma unroll
    for (int mt = 0; mt < 2; mt++)
#pragma unroll
        for (int nt = 0; nt < 8; nt++)
#pragma unroll
            for (int r = 0; r < 4; r++) acc[mt][nt][r] = 0.f;

    int r128 = t >> 1, kc = (t & 1) * 8, kp0 = (t & 1) * 4;
    const float* Ab = A + (size_t)(bm + r128) * K + kc;
    const float* Bb = B + (size_t)(bn + r128) * K + kc;
    float4 a0 = *(const float4*)(Ab);
    float4 a1 = *(const float4*)(Ab + 4);
    float4 b0 = *(const float4*)(Bb);
    float4 b1 = *(const float4*)(Bb + 4);

    As[0][kp0+0][r128] = bf2pack(a0.x, a0.y);
    As[0][kp0+1][r128] = bf2pack(a0.z, a0.w);
    As[0][kp0+2][r128] = bf2pack(a1.x, a1.y);
    As[0][kp0+3][r128] = bf2pack(a1.z, a1.w);
    Bs[0][kp0+0][r128] = bf2pack(b0.x, b0.y);
    Bs[0][kp0+1][r128] = bf2pack(b0.z, b0.w);
    Bs[0][kp0+2][r128] = bf2pack(b1.x, b1.y);
    Bs[0][kp0+3][r128] = bf2pack(b1.z, b1.w);
    __syncthreads();

    int cur = 0;
    for (int k0 = 0; k0 < K; k0 += BK) {
        bool more = (k0 + BK < K);
        if (more) {
            a0 = *(const float4*)(Ab + k0 + BK);
            a1 = *(const float4*)(Ab + k0 + BK + 4);
            b0 = *(const float4*)(Bb + k0 + BK);
            b1 = *(const float4*)(Bb + k0 + BK + 4);
        }
        {
            unsigned af[2][4], bf[8][2];
#pragma unroll
            for (int mt = 0; mt < 2; mt++) {
                int mb = wm * 32 + mt * 16 + g;
                af[mt][0] = As[cur][tg  ][mb];
                af[mt][1] = As[cur][tg  ][mb+8];
                af[mt][2] = As[cur][tg+4][mb];
                af[mt][3] = As[cur][tg+4][mb+8];
            }
#pragma unroll
            for (int nt = 0; nt < 8; nt++) {
                int nb = wn * 64 + nt * 8 + g;
                bf[nt][0] = Bs[cur][tg  ][nb];
                bf[nt][1] = Bs[cur][tg+4][nb];
            }
#pragma unroll
            for (int mt = 0; mt < 2; mt++)
#pragma unroll
                for (int nt = 0; nt < 8; nt++)
                    mma_bf16(acc[mt][nt], af[mt], bf[nt]);
        }
        if (more) {
            int nxt = cur ^ 1;
            As[nxt][kp0+0][r128] = bf2pack(a0.x, a0.y);
            As[nxt][kp0+1][r128] = bf2pack(a0.z, a0.w);
            As[nxt][kp0+2][r128] = bf2pack(a1.x, a1.y);
            As[nxt][kp0+3][r128] = bf2pack(a1.z, a1.w);
            Bs[nxt][kp0+0][r128] = bf2pack(b0.x, b0.y);
            Bs[nxt][kp0+1][r128] = bf2pack(b0.z, b0.w);
            Bs[nxt][kp0+2][r128] = bf2pack(b1.x, b1.y);
            Bs[nxt][kp0+3][r128] = bf2pack(b1.z, b1.w);
            __syncthreads();
            cur = nxt;
        }
    }

    float bs2[8][2], gv2[8][2];
#pragma unroll
    for (int nt = 0; nt < 8; nt++) {
        int col = bn + wn * 64 + nt * 8 + tg * 2;
        if (bias) { bs2[nt][0] = bias[col]; bs2[nt][1] = bias[col+1]; }
        else      { bs2[nt][0] = 0.f;       bs2[nt][1] = 0.f; }
        if (gate) { gv2[nt][0] = tanhf(gate[col]); gv2[nt][1] = tanhf(gate[col+1]); }
    }
#pragma unroll
    for (int mt = 0; mt < 2; mt++) {
        int row0 = bm + wm * 32 + mt * 16 + g;
#pragma unroll
        for (int nt = 0; nt < 8; nt++) {
            int col = bn + wn * 64 + nt * 8 + tg * 2;
            float v0 = acc[mt][nt][0] + bs2[nt][0];
            float v1 = acc[mt][nt][1] + bs2[nt][1];
            float v2 = acc[mt][nt][2] + bs2[nt][0];
            float v3 = acc[mt][nt][3] + bs2[nt][1];
            if (gate) {
                float2 r0 = *(const float2*)(res + (size_t)row0 * N + col);
                float2 r1 = *(const float2*)(res + (size_t)(row0+8) * N + col);
                v0 = r0.x + gv2[nt][0] * v0; v1 = r0.y + gv2[nt][1] * v1;
                v2 = r1.x + gv2[nt][0] * v2; v3 = r1.y + gv2[nt][1] * v3;
            } else if (res) {
                float2 r0 = *(const float2*)(res + (size_t)row0 * N + col);
                float2 r1 = *(const float2*)(res + (size_t)(row0+8) * N + col);
                v0 += r0.x; v1 += r0.y; v2 += r1.x; v3 += r1.y;
            }
            *(float2*)(C + (size_t)row0 * N + col)     = make_float2(v0, v1);
            *(float2*)(C + (size_t)(row0+8) * N + col) = make_float2(v2, v3);
        }
    }
}

__global__ __launch_bounds__(256, 2) void gemm_nt_kernel(
    const float* __restrict__ A, const float* __restrict__ B, float* __restrict__ C,
    const float* __restrict__ bias, const float* __restrict__ res,
    const float* __restrict__ gate)
{
    gemm_core(A, B, C, bias, res, gate, blockIdx.y * 128, blockIdx.x * 128);
}

__global__ __launch_bounds__(256, 2) void gemm3_nt_kernel(
    const float* __restrict__ A,
    const float* __restrict__ B0, const float* __restrict__ B1, const float* __restrict__ B2,
    float* __restrict__ C0, float* __restrict__ C1, float* __restrict__ C2,
    const float* __restrict__ b0, const float* __restrict__ b1, const float* __restrict__ b2)
{
    const float* B; float* C; const float* bias;
    if (blockIdx.z == 0)      { B = B0; C = C0; bias = b0; }
    else if (blockIdx.z == 1) { B = B1; C = C1; bias = b1; }
    else                      { B = B2; C = C2; bias = b2; }
    gemm_core(A, B, C, bias, nullptr, nullptr, blockIdx.y * 128, blockIdx.x * 128);
}

// ---------------- Flash attention: bf16 mma ----------------
#define ATS 68
#define APS 68
#define ASS 68
#define ATT_SMEM ((5*64*ATS + 192) * 4)

__global__ __launch_bounds__(256) void attn_flash_kernel(
    const float* __restrict__ q, const float* __restrict__ k,
    const float* __restrict__ v, float* __restrict__ o)
{
    extern __shared__ float sm[];
    float* Qs = sm;                 // [e][ATS] transposed
    float* Ks = Qs + 64 * ATS;      // [e][ATS] transposed
    float* Vs = Ks + 64 * ATS;      // [j][ATS]
    float* Ps = Vs + 64 * ATS;      // [j][APS] transposed
    float* Ss = Ps + 64 * APS;      // [i][ASS]
    float* smm  = Ss + 64 * ASS;
    float* sml  = smm + 64;
    float* scor = sml + 64;

    int qt = blockIdx.x, bh = blockIdx.y;
    int b = bh >> 4, h = bh & 15;
    int tid = threadIdx.x, warp = tid >> 5, lane = tid & 31;
    int wm = warp >> 1, wn = warp & 1;
    int mi = wm * 16, ng = wn * 32;
    int g = lane >> 2, tg = lane & 3;
    size_t base = ((size_t)b * Sn) * Dn + h * HDn;

    for (int idx = tid; idx < 4096; idx += 256) {
        int r = idx >> 6, e = idx & 63;
        Qs[e * ATS + r] = q[base + (size_t)(qt * 64 + r) * Dn + e] * 0.125f;
    }
    if (tid < 64) { smm[tid] = -1e30f; sml[tid] = 0.f; }
    float co[4][4];
#pragma unroll
    for (int nt = 0; nt < 4; nt++)
#pragma unroll
        for (int r = 0; r < 4; r++) co[nt][r] = 0.f;
    __syncthreads();

    for (int kt = 0; kt <= qt; kt++) {
        for (int idx = tid; idx < 4096; idx += 256) {
            int r = idx >> 6, e = idx & 63;
            size_t gg = base + (size_t)(kt * 64 + r) * Dn + e;
            Ks[e * ATS + r] = k[gg];
            Vs[r * ATS + e] = v[gg];
        }
        __syncthreads();

        // S = Q K^T (bf16 mma, k pairs along e)
        float c[4][4];
#pragma unroll
        for (int nt = 0; nt < 4; nt++)
#pragma unroll
            for (int r = 0; r < 4; r++) c[nt][r] = 0.f;
#pragma unroll
        for (int kb = 0; kb < 64; kb += 16) {
            int k0 = kb + 2 * tg;
            unsigned a[4];
            a[0] = bf2pack(Qs[k0*ATS + mi+g],       Qs[(k0+1)*ATS + mi+g]);
            a[1] = bf2pack(Qs[k0*ATS + mi+g+8],     Qs[(k0+1)*ATS + mi+g+8]);
            a[2] = bf2pack(Qs[(k0+8)*ATS + mi+g],   Qs[(k0+9)*ATS + mi+g]);
            a[3] = bf2pack(Qs[(k0+8)*ATS + mi+g+8], Qs[(k0+9)*ATS + mi+g+8]);
#pragma unroll
            for (int nt = 0; nt < 4; nt++) {
                int col = ng + nt * 8 + g;
                unsigned bb[2];
                bb[0] = bf2pack(Ks[k0*ATS + col],     Ks[(k0+1)*ATS + col]);
                bb[1] = bf2pack(Ks[(k0+8)*ATS + col], Ks[(k0+9)*ATS + col]);
                mma_bf16(c[nt], a, bb);
            }
        }
        bool diag = (kt == qt);
        int r0 = mi + g, r1 = mi + g + 8;
#pragma unroll
        for (int nt = 0; nt < 4; nt++) {
            int col = ng + nt * 8 + tg * 2;
            if (diag) {
                if (col   > r0) c[nt][0] = -1e30f;
                if (col+1 > r0) c[nt][1] = -1e30f;
                if (col   > r1) c[nt][2] = -1e30f;
                if (col+1 > r1) c[nt][3] = -1e30f;
            }
            Ss[r0*ASS + col]   = c[nt][0];
            Ss[r0*ASS + col+1] = c[nt][1];
            Ss[r1*ASS + col]   = c[nt][2];
            Ss[r1*ASS + col+1] = c[nt][3];
        }
        __syncthreads();

        // online softmax rows (warp per 8 rows), P^T in float
        for (int i = warp; i < 64; i += 8) {
            float s0 = Ss[i*ASS + lane], s1 = Ss[i*ASS + lane + 32];
            float mx = warpmax(fmaxf(s0, s1));
            float nm = fmaxf(smm[i], mx);
            float corr = __expf(smm[i] - nm);
            float p0 = __expf(s0 - nm), p1 = __expf(s1 - nm);
            float ps = warpsum(p0 + p1);
            if (lane == 0) { sml[i] = sml[i] * corr + ps; smm[i] = nm; scor[i] = corr; }
            Ps[lane*APS + i]      = p0;
            Ps[(lane+32)*APS + i] = p1;
        }
        __syncthreads();

        // O = O*corr + P V (bf16 mma, k pairs along j)
        float cr0 = scor[r0], cr1 = scor[r1];
#pragma unroll
        for (int nt = 0; nt < 4; nt++) {
            co[nt][0] *= cr0; co[nt][1] *= cr0;
            co[nt][2] *= cr1; co[nt][3] *= cr1;
        }
#pragma unroll
        for (int kb = 0; kb < 64; kb += 16) {
            int k0 = kb + 2 * tg;
            unsigned a[4];
            a[0] = bf2pack(Ps[k0*APS + mi+g],       Ps[(k0+1)*APS + mi+g]);
            a[1] = bf2pack(Ps[k0*APS + mi+g+8],     Ps[(k0+1)*APS + mi+g+8]);
            a[2] = bf2pack(Ps[(k0+8)*APS + mi+g],   Ps[(k0+9)*APS + mi+g]);
            a[3] = bf2pack(Ps[(k0+8)*APS + mi+g+8], Ps[(k0+9)*APS + mi+g+8]);
#pragma unroll
            for (int nt = 0; nt < 4; nt++) {
                int col = ng + nt * 8 + g;
                unsigned bb[2];
                bb[0] = bf2pack(Vs[k0*ATS + col],     Vs[(k0+1)*ATS + col]);
                bb[1] = bf2pack(Vs[(k0+8)*ATS + col], Vs[(k0+9)*ATS + col]);
                mma_bf16(co[nt], a, bb);
            }
        }
        __syncthreads();
    }

    int r0 = mi + g, r1 = mi + g + 8;
    float inv0 = __fdividef(1.f, sml[r0]);
    float inv1 = __fdividef(1.f, sml[r1]);
#pragma unroll
    for (int nt = 0; nt < 4; nt++) {
        int col = ng + nt * 8 + tg * 2;
        *(float2*)(o + base + (size_t)(qt*64 + r0) * Dn + col) =
            make_float2(co[nt][0]*inv0, co[nt][1]*inv0);
        *(float2*)(o + base + (size_t)(qt*64 + r1) * Dn + col) =
            make_float2(co[nt][2]*inv1, co[nt][3]*inv1);
    }
}

// ---------------- prep + lr fused ----------------
__global__ __launch_bounds__(256) void prep_kernel(
    float* __restrict__ XQ, float* __restrict__ XK, float* __restrict__ XV,
    const float* __restrict__ nw, const float* __restrict__ nb,
    const float* __restrict__ x1, const float* __restrict__ lrw,
    const float* __restrict__ lrb, float* __restrict__ lro)
{
    int w = (blockIdx.x * blockDim.x + threadIdx.x) >> 5;
    if (w >= Bn * Sn * Hn) return;
    int lane = threadIdx.x & 31;
    int h = w & 15, bs = w >> 4;
    size_t base = (size_t)bs * Dn + h * HDn;
    float q0 = XQ[base + lane], q1 = XQ[base + lane + 32];
    float qi = 1.f / fmaxf(sqrtf(warpsum(q0*q0 + q1*q1)), 1e-12f);
    XQ[base + lane] = q0 * qi; XQ[base + lane + 32] = q1 * qi;
    float k0 = XK[base + lane], k1 = XK[base + lane + 32];
    float ki = 1.f / fmaxf(sqrtf(warpsum(k0*k0 + k1*k1)), 1e-12f);
    k0 *= ki; k1 *= ki;
    XK[base + lane] = k0; XK[base + lane + 32] = k1;
    float v0 = XV[base + lane], v1 = XV[base + lane + 32];
    float mu = warpsum(v0 + v1) * (1.f / 64.f);
    float d0 = v0 - mu, d1 = v1 - mu;
    float var = warpsum(d0*d0 + d1*d1) * (1.f / 64.f);
    float rstd = rsqrtf(var + EPSc);
    XV[base + lane]      = nw[h*64+lane]    * d0 * rstd + nb[h*64+lane]    + k0;
    XV[base + lane + 32] = nw[h*64+lane+32] * d1 * rstd + nb[h*64+lane+32] + k1;

    // fused lr
    int b = bs >> 10, s = bs & (Sn - 1);
    const float* xr = x1 + (size_t)bs * Dn;
    const float* wr = lrw + h * Dn;
    float acc = 0.f;
    for (int c = lane; c < Dn; c += 32) acc += xr[c] * wr[c];
    acc = warpsum(acc);
    if (lane == 0)
        lro[(size_t)(b * Hn + h) * Sn + s] = 1.f / (1.f + __expf(-(acc + lrb[h])));
}

// ---------------- TTT scan: bf16 mma A/B/D/E/F/G/H ------------
#define SV 65
#define PS 68
#define TS 68
#define WS 260
#define SCAN_FLOATS (64*SV + 2*64*PS + 4*64*TS + 16*WS + 64*WS + 256 + 64 + 64)
#define SCAN_SMEM (SCAN_FLOATS * 4)

__global__ __launch_bounds__(512) void ttt_scan_kernel(
    const float* __restrict__ XQ, const float* __restrict__ XK, const float* __restrict__ XV,
    const float* __restrict__ lr,
    const float* __restrict__ W1i, const float* __restrict__ b1i,
    const float* __restrict__ W2i, const float* __restrict__ b2i,
    const float* __restrict__ nw,  const float* __restrict__ nb,
    float* __restrict__ W2TG,
    float* __restrict__ X2G, float* __restrict__ gZ1G, float* __restrict__ X2bG,
    float* __restrict__ outp)
{
    extern __shared__ float sm[];
    float* sxv   = sm;
    float* ssc   = sxv  + 64 * SV;
    float* sgZ2  = ssc  + 64 * PS;
    float* sxqT  = sgZ2 + 64 * PS;
    float* sxkT  = sxqT + 64 * TS;
    float* sscT  = sxkT + 64 * TS;
    float* sgZ2T = sscT + 64 * TS;
    float* sstg  = sgZ2T+ 64 * TS;
    float* sW1   = sstg + 16 * WS;
    float* b1sm  = sW1  + 64 * WS;
    float* b2sm  = b1sm + 256;
    float* seta  = b2sm + 64;

    int bh = blockIdx.x, b = bh >> 4, h = bh & 15;
    int tid = threadIdx.x, w = tid >> 5, l = tid & 31;
    int g = l >> 2, tg = l & 3;
    int ft = tid >> 3, jt = tid & 7;
    int mi = (w & 3) * 16, ng = (w >> 2) * 64;
    int wm3 = w & 3, wn3 = w >> 2;
    int mi3 = wm3 * 16, nb3 = wn3 * 16;
    float* W2Tr = W2TG + (size_t)bh * 16384;
    float* X2r  = X2G  + (size_t)bh * 16384;
    float* gZ1r = gZ1G + (size_t)bh * 16384;
    float* X2br = X2bG + (size_t)bh * 16384;
    const float* nwh = nw + h * 64;
    const float* nbh = nb + h * 64;

    for (int idx = tid; idx < 16384; idx += 512) {
        int e = idx >> 8, f = idx & 255;
        sW1[e * WS + f] = W1i[(size_t)h * 16384 + idx];
        W2Tr[idx] = W2i[(size_t)h * 16384 + f * 64 + e];
    }
    if (tid < 256) b1sm[tid] = b1i[h * 256 + tid];
    if (tid < 64)  b2sm[tid] = b2i[h * 64 + tid];
    __syncthreads();

    for (int n = 0; n < NCn; n++) {
        size_t tokbase = (size_t)b * Sn + n * Cn;
        for (int idx = tid; idx < 4096; idx += 512) {
            int i = idx >> 6, e = idx & 63;
            size_t gg = (tokbase + i) * Dn + h * 64 + e;
            sxqT[e * TS + i] = XQ[gg];
            sxkT[e * TS + i] = XK[gg];
            sxv [i * SV + e] = XV[gg];
        }
        if (tid < 64) seta[tid] = lr[(size_t)bh * Sn + n * 64 + tid] * (1.f / 64.f);
        __syncthreads();

        // ---- A (bf16 mma, 2 passes): Z1=xk@W1+b1 ; Z1q=xq@W1+b1
#pragma unroll
        for (int p = 0; p < 2; p++) {
            const float* T = p ? sxqT : sxkT;
            float c[8][4];
#pragma unroll
            for (int nt = 0; nt < 8; nt++) {
                int col = ng + nt * 8 + tg * 2;
                c[nt][0] = b1sm[col];   c[nt][1] = b1sm[col+1];
                c[nt][2] = b1sm[col];   c[nt][3] = b1sm[col+1];
            }
#pragma unroll
            for (int kb = 0; kb < 64; kb += 16) {
                int k0 = kb + 2 * tg;
                unsigned a[4];
                a[0] = bf2pack(T[k0*TS + mi+g],       T[(k0+1)*TS + mi+g]);
                a[1] = bf2pack(T[k0*TS + mi+g+8],     T[(k0+1)*TS + mi+g+8]);
                a[2] = bf2pack(T[(k0+8)*TS + mi+g],   T[(k0+9)*TS + mi+g]);
                a[3] = bf2pack(T[(k0+8)*TS + mi+g+8], T[(k0+9)*TS + mi+g+8]);
#pragma unroll
                for (int nt = 0; nt < 8; nt++) {
                    int col = ng + nt * 8 + g;
                    unsigned bb[2];
                    bb[0] = bf2pack(sW1[k0*WS + col],     sW1[(k0+1)*WS + col]);
                    bb[1] = bf2pack(sW1[(k0+8)*WS + col], sW1[(k0+9)*WS + col]);
                    mma_bf16(c[nt], a, bb);
                }
            }
#pragma unroll
            for (int nt = 0; nt < 8; nt++) {
                int col = ng + nt * 8 + tg * 2;
                int r0 = mi + g;
                if (p == 0) {
                    float x2o[4], gbo[4];
#pragma unroll
                    for (int r = 0; r < 4; r++) {
                        float z = c[nt][r];
                        float t = tanh_fast(0.79788456f * (z + 0.044715f * z * z * z));
                        x2o[r] = 0.5f * z * (1.f + t);
                        gbo[r] = 0.5f * z * (1.f - t * t) * (0.79788456f + 0.1070322243f * z * z)
                               + 0.5f * (1.f + t);
                    }
                    *(float2*)(X2r  + r0*256 + col)     = make_float2(x2o[0], x2o[1]);
                    *(float2*)(X2r  + (r0+8)*256 + col) = make_float2(x2o[2], x2o[3]);
                    *(float2*)(gZ1r + r0*256 + col)     = make_float2(gbo[0], gbo[1]);
                    *(float2*)(gZ1r + (r0+8)*256 + col) = make_float2(gbo[2], gbo[3]);
                } else {
                    *(float2*)(X2br + r0*256 + col)     = make_float2(c[nt][0], c[nt][1]);
                    *(float2*)(X2br + (r0+8)*256 + col) = make_float2(c[nt][2], c[nt][3]);
                }
            }
        }
        __syncthreads();

        // ---- B (bf16 mma): Z2 = X2@W2 + b2 -> ssc
        {
            float c[2][4];
#pragma unroll
            for (int nt = 0; nt < 2; nt++) {
                int col = nb3 + nt * 8 + tg * 2;
                c[nt][0] = b2sm[col]; c[nt][1] = b2sm[col+1];
                c[nt][2] = b2sm[col]; c[nt][3] = b2sm[col+1];
            }
#pragma unroll 4
            for (int kb = 0; kb < 256; kb += 16) {
                const float* xa = X2r + (mi3+g)*256 + kb + 2*tg;
                float2 v0 = *(const float2*)(xa);
                float2 v1 = *(const float2*)(xa + 2048);
                float2 v2 = *(const float2*)(xa + 8);
                float2 v3 = *(const float2*)(xa + 2056);
                unsigned a[4] = { bf2pack(v0.x,v0.y), bf2pack(v1.x,v1.y),
                                  bf2pack(v2.x,v2.y), bf2pack(v3.x,v3.y) };
#pragma unroll
                for (int nt = 0; nt < 2; nt++) {
                    int col = nb3 + nt * 8 + g;
                    float2 w0 = *(const float2*)(W2Tr + col*256 + kb + 2*tg);
                    float2 w1 = *(const float2*)(W2Tr + col*256 + kb + 8 + 2*tg);
                    unsigned bb[2] = { bf2pack(w0.x,w0.y), bf2pack(w1.x,w1.y) };
                    mma_bf16(c[nt], a, bb);
                }
            }
#pragma unroll
            for (int nt = 0; nt < 2; nt++) {
                int col = nb3 + nt * 8 + tg * 2;
                int r0 = mi3 + g;
                ssc[r0*PS + col]       = c[nt][0];
                ssc[r0*PS + col+1]     = c[nt][1];
                ssc[(r0+8)*PS + col]   = c[nt][2];
                ssc[(r0+8)*PS + col+1] = c[nt][3];
            }
        }
        __syncthreads();

        // ---- C: gZ2 = ln_l2_bwd -> sgZ2 + sgZ2T
        for (int i = w; i < 64; i += 16) {
            float z0 = ssc[i*PS + l], z1 = ssc[i*PS + l + 32];
            float mu = warpsum(z0 + z1) * (1.f/64.f);
            float d0 = z0 - mu, d1 = z1 - mu;
            float var = warpsum(d0*d0 + d1*d1) * (1.f/64.f);
            float rstd = rsqrtf(var + EPSc);
            float xh0 = d0 * rstd, xh1 = d1 * rstd;
            float g0 = nwh[l], g1 = nwh[l+32];
            float t0 = sxv[i*SV + l]      - sxkT[l*TS + i];
            float t1 = sxv[i*SV + l + 32] - sxkT[(l+32)*TS + i];
            float gh0 = (g0*xh0 + nbh[l]    - t0) * g0;
            float gh1 = (g1*xh1 + nbh[l+32] - t1) * g1;
            float sgh = warpsum(gh0 + gh1);
            float sgx = warpsum(gh0*xh0 + gh1*xh1);
            float cc = rstd * (1.f/64.f);
            float o0 = (64.f*gh0 - sgh - xh0*sgx) * cc;
            float o1 = (64.f*gh1 - sgh - xh1*sgx) * cc;
            sgZ2[i*PS + l]        = o0;
            sgZ2[i*PS + l + 32]   = o1;
            sgZ2T[l*TS + i]       = o0;
            sgZ2T[(l+32)*TS + i]  = o1;
        }
        __syncthreads();

        // ---- D (bf16 mma): gZ1 = (gZ2 @ W2^T) * gb   (16-row staging)
        {
            float c[8][4];
#pragma unroll
            for (int nt = 0; nt < 8; nt++)
#pragma unroll
                for (int r = 0; r < 4; r++) c[nt][r] = 0.f;
#pragma unroll
            for (int kbb = 0; kbb < 64; kbb += 16) {
                __syncthreads();
                for (int idx = tid; idx < 4096; idx += 512) {
                    int rr = idx >> 8, cf = idx & 255;
                    sstg[rr*WS + cf] = W2Tr[(kbb+rr)*256 + cf];
                }
                __syncthreads();
                int k0 = 2 * tg;
                unsigned a[4];
                a[0] = bf2pack(sgZ2T[(kbb+k0)*TS + mi+g],     sgZ2T[(kbb+k0+1)*TS + mi+g]);
                a[1] = bf2pack(sgZ2T[(kbb+k0)*TS + mi+g+8],   sgZ2T[(kbb+k0+1)*TS + mi+g+8]);
                a[2] = bf2pack(sgZ2T[(kbb+k0+8)*TS + mi+g],   sgZ2T[(kbb+k0+9)*TS + mi+g]);
                a[3] = bf2pack(sgZ2T[(kbb+k0+8)*TS + mi+g+8], sgZ2T[(kbb+k0+9)*TS + mi+g+8]);
#pragma unroll
                for (int nt = 0; nt < 8; nt++) {
                    int col = ng + nt * 8 + g;
                    unsigned bb[2];
                    bb[0] = bf2pack(sstg[k0*WS + col],     sstg[(k0+1)*WS + col]);
                    bb[1] = bf2pack(sstg[(k0+8)*WS + col], sstg[(k0+9)*WS + col]);
                    mma_bf16(c[nt], a, bb);
                }
            }
#pragma unroll
            for (int nt = 0; nt < 8; nt++) {
                int col = ng + nt * 8 + tg * 2;
                int r0 = mi + g;
                float2 gb0 = *(const float2*)(gZ1r + r0*256 + col);
                float2 gb1 = *(const float2*)(gZ1r + (r0+8)*256 + col);
                *(float2*)(gZ1r + r0*256 + col)     = make_float2(c[nt][0]*gb0.x, c[nt][1]*gb0.y);
                *(float2*)(gZ1r + (r0+8)*256 + col) = make_float2(c[nt][2]*gb1.x, c[nt][3]*gb1.y);
            }
        }
        __syncthreads();

        // ---- E (bf16 mma): coef1 = -eta[k2]*(tril(xq@xk^T)+1) -> sscT
#pragma unroll
        for (int sub = 0; sub < 2; sub++) {
            int ncol = ((w >> 2) * 2 + sub) * 8;
            float c[4] = {0.f, 0.f, 0.f, 0.f};
#pragma unroll
            for (int kb = 0; kb < 64; kb += 16) {
                int k0 = kb + 2 * tg;
                unsigned a[4], bb[2];
                a[0] = bf2pack(sxqT[k0*TS + mi+g],       sxqT[(k0+1)*TS + mi+g]);
                a[1] = bf2pack(sxqT[k0*TS + mi+g+8],     sxqT[(k0+1)*TS + mi+g+8]);
                a[2] = bf2pack(sxqT[(k0+8)*TS + mi+g],   sxqT[(k0+9)*TS + mi+g]);
                a[3] = bf2pack(sxqT[(k0+8)*TS + mi+g+8], sxqT[(k0+9)*TS + mi+g+8]);
                bb[0] = bf2pack(sxkT[k0*TS + ncol+g],     sxkT[(k0+1)*TS + ncol+g]);
                bb[1] = bf2pack(sxkT[(k0+8)*TS + ncol+g], sxkT[(k0+9)*TS + ncol+g]);
                mma_bf16(c, a, bb);
            }
            int r0 = mi + g, k2 = ncol + tg * 2;
            sscT[k2*TS + r0]       = (k2   <= r0)   ? -seta[k2]  *(c[0]+1.f) : 0.f;
            sscT[(k2+1)*TS + r0]   = (k2+1 <= r0)   ? -seta[k2+1]*(c[1]+1.f) : 0.f;
            sscT[k2*TS + r0+8]     = (k2   <= r0+8) ? -seta[k2]  *(c[2]+1.f) : 0.f;
            sscT[(k2+1)*TS + r0+8] = (k2+1 <= r0+8) ? -seta[k2+1]*(c[3]+1.f) : 0.f;
        }
        __syncthreads();

        // ---- F (bf16 mma): Z1b = Z1q + coef1neg@gZ1 ; X2b = gelu
        {
            float c[8][4];
#pragma unroll
            for (int nt = 0; nt < 8; nt++) {
                int col = ng + nt * 8 + tg * 2;
                int r0 = mi + g;
                float2 q0 = *(const float2*)(X2br + r0*256 + col);
                float2 q1 = *(const float2*)(X2br + (r0+8)*256 + col);
                c[nt][0] = q0.x; c[nt][1] = q0.y; c[nt][2] = q1.x; c[nt][3] = q1.y;
            }
#pragma unroll
            for (int kbb = 0; kbb < 64; kbb += 16) {
                __syncthreads();
                for (int idx = tid; idx < 4096; idx += 512) {
                    int rr = idx >> 8, cf = idx & 255;
                    sstg[rr*WS + cf] = gZ1r[(kbb+rr)*256 + cf];
                }
                __syncthreads();
                int k0 = 2 * tg;
                unsigned a[4];
                a[0] = bf2pack(sscT[(kbb+k0)*TS + mi+g],     sscT[(kbb+k0+1)*TS + mi+g]);
                a[1] = bf2pack(sscT[(kbb+k0)*TS + mi+g+8],   sscT[(kbb+k0+1)*TS + mi+g+8]);
                a[2] = bf2pack(sscT[(kbb+k0+8)*TS + mi+g],   sscT[(kbb+k0+9)*TS + mi+g]);
                a[3] = bf2pack(sscT[(kbb+k0+8)*TS + mi+g+8], sscT[(kbb+k0+9)*TS + mi+g+8]);
#pragma unroll
                for (int nt = 0; nt < 8; nt++) {
                    int col = ng + nt * 8 + g;
                    unsigned bb[2];
                    bb[0] = bf2pack(sstg[k0*WS + col],     sstg[(k0+1)*WS + col]);
                    bb[1] = bf2pack(sstg[(k0+8)*WS + col], sstg[(k0+9)*WS + col]);
                    mma_bf16(c[nt], a, bb);
                }
            }
#pragma unroll
            for (int nt = 0; nt < 8; nt++) {
                int col = ng + nt * 8 + tg * 2;
                int r0 = mi + g;
                float xo[4];
#pragma unroll
                for (int r = 0; r < 4; r++) {
                    float z = c[nt][r];
                    float t = tanh_fast(0.79788456f * (z + 0.044715f * z * z * z));
                    xo[r] = 0.5f * z * (1.f + t);
                }
                *(float2*)(X2br + r0*256 + col)     = make_float2(xo[0], xo[1]);
                *(float2*)(X2br + (r0+8)*256 + col) = make_float2(xo[2], xo[3]);
            }
        }
        __syncthreads();

        // ---- G (bf16 mma): coef2neg -> ssc [i][j]
        {
            float c[2][4] = {{0.f,0.f,0.f,0.f},{0.f,0.f,0.f,0.f}};
            if (nb3 <= mi3) {
#pragma unroll 4
                for (int kb = 0; kb < 256; kb += 16) {
                    const float* xa = X2br + (mi3+g)*256 + kb + 2*tg;
                    float2 v0 = *(const float2*)(xa);
                    float2 v1 = *(const float2*)(xa + 2048);
                    float2 v2 = *(const float2*)(xa + 8);
                    float2 v3 = *(const float2*)(xa + 2056);
                    unsigned a[4] = { bf2pack(v0.x,v0.y), bf2pack(v1.x,v1.y),
                                      bf2pack(v2.x,v2.y), bf2pack(v3.x,v3.y) };
#pragma unroll
                    for (int nt = 0; nt < 2; nt++) {
                        int col = nb3 + nt * 8 + g;
                        const float* xb = X2r + col*256 + kb + 2*tg;
                        float2 w0 = *(const float2*)(xb);
                        float2 w1 = *(const float2*)(xb + 8);
                        unsigned bb[2] = { bf2pack(w0.x,w0.y), bf2pack(w1.x,w1.y) };
                        mma_bf16(c[nt], a, bb);
                    }
                }
            }
#pragma unroll
            for (int nt = 0; nt < 2; nt++) {
                int col = nb3 + nt * 8 + tg * 2;
                int r0 = mi3 + g, r1 = mi3 + g + 8;
                ssc[r0*PS + col]     = (col   <= r0) ? -seta[col]  *(c[nt][0]+1.f) : 0.f;
                ssc[r0*PS + col+1]   = (col+1 <= r0) ? -seta[col+1]*(c[nt][1]+1.f) : 0.f;
                ssc[r1*PS + col]     = (col   <= r1) ? -seta[col]  *(c[nt][2]+1.f) : 0.f;
                ssc[r1*PS + col+1]   = (col+1 <= r1) ? -seta[col+1]*(c[nt][3]+1.f) : 0.f;
            }
        }
        __syncthreads();

        // ---- H (bf16 mma): Z2b = X2b@W2 + b2 + coef2neg@gZ2 -> sxv
        {
            float c[2][4];
#pragma unroll
            for (int nt = 0; nt < 2; nt++) {
                int col = nb3 + nt * 8 + tg * 2;
                c[nt][0] = b2sm[col]; c[nt][1] = b2sm[col+1];
                c[nt][2] = b2sm[col]; c[nt][3] = b2sm[col+1];
            }
#pragma unroll 4
            for (int kb = 0; kb < 256; kb += 16) {
                const float* xa = X2br + (mi3+g)*256 + kb + 2*tg;
                float2 v0 = *(const float2*)(xa);
                float2 v1 = *(const float2*)(xa + 2048);
                float2 v2 = *(const float2*)(xa + 8);
                float2 v3 = *(const float2*)(xa + 2056);
                unsigned a[4] = { bf2pack(v0.x,v0.y), bf2pack(v1.x,v1.y),
                                  bf2pack(v2.x,v2.y), bf2pack(v3.x,v3.y) };
#pragma unroll
                for (int nt = 0; nt < 2; nt++) {
                    int col = nb3 + nt * 8 + g;
                    float2 w0 = *(const float2*)(W2Tr + col*256 + kb + 2*tg);
                    float2 w1 = *(const float2*)(W2Tr + col*256 + kb + 8 + 2*tg);
                    unsigned bb[2] = { bf2pack(w0.x,w0.y), bf2pack(w1.x,w1.y) };
                    mma_bf16(c[nt], a, bb);
                }
            }
#pragma unroll
            for (int kb = 0; kb < 64; kb += 16) {
                int k0 = kb + 2 * tg;
                unsigned a[4];
                a[0] = bf2pack(ssc[(mi3+g)*PS + k0],     ssc[(mi3+g)*PS + k0+1]);
                a[1] = bf2pack(ssc[(mi3+g+8)*PS + k0],   ssc[(mi3+g+8)*PS + k0+1]);
                a[2] = bf2pack(ssc[(mi3+g)*PS + k0+8],   ssc[(mi3+g)*PS + k0+9]);
                a[3] = bf2pack(ssc[(mi3+g+8)*PS + k0+8], ssc[(mi3+g+8)*PS + k0+9]);
#pragma unroll
                for (int nt = 0; nt < 2; nt++) {
                    int col = nb3 + nt * 8 + g;
                    unsigned bb[2];
                    bb[0] = bf2pack(sgZ2T[col*TS + k0],   sgZ2T[col*TS + k0+1]);
                    bb[1] = bf2pack(sgZ2T[col*TS + k0+8], sgZ2T[col*TS + k0+9]);
                    mma_bf16(c[nt], a, bb);
                }
            }
#pragma unroll
            for (int nt = 0; nt < 2; nt++) {
                int col = nb3 + nt * 8 + tg * 2;
                int r0 = mi3 + g;
                sxv[r0*SV + col]       = c[nt][0];
                sxv[r0*SV + col+1]     = c[nt][1];
                sxv[(r0+8)*SV + col]   = c[nt][2];
                sxv[(r0+8)*SV + col+1] = c[nt][3];
            }
        }
        __syncthreads();

        // ---- I: out = xq + LN(Z2b)
        for (int i = w; i < 64; i += 16) {
            float z0 = sxv[i*SV + l], z1 = sxv[i*SV + l + 32];
            float mu = warpsum(z0 + z1) * (1.f/64.f);
            float d0 = z0 - mu, d1 = z1 - mu;
            float var = warpsum(d0*d0 + d1*d1) * (1.f/64.f);
            float rstd = rsqrtf(var + EPSc);
            size_t gg = (tokbase + i) * Dn + h * 64;
            outp[gg + l]      = sxqT[l*TS + i]      + nwh[l]    * d0 * rstd + nbh[l];
            outp[gg + l + 32] = sxqT[(l+32)*TS + i] + nwh[l+32] * d1 * rstd + nbh[l+32];
        }

        // ---- J1: W1 -= (eta*xk)^T @ gZ1  (sW1 smem)
        {
            u64 acc2[4][4];
#pragma unroll
            for (int u = 0; u < 4; u++)
#pragma unroll
                for (int p = 0; p < 4; p++) acc2[u][p] = 0ULL;
#pragma unroll 4
            for (int i = 0; i < 64; i++) {
                float et = seta[i];
                float4 g0 = *(const float4*)(gZ1r + i*256 + l*8);
                float4 g1 = *(const float4*)(gZ1r + i*256 + l*8 + 4);
                u64 gv2[4];
                f4tou2(g0, gv2[0], gv2[1]); f4tou2(g1, gv2[2], gv2[3]);
#pragma unroll
                for (int u = 0; u < 4; u++) {
                    float a = et * sxkT[(w*4+u)*TS + i];
                    u64 a2 = f2pack(a, a);
#pragma unroll
                    for (int p = 0; p < 4; p++) acc2[u][p] = ffma2(a2, gv2[p], acc2[u][p]);
                }
            }
#pragma unroll
            for (int u = 0; u < 4; u++) {
                int e = w * 4 + u;
                float av[8];
#pragma unroll
                for (int p = 0; p < 4; p++) f2unpack(acc2[u][p], av[2*p], av[2*p+1]);
                float4* wp = (float4*)(sW1 + e*WS + l*8);
                float4 o0 = wp[0], o1 = wp[1];
                wp[0] = make_float4(o0.x-av[0], o0.y-av[1], o0.z-av[2], o0.w-av[3]);
                wp[1] = make_float4(o1.x-av[4], o1.y-av[5], o1.z-av[6], o1.w-av[7]);
            }
        }
        // J2: b1
        if (tid < 256) {
            float acc = 0.f;
#pragma unroll 8
            for (int i = 0; i < 64; i++) acc += seta[i] * gZ1r[i*256 + tid];
            b1sm[tid] -= acc;
        }
        // J3: W2T (global)
        {
            u64 acc2[4][4];
#pragma unroll
            for (int u = 0; u < 4; u++)
#pragma unroll
                for (int p = 0; p < 4; p++) acc2[u][p] = 0ULL;
#pragma unroll 4
            for (int i = 0; i < 64; i++) {
                float et = seta[i];
                float4 x0 = *(const float4*)(X2r + i*256 + ft*4);
                float4 gv0 = *(const float4*)(sgZ2 + i*PS + jt*8);
                float4 gv1 = *(const float4*)(sgZ2 + i*PS + jt*8 + 4);
                u64 gv2[4];
                f4tou2(gv0, gv2[0], gv2[1]); f4tou2(gv1, gv2[2], gv2[3]);
                float a[4] = {et*x0.x, et*x0.y, et*x0.z, et*x0.w};
#pragma unroll
                for (int u = 0; u < 4; u++) {
                    u64 a2 = f2pack(a[u], a[u]);
#pragma unroll
                    for (int p = 0; p < 4; p++) acc2[u][p] = ffma2(a2, gv2[p], acc2[u][p]);
                }
            }
#pragma unroll
            for (int u = 0; u < 4; u++) {
                int f = ft * 4 + u;
                float av[8];
#pragma unroll
                for (int p = 0; p < 4; p++) f2unpack(acc2[u][p], av[2*p], av[2*p+1]);
#pragma unroll
                for (int v = 0; v < 8; v++)
                    W2Tr[(jt*8+v)*256 + f] -= av[v];
            }
        }
        // J4: b2
        if (tid < 64) {
            float acc = 0.f;
#pragma unroll 8
            for (int i = 0; i < 64; i++) acc += seta[i] * sgZ2[i*PS + tid];
            b2sm[tid] -= acc;
        }
        __syncthreads();
    }
}

// ---------------- Launch ----------------
extern "C" void kernel_launch(void* const* d_in, const int* in_sizes, int n_in,
                              void* d_out, int out_size)
{
    const float* x       = (const float*)d_in[0];
    const float* ln1_w   = (const float*)d_in[1];
    const float* ln1_b   = (const float*)d_in[2];
    const float* attn_wq = (const float*)d_in[3];
    const float* attn_wk = (const float*)d_in[4];
    const float* attn_wv = (const float*)d_in[5];
    const float* attn_wo = (const float*)d_in[6];
    const float* wq_w    = (const float*)d_in[7];
    const float* wq_b    = (const float*)d_in[8];
    const float* wk_w    = (const float*)d_in[9];
    const float* wk_b    = (const float*)d_in[10];
    const float* wv_w    = (const float*)d_in[11];
    const float* wv_b    = (const float*)d_in[12];
    const float* wo_w    = (const float*)d_in[13];
    const float* wo_b    = (const float*)d_in[14];
    const float* W1      = (const float*)d_in[15];
    const float* b1      = (const float*)d_in[16];
    const float* W2      = (const float*)d_in[17];
    const float* b2      = (const float*)d_in[18];
    const float* ttt_nw  = (const float*)d_in[19];
    const float* ttt_nb  = (const float*)d_in[20];
    const float* lr_w    = (const float*)d_in[21];
    const float* lr_b    = (const float*)d_in[22];
    const float* pn_w    = (const float*)d_in[23];
    const float* pn_b    = (const float*)d_in[24];
    const float* gate_a  = (const float*)d_in[25];
    float* out = (float*)d_out;

    float *p_h,*p_q,*p_k,*p_v,*p_o,*p_x1,*p_lr,*p_W2T,*p_X2,*p_gZ1,*p_X2b;
    cudaGetSymbolAddress((void**)&p_h,  g_h);
    cudaGetSymbolAddress((void**)&p_q,  g_q);
    cudaGetSymbolAddress((void**)&p_k,  g_k);
    cudaGetSymbolAddress((void**)&p_v,  g_v);
    cudaGetSymbolAddress((void**)&p_o,  g_o);
    cudaGetSymbolAddress((void**)&p_x1, g_x1);
    cudaGetSymbolAddress((void**)&p_lr, g_lr);
    cudaGetSymbolAddress((void**)&p_W2T,g_W2Ts);
    cudaGetSymbolAddress((void**)&p_X2, g_X2);
    cudaGetSymbolAddress((void**)&p_gZ1,g_gZ1);
    cudaGetSymbolAddress((void**)&p_X2b,g_X2b);

    cudaFuncSetAttribute(ttt_scan_kernel,   cudaFuncAttributeMaxDynamicSharedMemorySize, SCAN_SMEM);
    cudaFuncSetAttribute(attn_flash_kernel, cudaFuncAttributeMaxDynamicSharedMemorySize, ATT_SMEM);

    const int M = Bn * Sn;
    dim3 ggrid(Dn / 128, M / 128);
    dim3 ggrid3(Dn / 128, M / 128, 3);
    int nwarp_grid = (Bn * Sn * Hn) / 8;

    ln_kernel<<<M, 256>>>(x, ln1_w, ln1_b, p_h);
    gemm3_nt_kernel<<<ggrid3, 256>>>(p_h, attn_wq, attn_wk, attn_wv,
                                     p_q, p_k, p_v, nullptr, nullptr, nullptr);
    attn_flash_kernel<<<dim3(16, 64), 256, ATT_SMEM>>>(p_q, p_k, p_v, p_o);
    gemm_nt_kernel<<<ggrid, 256>>>(p_o, attn_wo, p_x1, nullptr, x, nullptr);
    gemm3_nt_kernel<<<ggrid3, 256>>>(p_x1, wq_w, wk_w, wv_w,
                                     p_q, p_k, p_v, wq_b, wk_b, wv_b);
    prep_kernel<<<nwarp_grid, 256>>>(p_q, p_k, p_v, ttt_nw, ttt_nb,
                                     p_x1, lr_w, lr_b, p_lr);
    ttt_scan_kernel<<<Bn * Hn, 512, SCAN_SMEM>>>(
        p_q, p_k, p_v, p_lr, W1, b1, W2, b2, ttt_nw, ttt_nb,
        p_W2T, p_X2, p_gZ1, p_X2b, p_o);
    ln_kernel<<<M, 256>>>(p_o, pn_w, pn_b, p_h);
    gemm_nt_kernel<<<ggrid, 256>>>(p_h, wo_w, out, wo_b, p_x1, gate_a);
}